// round 1
// baseline (speedup 1.0000x reference)
#include <cuda_runtime.h>
#include <math.h>

// Problem constants
#define HN   16          // num_heads
#define KVH  4           // num_kv_heads
#define HD   128         // head_dim
#define BB   4           // batch
#define TT   2048        // seq len
#define DD   (HN*HD)     // 2048
#define KVD  (KVH*HD)    // 512
#define NTOK (BB*TT)     // 8192
#define RMS_EPS 1.1920928955078125e-07f

// ---------------- scratch (device globals: allocation-free) ----------------
__device__ float g_tmp[(size_t)NTOK * DD];        // raw GEMM output (reused Q/K/V)
__device__ float g_q[(size_t)BB * HN  * TT * HD]; // [B][H][T][HD]
__device__ float g_k[(size_t)BB * KVH * TT * HD]; // [B][KVH][T][HD]
__device__ float g_v[(size_t)BB * KVH * TT * HD]; // [B][KVH][T][HD]
__device__ float g_y[(size_t)NTOK * DD];          // attention out [B*T][D]

// ---------------- GEMM: C[M,N] = A[M,K] * B[N,K]^T (all row-major) ---------
// BM=BN=128, BK=16, 256 threads, 8x8 per thread.
__global__ void __launch_bounds__(256) gemm_nt_kernel(
    const float* __restrict__ A, const float* __restrict__ Bm,
    float* __restrict__ C, int M, int N, int K)
{
    __shared__ float As[16][128];
    __shared__ float Bs[16][128];

    const int tid = threadIdx.x;
    const int m0 = blockIdx.y * 128;
    const int n0 = blockIdx.x * 128;
    const int tr = tid >> 4;   // 0..15
    const int tc = tid & 15;   // 0..15

    float acc[8][8];
#pragma unroll
    for (int i = 0; i < 8; ++i)
#pragma unroll
        for (int j = 0; j < 8; ++j) acc[i][j] = 0.f;

    for (int k0 = 0; k0 < K; k0 += 16) {
        // load A & B tiles, transposed into smem: [BK][BM]
#pragma unroll
        for (int t4 = 0; t4 < 2; ++t4) {
            int idx = tid + t4 * 256;     // float4 index, 512 total
            int row = idx >> 2;           // 0..127
            int c4  = idx & 3;            // 0..3
            float4 v = *(const float4*)&A[(size_t)(m0 + row) * K + k0 + c4 * 4];
            As[c4 * 4 + 0][row] = v.x;
            As[c4 * 4 + 1][row] = v.y;
            As[c4 * 4 + 2][row] = v.z;
            As[c4 * 4 + 3][row] = v.w;
            float4 w = *(const float4*)&Bm[(size_t)(n0 + row) * K + k0 + c4 * 4];
            Bs[c4 * 4 + 0][row] = w.x;
            Bs[c4 * 4 + 1][row] = w.y;
            Bs[c4 * 4 + 2][row] = w.z;
            Bs[c4 * 4 + 3][row] = w.w;
        }
        __syncthreads();
#pragma unroll
        for (int k = 0; k < 16; ++k) {
            float a[8], b[8];
            *(float4*)&a[0] = *(const float4*)&As[k][tr * 8];
            *(float4*)&a[4] = *(const float4*)&As[k][tr * 8 + 4];
            *(float4*)&b[0] = *(const float4*)&Bs[k][tc * 8];
            *(float4*)&b[4] = *(const float4*)&Bs[k][tc * 8 + 4];
#pragma unroll
            for (int i = 0; i < 8; ++i)
#pragma unroll
                for (int j = 0; j < 8; ++j)
                    acc[i][j] = fmaf(a[i], b[j], acc[i][j]);
        }
        __syncthreads();
    }

#pragma unroll
    for (int i = 0; i < 8; ++i) {
        int m = m0 + tr * 8 + i;
#pragma unroll
        for (int j4 = 0; j4 < 2; ++j4) {
            float4 v = make_float4(acc[i][j4 * 4 + 0], acc[i][j4 * 4 + 1],
                                   acc[i][j4 * 4 + 2], acc[i][j4 * 4 + 3]);
            *(float4*)&C[(size_t)m * N + n0 + tc * 8 + j4 * 4] = v;
        }
    }
}

// -------- fused per-(token,head) RMSNorm + RoPE (+ gain * 1/sqrt(HD)) ------
// in : [NTOK][nheads*HD] row-major (raw projection output)
// out: [B][nheads][T][HD]
__global__ void __launch_bounds__(128) normrope_kernel(
    const float* __restrict__ in, float* __restrict__ out,
    const float* __restrict__ gain, int nheads, float extra_scale)
{
    const int idx = blockIdx.x;        // token*nheads + h
    const int h = idx % nheads;
    const int token = idx / nheads;
    const int b = token / TT, t = token % TT;
    const int d = threadIdx.x;

    float v = in[(size_t)token * (nheads * HD) + h * HD + d];

    // sum of squares over 128 lanes
    float ss = v * v;
#pragma unroll
    for (int o = 16; o > 0; o >>= 1) ss += __shfl_xor_sync(0xffffffff, ss, o);

    __shared__ float wsum[4];
    __shared__ float sh[HD];
    if ((d & 31) == 0) wsum[d >> 5] = ss;
    __syncthreads();
    float tot = wsum[0] + wsum[1] + wsum[2] + wsum[3];
    float rms = rsqrtf(tot * (1.0f / HD) + RMS_EPS);
    float nv = v * rms;
    sh[d] = nv;
    __syncthreads();
    float partner = (d < 64) ? -sh[d + 64] : sh[d - 64];

    int fi = d & 63;
    float inv_freq = 1.0f / powf(10000.0f, (float)fi * (1.0f / 64.0f));
    float ang = (float)t * inv_freq;
    float s, c;
    sincosf(ang, &s, &c);
    float r = nv * c + partner * s;
    float g = gain ? gain[h] : 1.0f;
    r *= g * extra_scale;

    out[(((size_t)b * nheads + h) * TT + t) * HD + d] = r;
}

// -------- V layout transform: [NTOK][KVD] -> [B][KVH][T][HD] ---------------
__global__ void __launch_bounds__(256) vtrans_kernel(
    const float* __restrict__ in, float* __restrict__ out)
{
    int f4 = blockIdx.x * blockDim.x + threadIdx.x;  // float4 index
    const int total4 = NTOK * KVD / 4;
    if (f4 >= total4) return;
    int dc = f4 & (HD / 4 - 1);
    int rest = f4 / (HD / 4);
    int hk = rest % KVH;
    int token = rest / KVH;
    int b = token / TT, t = token % TT;
    float4 v = ((const float4*)in)[f4];
    ((float4*)out)[(((size_t)b * KVH + hk) * TT + t) * (HD / 4) + dc] = v;
}

// ---------------- causal flash attention (fp32 SIMT) -----------------------
// grid: (32 q-blocks, 16 heads, 4 batches), 256 threads, BM=BN=64.
#define ATT_BM 64
#define ATT_BN 64
#define QT_S 68           // k-major stride for Q/K tiles
#define VS_S 132          // row-major stride for V tile
#define PS_S 65           // score tile stride

#define ATT_SMEM ((2*128*QT_S + ATT_BN*VS_S + ATT_BM*PS_S + 3*ATT_BM) * (int)sizeof(float))

__global__ void __launch_bounds__(256) attn_kernel(
    const float* __restrict__ Q, const float* __restrict__ Kg,
    const float* __restrict__ Vg, float* __restrict__ Y)
{
    extern __shared__ float sm[];
    float* Qt   = sm;                      // [128][QT_S] (k-major)
    float* Kt   = Qt + 128 * QT_S;         // [128][QT_S] (k-major)
    float* Vs   = Kt + 128 * QT_S;         // [64][VS_S]  (row-major)
    float* Ps   = Vs + ATT_BN * VS_S;      // [64][PS_S]
    float* mrow = Ps + ATT_BM * PS_S;      // [64]
    float* lrow = mrow + ATT_BM;           // [64]
    float* arow = lrow + ATT_BM;           // [64]

    const int tid = threadIdx.x;
    const int qb = 31 - blockIdx.x;        // heavy blocks first
    const int h  = blockIdx.y;
    const int b  = blockIdx.z;
    const int hk = h / (HN / KVH);

    const float* Qp = Q  + ((((size_t)b * HN  + h ) * TT) + (size_t)qb * ATT_BM) * HD;
    const float* Kp = Kg + (((size_t)b * KVH + hk) * TT) * HD;
    const float* Vp = Vg + (((size_t)b * KVH + hk) * TT) * HD;

    // load Q tile transposed: Qt[k][m]
#pragma unroll
    for (int it = 0; it < 8; ++it) {
        int f4 = tid + it * 256;           // 2048 float4
        int row = f4 >> 5;                 // 0..63
        int c4 = f4 & 31;                  // 0..31
        float4 v = *(const float4*)&Qp[(size_t)row * HD + c4 * 4];
        Qt[(c4 * 4 + 0) * QT_S + row] = v.x;
        Qt[(c4 * 4 + 1) * QT_S + row] = v.y;
        Qt[(c4 * 4 + 2) * QT_S + row] = v.z;
        Qt[(c4 * 4 + 3) * QT_S + row] = v.w;
    }
    if (tid < ATT_BM) { mrow[tid] = -1e30f; lrow[tid] = 0.f; }

    const int ty = tid >> 4;   // 0..15
    const int tx = tid & 15;   // 0..15

    float o[4][8];
#pragma unroll
    for (int i = 0; i < 4; ++i)
#pragma unroll
        for (int c = 0; c < 8; ++c) o[i][c] = 0.f;

    const int nkb = qb + 1;
    for (int kb = 0; kb < nkb; ++kb) {
        __syncthreads();  // protect smem tiles from previous-iteration readers
        // load K (transposed) and V (row-major)
#pragma unroll
        for (int it = 0; it < 8; ++it) {
            int f4 = tid + it * 256;
            int row = f4 >> 5;
            int c4 = f4 & 31;
            float4 v = *(const float4*)&Kp[((size_t)kb * ATT_BN + row) * HD + c4 * 4];
            Kt[(c4 * 4 + 0) * QT_S + row] = v.x;
            Kt[(c4 * 4 + 1) * QT_S + row] = v.y;
            Kt[(c4 * 4 + 2) * QT_S + row] = v.z;
            Kt[(c4 * 4 + 3) * QT_S + row] = v.w;
            float4 w = *(const float4*)&Vp[((size_t)kb * ATT_BN + row) * HD + c4 * 4];
            *(float4*)&Vs[row * VS_S + c4 * 4] = w;
        }
        __syncthreads();

        // S = Q K^T : thread computes rows 4ty+i, cols 4tx+j
        float s[4][4];
#pragma unroll
        for (int i = 0; i < 4; ++i)
#pragma unroll
            for (int j = 0; j < 4; ++j) s[i][j] = 0.f;

#pragma unroll 4
        for (int k = 0; k < HD; ++k) {
            float4 aq = *(const float4*)&Qt[k * QT_S + 4 * ty];
            float4 bk = *(const float4*)&Kt[k * QT_S + 4 * tx];
            float a[4] = {aq.x, aq.y, aq.z, aq.w};
            float bb2[4] = {bk.x, bk.y, bk.z, bk.w};
#pragma unroll
            for (int i = 0; i < 4; ++i)
#pragma unroll
                for (int j = 0; j < 4; ++j)
                    s[i][j] = fmaf(a[i], bb2[j], s[i][j]);
        }

        const bool diag = (kb == qb);
#pragma unroll
        for (int i = 0; i < 4; ++i)
#pragma unroll
            for (int j = 0; j < 4; ++j) {
                int r = 4 * ty + i, c = 4 * tx + j;
                float val = s[i][j];
                if (diag && c > r) val = -1e30f;
                Ps[r * PS_S + c] = val;
            }
        __syncthreads();

        // online softmax per row (64 row threads)
        if (tid < ATT_BM) {
            const int r = tid;
            float m_old = mrow[r];
            float mmax = m_old;
#pragma unroll 8
            for (int j = 0; j < ATT_BN; ++j) mmax = fmaxf(mmax, Ps[r * PS_S + j]);
            float alpha = expf(m_old - mmax);
            float lsum = 0.f;
#pragma unroll 4
            for (int j = 0; j < ATT_BN; ++j) {
                float p = expf(Ps[r * PS_S + j] - mmax);
                Ps[r * PS_S + j] = p;
                lsum += p;
            }
            mrow[r] = mmax;
            lrow[r] = lrow[r] * alpha + lsum;
            arow[r] = alpha;
        }
        __syncthreads();

        // O = O*alpha + P @ V : thread rows 4ty+i, cols tx*8..tx*8+7
#pragma unroll
        for (int i = 0; i < 4; ++i) {
            float al = arow[4 * ty + i];
#pragma unroll
            for (int c = 0; c < 8; ++c) o[i][c] *= al;
        }
#pragma unroll 2
        for (int j = 0; j < ATT_BN; ++j) {
            float p0 = Ps[(4 * ty + 0) * PS_S + j];
            float p1 = Ps[(4 * ty + 1) * PS_S + j];
            float p2 = Ps[(4 * ty + 2) * PS_S + j];
            float p3 = Ps[(4 * ty + 3) * PS_S + j];
            float4 v0 = *(const float4*)&Vs[j * VS_S + tx * 8];
            float4 v1 = *(const float4*)&Vs[j * VS_S + tx * 8 + 4];
            float vv[8] = {v0.x, v0.y, v0.z, v0.w, v1.x, v1.y, v1.z, v1.w};
#pragma unroll
            for (int c = 0; c < 8; ++c) {
                o[0][c] = fmaf(p0, vv[c], o[0][c]);
                o[1][c] = fmaf(p1, vv[c], o[1][c]);
                o[2][c] = fmaf(p2, vv[c], o[2][c]);
                o[3][c] = fmaf(p3, vv[c], o[3][c]);
            }
        }
    }

    // epilogue: divide by l, write to Y[b,t,h*HD+c]
#pragma unroll
    for (int i = 0; i < 4; ++i) {
        int r = 4 * ty + i;
        float inv_l = 1.0f / lrow[r];
        int trow = qb * ATT_BM + r;
        size_t off = ((size_t)(b * TT + trow)) * DD + h * HD + tx * 8;
        float4 w0 = make_float4(o[i][0] * inv_l, o[i][1] * inv_l,
                                o[i][2] * inv_l, o[i][3] * inv_l);
        float4 w1 = make_float4(o[i][4] * inv_l, o[i][5] * inv_l,
                                o[i][6] * inv_l, o[i][7] * inv_l);
        *(float4*)&Y[off]     = w0;
        *(float4*)&Y[off + 4] = w1;
    }
}

// ---------------------------- launch ---------------------------------------
extern "C" void kernel_launch(void* const* d_in, const int* in_sizes, int n_in,
                              void* d_out, int out_size)
{
    const float* x   = (const float*)d_in[0];
    const float* Wq  = (const float*)d_in[1];
    const float* Wk  = (const float*)d_in[2];
    const float* Wv  = (const float*)d_in[3];
    const float* Wp  = (const float*)d_in[4];
    const float* qg  = (const float*)d_in[5];
    float* out = (float*)d_out;

    float *tmp, *q, *k, *v, *y;
    cudaGetSymbolAddress((void**)&tmp, g_tmp);
    cudaGetSymbolAddress((void**)&q,   g_q);
    cudaGetSymbolAddress((void**)&k,   g_k);
    cudaGetSymbolAddress((void**)&v,   g_v);
    cudaGetSymbolAddress((void**)&y,   g_y);

    cudaFuncSetAttribute(attn_kernel, cudaFuncAttributeMaxDynamicSharedMemorySize,
                         ATT_SMEM);

    const float qscale = 1.0f / sqrtf((float)HD);

    // Q projection + norm/rope/gain
    gemm_nt_kernel<<<dim3(DD / 128, NTOK / 128), 256>>>(x, Wq, tmp, NTOK, DD, DD);
    normrope_kernel<<<NTOK * HN, 128>>>(tmp, q, qg, HN, qscale);

    // K projection + norm/rope
    gemm_nt_kernel<<<dim3(KVD / 128, NTOK / 128), 256>>>(x, Wk, tmp, NTOK, KVD, DD);
    normrope_kernel<<<NTOK * KVH, 128>>>(tmp, k, nullptr, KVH, 1.0f);

    // V projection + layout transform
    gemm_nt_kernel<<<dim3(KVD / 128, NTOK / 128), 256>>>(x, Wv, tmp, NTOK, KVD, DD);
    vtrans_kernel<<<(NTOK * KVD / 4 + 255) / 256, 256>>>(tmp, v);

    // causal flash attention
    attn_kernel<<<dim3(TT / ATT_BM, HN, BB), 256, ATT_SMEM>>>(q, k, v, y);

    // output projection
    gemm_nt_kernel<<<dim3(DD / 128, NTOK / 128), 256>>>(y, Wp, out, NTOK, DD, DD);
}

// round 3
// speedup vs baseline: 1.4916x; 1.4916x over previous
#include <cuda_runtime.h>
#include <cuda_bf16.h>
#include <cstdint>
#include <math.h>

// Problem constants
#define HN   16          // num_heads
#define KVH  4           // num_kv_heads
#define HD   128         // head_dim
#define BB   4           // batch
#define TT   2048        // seq len
#define DD   (HN*HD)     // 2048
#define KVD  (KVH*HD)    // 512
#define NTOK (BB*TT)     // 8192
#define KTOT DD          // inner dim of all GEMMs = 2048
#define RMS_EPS 1.1920928955078125e-07f

// ---------------- scratch (device globals: allocation-free) ----------------
__device__ float g_tmp[(size_t)NTOK * DD];        // raw GEMM output (Q/K/V reuse)
__device__ float g_q[(size_t)BB * HN  * TT * HD]; // [B][H][T][HD]
__device__ float g_k[(size_t)BB * KVH * TT * HD]; // [B][KVH][T][HD]
__device__ float g_v[(size_t)BB * KVH * TT * HD]; // [B][KVH][T][HD]
__device__ float g_y[(size_t)NTOK * DD];          // attention out [B*T][D]

// bf16 hi/lo split operands
__device__ __nv_bfloat16 g_xhi[(size_t)NTOK * KTOT], g_xlo[(size_t)NTOK * KTOT];
__device__ __nv_bfloat16 g_wqhi[(size_t)DD * KTOT],  g_wqlo[(size_t)DD * KTOT];
__device__ __nv_bfloat16 g_wkhi[(size_t)KVD * KTOT], g_wklo[(size_t)KVD * KTOT];
__device__ __nv_bfloat16 g_wvhi[(size_t)KVD * KTOT], g_wvlo[(size_t)KVD * KTOT];
__device__ __nv_bfloat16 g_wphi[(size_t)DD * KTOT],  g_wplo[(size_t)DD * KTOT];
__device__ __nv_bfloat16 g_yhi[(size_t)NTOK * KTOT], g_ylo[(size_t)NTOK * KTOT];

// ======================= PTX helpers (baseline compute_103) ================
__device__ __forceinline__ uint32_t smem_u32(const void* p) {
    uint32_t a;
    asm("{ .reg .u64 t; cvta.to.shared.u64 t, %1; cvt.u32.u64 %0, t; }"
        : "=r"(a) : "l"(p));
    return a;
}
__device__ __forceinline__ void cp16(uint32_t dst, const void* src) {
    asm volatile("cp.async.cg.shared.global [%0], [%1], 16;" :: "r"(dst), "l"(src));
}
#define CP_COMMIT() asm volatile("cp.async.commit_group;" ::: "memory")
#define CP_WAIT1()  asm volatile("cp.async.wait_group 1;" ::: "memory")

__device__ __forceinline__ void ldsm_x4(uint32_t* r, uint32_t addr) {
    asm volatile("ldmatrix.sync.aligned.m8n8.x4.shared.b16 {%0,%1,%2,%3}, [%4];"
                 : "=r"(r[0]), "=r"(r[1]), "=r"(r[2]), "=r"(r[3]) : "r"(addr));
}
__device__ __forceinline__ void mma16816(float* c, const uint32_t* a, const uint32_t* b) {
    asm volatile(
        "mma.sync.aligned.m16n8k16.row.col.f32.bf16.bf16.f32 "
        "{%0,%1,%2,%3}, {%4,%5,%6,%7}, {%8,%9}, {%0,%1,%2,%3};"
        : "+f"(c[0]), "+f"(c[1]), "+f"(c[2]), "+f"(c[3])
        : "r"(a[0]), "r"(a[1]), "r"(a[2]), "r"(a[3]), "r"(b[0]), "r"(b[1]));
}

// ================= fp32 -> bf16 hi/lo split conversion =====================
__global__ void __launch_bounds__(256) split_kernel(
    const float* __restrict__ in, __nv_bfloat16* __restrict__ hi,
    __nv_bfloat16* __restrict__ lo, int n4)
{
    int i = blockIdx.x * blockDim.x + threadIdx.x;
    if (i >= n4) return;
    float4 v = ((const float4*)in)[i];
    __nv_bfloat16 h0 = __float2bfloat16(v.x), h1 = __float2bfloat16(v.y);
    __nv_bfloat16 h2 = __float2bfloat16(v.z), h3 = __float2bfloat16(v.w);
    __nv_bfloat16 l0 = __float2bfloat16(v.x - __bfloat162float(h0));
    __nv_bfloat16 l1 = __float2bfloat16(v.y - __bfloat162float(h1));
    __nv_bfloat16 l2 = __float2bfloat16(v.z - __bfloat162float(h2));
    __nv_bfloat16 l3 = __float2bfloat16(v.w - __bfloat162float(h3));
    ((__nv_bfloat162*)hi)[2 * i]     = __nv_bfloat162(h0, h1);
    ((__nv_bfloat162*)hi)[2 * i + 1] = __nv_bfloat162(h2, h3);
    ((__nv_bfloat162*)lo)[2 * i]     = __nv_bfloat162(l0, l1);
    ((__nv_bfloat162*)lo)[2 * i + 1] = __nv_bfloat162(l2, l3);
}

// ========= mma.sync bf16-split GEMM: C[M,N] = A[M,K]*B[N,K]^T (fp32) =======
// BM=BN=128, BK=32, 256 threads = 8 warps (2x4), warp tile 64x32.
#define GBM 128
#define GBN 128
#define GBK 32
#define GNK (KTOT / GBK)       // 64
#define LDA 40                 // padded smem stride (elements); 80B, 16B-aligned
#define TILE_EL  (GBM * LDA)   // 5120 elements per array tile
#define STAGE_EL (4 * TILE_EL) // Ahi,Alo,Bhi,Blo
#define GEMM_SMEM (2 * STAGE_EL * 2)  // bytes = 81920

__device__ __forceinline__ void gemm_load_stage(
    uint32_t sb, int tid, int k0,
    const __nv_bfloat16* gAhi, const __nv_bfloat16* gAlo,
    const __nv_bfloat16* gBhi, const __nv_bfloat16* gBlo)
{
#pragma unroll
    for (int i = 0; i < 2; ++i) {
        int ch = tid + i * 256;            // 0..511
        int r = ch >> 2, sg = ch & 3;      // row 0..127, 16B seg 0..3
        uint32_t so = (uint32_t)((r * LDA + sg * 8) * 2);
        size_t go = (size_t)r * KTOT + k0 + sg * 8;
        cp16(sb + 0 * TILE_EL * 2 + so, gAhi + go);
        cp16(sb + 1 * TILE_EL * 2 + so, gAlo + go);
        cp16(sb + 2 * TILE_EL * 2 + so, gBhi + go);
        cp16(sb + 3 * TILE_EL * 2 + so, gBlo + go);
    }
    CP_COMMIT();
}

__global__ void __launch_bounds__(256, 1) gemm_mma_kernel(
    const __nv_bfloat16* __restrict__ Ahi, const __nv_bfloat16* __restrict__ Alo,
    const __nv_bfloat16* __restrict__ Bhi, const __nv_bfloat16* __restrict__ Blo,
    float* __restrict__ C, int N)
{
    extern __shared__ __nv_bfloat16 smem[];
    const uint32_t sbase = smem_u32(smem);
    const int tid = threadIdx.x;
    const int lane = tid & 31, wid = tid >> 5;
    const int wm = wid >> 2, wn = wid & 3;   // warp grid 2 x 4
    const int m0 = blockIdx.y * GBM;
    const int n0 = blockIdx.x * GBN;

    const __nv_bfloat16* gAhi = Ahi + (size_t)m0 * KTOT;
    const __nv_bfloat16* gAlo = Alo + (size_t)m0 * KTOT;
    const __nv_bfloat16* gBhi = Bhi + (size_t)n0 * KTOT;
    const __nv_bfloat16* gBlo = Blo + (size_t)n0 * KTOT;

    float acc[4][4][4];
#pragma unroll
    for (int mi = 0; mi < 4; ++mi)
#pragma unroll
        for (int nj = 0; nj < 4; ++nj)
#pragma unroll
            for (int e = 0; e < 4; ++e) acc[mi][nj][e] = 0.f;

    // ldmatrix per-lane base offsets (byte offsets within a tile array)
    const int arow = wm * 64 + (lane & 15);
    const uint32_t aoffbase = (uint32_t)(arow * LDA * 2) + ((lane >> 4) << 4); // +8 elems
    const int g = lane >> 3;
    const int brow = wn * 32 + (lane & 7) + ((g >> 1) << 3);
    const uint32_t boffbase = (uint32_t)(brow * LDA * 2) + ((g & 1) << 4);

    gemm_load_stage(sbase, tid, 0, gAhi, gAlo, gBhi, gBlo);
    gemm_load_stage(sbase + STAGE_EL * 2, tid, GBK, gAhi, gAlo, gBhi, gBlo);

    for (int kt = 0; kt < GNK; ++kt) {
        const int buf = kt & 1;
        CP_WAIT1();
        __syncthreads();

        const uint32_t st   = sbase + (uint32_t)buf * STAGE_EL * 2;
        const uint32_t sAhi = st;
        const uint32_t sAlo = st + TILE_EL * 2;
        const uint32_t sBhi = st + 2 * TILE_EL * 2;
        const uint32_t sBlo = st + 3 * TILE_EL * 2;

#pragma unroll
        for (int kk = 0; kk < GBK; kk += 16) {
            uint32_t a_hi[4][4], a_lo[4][4], b_hi[4][2], b_lo[4][2];
            const uint32_t akk = aoffbase + kk * 2;
            const uint32_t bkk = boffbase + kk * 2;
#pragma unroll
            for (int mi = 0; mi < 4; ++mi) {
                ldsm_x4(a_hi[mi], sAhi + akk + mi * 16 * LDA * 2);
                ldsm_x4(a_lo[mi], sAlo + akk + mi * 16 * LDA * 2);
            }
#pragma unroll
            for (int nt = 0; nt < 2; ++nt) {
                uint32_t r[4];
                ldsm_x4(r, sBhi + bkk + nt * 16 * LDA * 2);
                b_hi[2 * nt][0] = r[0]; b_hi[2 * nt][1] = r[1];
                b_hi[2 * nt + 1][0] = r[2]; b_hi[2 * nt + 1][1] = r[3];
                ldsm_x4(r, sBlo + bkk + nt * 16 * LDA * 2);
                b_lo[2 * nt][0] = r[0]; b_lo[2 * nt][1] = r[1];
                b_lo[2 * nt + 1][0] = r[2]; b_lo[2 * nt + 1][1] = r[3];
            }
#pragma unroll
            for (int mi = 0; mi < 4; ++mi)
#pragma unroll
                for (int nj = 0; nj < 4; ++nj) {
                    mma16816(acc[mi][nj], a_hi[mi], b_hi[nj]);
                    mma16816(acc[mi][nj], a_hi[mi], b_lo[nj]);
                    mma16816(acc[mi][nj], a_lo[mi], b_hi[nj]);
                }
        }
        __syncthreads();
        if (kt + 2 < GNK)
            gemm_load_stage(st, tid, (kt + 2) * GBK, gAhi, gAlo, gBhi, gBlo);
    }

    // epilogue: fp32 store
#pragma unroll
    for (int mi = 0; mi < 4; ++mi) {
        int r0 = m0 + wm * 64 + mi * 16 + (lane >> 2);
#pragma unroll
        for (int nj = 0; nj < 4; ++nj) {
            int c = n0 + wn * 32 + nj * 8 + ((lane & 3) << 1);
            *(float2*)&C[(size_t)r0 * N + c]       = make_float2(acc[mi][nj][0], acc[mi][nj][1]);
            *(float2*)&C[(size_t)(r0 + 8) * N + c] = make_float2(acc[mi][nj][2], acc[mi][nj][3]);
        }
    }
}

// -------- fused per-(token,head) RMSNorm + RoPE (+ gain * 1/sqrt(HD)) ------
__global__ void __launch_bounds__(128) normrope_kernel(
    const float* __restrict__ in, float* __restrict__ out,
    const float* __restrict__ gain, int nheads, float extra_scale)
{
    const int idx = blockIdx.x;
    const int h = idx % nheads;
    const int token = idx / nheads;
    const int b = token / TT, t = token % TT;
    const int d = threadIdx.x;

    float v = in[(size_t)token * (nheads * HD) + h * HD + d];

    float ss = v * v;
#pragma unroll
    for (int o = 16; o > 0; o >>= 1) ss += __shfl_xor_sync(0xffffffff, ss, o);

    __shared__ float wsum[4];
    __shared__ float sh[HD];
    if ((d & 31) == 0) wsum[d >> 5] = ss;
    __syncthreads();
    float tot = wsum[0] + wsum[1] + wsum[2] + wsum[3];
    float rms = rsqrtf(tot * (1.0f / HD) + RMS_EPS);
    float nv = v * rms;
    sh[d] = nv;
    __syncthreads();
    float partner = (d < 64) ? -sh[d + 64] : sh[d - 64];

    int fi = d & 63;
    float inv_freq = 1.0f / powf(10000.0f, (float)fi * (1.0f / 64.0f));
    float ang = (float)t * inv_freq;
    float s, c;
    sincosf(ang, &s, &c);
    float r = nv * c + partner * s;
    float gn = gain ? gain[h] : 1.0f;
    r *= gn * extra_scale;

    out[(((size_t)b * nheads + h) * TT + t) * HD + d] = r;
}

// -------- V layout transform: [NTOK][KVD] -> [B][KVH][T][HD] ---------------
__global__ void __launch_bounds__(256) vtrans_kernel(
    const float* __restrict__ in, float* __restrict__ out)
{
    int f4 = blockIdx.x * blockDim.x + threadIdx.x;
    const int total4 = NTOK * KVD / 4;
    if (f4 >= total4) return;
    int dc = f4 & (HD / 4 - 1);
    int rest = f4 / (HD / 4);
    int hk = rest % KVH;
    int token = rest / KVH;
    int b = token / TT, t = token % TT;
    float4 v = ((const float4*)in)[f4];
    ((float4*)out)[(((size_t)b * KVH + hk) * TT + t) * (HD / 4) + dc] = v;
}

// ---------------- causal flash attention (fp32 SIMT) -----------------------
#define ATT_BM 64
#define ATT_BN 64
#define QT_S 68
#define VS_S 132
#define PS_S 65
#define ATT_SMEM ((2*128*QT_S + ATT_BN*VS_S + ATT_BM*PS_S + 3*ATT_BM) * (int)sizeof(float))

__global__ void __launch_bounds__(256) attn_kernel(
    const float* __restrict__ Q, const float* __restrict__ Kg,
    const float* __restrict__ Vg, float* __restrict__ Y)
{
    extern __shared__ float sm[];
    float* Qt   = sm;
    float* Kt   = Qt + 128 * QT_S;
    float* Vs   = Kt + 128 * QT_S;
    float* Ps   = Vs + ATT_BN * VS_S;
    float* mrow = Ps + ATT_BM * PS_S;
    float* lrow = mrow + ATT_BM;
    float* arow = lrow + ATT_BM;

    const int tid = threadIdx.x;
    const int qb = 31 - blockIdx.x;
    const int h  = blockIdx.y;
    const int b  = blockIdx.z;
    const int hk = h / (HN / KVH);

    const float* Qp = Q  + ((((size_t)b * HN  + h ) * TT) + (size_t)qb * ATT_BM) * HD;
    const float* Kp = Kg + (((size_t)b * KVH + hk) * TT) * HD;
    const float* Vp = Vg + (((size_t)b * KVH + hk) * TT) * HD;

#pragma unroll
    for (int it = 0; it < 8; ++it) {
        int f4 = tid + it * 256;
        int row = f4 >> 5;
        int c4 = f4 & 31;
        float4 v = *(const float4*)&Qp[(size_t)row * HD + c4 * 4];
        Qt[(c4 * 4 + 0) * QT_S + row] = v.x;
        Qt[(c4 * 4 + 1) * QT_S + row] = v.y;
        Qt[(c4 * 4 + 2) * QT_S + row] = v.z;
        Qt[(c4 * 4 + 3) * QT_S + row] = v.w;
    }
    if (tid < ATT_BM) { mrow[tid] = -1e30f; lrow[tid] = 0.f; }

    const int ty = tid >> 4;
    const int tx = tid & 15;

    float o[4][8];
#pragma unroll
    for (int i = 0; i < 4; ++i)
#pragma unroll
        for (int c = 0; c < 8; ++c) o[i][c] = 0.f;

    const int nkb = qb + 1;
    for (int kb = 0; kb < nkb; ++kb) {
        __syncthreads();
#pragma unroll
        for (int it = 0; it < 8; ++it) {
            int f4 = tid + it * 256;
            int row = f4 >> 5;
            int c4 = f4 & 31;
            float4 v = *(const float4*)&Kp[((size_t)kb * ATT_BN + row) * HD + c4 * 4];
            Kt[(c4 * 4 + 0) * QT_S + row] = v.x;
            Kt[(c4 * 4 + 1) * QT_S + row] = v.y;
            Kt[(c4 * 4 + 2) * QT_S + row] = v.z;
            Kt[(c4 * 4 + 3) * QT_S + row] = v.w;
            float4 w = *(const float4*)&Vp[((size_t)kb * ATT_BN + row) * HD + c4 * 4];
            *(float4*)&Vs[row * VS_S + c4 * 4] = w;
        }
        __syncthreads();

        float s[4][4];
#pragma unroll
        for (int i = 0; i < 4; ++i)
#pragma unroll
            for (int j = 0; j < 4; ++j) s[i][j] = 0.f;

#pragma unroll 4
        for (int k = 0; k < HD; ++k) {
            float4 aq = *(const float4*)&Qt[k * QT_S + 4 * ty];
            float4 bk = *(const float4*)&Kt[k * QT_S + 4 * tx];
            float a[4] = {aq.x, aq.y, aq.z, aq.w};
            float bb2[4] = {bk.x, bk.y, bk.z, bk.w};
#pragma unroll
            for (int i = 0; i < 4; ++i)
#pragma unroll
                for (int j = 0; j < 4; ++j)
                    s[i][j] = fmaf(a[i], bb2[j], s[i][j]);
        }

        const bool diag = (kb == qb);
#pragma unroll
        for (int i = 0; i < 4; ++i)
#pragma unroll
            for (int j = 0; j < 4; ++j) {
                int r = 4 * ty + i, c = 4 * tx + j;
                float val = s[i][j];
                if (diag && c > r) val = -1e30f;
                Ps[r * PS_S + c] = val;
            }
        __syncthreads();

        if (tid < ATT_BM) {
            const int r = tid;
            float m_old = mrow[r];
            float mmax = m_old;
#pragma unroll 8
            for (int j = 0; j < ATT_BN; ++j) mmax = fmaxf(mmax, Ps[r * PS_S + j]);
            float alpha = __expf(m_old - mmax);
            float lsum = 0.f;
#pragma unroll 4
            for (int j = 0; j < ATT_BN; ++j) {
                float p = __expf(Ps[r * PS_S + j] - mmax);
                Ps[r * PS_S + j] = p;
                lsum += p;
            }
            mrow[r] = mmax;
            lrow[r] = lrow[r] * alpha + lsum;
            arow[r] = alpha;
        }
        __syncthreads();

#pragma unroll
        for (int i = 0; i < 4; ++i) {
            float al = arow[4 * ty + i];
#pragma unroll
            for (int c = 0; c < 8; ++c) o[i][c] *= al;
        }
#pragma unroll 2
        for (int j = 0; j < ATT_BN; ++j) {
            float p0 = Ps[(4 * ty + 0) * PS_S + j];
            float p1 = Ps[(4 * ty + 1) * PS_S + j];
            float p2 = Ps[(4 * ty + 2) * PS_S + j];
            float p3 = Ps[(4 * ty + 3) * PS_S + j];
            float4 v0 = *(const float4*)&Vs[j * VS_S + tx * 8];
            float4 v1 = *(const float4*)&Vs[j * VS_S + tx * 8 + 4];
            float vv[8] = {v0.x, v0.y, v0.z, v0.w, v1.x, v1.y, v1.z, v1.w};
#pragma unroll
            for (int c = 0; c < 8; ++c) {
                o[0][c] = fmaf(p0, vv[c], o[0][c]);
                o[1][c] = fmaf(p1, vv[c], o[1][c]);
                o[2][c] = fmaf(p2, vv[c], o[2][c]);
                o[3][c] = fmaf(p3, vv[c], o[3][c]);
            }
        }
    }

#pragma unroll
    for (int i = 0; i < 4; ++i) {
        int r = 4 * ty + i;
        float inv_l = 1.0f / lrow[r];
        int trow = qb * ATT_BM + r;
        size_t off = ((size_t)(b * TT + trow)) * DD + h * HD + tx * 8;
        float4 w0 = make_float4(o[i][0] * inv_l, o[i][1] * inv_l,
                                o[i][2] * inv_l, o[i][3] * inv_l);
        float4 w1 = make_float4(o[i][4] * inv_l, o[i][5] * inv_l,
                                o[i][6] * inv_l, o[i][7] * inv_l);
        *(float4*)&Y[off]     = w0;
        *(float4*)&Y[off + 4] = w1;
    }
}

// ---------------------------- launch ---------------------------------------
static inline void split(const float* src, __nv_bfloat16* hi, __nv_bfloat16* lo,
                         size_t n)
{
    int n4 = (int)(n / 4);
    split_kernel<<<(n4 + 255) / 256, 256>>>(src, hi, lo, n4);
}

extern "C" void kernel_launch(void* const* d_in, const int* in_sizes, int n_in,
                              void* d_out, int out_size)
{
    const float* x   = (const float*)d_in[0];
    const float* Wq  = (const float*)d_in[1];
    const float* Wk  = (const float*)d_in[2];
    const float* Wv  = (const float*)d_in[3];
    const float* Wp  = (const float*)d_in[4];
    const float* qg  = (const float*)d_in[5];
    float* out = (float*)d_out;

    float *tmp, *q, *k, *v, *y;
    cudaGetSymbolAddress((void**)&tmp, g_tmp);
    cudaGetSymbolAddress((void**)&q,   g_q);
    cudaGetSymbolAddress((void**)&k,   g_k);
    cudaGetSymbolAddress((void**)&v,   g_v);
    cudaGetSymbolAddress((void**)&y,   g_y);

    __nv_bfloat16 *xhi, *xlo, *wqhi, *wqlo, *wkhi, *wklo, *wvhi, *wvlo, *wphi, *wplo, *yhi, *ylo;
    cudaGetSymbolAddress((void**)&xhi, g_xhi);   cudaGetSymbolAddress((void**)&xlo, g_xlo);
    cudaGetSymbolAddress((void**)&wqhi, g_wqhi); cudaGetSymbolAddress((void**)&wqlo, g_wqlo);
    cudaGetSymbolAddress((void**)&wkhi, g_wkhi); cudaGetSymbolAddress((void**)&wklo, g_wklo);
    cudaGetSymbolAddress((void**)&wvhi, g_wvhi); cudaGetSymbolAddress((void**)&wvlo, g_wvlo);
    cudaGetSymbolAddress((void**)&wphi, g_wphi); cudaGetSymbolAddress((void**)&wplo, g_wplo);
    cudaGetSymbolAddress((void**)&yhi, g_yhi);   cudaGetSymbolAddress((void**)&ylo, g_ylo);

    cudaFuncSetAttribute(attn_kernel, cudaFuncAttributeMaxDynamicSharedMemorySize,
                         ATT_SMEM);
    cudaFuncSetAttribute(gemm_mma_kernel,
                         cudaFuncAttributeMaxDynamicSharedMemorySize, GEMM_SMEM);

    const float qscale = 1.0f / sqrtf((float)HD);

    // hi/lo splits of activations and weights
    split(x,  xhi,  xlo,  (size_t)NTOK * KTOT);
    split(Wq, wqhi, wqlo, (size_t)DD * KTOT);
    split(Wk, wkhi, wklo, (size_t)KVD * KTOT);
    split(Wv, wvhi, wvlo, (size_t)KVD * KTOT);
    split(Wp, wphi, wplo, (size_t)DD * KTOT);

    // Q projection + norm/rope/gain
    gemm_mma_kernel<<<dim3(DD / GBN, NTOK / GBM), 256, GEMM_SMEM>>>(
        xhi, xlo, wqhi, wqlo, tmp, DD);
    normrope_kernel<<<NTOK * HN, 128>>>(tmp, q, qg, HN, qscale);

    // K projection + norm/rope
    gemm_mma_kernel<<<dim3(KVD / GBN, NTOK / GBM), 256, GEMM_SMEM>>>(
        xhi, xlo, wkhi, wklo, tmp, KVD);
    normrope_kernel<<<NTOK * KVH, 128>>>(tmp, k, nullptr, KVH, 1.0f);

    // V projection + layout transform
    gemm_mma_kernel<<<dim3(KVD / GBN, NTOK / GBM), 256, GEMM_SMEM>>>(
        xhi, xlo, wvhi, wvlo, tmp, KVD);
    vtrans_kernel<<<(NTOK * KVD / 4 + 255) / 256, 256>>>(tmp, v);

    // causal flash attention (fp32 SIMT)
    attn_kernel<<<dim3(TT / ATT_BM, HN, BB), 256, ATT_SMEM>>>(q, k, v, y);

    // output projection
    split(y, yhi, ylo, (size_t)NTOK * KTOT);
    gemm_mma_kernel<<<dim3(DD / GBN, NTOK / GBM), 256, GEMM_SMEM>>>(
        yhi, ylo, wphi, wplo, out, DD);
}

// round 4
// speedup vs baseline: 3.0904x; 2.0719x over previous
#include <cuda_runtime.h>
#include <cuda_bf16.h>
#include <cstdint>
#include <math.h>

// Problem constants
#define HN   16          // num_heads
#define KVH  4           // num_kv_heads
#define HD   128         // head_dim
#define BB   4           // batch
#define TT   2048        // seq len
#define DD   (HN*HD)     // 2048
#define KVD  (KVH*HD)    // 512
#define NTOK (BB*TT)     // 8192
#define KTOT DD          // inner dim of all GEMMs = 2048
#define RMS_EPS 1.1920928955078125e-07f

// ---------------- scratch (device globals: allocation-free) ----------------
__device__ float g_tmp[(size_t)NTOK * DD];        // raw GEMM output (Q/K/V reuse)

// bf16 hi/lo split operands for GEMMs
__device__ __nv_bfloat16 g_xhi[(size_t)NTOK * KTOT], g_xlo[(size_t)NTOK * KTOT];
__device__ __nv_bfloat16 g_wqhi[(size_t)DD * KTOT],  g_wqlo[(size_t)DD * KTOT];
__device__ __nv_bfloat16 g_wkhi[(size_t)KVD * KTOT], g_wklo[(size_t)KVD * KTOT];
__device__ __nv_bfloat16 g_wvhi[(size_t)KVD * KTOT], g_wvlo[(size_t)KVD * KTOT];
__device__ __nv_bfloat16 g_wphi[(size_t)DD * KTOT],  g_wplo[(size_t)DD * KTOT];
__device__ __nv_bfloat16 g_yhi[(size_t)NTOK * KTOT], g_ylo[(size_t)NTOK * KTOT];

// bf16 hi/lo Q/K/V for tensor-core attention
__device__ __nv_bfloat16 g_qhi[(size_t)BB * HN  * TT * HD], g_qlo[(size_t)BB * HN  * TT * HD];
__device__ __nv_bfloat16 g_khi[(size_t)BB * KVH * TT * HD], g_klo[(size_t)BB * KVH * TT * HD];
__device__ __nv_bfloat16 g_vhi[(size_t)BB * KVH * TT * HD], g_vlo[(size_t)BB * KVH * TT * HD];

// ======================= PTX helpers (baseline compute_103) ================
__device__ __forceinline__ uint32_t smem_u32(const void* p) {
    uint32_t a;
    asm("{ .reg .u64 t; cvta.to.shared.u64 t, %1; cvt.u32.u64 %0, t; }"
        : "=r"(a) : "l"(p));
    return a;
}
__device__ __forceinline__ void cp16(uint32_t dst, const void* src) {
    asm volatile("cp.async.cg.shared.global [%0], [%1], 16;" :: "r"(dst), "l"(src));
}
#define CP_COMMIT() asm volatile("cp.async.commit_group;" ::: "memory")
#define CP_WAIT1()  asm volatile("cp.async.wait_group 1;" ::: "memory")
#define CP_WAIT0()  asm volatile("cp.async.wait_group 0;" ::: "memory")

__device__ __forceinline__ void ldsm_x4(uint32_t* r, uint32_t addr) {
    asm volatile("ldmatrix.sync.aligned.m8n8.x4.shared.b16 {%0,%1,%2,%3}, [%4];"
                 : "=r"(r[0]), "=r"(r[1]), "=r"(r[2]), "=r"(r[3]) : "r"(addr));
}
__device__ __forceinline__ void ldsm_x4_t(uint32_t* r, uint32_t addr) {
    asm volatile("ldmatrix.sync.aligned.m8n8.x4.trans.shared.b16 {%0,%1,%2,%3}, [%4];"
                 : "=r"(r[0]), "=r"(r[1]), "=r"(r[2]), "=r"(r[3]) : "r"(addr));
}
__device__ __forceinline__ void mma16816(float* c, const uint32_t* a, const uint32_t* b) {
    asm volatile(
        "mma.sync.aligned.m16n8k16.row.col.f32.bf16.bf16.f32 "
        "{%0,%1,%2,%3}, {%4,%5,%6,%7}, {%8,%9}, {%0,%1,%2,%3};"
        : "+f"(c[0]), "+f"(c[1]), "+f"(c[2]), "+f"(c[3])
        : "r"(a[0]), "r"(a[1]), "r"(a[2]), "r"(a[3]), "r"(b[0]), "r"(b[1]));
}
__device__ __forceinline__ uint32_t pack_bf16(float x, float y) {
    __nv_bfloat162 t = __floats2bfloat162_rn(x, y);
    return *(uint32_t*)&t;
}

// ================= fp32 -> bf16 hi/lo split conversion =====================
__global__ void __launch_bounds__(256) split_kernel(
    const float* __restrict__ in, __nv_bfloat16* __restrict__ hi,
    __nv_bfloat16* __restrict__ lo, int n4)
{
    int i = blockIdx.x * blockDim.x + threadIdx.x;
    if (i >= n4) return;
    float4 v = ((const float4*)in)[i];
    __nv_bfloat16 h0 = __float2bfloat16(v.x), h1 = __float2bfloat16(v.y);
    __nv_bfloat16 h2 = __float2bfloat16(v.z), h3 = __float2bfloat16(v.w);
    __nv_bfloat16 l0 = __float2bfloat16(v.x - __bfloat162float(h0));
    __nv_bfloat16 l1 = __float2bfloat16(v.y - __bfloat162float(h1));
    __nv_bfloat16 l2 = __float2bfloat16(v.z - __bfloat162float(h2));
    __nv_bfloat16 l3 = __float2bfloat16(v.w - __bfloat162float(h3));
    ((__nv_bfloat162*)hi)[2 * i]     = __nv_bfloat162(h0, h1);
    ((__nv_bfloat162*)hi)[2 * i + 1] = __nv_bfloat162(h2, h3);
    ((__nv_bfloat162*)lo)[2 * i]     = __nv_bfloat162(l0, l1);
    ((__nv_bfloat162*)lo)[2 * i + 1] = __nv_bfloat162(l2, l3);
}

// ========= mma.sync bf16-split GEMM: C[M,N] = A[M,K]*B[N,K]^T (fp32) =======
#define GBM 128
#define GBN 128
#define GBK 32
#define GNK (KTOT / GBK)       // 64
#define LDA 40
#define TILE_EL  (GBM * LDA)
#define STAGE_EL (4 * TILE_EL)
#define GEMM_SMEM (2 * STAGE_EL * 2)

__device__ __forceinline__ void gemm_load_stage(
    uint32_t sb, int tid, int k0,
    const __nv_bfloat16* gAhi, const __nv_bfloat16* gAlo,
    const __nv_bfloat16* gBhi, const __nv_bfloat16* gBlo)
{
#pragma unroll
    for (int i = 0; i < 2; ++i) {
        int ch = tid + i * 256;
        int r = ch >> 2, sg = ch & 3;
        uint32_t so = (uint32_t)((r * LDA + sg * 8) * 2);
        size_t go = (size_t)r * KTOT + k0 + sg * 8;
        cp16(sb + 0 * TILE_EL * 2 + so, gAhi + go);
        cp16(sb + 1 * TILE_EL * 2 + so, gAlo + go);
        cp16(sb + 2 * TILE_EL * 2 + so, gBhi + go);
        cp16(sb + 3 * TILE_EL * 2 + so, gBlo + go);
    }
    CP_COMMIT();
}

__global__ void __launch_bounds__(256, 1) gemm_mma_kernel(
    const __nv_bfloat16* __restrict__ Ahi, const __nv_bfloat16* __restrict__ Alo,
    const __nv_bfloat16* __restrict__ Bhi, const __nv_bfloat16* __restrict__ Blo,
    float* __restrict__ C, int N)
{
    extern __shared__ __nv_bfloat16 smem[];
    const uint32_t sbase = smem_u32(smem);
    const int tid = threadIdx.x;
    const int lane = tid & 31, wid = tid >> 5;
    const int wm = wid >> 2, wn = wid & 3;
    const int m0 = blockIdx.y * GBM;
    const int n0 = blockIdx.x * GBN;

    const __nv_bfloat16* gAhi = Ahi + (size_t)m0 * KTOT;
    const __nv_bfloat16* gAlo = Alo + (size_t)m0 * KTOT;
    const __nv_bfloat16* gBhi = Bhi + (size_t)n0 * KTOT;
    const __nv_bfloat16* gBlo = Blo + (size_t)n0 * KTOT;

    float acc[4][4][4];
#pragma unroll
    for (int mi = 0; mi < 4; ++mi)
#pragma unroll
        for (int nj = 0; nj < 4; ++nj)
#pragma unroll
            for (int e = 0; e < 4; ++e) acc[mi][nj][e] = 0.f;

    const int arow = wm * 64 + (lane & 15);
    const uint32_t aoffbase = (uint32_t)(arow * LDA * 2) + ((lane >> 4) << 4);
    const int g = lane >> 3;
    const int brow = wn * 32 + (lane & 7) + ((g >> 1) << 3);
    const uint32_t boffbase = (uint32_t)(brow * LDA * 2) + ((g & 1) << 4);

    gemm_load_stage(sbase, tid, 0, gAhi, gAlo, gBhi, gBlo);
    gemm_load_stage(sbase + STAGE_EL * 2, tid, GBK, gAhi, gAlo, gBhi, gBlo);

    for (int kt = 0; kt < GNK; ++kt) {
        const int buf = kt & 1;
        CP_WAIT1();
        __syncthreads();

        const uint32_t st   = sbase + (uint32_t)buf * STAGE_EL * 2;
        const uint32_t sAhi = st;
        const uint32_t sAlo = st + TILE_EL * 2;
        const uint32_t sBhi = st + 2 * TILE_EL * 2;
        const uint32_t sBlo = st + 3 * TILE_EL * 2;

#pragma unroll
        for (int kk = 0; kk < GBK; kk += 16) {
            uint32_t a_hi[4][4], a_lo[4][4], b_hi[4][2], b_lo[4][2];
            const uint32_t akk = aoffbase + kk * 2;
            const uint32_t bkk = boffbase + kk * 2;
#pragma unroll
            for (int mi = 0; mi < 4; ++mi) {
                ldsm_x4(a_hi[mi], sAhi + akk + mi * 16 * LDA * 2);
                ldsm_x4(a_lo[mi], sAlo + akk + mi * 16 * LDA * 2);
            }
#pragma unroll
            for (int nt = 0; nt < 2; ++nt) {
                uint32_t r[4];
                ldsm_x4(r, sBhi + bkk + nt * 16 * LDA * 2);
                b_hi[2 * nt][0] = r[0]; b_hi[2 * nt][1] = r[1];
                b_hi[2 * nt + 1][0] = r[2]; b_hi[2 * nt + 1][1] = r[3];
                ldsm_x4(r, sBlo + bkk + nt * 16 * LDA * 2);
                b_lo[2 * nt][0] = r[0]; b_lo[2 * nt][1] = r[1];
                b_lo[2 * nt + 1][0] = r[2]; b_lo[2 * nt + 1][1] = r[3];
            }
#pragma unroll
            for (int mi = 0; mi < 4; ++mi)
#pragma unroll
                for (int nj = 0; nj < 4; ++nj) {
                    mma16816(acc[mi][nj], a_hi[mi], b_hi[nj]);
                    mma16816(acc[mi][nj], a_hi[mi], b_lo[nj]);
                    mma16816(acc[mi][nj], a_lo[mi], b_hi[nj]);
                }
        }
        __syncthreads();
        if (kt + 2 < GNK)
            gemm_load_stage(st, tid, (kt + 2) * GBK, gAhi, gAlo, gBhi, gBlo);
    }

#pragma unroll
    for (int mi = 0; mi < 4; ++mi) {
        int r0 = m0 + wm * 64 + mi * 16 + (lane >> 2);
#pragma unroll
        for (int nj = 0; nj < 4; ++nj) {
            int c = n0 + wn * 32 + nj * 8 + ((lane & 3) << 1);
            *(float2*)&C[(size_t)r0 * N + c]       = make_float2(acc[mi][nj][0], acc[mi][nj][1]);
            *(float2*)&C[(size_t)(r0 + 8) * N + c] = make_float2(acc[mi][nj][2], acc[mi][nj][3]);
        }
    }
}

// -------- fused RMSNorm + RoPE (+ gain/scale), writes bf16 hi/lo -----------
__global__ void __launch_bounds__(128) normrope_kernel(
    const float* __restrict__ in, __nv_bfloat16* __restrict__ ohi,
    __nv_bfloat16* __restrict__ olo, const float* __restrict__ gain,
    int nheads, float extra_scale)
{
    const int idx = blockIdx.x;
    const int h = idx % nheads;
    const int token = idx / nheads;
    const int b = token / TT, t = token % TT;
    const int d = threadIdx.x;

    float v = in[(size_t)token * (nheads * HD) + h * HD + d];

    float ss = v * v;
#pragma unroll
    for (int o = 16; o > 0; o >>= 1) ss += __shfl_xor_sync(0xffffffff, ss, o);

    __shared__ float wsum[4];
    __shared__ float sh[HD];
    if ((d & 31) == 0) wsum[d >> 5] = ss;
    __syncthreads();
    float tot = wsum[0] + wsum[1] + wsum[2] + wsum[3];
    float rms = rsqrtf(tot * (1.0f / HD) + RMS_EPS);
    float nv = v * rms;
    sh[d] = nv;
    __syncthreads();
    float partner = (d < 64) ? -sh[d + 64] : sh[d - 64];

    int fi = d & 63;
    float inv_freq = 1.0f / powf(10000.0f, (float)fi * (1.0f / 64.0f));
    float ang = (float)t * inv_freq;
    float s, c;
    sincosf(ang, &s, &c);
    float r = nv * c + partner * s;
    float gn = gain ? gain[h] : 1.0f;
    r *= gn * extra_scale;

    size_t off = (((size_t)b * nheads + h) * TT + t) * HD + d;
    __nv_bfloat16 hi = __float2bfloat16(r);
    __nv_bfloat16 lo = __float2bfloat16(r - __bfloat162float(hi));
    ohi[off] = hi;
    olo[off] = lo;
}

// -------- V: [NTOK][KVD] fp32 -> [B][KVH][T][HD] bf16 hi/lo ----------------
__global__ void __launch_bounds__(256) vtrans_kernel(
    const float* __restrict__ in, __nv_bfloat16* __restrict__ ohi,
    __nv_bfloat16* __restrict__ olo)
{
    int f4 = blockIdx.x * blockDim.x + threadIdx.x;
    const int total4 = NTOK * KVD / 4;
    if (f4 >= total4) return;
    int dc = f4 & (HD / 4 - 1);
    int rest = f4 / (HD / 4);
    int hk = rest % KVH;
    int token = rest / KVH;
    int b = token / TT, t = token % TT;
    float4 v = ((const float4*)in)[f4];
    __nv_bfloat16 h0 = __float2bfloat16(v.x), h1 = __float2bfloat16(v.y);
    __nv_bfloat16 h2 = __float2bfloat16(v.z), h3 = __float2bfloat16(v.w);
    __nv_bfloat16 l0 = __float2bfloat16(v.x - __bfloat162float(h0));
    __nv_bfloat16 l1 = __float2bfloat16(v.y - __bfloat162float(h1));
    __nv_bfloat16 l2 = __float2bfloat16(v.z - __bfloat162float(h2));
    __nv_bfloat16 l3 = __float2bfloat16(v.w - __bfloat162float(h3));
    size_t o2 = ((((size_t)b * KVH + hk) * TT + t) * HD) / 2 + dc * 2;
    ((__nv_bfloat162*)ohi)[o2]     = __nv_bfloat162(h0, h1);
    ((__nv_bfloat162*)ohi)[o2 + 1] = __nv_bfloat162(h2, h3);
    ((__nv_bfloat162*)olo)[o2]     = __nv_bfloat162(l0, l1);
    ((__nv_bfloat162*)olo)[o2 + 1] = __nv_bfloat162(l2, l3);
}

// ============ tensor-core causal flash attention (bf16-split) ==============
// BM=128 (8 warps x 16 rows), BN=64, HD=128. smem stride 136 els (272B).
#define FBM 128
#define FBN 64
#define LDQ 136
#define QSZB   (FBM * LDQ * 2)        // 34816 bytes per Q array
#define KTILEB (FBN * LDQ * 2)        // 17408 bytes per K/V array
#define STAGEB (4 * KTILEB)           // 69632
#define FATT_SMEM (2 * QSZB + 2 * STAGEB)  // 208896

__device__ __forceinline__ void fatt_load_kv(
    uint32_t st, int tid,
    const __nv_bfloat16* kp_hi, const __nv_bfloat16* kp_lo,
    const __nv_bfloat16* vp_hi, const __nv_bfloat16* vp_lo, int kb)
{
    const size_t base = (size_t)kb * FBN * HD;
#pragma unroll
    for (int i = 0; i < 4; ++i) {
        int ch = tid + i * 256;            // 0..1023
        int row = ch >> 4, seg = ch & 15;  // row 0..63, seg 0..15 (16B)
        uint32_t so = (uint32_t)(row * (LDQ * 2) + seg * 16);
        size_t go = base + (size_t)row * HD + seg * 8;
        cp16(st + 0 * KTILEB + so, kp_hi + go);
        cp16(st + 1 * KTILEB + so, kp_lo + go);
        cp16(st + 2 * KTILEB + so, vp_hi + go);
        cp16(st + 3 * KTILEB + so, vp_lo + go);
    }
    CP_COMMIT();
}

__global__ void __launch_bounds__(256, 1) fattn_kernel(
    const __nv_bfloat16* __restrict__ Qhi, const __nv_bfloat16* __restrict__ Qlo,
    const __nv_bfloat16* __restrict__ Khi, const __nv_bfloat16* __restrict__ Klo,
    const __nv_bfloat16* __restrict__ Vhi, const __nv_bfloat16* __restrict__ Vlo,
    __nv_bfloat16* __restrict__ Yhi, __nv_bfloat16* __restrict__ Ylo)
{
    extern __shared__ char smraw[];
    const uint32_t sb = smem_u32(smraw);
    const uint32_t sQh = sb, sQl = sb + QSZB;
    const uint32_t sSt = sb + 2 * QSZB;   // stage s at sSt + s*STAGEB

    const int tid = threadIdx.x;
    const int lane = tid & 31, wid = tid >> 5;
    const int qb = (int)(gridDim.x - 1 - blockIdx.x);  // heavy first
    const int h  = blockIdx.y;
    const int b  = blockIdx.z;
    const int hk = h / (HN / KVH);
    const int nkb = 2 * qb + 2;

    const __nv_bfloat16* qp_hi = Qhi + ((((size_t)b * HN + h) * TT) + (size_t)qb * FBM) * HD;
    const __nv_bfloat16* qp_lo = Qlo + ((((size_t)b * HN + h) * TT) + (size_t)qb * FBM) * HD;
    const __nv_bfloat16* kp_hi = Khi + (((size_t)b * KVH + hk) * TT) * HD;
    const __nv_bfloat16* kp_lo = Klo + (((size_t)b * KVH + hk) * TT) * HD;
    const __nv_bfloat16* vp_hi = Vhi + (((size_t)b * KVH + hk) * TT) * HD;
    const __nv_bfloat16* vp_lo = Vlo + (((size_t)b * KVH + hk) * TT) * HD;

    // Q load: 128 rows x 16 segs x 2 arrays
#pragma unroll
    for (int i = 0; i < 8; ++i) {
        int ch = tid + i * 256;            // 0..2047
        int row = ch >> 4, seg = ch & 15;
        uint32_t so = (uint32_t)(row * (LDQ * 2) + seg * 16);
        size_t go = (size_t)row * HD + seg * 8;
        cp16(sQh + so, qp_hi + go);
        cp16(sQl + so, qp_lo + go);
    }
    fatt_load_kv(sSt, tid, kp_hi, kp_lo, vp_hi, vp_lo, 0);   // group 0 = Q + kv0
    if (nkb > 1)
        fatt_load_kv(sSt + STAGEB, tid, kp_hi, kp_lo, vp_hi, vp_lo, 1);  // group 1

    // per-warp fragment bases
    const uint32_t aoff = (uint32_t)((wid * 16 + (lane & 15)) * (LDQ * 2)) + ((lane >> 4) << 4);
    const int g = lane >> 3;
    const uint32_t boff = (uint32_t)(((lane & 7) + ((g >> 1) << 3)) * (LDQ * 2)) + ((g & 1) << 4);
    const uint32_t voff = (uint32_t)((lane & 15) * (LDQ * 2)) + (((lane >> 4) & 1) << 4);

    float o[16][4];
#pragma unroll
    for (int nf = 0; nf < 16; ++nf)
#pragma unroll
        for (int e = 0; e < 4; ++e) o[nf][e] = 0.f;
    float m_i[2] = {-1e30f, -1e30f};
    float l_i[2] = {0.f, 0.f};

    const int qrow0 = qb * FBM + wid * 16 + (lane >> 2);  // row for rr=0 (rr=1: +8)

    for (int kb = 0; kb < nkb; ++kb) {
        const int buf = kb & 1;
        if (kb + 1 < nkb) { CP_WAIT1(); } else { CP_WAIT0(); }
        __syncthreads();

        const uint32_t sKh = sSt + (uint32_t)buf * STAGEB;
        const uint32_t sKl = sKh + KTILEB;
        const uint32_t sVh = sKh + 2 * KTILEB;
        const uint32_t sVl = sKh + 3 * KTILEB;

        // ---- S = Q K^T (3-term split), s[j][4], j = n8 fragment 0..7 ----
        float s[8][4];
#pragma unroll
        for (int j = 0; j < 8; ++j)
#pragma unroll
            for (int e = 0; e < 4; ++e) s[j][e] = 0.f;

#pragma unroll
        for (int kc = 0; kc < 8; ++kc) {
            uint32_t aq_hi[4], aq_lo[4];
            ldsm_x4(aq_hi, sQh + aoff + kc * 32);
            ldsm_x4(aq_lo, sQl + aoff + kc * 32);
#pragma unroll
            for (int n16 = 0; n16 < 4; ++n16) {
                uint32_t bh[4], bl[4];
                ldsm_x4(bh, sKh + boff + n16 * 16 * (LDQ * 2) + kc * 32);
                ldsm_x4(bl, sKl + boff + n16 * 16 * (LDQ * 2) + kc * 32);
                mma16816(s[2 * n16],     aq_hi, &bh[0]);
                mma16816(s[2 * n16],     aq_hi, &bl[0]);
                mma16816(s[2 * n16],     aq_lo, &bh[0]);
                mma16816(s[2 * n16 + 1], aq_hi, &bh[2]);
                mma16816(s[2 * n16 + 1], aq_hi, &bl[2]);
                mma16816(s[2 * n16 + 1], aq_lo, &bh[2]);
            }
        }

        // ---- causal mask (diagonal blocks only) ----
        if (kb >= nkb - 2) {
            const int kc0 = kb * FBN + 2 * (lane & 3);
#pragma unroll
            for (int j = 0; j < 8; ++j)
#pragma unroll
                for (int e = 0; e < 4; ++e) {
                    int row = qrow0 + (e >> 1) * 8;
                    int col = kc0 + 8 * j + (e & 1);
                    if (col > row) s[j][e] = -1e30f;
                }
        }

        // ---- online softmax ----
        float alpha[2];
#pragma unroll
        for (int rr = 0; rr < 2; ++rr) {
            float mx = m_i[rr];
#pragma unroll
            for (int j = 0; j < 8; ++j)
                mx = fmaxf(mx, fmaxf(s[j][2 * rr], s[j][2 * rr + 1]));
            mx = fmaxf(mx, __shfl_xor_sync(0xffffffff, mx, 1));
            mx = fmaxf(mx, __shfl_xor_sync(0xffffffff, mx, 2));
            alpha[rr] = __expf(m_i[rr] - mx);
            float lsum = 0.f;
#pragma unroll
            for (int j = 0; j < 8; ++j) {
                float p0 = __expf(s[j][2 * rr] - mx);
                float p1 = __expf(s[j][2 * rr + 1] - mx);
                s[j][2 * rr] = p0; s[j][2 * rr + 1] = p1;
                lsum += p0 + p1;
            }
            m_i[rr] = mx;
            l_i[rr] = l_i[rr] * alpha[rr] + lsum;
        }
#pragma unroll
        for (int nf = 0; nf < 16; ++nf) {
            o[nf][0] *= alpha[0]; o[nf][1] *= alpha[0];
            o[nf][2] *= alpha[1]; o[nf][3] *= alpha[1];
        }

        // ---- O += P V (3-term split) ----
#pragma unroll
        for (int kc2 = 0; kc2 < 4; ++kc2) {
            const int j0 = 2 * kc2, j1 = 2 * kc2 + 1;
            uint32_t ap_hi[4], ap_lo[4];
            {
                float v00 = s[j0][0], v01 = s[j0][1], v02 = s[j0][2], v03 = s[j0][3];
                float v10 = s[j1][0], v11 = s[j1][1], v12 = s[j1][2], v13 = s[j1][3];
                float h00 = __bfloat162float(__float2bfloat16(v00));
                float h01 = __bfloat162float(__float2bfloat16(v01));
                float h02 = __bfloat162float(__float2bfloat16(v02));
                float h03 = __bfloat162float(__float2bfloat16(v03));
                float h10 = __bfloat162float(__float2bfloat16(v10));
                float h11 = __bfloat162float(__float2bfloat16(v11));
                float h12 = __bfloat162float(__float2bfloat16(v12));
                float h13 = __bfloat162float(__float2bfloat16(v13));
                ap_hi[0] = pack_bf16(h00, h01);
                ap_hi[1] = pack_bf16(h02, h03);
                ap_hi[2] = pack_bf16(h10, h11);
                ap_hi[3] = pack_bf16(h12, h13);
                ap_lo[0] = pack_bf16(v00 - h00, v01 - h01);
                ap_lo[1] = pack_bf16(v02 - h02, v03 - h03);
                ap_lo[2] = pack_bf16(v10 - h10, v11 - h11);
                ap_lo[3] = pack_bf16(v12 - h12, v13 - h13);
            }
            const uint32_t vrow = voff + kc2 * 16 * (LDQ * 2);
#pragma unroll
            for (int nf16 = 0; nf16 < 8; ++nf16) {
                uint32_t bvh[4], bvl[4];
                ldsm_x4_t(bvh, sVh + vrow + nf16 * 32);
                ldsm_x4_t(bvl, sVl + vrow + nf16 * 32);
                mma16816(o[2 * nf16],     ap_hi, &bvh[0]);
                mma16816(o[2 * nf16],     ap_lo, &bvh[0]);
                mma16816(o[2 * nf16],     ap_hi, &bvl[0]);
                mma16816(o[2 * nf16 + 1], ap_hi, &bvh[2]);
                mma16816(o[2 * nf16 + 1], ap_lo, &bvh[2]);
                mma16816(o[2 * nf16 + 1], ap_hi, &bvl[2]);
            }
        }

        __syncthreads();  // everyone done reading buf before refill
        if (kb + 2 < nkb)
            fatt_load_kv(sSt + (uint32_t)buf * STAGEB, tid,
                         kp_hi, kp_lo, vp_hi, vp_lo, kb + 2);
    }

    // ---- epilogue: normalize, split to bf16 hi/lo, store ----
#pragma unroll
    for (int rr = 0; rr < 2; ++rr) {
        float lf = l_i[rr];
        lf += __shfl_xor_sync(0xffffffff, lf, 1);
        lf += __shfl_xor_sync(0xffffffff, lf, 2);
        float inv = 1.0f / lf;
        int trow = qrow0 + rr * 8;
        size_t rbase = ((size_t)(b * TT + trow)) * DD + h * HD + 2 * (lane & 3);
#pragma unroll
        for (int nf = 0; nf < 16; ++nf) {
            float v0 = o[nf][2 * rr] * inv;
            float v1 = o[nf][2 * rr + 1] * inv;
            __nv_bfloat16 h0 = __float2bfloat16(v0);
            __nv_bfloat16 h1 = __float2bfloat16(v1);
            __nv_bfloat16 l0 = __float2bfloat16(v0 - __bfloat162float(h0));
            __nv_bfloat16 l1 = __float2bfloat16(v1 - __bfloat162float(h1));
            *(__nv_bfloat162*)&Yhi[rbase + nf * 8] = __nv_bfloat162(h0, h1);
            *(__nv_bfloat162*)&Ylo[rbase + nf * 8] = __nv_bfloat162(l0, l1);
        }
    }
}

// ---------------------------- launch ---------------------------------------
static inline void split(const float* src, __nv_bfloat16* hi, __nv_bfloat16* lo,
                         size_t n)
{
    int n4 = (int)(n / 4);
    split_kernel<<<(n4 + 255) / 256, 256>>>(src, hi, lo, n4);
}

extern "C" void kernel_launch(void* const* d_in, const int* in_sizes, int n_in,
                              void* d_out, int out_size)
{
    const float* x   = (const float*)d_in[0];
    const float* Wq  = (const float*)d_in[1];
    const float* Wk  = (const float*)d_in[2];
    const float* Wv  = (const float*)d_in[3];
    const float* Wp  = (const float*)d_in[4];
    const float* qg  = (const float*)d_in[5];
    float* out = (float*)d_out;

    float* tmp;
    cudaGetSymbolAddress((void**)&tmp, g_tmp);

    __nv_bfloat16 *xhi, *xlo, *wqhi, *wqlo, *wkhi, *wklo, *wvhi, *wvlo, *wphi, *wplo, *yhi, *ylo;
    __nv_bfloat16 *qhi, *qlo, *khi, *klo, *vhi, *vlo;
    cudaGetSymbolAddress((void**)&xhi, g_xhi);   cudaGetSymbolAddress((void**)&xlo, g_xlo);
    cudaGetSymbolAddress((void**)&wqhi, g_wqhi); cudaGetSymbolAddress((void**)&wqlo, g_wqlo);
    cudaGetSymbolAddress((void**)&wkhi, g_wkhi); cudaGetSymbolAddress((void**)&wklo, g_wklo);
    cudaGetSymbolAddress((void**)&wvhi, g_wvhi); cudaGetSymbolAddress((void**)&wvlo, g_wvlo);
    cudaGetSymbolAddress((void**)&wphi, g_wphi); cudaGetSymbolAddress((void**)&wplo, g_wplo);
    cudaGetSymbolAddress((void**)&yhi, g_yhi);   cudaGetSymbolAddress((void**)&ylo, g_ylo);
    cudaGetSymbolAddress((void**)&qhi, g_qhi);   cudaGetSymbolAddress((void**)&qlo, g_qlo);
    cudaGetSymbolAddress((void**)&khi, g_khi);   cudaGetSymbolAddress((void**)&klo, g_klo);
    cudaGetSymbolAddress((void**)&vhi, g_vhi);   cudaGetSymbolAddress((void**)&vlo, g_vlo);

    cudaFuncSetAttribute(gemm_mma_kernel,
                         cudaFuncAttributeMaxDynamicSharedMemorySize, GEMM_SMEM);
    cudaFuncSetAttribute(fattn_kernel,
                         cudaFuncAttributeMaxDynamicSharedMemorySize, FATT_SMEM);

    const float qscale = 1.0f / sqrtf((float)HD);

    // hi/lo splits of activations and weights
    split(x,  xhi,  xlo,  (size_t)NTOK * KTOT);
    split(Wq, wqhi, wqlo, (size_t)DD * KTOT);
    split(Wk, wkhi, wklo, (size_t)KVD * KTOT);
    split(Wv, wvhi, wvlo, (size_t)KVD * KTOT);
    split(Wp, wphi, wplo, (size_t)DD * KTOT);

    // Q projection + norm/rope/gain -> bf16 hi/lo
    gemm_mma_kernel<<<dim3(DD / GBN, NTOK / GBM), 256, GEMM_SMEM>>>(
        xhi, xlo, wqhi, wqlo, tmp, DD);
    normrope_kernel<<<NTOK * HN, 128>>>(tmp, qhi, qlo, qg, HN, qscale);

    // K projection + norm/rope -> bf16 hi/lo
    gemm_mma_kernel<<<dim3(KVD / GBN, NTOK / GBM), 256, GEMM_SMEM>>>(
        xhi, xlo, wkhi, wklo, tmp, KVD);
    normrope_kernel<<<NTOK * KVH, 128>>>(tmp, khi, klo, nullptr, KVH, 1.0f);

    // V projection + layout transform -> bf16 hi/lo
    gemm_mma_kernel<<<dim3(KVD / GBN, NTOK / GBM), 256, GEMM_SMEM>>>(
        xhi, xlo, wvhi, wvlo, tmp, KVD);
    vtrans_kernel<<<(NTOK * KVD / 4 + 255) / 256, 256>>>(tmp, vhi, vlo);

    // tensor-core causal flash attention -> y bf16 hi/lo
    fattn_kernel<<<dim3(TT / FBM, HN, BB), 256, FATT_SMEM>>>(
        qhi, qlo, khi, klo, vhi, vlo, yhi, ylo);

    // output projection
    gemm_mma_kernel<<<dim3(DD / GBN, NTOK / GBM), 256, GEMM_SMEM>>>(
        yhi, ylo, wphi, wplo, out, DD);
}

// round 5
// speedup vs baseline: 3.3741x; 1.0918x over previous
#include <cuda_runtime.h>
#include <cuda_bf16.h>
#include <cstdint>
#include <math.h>

// Problem constants
#define HN   16          // num_heads
#define KVH  4           // num_kv_heads
#define HD   128         // head_dim
#define BB   4           // batch
#define TT   2048        // seq len
#define DD   (HN*HD)     // 2048
#define KVD  (KVH*HD)    // 512
#define NTOK (BB*TT)     // 8192
#define KTOT DD          // inner dim of all GEMMs = 2048
#define QKVN (DD + 2*KVD)  // 3072 fused projection width
#define RMS_EPS 1.1920928955078125e-07f

// ---------------- scratch (device globals: allocation-free) ----------------
__device__ float g_tmp[(size_t)NTOK * QKVN];      // fused QKV GEMM output

// bf16 hi/lo split operands for GEMMs
__device__ __nv_bfloat16 g_xhi[(size_t)NTOK * KTOT], g_xlo[(size_t)NTOK * KTOT];
__device__ __nv_bfloat16 g_wchi[(size_t)QKVN * KTOT], g_wclo[(size_t)QKVN * KTOT]; // Wq|Wk|Wv
__device__ __nv_bfloat16 g_wphi[(size_t)DD * KTOT],  g_wplo[(size_t)DD * KTOT];
__device__ __nv_bfloat16 g_yhi[(size_t)NTOK * KTOT], g_ylo[(size_t)NTOK * KTOT];

// bf16 hi/lo Q/K/V for tensor-core attention
__device__ __nv_bfloat16 g_qhi[(size_t)BB * HN  * TT * HD], g_qlo[(size_t)BB * HN  * TT * HD];
__device__ __nv_bfloat16 g_khi[(size_t)BB * KVH * TT * HD], g_klo[(size_t)BB * KVH * TT * HD];
__device__ __nv_bfloat16 g_vhi[(size_t)BB * KVH * TT * HD], g_vlo[(size_t)BB * KVH * TT * HD];

// ======================= PTX helpers (baseline compute_103) ================
__device__ __forceinline__ uint32_t smem_u32(const void* p) {
    uint32_t a;
    asm("{ .reg .u64 t; cvta.to.shared.u64 t, %1; cvt.u32.u64 %0, t; }"
        : "=r"(a) : "l"(p));
    return a;
}
__device__ __forceinline__ void cp16(uint32_t dst, const void* src) {
    asm volatile("cp.async.cg.shared.global [%0], [%1], 16;" :: "r"(dst), "l"(src));
}
#define CP_COMMIT() asm volatile("cp.async.commit_group;" ::: "memory")
#define CP_WAIT1()  asm volatile("cp.async.wait_group 1;" ::: "memory")
#define CP_WAIT0()  asm volatile("cp.async.wait_group 0;" ::: "memory")

__device__ __forceinline__ void ldsm_x4(uint32_t* r, uint32_t addr) {
    asm volatile("ldmatrix.sync.aligned.m8n8.x4.shared.b16 {%0,%1,%2,%3}, [%4];"
                 : "=r"(r[0]), "=r"(r[1]), "=r"(r[2]), "=r"(r[3]) : "r"(addr));
}
__device__ __forceinline__ void ldsm_x4_t(uint32_t* r, uint32_t addr) {
    asm volatile("ldmatrix.sync.aligned.m8n8.x4.trans.shared.b16 {%0,%1,%2,%3}, [%4];"
                 : "=r"(r[0]), "=r"(r[1]), "=r"(r[2]), "=r"(r[3]) : "r"(addr));
}
__device__ __forceinline__ void mma16816(float* c, const uint32_t* a, const uint32_t* b) {
    asm volatile(
        "mma.sync.aligned.m16n8k16.row.col.f32.bf16.bf16.f32 "
        "{%0,%1,%2,%3}, {%4,%5,%6,%7}, {%8,%9}, {%0,%1,%2,%3};"
        : "+f"(c[0]), "+f"(c[1]), "+f"(c[2]), "+f"(c[3])
        : "r"(a[0]), "r"(a[1]), "r"(a[2]), "r"(a[3]), "r"(b[0]), "r"(b[1]));
}
__device__ __forceinline__ uint32_t pack_bf16(float x, float y) {
    __nv_bfloat162 t = __floats2bfloat162_rn(x, y);
    return *(uint32_t*)&t;
}

// ================= fp32 -> bf16 hi/lo split conversion =====================
__global__ void __launch_bounds__(256) split_kernel(
    const float* __restrict__ in, __nv_bfloat16* __restrict__ hi,
    __nv_bfloat16* __restrict__ lo, int n4)
{
    int i = blockIdx.x * blockDim.x + threadIdx.x;
    if (i >= n4) return;
    float4 v = ((const float4*)in)[i];
    __nv_bfloat16 h0 = __float2bfloat16(v.x), h1 = __float2bfloat16(v.y);
    __nv_bfloat16 h2 = __float2bfloat16(v.z), h3 = __float2bfloat16(v.w);
    __nv_bfloat16 l0 = __float2bfloat16(v.x - __bfloat162float(h0));
    __nv_bfloat16 l1 = __float2bfloat16(v.y - __bfloat162float(h1));
    __nv_bfloat16 l2 = __float2bfloat16(v.z - __bfloat162float(h2));
    __nv_bfloat16 l3 = __float2bfloat16(v.w - __bfloat162float(h3));
    ((__nv_bfloat162*)hi)[2 * i]     = __nv_bfloat162(h0, h1);
    ((__nv_bfloat162*)hi)[2 * i + 1] = __nv_bfloat162(h2, h3);
    ((__nv_bfloat162*)lo)[2 * i]     = __nv_bfloat162(l0, l1);
    ((__nv_bfloat162*)lo)[2 * i + 1] = __nv_bfloat162(l2, l3);
}

// ========= mma.sync bf16-split GEMM: C[M,N] = A[M,K]*B[N,K]^T (fp32) =======
#define GBM 128
#define GBN 128
#define GBK 32
#define GNK (KTOT / GBK)       // 64
#define LDA 40
#define TILE_EL  (GBM * LDA)
#define STAGE_EL (4 * TILE_EL)
#define GEMM_SMEM (2 * STAGE_EL * 2)

__device__ __forceinline__ void gemm_load_stage(
    uint32_t sb, int tid, int k0,
    const __nv_bfloat16* gAhi, const __nv_bfloat16* gAlo,
    const __nv_bfloat16* gBhi, const __nv_bfloat16* gBlo)
{
#pragma unroll
    for (int i = 0; i < 2; ++i) {
        int ch = tid + i * 256;
        int r = ch >> 2, sg = ch & 3;
        uint32_t so = (uint32_t)((r * LDA + sg * 8) * 2);
        size_t go = (size_t)r * KTOT + k0 + sg * 8;
        cp16(sb + 0 * TILE_EL * 2 + so, gAhi + go);
        cp16(sb + 1 * TILE_EL * 2 + so, gAlo + go);
        cp16(sb + 2 * TILE_EL * 2 + so, gBhi + go);
        cp16(sb + 3 * TILE_EL * 2 + so, gBlo + go);
    }
    CP_COMMIT();
}

__global__ void __launch_bounds__(256, 2) gemm_mma_kernel(
    const __nv_bfloat16* __restrict__ Ahi, const __nv_bfloat16* __restrict__ Alo,
    const __nv_bfloat16* __restrict__ Bhi, const __nv_bfloat16* __restrict__ Blo,
    float* __restrict__ C, int N)
{
    extern __shared__ __nv_bfloat16 smem[];
    const uint32_t sbase = smem_u32(smem);
    const int tid = threadIdx.x;
    const int lane = tid & 31, wid = tid >> 5;
    const int wm = wid >> 2, wn = wid & 3;
    const int m0 = blockIdx.y * GBM;
    const int n0 = blockIdx.x * GBN;

    const __nv_bfloat16* gAhi = Ahi + (size_t)m0 * KTOT;
    const __nv_bfloat16* gAlo = Alo + (size_t)m0 * KTOT;
    const __nv_bfloat16* gBhi = Bhi + (size_t)n0 * KTOT;
    const __nv_bfloat16* gBlo = Blo + (size_t)n0 * KTOT;

    float acc[4][4][4];
#pragma unroll
    for (int mi = 0; mi < 4; ++mi)
#pragma unroll
        for (int nj = 0; nj < 4; ++nj)
#pragma unroll
            for (int e = 0; e < 4; ++e) acc[mi][nj][e] = 0.f;

    const int arow = wm * 64 + (lane & 15);
    const uint32_t aoffbase = (uint32_t)(arow * LDA * 2) + ((lane >> 4) << 4);
    const int g = lane >> 3;
    const int brow = wn * 32 + (lane & 7) + ((g >> 1) << 3);
    const uint32_t boffbase = (uint32_t)(brow * LDA * 2) + ((g & 1) << 4);

    gemm_load_stage(sbase, tid, 0, gAhi, gAlo, gBhi, gBlo);
    gemm_load_stage(sbase + STAGE_EL * 2, tid, GBK, gAhi, gAlo, gBhi, gBlo);

    for (int kt = 0; kt < GNK; ++kt) {
        const int buf = kt & 1;
        CP_WAIT1();
        __syncthreads();

        const uint32_t st   = sbase + (uint32_t)buf * STAGE_EL * 2;
        const uint32_t sAhi = st;
        const uint32_t sAlo = st + TILE_EL * 2;
        const uint32_t sBhi = st + 2 * TILE_EL * 2;
        const uint32_t sBlo = st + 3 * TILE_EL * 2;

#pragma unroll
        for (int kk = 0; kk < GBK; kk += 16) {
            const uint32_t akk = aoffbase + kk * 2;
            const uint32_t bkk = boffbase + kk * 2;
            uint32_t b_hi[4][2], b_lo[4][2];
#pragma unroll
            for (int nt = 0; nt < 2; ++nt) {
                uint32_t r[4];
                ldsm_x4(r, sBhi + bkk + nt * 16 * LDA * 2);
                b_hi[2 * nt][0] = r[0]; b_hi[2 * nt][1] = r[1];
                b_hi[2 * nt + 1][0] = r[2]; b_hi[2 * nt + 1][1] = r[3];
                ldsm_x4(r, sBlo + bkk + nt * 16 * LDA * 2);
                b_lo[2 * nt][0] = r[0]; b_lo[2 * nt][1] = r[1];
                b_lo[2 * nt + 1][0] = r[2]; b_lo[2 * nt + 1][1] = r[3];
            }
#pragma unroll
            for (int mi = 0; mi < 4; ++mi) {
                uint32_t a_hi[4], a_lo[4];
                ldsm_x4(a_hi, sAhi + akk + mi * 16 * LDA * 2);
                ldsm_x4(a_lo, sAlo + akk + mi * 16 * LDA * 2);
#pragma unroll
                for (int nj = 0; nj < 4; ++nj) {
                    mma16816(acc[mi][nj], a_hi, b_hi[nj]);
                    mma16816(acc[mi][nj], a_hi, b_lo[nj]);
                    mma16816(acc[mi][nj], a_lo, b_hi[nj]);
                }
            }
        }
        __syncthreads();
        if (kt + 2 < GNK)
            gemm_load_stage(st, tid, (kt + 2) * GBK, gAhi, gAlo, gBhi, gBlo);
    }

#pragma unroll
    for (int mi = 0; mi < 4; ++mi) {
        int r0 = m0 + wm * 64 + mi * 16 + (lane >> 2);
#pragma unroll
        for (int nj = 0; nj < 4; ++nj) {
            int c = n0 + wn * 32 + nj * 8 + ((lane & 3) << 1);
            *(float2*)&C[(size_t)r0 * N + c]       = make_float2(acc[mi][nj][0], acc[mi][nj][1]);
            *(float2*)&C[(size_t)(r0 + 8) * N + c] = make_float2(acc[mi][nj][2], acc[mi][nj][3]);
        }
    }
}

// -------- fused RMSNorm + RoPE (+ gain/scale), writes bf16 hi/lo -----------
// in: [NTOK][stride] at column offset base (fused QKV layout)
__global__ void __launch_bounds__(128) normrope_kernel(
    const float* __restrict__ in, int stride, int base,
    __nv_bfloat16* __restrict__ ohi, __nv_bfloat16* __restrict__ olo,
    const float* __restrict__ gain, int nheads, float extra_scale)
{
    const int idx = blockIdx.x;
    const int h = idx % nheads;
    const int token = idx / nheads;
    const int b = token / TT, t = token % TT;
    const int d = threadIdx.x;

    float v = in[(size_t)token * stride + base + h * HD + d];

    float ss = v * v;
#pragma unroll
    for (int o = 16; o > 0; o >>= 1) ss += __shfl_xor_sync(0xffffffff, ss, o);

    __shared__ float wsum[4];
    __shared__ float sh[HD];
    if ((d & 31) == 0) wsum[d >> 5] = ss;
    __syncthreads();
    float tot = wsum[0] + wsum[1] + wsum[2] + wsum[3];
    float rms = rsqrtf(tot * (1.0f / HD) + RMS_EPS);
    float nv = v * rms;
    sh[d] = nv;
    __syncthreads();
    float partner = (d < 64) ? -sh[d + 64] : sh[d - 64];

    int fi = d & 63;
    float inv_freq = 1.0f / powf(10000.0f, (float)fi * (1.0f / 64.0f));
    float ang = (float)t * inv_freq;
    float s, c;
    sincosf(ang, &s, &c);
    float r = nv * c + partner * s;
    float gn = gain ? gain[h] : 1.0f;
    r *= gn * extra_scale;

    size_t off = (((size_t)b * nheads + h) * TT + t) * HD + d;
    __nv_bfloat16 hi = __float2bfloat16(r);
    __nv_bfloat16 lo = __float2bfloat16(r - __bfloat162float(hi));
    ohi[off] = hi;
    olo[off] = lo;
}

// -------- V: [NTOK][stride] @base fp32 -> [B][KVH][T][HD] bf16 hi/lo -------
__global__ void __launch_bounds__(256) vtrans_kernel(
    const float* __restrict__ in, int stride, int base,
    __nv_bfloat16* __restrict__ ohi, __nv_bfloat16* __restrict__ olo)
{
    int f4 = blockIdx.x * blockDim.x + threadIdx.x;
    const int total4 = NTOK * KVD / 4;
    if (f4 >= total4) return;
    int dc = f4 & (HD / 4 - 1);
    int rest = f4 / (HD / 4);
    int hk = rest % KVH;
    int token = rest / KVH;
    int b = token / TT, t = token % TT;
    float4 v = *(const float4*)&in[(size_t)token * stride + base + hk * HD + dc * 4];
    __nv_bfloat16 h0 = __float2bfloat16(v.x), h1 = __float2bfloat16(v.y);
    __nv_bfloat16 h2 = __float2bfloat16(v.z), h3 = __float2bfloat16(v.w);
    __nv_bfloat16 l0 = __float2bfloat16(v.x - __bfloat162float(h0));
    __nv_bfloat16 l1 = __float2bfloat16(v.y - __bfloat162float(h1));
    __nv_bfloat16 l2 = __float2bfloat16(v.z - __bfloat162float(h2));
    __nv_bfloat16 l3 = __float2bfloat16(v.w - __bfloat162float(h3));
    size_t o2 = ((((size_t)b * KVH + hk) * TT + t) * HD) / 2 + dc * 2;
    ((__nv_bfloat162*)ohi)[o2]     = __nv_bfloat162(h0, h1);
    ((__nv_bfloat162*)ohi)[o2 + 1] = __nv_bfloat162(h2, h3);
    ((__nv_bfloat162*)olo)[o2]     = __nv_bfloat162(l0, l1);
    ((__nv_bfloat162*)olo)[o2 + 1] = __nv_bfloat162(l2, l3);
}

// ============ tensor-core causal flash attention (bf16-split) ==============
#define FBM 128
#define FBN 64
#define LDQ 136
#define QSZB   (FBM * LDQ * 2)
#define KTILEB (FBN * LDQ * 2)
#define STAGEB (4 * KTILEB)
#define FATT_SMEM (2 * QSZB + 2 * STAGEB)

__device__ __forceinline__ void fatt_load_kv(
    uint32_t st, int tid,
    const __nv_bfloat16* kp_hi, const __nv_bfloat16* kp_lo,
    const __nv_bfloat16* vp_hi, const __nv_bfloat16* vp_lo, int kb)
{
    const size_t base = (size_t)kb * FBN * HD;
#pragma unroll
    for (int i = 0; i < 4; ++i) {
        int ch = tid + i * 256;
        int row = ch >> 4, seg = ch & 15;
        uint32_t so = (uint32_t)(row * (LDQ * 2) + seg * 16);
        size_t go = base + (size_t)row * HD + seg * 8;
        cp16(st + 0 * KTILEB + so, kp_hi + go);
        cp16(st + 1 * KTILEB + so, kp_lo + go);
        cp16(st + 2 * KTILEB + so, vp_hi + go);
        cp16(st + 3 * KTILEB + so, vp_lo + go);
    }
    CP_COMMIT();
}

__global__ void __launch_bounds__(256, 1) fattn_kernel(
    const __nv_bfloat16* __restrict__ Qhi, const __nv_bfloat16* __restrict__ Qlo,
    const __nv_bfloat16* __restrict__ Khi, const __nv_bfloat16* __restrict__ Klo,
    const __nv_bfloat16* __restrict__ Vhi, const __nv_bfloat16* __restrict__ Vlo,
    __nv_bfloat16* __restrict__ Yhi, __nv_bfloat16* __restrict__ Ylo)
{
    extern __shared__ char smraw[];
    const uint32_t sb = smem_u32(smraw);
    const uint32_t sQh = sb, sQl = sb + QSZB;
    const uint32_t sSt = sb + 2 * QSZB;

    const int tid = threadIdx.x;
    const int lane = tid & 31, wid = tid >> 5;
    const int qb = (int)(gridDim.x - 1 - blockIdx.x);
    const int h  = blockIdx.y;
    const int b  = blockIdx.z;
    const int hk = h / (HN / KVH);
    const int nkb = 2 * qb + 2;

    const __nv_bfloat16* qp_hi = Qhi + ((((size_t)b * HN + h) * TT) + (size_t)qb * FBM) * HD;
    const __nv_bfloat16* qp_lo = Qlo + ((((size_t)b * HN + h) * TT) + (size_t)qb * FBM) * HD;
    const __nv_bfloat16* kp_hi = Khi + (((size_t)b * KVH + hk) * TT) * HD;
    const __nv_bfloat16* kp_lo = Klo + (((size_t)b * KVH + hk) * TT) * HD;
    const __nv_bfloat16* vp_hi = Vhi + (((size_t)b * KVH + hk) * TT) * HD;
    const __nv_bfloat16* vp_lo = Vlo + (((size_t)b * KVH + hk) * TT) * HD;

#pragma unroll
    for (int i = 0; i < 8; ++i) {
        int ch = tid + i * 256;
        int row = ch >> 4, seg = ch & 15;
        uint32_t so = (uint32_t)(row * (LDQ * 2) + seg * 16);
        size_t go = (size_t)row * HD + seg * 8;
        cp16(sQh + so, qp_hi + go);
        cp16(sQl + so, qp_lo + go);
    }
    fatt_load_kv(sSt, tid, kp_hi, kp_lo, vp_hi, vp_lo, 0);
    if (nkb > 1)
        fatt_load_kv(sSt + STAGEB, tid, kp_hi, kp_lo, vp_hi, vp_lo, 1);

    const uint32_t aoff = (uint32_t)((wid * 16 + (lane & 15)) * (LDQ * 2)) + ((lane >> 4) << 4);
    const int g = lane >> 3;
    const uint32_t boff = (uint32_t)(((lane & 7) + ((g >> 1) << 3)) * (LDQ * 2)) + ((g & 1) << 4);
    const uint32_t voff = (uint32_t)((lane & 15) * (LDQ * 2)) + (((lane >> 4) & 1) << 4);

    float o[16][4];
#pragma unroll
    for (int nf = 0; nf < 16; ++nf)
#pragma unroll
        for (int e = 0; e < 4; ++e) o[nf][e] = 0.f;
    float m_i[2] = {-1e30f, -1e30f};
    float l_i[2] = {0.f, 0.f};

    const int qrow0 = qb * FBM + wid * 16 + (lane >> 2);

    for (int kb = 0; kb < nkb; ++kb) {
        const int buf = kb & 1;
        if (kb + 1 < nkb) { CP_WAIT1(); } else { CP_WAIT0(); }
        __syncthreads();

        const uint32_t sKh = sSt + (uint32_t)buf * STAGEB;
        const uint32_t sKl = sKh + KTILEB;
        const uint32_t sVh = sKh + 2 * KTILEB;
        const uint32_t sVl = sKh + 3 * KTILEB;

        float s[8][4];
#pragma unroll
        for (int j = 0; j < 8; ++j)
#pragma unroll
            for (int e = 0; e < 4; ++e) s[j][e] = 0.f;

#pragma unroll
        for (int kc = 0; kc < 8; ++kc) {
            uint32_t aq_hi[4], aq_lo[4];
            ldsm_x4(aq_hi, sQh + aoff + kc * 32);
            ldsm_x4(aq_lo, sQl + aoff + kc * 32);
#pragma unroll
            for (int n16 = 0; n16 < 4; ++n16) {
                uint32_t bh[4], bl[4];
                ldsm_x4(bh, sKh + boff + n16 * 16 * (LDQ * 2) + kc * 32);
                ldsm_x4(bl, sKl + boff + n16 * 16 * (LDQ * 2) + kc * 32);
                mma16816(s[2 * n16],     aq_hi, &bh[0]);
                mma16816(s[2 * n16],     aq_hi, &bl[0]);
                mma16816(s[2 * n16],     aq_lo, &bh[0]);
                mma16816(s[2 * n16 + 1], aq_hi, &bh[2]);
                mma16816(s[2 * n16 + 1], aq_hi, &bl[2]);
                mma16816(s[2 * n16 + 1], aq_lo, &bh[2]);
            }
        }

        if (kb >= nkb - 2) {
            const int kc0 = kb * FBN + 2 * (lane & 3);
#pragma unroll
            for (int j = 0; j < 8; ++j)
#pragma unroll
                for (int e = 0; e < 4; ++e) {
                    int row = qrow0 + (e >> 1) * 8;
                    int col = kc0 + 8 * j + (e & 1);
                    if (col > row) s[j][e] = -1e30f;
                }
        }

        float alpha[2];
#pragma unroll
        for (int rr = 0; rr < 2; ++rr) {
            float mx = m_i[rr];
#pragma unroll
            for (int j = 0; j < 8; ++j)
                mx = fmaxf(mx, fmaxf(s[j][2 * rr], s[j][2 * rr + 1]));
            mx = fmaxf(mx, __shfl_xor_sync(0xffffffff, mx, 1));
            mx = fmaxf(mx, __shfl_xor_sync(0xffffffff, mx, 2));
            alpha[rr] = __expf(m_i[rr] - mx);
            float lsum = 0.f;
#pragma unroll
            for (int j = 0; j < 8; ++j) {
                float p0 = __expf(s[j][2 * rr] - mx);
                float p1 = __expf(s[j][2 * rr + 1] - mx);
                s[j][2 * rr] = p0; s[j][2 * rr + 1] = p1;
                lsum += p0 + p1;
            }
            m_i[rr] = mx;
            l_i[rr] = l_i[rr] * alpha[rr] + lsum;
        }
#pragma unroll
        for (int nf = 0; nf < 16; ++nf) {
            o[nf][0] *= alpha[0]; o[nf][1] *= alpha[0];
            o[nf][2] *= alpha[1]; o[nf][3] *= alpha[1];
        }

#pragma unroll
        for (int kc2 = 0; kc2 < 4; ++kc2) {
            const int j0 = 2 * kc2, j1 = 2 * kc2 + 1;
            uint32_t ap_hi[4], ap_lo[4];
            {
                float v00 = s[j0][0], v01 = s[j0][1], v02 = s[j0][2], v03 = s[j0][3];
                float v10 = s[j1][0], v11 = s[j1][1], v12 = s[j1][2], v13 = s[j1][3];
                float h00 = __bfloat162float(__float2bfloat16(v00));
                float h01 = __bfloat162float(__float2bfloat16(v01));
                float h02 = __bfloat162float(__float2bfloat16(v02));
                float h03 = __bfloat162float(__float2bfloat16(v03));
                float h10 = __bfloat162float(__float2bfloat16(v10));
                float h11 = __bfloat162float(__float2bfloat16(v11));
                float h12 = __bfloat162float(__float2bfloat16(v12));
                float h13 = __bfloat162float(__float2bfloat16(v13));
                ap_hi[0] = pack_bf16(h00, h01);
                ap_hi[1] = pack_bf16(h02, h03);
                ap_hi[2] = pack_bf16(h10, h11);
                ap_hi[3] = pack_bf16(h12, h13);
                ap_lo[0] = pack_bf16(v00 - h00, v01 - h01);
                ap_lo[1] = pack_bf16(v02 - h02, v03 - h03);
                ap_lo[2] = pack_bf16(v10 - h10, v11 - h11);
                ap_lo[3] = pack_bf16(v12 - h12, v13 - h13);
            }
            const uint32_t vrow = voff + kc2 * 16 * (LDQ * 2);
#pragma unroll
            for (int nf16 = 0; nf16 < 8; ++nf16) {
                uint32_t bvh[4], bvl[4];
                ldsm_x4_t(bvh, sVh + vrow + nf16 * 32);
                ldsm_x4_t(bvl, sVl + vrow + nf16 * 32);
                mma16816(o[2 * nf16],     ap_hi, &bvh[0]);
                mma16816(o[2 * nf16],     ap_lo, &bvh[0]);
                mma16816(o[2 * nf16],     ap_hi, &bvl[0]);
                mma16816(o[2 * nf16 + 1], ap_hi, &bvh[2]);
                mma16816(o[2 * nf16 + 1], ap_lo, &bvh[2]);
                mma16816(o[2 * nf16 + 1], ap_hi, &bvl[2]);
            }
        }

        __syncthreads();
        if (kb + 2 < nkb)
            fatt_load_kv(sSt + (uint32_t)buf * STAGEB, tid,
                         kp_hi, kp_lo, vp_hi, vp_lo, kb + 2);
    }

#pragma unroll
    for (int rr = 0; rr < 2; ++rr) {
        float lf = l_i[rr];
        lf += __shfl_xor_sync(0xffffffff, lf, 1);
        lf += __shfl_xor_sync(0xffffffff, lf, 2);
        float inv = 1.0f / lf;
        int trow = qrow0 + rr * 8;
        size_t rbase = ((size_t)(b * TT + trow)) * DD + h * HD + 2 * (lane & 3);
#pragma unroll
        for (int nf = 0; nf < 16; ++nf) {
            float v0 = o[nf][2 * rr] * inv;
            float v1 = o[nf][2 * rr + 1] * inv;
            __nv_bfloat16 h0 = __float2bfloat16(v0);
            __nv_bfloat16 h1 = __float2bfloat16(v1);
            __nv_bfloat16 l0 = __float2bfloat16(v0 - __bfloat162float(h0));
            __nv_bfloat16 l1 = __float2bfloat16(v1 - __bfloat162float(h1));
            *(__nv_bfloat162*)&Yhi[rbase + nf * 8] = __nv_bfloat162(h0, h1);
            *(__nv_bfloat162*)&Ylo[rbase + nf * 8] = __nv_bfloat162(l0, l1);
        }
    }
}

// ---------------------------- launch ---------------------------------------
static inline void split(const float* src, __nv_bfloat16* hi, __nv_bfloat16* lo,
                         size_t n)
{
    int n4 = (int)(n / 4);
    split_kernel<<<(n4 + 255) / 256, 256>>>(src, hi, lo, n4);
}

extern "C" void kernel_launch(void* const* d_in, const int* in_sizes, int n_in,
                              void* d_out, int out_size)
{
    const float* x   = (const float*)d_in[0];
    const float* Wq  = (const float*)d_in[1];
    const float* Wk  = (const float*)d_in[2];
    const float* Wv  = (const float*)d_in[3];
    const float* Wp  = (const float*)d_in[4];
    const float* qg  = (const float*)d_in[5];
    float* out = (float*)d_out;

    float* tmp;
    cudaGetSymbolAddress((void**)&tmp, g_tmp);

    __nv_bfloat16 *xhi, *xlo, *wchi, *wclo, *wphi, *wplo, *yhi, *ylo;
    __nv_bfloat16 *qhi, *qlo, *khi, *klo, *vhi, *vlo;
    cudaGetSymbolAddress((void**)&xhi, g_xhi);   cudaGetSymbolAddress((void**)&xlo, g_xlo);
    cudaGetSymbolAddress((void**)&wchi, g_wchi); cudaGetSymbolAddress((void**)&wclo, g_wclo);
    cudaGetSymbolAddress((void**)&wphi, g_wphi); cudaGetSymbolAddress((void**)&wplo, g_wplo);
    cudaGetSymbolAddress((void**)&yhi, g_yhi);   cudaGetSymbolAddress((void**)&ylo, g_ylo);
    cudaGetSymbolAddress((void**)&qhi, g_qhi);   cudaGetSymbolAddress((void**)&qlo, g_qlo);
    cudaGetSymbolAddress((void**)&khi, g_khi);   cudaGetSymbolAddress((void**)&klo, g_klo);
    cudaGetSymbolAddress((void**)&vhi, g_vhi);   cudaGetSymbolAddress((void**)&vlo, g_vlo);

    cudaFuncSetAttribute(gemm_mma_kernel,
                         cudaFuncAttributeMaxDynamicSharedMemorySize, GEMM_SMEM);
    cudaFuncSetAttribute(fattn_kernel,
                         cudaFuncAttributeMaxDynamicSharedMemorySize, FATT_SMEM);

    const float qscale = 1.0f / sqrtf((float)HD);

    // hi/lo splits: x, combined W = [Wq; Wk; Wv] (row-contiguous), Wp
    split(x,  xhi,  xlo,  (size_t)NTOK * KTOT);
    split(Wq, wchi,                          wclo,                          (size_t)DD * KTOT);
    split(Wk, wchi + (size_t)DD * KTOT,      wclo + (size_t)DD * KTOT,      (size_t)KVD * KTOT);
    split(Wv, wchi + (size_t)(DD+KVD)*KTOT,  wclo + (size_t)(DD+KVD)*KTOT,  (size_t)KVD * KTOT);
    split(Wp, wphi, wplo, (size_t)DD * KTOT);

    // fused QKV projection: tmp[NTOK][3072]
    gemm_mma_kernel<<<dim3(QKVN / GBN, NTOK / GBM), 256, GEMM_SMEM>>>(
        xhi, xlo, wchi, wclo, tmp, QKVN);

    // epilogues
    normrope_kernel<<<NTOK * HN, 128>>>(tmp, QKVN, 0,       qhi, qlo, qg, HN, qscale);
    normrope_kernel<<<NTOK * KVH, 128>>>(tmp, QKVN, DD,     khi, klo, nullptr, KVH, 1.0f);
    vtrans_kernel<<<(NTOK * KVD / 4 + 255) / 256, 256>>>(tmp, QKVN, DD + KVD, vhi, vlo);

    // tensor-core causal flash attention -> y bf16 hi/lo
    fattn_kernel<<<dim3(TT / FBM, HN, BB), 256, FATT_SMEM>>>(
        qhi, qlo, khi, klo, vhi, vlo, yhi, ylo);

    // output projection
    gemm_mma_kernel<<<dim3(DD / GBN, NTOK / GBM), 256, GEMM_SMEM>>>(
        yhi, ylo, wphi, wplo, out, DD);
}

// round 6
// speedup vs baseline: 3.5564x; 1.0540x over previous
#include <cuda_runtime.h>
#include <cuda_bf16.h>
#include <cstdint>
#include <math.h>

// Problem constants
#define HN   16          // num_heads
#define KVH  4           // num_kv_heads
#define HD   128         // head_dim
#define BB   4           // batch
#define TT   2048        // seq len
#define DD   (HN*HD)     // 2048
#define KVD  (KVH*HD)    // 512
#define NTOK (BB*TT)     // 8192
#define KTOT DD          // inner dim of all GEMMs = 2048
#define QKVN (DD + 2*KVD)  // 3072 fused projection width
#define RMS_EPS 1.1920928955078125e-07f

// ---------------- scratch (device globals: allocation-free) ----------------
// bf16 hi/lo split operands for GEMMs
__device__ __nv_bfloat16 g_xhi[(size_t)NTOK * KTOT], g_xlo[(size_t)NTOK * KTOT];
__device__ __nv_bfloat16 g_wchi[(size_t)QKVN * KTOT], g_wclo[(size_t)QKVN * KTOT]; // Wq|Wk|Wv
__device__ __nv_bfloat16 g_wphi[(size_t)DD * KTOT],  g_wplo[(size_t)DD * KTOT];
__device__ __nv_bfloat16 g_yhi[(size_t)NTOK * KTOT], g_ylo[(size_t)NTOK * KTOT];

// bf16 hi/lo Q/K/V for tensor-core attention
__device__ __nv_bfloat16 g_qhi[(size_t)BB * HN  * TT * HD], g_qlo[(size_t)BB * HN  * TT * HD];
__device__ __nv_bfloat16 g_khi[(size_t)BB * KVH * TT * HD], g_klo[(size_t)BB * KVH * TT * HD];
__device__ __nv_bfloat16 g_vhi[(size_t)BB * KVH * TT * HD], g_vlo[(size_t)BB * KVH * TT * HD];

// ======================= PTX helpers (baseline compute_103) ================
__device__ __forceinline__ uint32_t smem_u32(const void* p) {
    uint32_t a;
    asm("{ .reg .u64 t; cvta.to.shared.u64 t, %1; cvt.u32.u64 %0, t; }"
        : "=r"(a) : "l"(p));
    return a;
}
__device__ __forceinline__ void cp16(uint32_t dst, const void* src) {
    asm volatile("cp.async.cg.shared.global [%0], [%1], 16;" :: "r"(dst), "l"(src));
}
#define CP_COMMIT() asm volatile("cp.async.commit_group;" ::: "memory")
#define CP_WAIT1()  asm volatile("cp.async.wait_group 1;" ::: "memory")
#define CP_WAIT0()  asm volatile("cp.async.wait_group 0;" ::: "memory")

__device__ __forceinline__ void ldsm_x4(uint32_t* r, uint32_t addr) {
    asm volatile("ldmatrix.sync.aligned.m8n8.x4.shared.b16 {%0,%1,%2,%3}, [%4];"
                 : "=r"(r[0]), "=r"(r[1]), "=r"(r[2]), "=r"(r[3]) : "r"(addr));
}
__device__ __forceinline__ void ldsm_x4_t(uint32_t* r, uint32_t addr) {
    asm volatile("ldmatrix.sync.aligned.m8n8.x4.trans.shared.b16 {%0,%1,%2,%3}, [%4];"
                 : "=r"(r[0]), "=r"(r[1]), "=r"(r[2]), "=r"(r[3]) : "r"(addr));
}
__device__ __forceinline__ void mma16816(float* c, const uint32_t* a, const uint32_t* b) {
    asm volatile(
        "mma.sync.aligned.m16n8k16.row.col.f32.bf16.bf16.f32 "
        "{%0,%1,%2,%3}, {%4,%5,%6,%7}, {%8,%9}, {%0,%1,%2,%3};"
        : "+f"(c[0]), "+f"(c[1]), "+f"(c[2]), "+f"(c[3])
        : "r"(a[0]), "r"(a[1]), "r"(a[2]), "r"(a[3]), "r"(b[0]), "r"(b[1]));
}
__device__ __forceinline__ uint32_t pack_bf16(float x, float y) {
    __nv_bfloat162 t = __floats2bfloat162_rn(x, y);
    return *(uint32_t*)&t;
}

// ================= fp32 -> bf16 hi/lo split conversion (MLP=2) =============
__global__ void __launch_bounds__(256) split_kernel(
    const float* __restrict__ in, __nv_bfloat16* __restrict__ hi,
    __nv_bfloat16* __restrict__ lo, int n4)
{
    const int half = n4 >> 1;
    int i = blockIdx.x * blockDim.x + threadIdx.x;
    if (i >= half) return;
    float4 v0 = ((const float4*)in)[i];
    float4 v1 = ((const float4*)in)[i + half];
#pragma unroll
    for (int s = 0; s < 2; ++s) {
        float4 v = s ? v1 : v0;
        int j = s ? (i + half) : i;
        __nv_bfloat16 h0 = __float2bfloat16(v.x), h1 = __float2bfloat16(v.y);
        __nv_bfloat16 h2 = __float2bfloat16(v.z), h3 = __float2bfloat16(v.w);
        __nv_bfloat16 l0 = __float2bfloat16(v.x - __bfloat162float(h0));
        __nv_bfloat16 l1 = __float2bfloat16(v.y - __bfloat162float(h1));
        __nv_bfloat16 l2 = __float2bfloat16(v.z - __bfloat162float(h2));
        __nv_bfloat16 l3 = __float2bfloat16(v.w - __bfloat162float(h3));
        ((__nv_bfloat162*)hi)[2 * j]     = __nv_bfloat162(h0, h1);
        ((__nv_bfloat162*)hi)[2 * j + 1] = __nv_bfloat162(h2, h3);
        ((__nv_bfloat162*)lo)[2 * j]     = __nv_bfloat162(l0, l1);
        ((__nv_bfloat162*)lo)[2 * j + 1] = __nv_bfloat162(l2, l3);
    }
}

// ========= mma.sync bf16-split GEMM: C[M,N] = A[M,K]*B[N,K]^T ==============
// MODE 0: plain fp32 C store.  MODE 1: fused QKV epilogue (RMSNorm+RoPE+split).
#define GBM 128
#define GBN 128
#define GBK 32
#define GNK (KTOT / GBK)       // 64
#define LDA 40
#define TILE_EL  (GBM * LDA)
#define STAGE_EL (4 * TILE_EL)
#define GEMM_SMEM (2 * STAGE_EL * 2)   // 81920 bytes
#define LDC 132                        // epilogue fp32 tile stride

__device__ __forceinline__ void gemm_load_stage(
    uint32_t sb, int tid, int k0,
    const __nv_bfloat16* gAhi, const __nv_bfloat16* gAlo,
    const __nv_bfloat16* gBhi, const __nv_bfloat16* gBlo)
{
#pragma unroll
    for (int i = 0; i < 2; ++i) {
        int ch = tid + i * 256;
        int r = ch >> 2, sg = ch & 3;
        uint32_t so = (uint32_t)((r * LDA + sg * 8) * 2);
        size_t go = (size_t)r * KTOT + k0 + sg * 8;
        cp16(sb + 0 * TILE_EL * 2 + so, gAhi + go);
        cp16(sb + 1 * TILE_EL * 2 + so, gAlo + go);
        cp16(sb + 2 * TILE_EL * 2 + so, gBhi + go);
        cp16(sb + 3 * TILE_EL * 2 + so, gBlo + go);
    }
    CP_COMMIT();
}

template<int MODE>
__global__ void __launch_bounds__(256, 2) gemm_mma_kernel(
    const __nv_bfloat16* __restrict__ Ahi, const __nv_bfloat16* __restrict__ Alo,
    const __nv_bfloat16* __restrict__ Bhi, const __nv_bfloat16* __restrict__ Blo,
    float* __restrict__ C, int N,
    __nv_bfloat16* __restrict__ qhi, __nv_bfloat16* __restrict__ qlo,
    __nv_bfloat16* __restrict__ khi, __nv_bfloat16* __restrict__ klo,
    __nv_bfloat16* __restrict__ vhi, __nv_bfloat16* __restrict__ vlo,
    const float* __restrict__ qg, float qscale)
{
    extern __shared__ __nv_bfloat16 smem[];
    const uint32_t sbase = smem_u32(smem);
    const int tid = threadIdx.x;
    const int lane = tid & 31, wid = tid >> 5;
    const int wm = wid >> 2, wn = wid & 3;
    const int m0 = blockIdx.y * GBM;
    const int n0 = blockIdx.x * GBN;

    const __nv_bfloat16* gAhi = Ahi + (size_t)m0 * KTOT;
    const __nv_bfloat16* gAlo = Alo + (size_t)m0 * KTOT;
    const __nv_bfloat16* gBhi = Bhi + (size_t)n0 * KTOT;
    const __nv_bfloat16* gBlo = Blo + (size_t)n0 * KTOT;

    float acc[4][4][4];
#pragma unroll
    for (int mi = 0; mi < 4; ++mi)
#pragma unroll
        for (int nj = 0; nj < 4; ++nj)
#pragma unroll
            for (int e = 0; e < 4; ++e) acc[mi][nj][e] = 0.f;

    const int arow = wm * 64 + (lane & 15);
    const uint32_t aoffbase = (uint32_t)(arow * LDA * 2) + ((lane >> 4) << 4);
    const int g = lane >> 3;
    const int brow = wn * 32 + (lane & 7) + ((g >> 1) << 3);
    const uint32_t boffbase = (uint32_t)(brow * LDA * 2) + ((g & 1) << 4);

    gemm_load_stage(sbase, tid, 0, gAhi, gAlo, gBhi, gBlo);
    gemm_load_stage(sbase + STAGE_EL * 2, tid, GBK, gAhi, gAlo, gBhi, gBlo);

    for (int kt = 0; kt < GNK; ++kt) {
        const int buf = kt & 1;
        if (kt + 1 < GNK) { CP_WAIT1(); } else { CP_WAIT0(); }
        __syncthreads();

        const uint32_t st   = sbase + (uint32_t)buf * STAGE_EL * 2;
        const uint32_t sAhi = st;
        const uint32_t sAlo = st + TILE_EL * 2;
        const uint32_t sBhi = st + 2 * TILE_EL * 2;
        const uint32_t sBlo = st + 3 * TILE_EL * 2;

#pragma unroll
        for (int kk = 0; kk < GBK; kk += 16) {
            const uint32_t akk = aoffbase + kk * 2;
            const uint32_t bkk = boffbase + kk * 2;
            uint32_t b_hi[4][2], b_lo[4][2];
#pragma unroll
            for (int nt = 0; nt < 2; ++nt) {
                uint32_t r[4];
                ldsm_x4(r, sBhi + bkk + nt * 16 * LDA * 2);
                b_hi[2 * nt][0] = r[0]; b_hi[2 * nt][1] = r[1];
                b_hi[2 * nt + 1][0] = r[2]; b_hi[2 * nt + 1][1] = r[3];
                ldsm_x4(r, sBlo + bkk + nt * 16 * LDA * 2);
                b_lo[2 * nt][0] = r[0]; b_lo[2 * nt][1] = r[1];
                b_lo[2 * nt + 1][0] = r[2]; b_lo[2 * nt + 1][1] = r[3];
            }
#pragma unroll
            for (int mi = 0; mi < 4; ++mi) {
                uint32_t a_hi[4], a_lo[4];
                ldsm_x4(a_hi, sAhi + akk + mi * 16 * LDA * 2);
                ldsm_x4(a_lo, sAlo + akk + mi * 16 * LDA * 2);
#pragma unroll
                for (int nj = 0; nj < 4; ++nj) {
                    mma16816(acc[mi][nj], a_hi, b_hi[nj]);
                    mma16816(acc[mi][nj], a_hi, b_lo[nj]);
                    mma16816(acc[mi][nj], a_lo, b_hi[nj]);
                }
            }
        }
        __syncthreads();
        if (kt + 2 < GNK)
            gemm_load_stage(st, tid, (kt + 2) * GBK, gAhi, gAlo, gBhi, gBlo);
    }

    if (MODE == 0) {
        // plain fp32 store
#pragma unroll
        for (int mi = 0; mi < 4; ++mi) {
            int r0 = m0 + wm * 64 + mi * 16 + (lane >> 2);
#pragma unroll
            for (int nj = 0; nj < 4; ++nj) {
                int c = n0 + wn * 32 + nj * 8 + ((lane & 3) << 1);
                *(float2*)&C[(size_t)r0 * N + c]       = make_float2(acc[mi][nj][0], acc[mi][nj][1]);
                *(float2*)&C[(size_t)(r0 + 8) * N + c] = make_float2(acc[mi][nj][2], acc[mi][nj][3]);
            }
        }
        return;
    }

    // ================= fused QKV epilogue (MODE 1) ==========================
    float* stile = (float*)smem;               // 128 x LDC fp32 tile
    float* sinv  = stile + 128 * LDC;          // 64-entry inv_freq table
    __syncthreads();                           // mainloop smem fully consumed

#pragma unroll
    for (int mi = 0; mi < 4; ++mi) {
        int r = wm * 64 + mi * 16 + (lane >> 2);
#pragma unroll
        for (int nj = 0; nj < 4; ++nj) {
            int c = wn * 32 + nj * 8 + ((lane & 3) << 1);
            stile[r * LDC + c]           = acc[mi][nj][0];
            stile[r * LDC + c + 1]       = acc[mi][nj][1];
            stile[(r + 8) * LDC + c]     = acc[mi][nj][2];
            stile[(r + 8) * LDC + c + 1] = acc[mi][nj][3];
        }
    }

    const bool isV = (n0 >= DD + KVD);
    const bool isK = (n0 >= DD) && !isV;
    if (!isV && tid < 64)
        sinv[tid] = 1.0f / powf(10000.0f, (float)tid * (1.0f / 64.0f));
    __syncthreads();

    if (!isV && tid < 128) {
        const int row = tid;
        const int t = (m0 + row) & (TT - 1);
        float ssq = 0.f;
#pragma unroll 8
        for (int d = 0; d < HD; ++d) {
            float x = stile[row * LDC + d];
            ssq += x * x;
        }
        float rms = rsqrtf(ssq * (1.0f / HD) + RMS_EPS);
        float gn = isK ? 1.0f : (qg[n0 >> 7] * qscale);
#pragma unroll 4
        for (int d = 0; d < 64; ++d) {
            float xa = stile[row * LDC + d] * rms;
            float xb = stile[row * LDC + d + 64] * rms;
            float s_, c_;
            sincosf((float)t * sinv[d], &s_, &c_);
            stile[row * LDC + d]      = (xa * c_ - xb * s_) * gn;
            stile[row * LDC + d + 64] = (xb * c_ + xa * s_) * gn;
        }
    }
    __syncthreads();

    // phase B: warp-coalesced hi/lo split store to [b, head, t, d]
    __nv_bfloat16 *dhi, *dlo;
    int hloc, nh;
    if (isV)      { hloc = (n0 - DD - KVD) >> 7; nh = KVH; dhi = vhi; dlo = vlo; }
    else if (isK) { hloc = (n0 - DD) >> 7;       nh = KVH; dhi = khi; dlo = klo; }
    else          { hloc = n0 >> 7;              nh = HN;  dhi = qhi; dlo = qlo; }

#pragma unroll
    for (int p = 0; p < 16; ++p) {
        int row = p * 8 + wid;
        int token = m0 + row;
        int b = token >> 11, t = token & (TT - 1);
        size_t off = (((size_t)b * nh + hloc) * TT + t) * HD + lane * 4;
        float v0 = stile[row * LDC + lane * 4];
        float v1 = stile[row * LDC + lane * 4 + 1];
        float v2 = stile[row * LDC + lane * 4 + 2];
        float v3 = stile[row * LDC + lane * 4 + 3];
        __nv_bfloat16 h0 = __float2bfloat16(v0), h1 = __float2bfloat16(v1);
        __nv_bfloat16 h2 = __float2bfloat16(v2), h3 = __float2bfloat16(v3);
        uint2 hv, lv;
        hv.x = pack_bf16(__bfloat162float(h0), __bfloat162float(h1));
        hv.y = pack_bf16(__bfloat162float(h2), __bfloat162float(h3));
        // pack exact hi then compute lo
        *(uint2*)&dhi[off] = *(uint2*)&(__nv_bfloat162[2]){ {h0, h1}, {h2, h3} };
        lv.x = pack_bf16(v0 - __bfloat162float(h0), v1 - __bfloat162float(h1));
        lv.y = pack_bf16(v2 - __bfloat162float(h2), v3 - __bfloat162float(h3));
        *(uint2*)&dlo[off] = lv;
        (void)hv;
    }
}

// ============ tensor-core causal flash attention (bf16-split) ==============
#define FBM 128
#define FBN 64
#define LDQ 136
#define QSZB   (FBM * LDQ * 2)
#define KTILEB (FBN * LDQ * 2)
#define STAGEB (4 * KTILEB)
#define FATT_SMEM (2 * QSZB + 2 * STAGEB)

__device__ __forceinline__ void fatt_load_kv(
    uint32_t st, int tid,
    const __nv_bfloat16* kp_hi, const __nv_bfloat16* kp_lo,
    const __nv_bfloat16* vp_hi, const __nv_bfloat16* vp_lo, int kb)
{
    const size_t base = (size_t)kb * FBN * HD;
#pragma unroll
    for (int i = 0; i < 4; ++i) {
        int ch = tid + i * 256;
        int row = ch >> 4, seg = ch & 15;
        uint32_t so = (uint32_t)(row * (LDQ * 2) + seg * 16);
        size_t go = base + (size_t)row * HD + seg * 8;
        cp16(st + 0 * KTILEB + so, kp_hi + go);
        cp16(st + 1 * KTILEB + so, kp_lo + go);
        cp16(st + 2 * KTILEB + so, vp_hi + go);
        cp16(st + 3 * KTILEB + so, vp_lo + go);
    }
    CP_COMMIT();
}

__global__ void __launch_bounds__(256, 1) fattn_kernel(
    const __nv_bfloat16* __restrict__ Qhi, const __nv_bfloat16* __restrict__ Qlo,
    const __nv_bfloat16* __restrict__ Khi, const __nv_bfloat16* __restrict__ Klo,
    const __nv_bfloat16* __restrict__ Vhi, const __nv_bfloat16* __restrict__ Vlo,
    __nv_bfloat16* __restrict__ Yhi, __nv_bfloat16* __restrict__ Ylo)
{
    extern __shared__ char smraw[];
    const uint32_t sb = smem_u32(smraw);
    const uint32_t sQh = sb, sQl = sb + QSZB;
    const uint32_t sSt = sb + 2 * QSZB;

    const int tid = threadIdx.x;
    const int lane = tid & 31, wid = tid >> 5;
    const int qb = (int)(gridDim.x - 1 - blockIdx.x);
    const int h  = blockIdx.y;
    const int b  = blockIdx.z;
    const int hk = h / (HN / KVH);
    const int nkb = 2 * qb + 2;

    const __nv_bfloat16* qp_hi = Qhi + ((((size_t)b * HN + h) * TT) + (size_t)qb * FBM) * HD;
    const __nv_bfloat16* qp_lo = Qlo + ((((size_t)b * HN + h) * TT) + (size_t)qb * FBM) * HD;
    const __nv_bfloat16* kp_hi = Khi + (((size_t)b * KVH + hk) * TT) * HD;
    const __nv_bfloat16* kp_lo = Klo + (((size_t)b * KVH + hk) * TT) * HD;
    const __nv_bfloat16* vp_hi = Vhi + (((size_t)b * KVH + hk) * TT) * HD;
    const __nv_bfloat16* vp_lo = Vlo + (((size_t)b * KVH + hk) * TT) * HD;

#pragma unroll
    for (int i = 0; i < 8; ++i) {
        int ch = tid + i * 256;
        int row = ch >> 4, seg = ch & 15;
        uint32_t so = (uint32_t)(row * (LDQ * 2) + seg * 16);
        size_t go = (size_t)row * HD + seg * 8;
        cp16(sQh + so, qp_hi + go);
        cp16(sQl + so, qp_lo + go);
    }
    fatt_load_kv(sSt, tid, kp_hi, kp_lo, vp_hi, vp_lo, 0);
    if (nkb > 1)
        fatt_load_kv(sSt + STAGEB, tid, kp_hi, kp_lo, vp_hi, vp_lo, 1);

    const uint32_t aoff = (uint32_t)((wid * 16 + (lane & 15)) * (LDQ * 2)) + ((lane >> 4) << 4);
    const int g = lane >> 3;
    const uint32_t boff = (uint32_t)(((lane & 7) + ((g >> 1) << 3)) * (LDQ * 2)) + ((g & 1) << 4);
    const uint32_t voff = (uint32_t)((lane & 15) * (LDQ * 2)) + (((lane >> 4) & 1) << 4);

    float o[16][4];
#pragma unroll
    for (int nf = 0; nf < 16; ++nf)
#pragma unroll
        for (int e = 0; e < 4; ++e) o[nf][e] = 0.f;
    float m_i[2] = {-1e30f, -1e30f};
    float l_i[2] = {0.f, 0.f};

    const int qrow0 = qb * FBM + wid * 16 + (lane >> 2);

    for (int kb = 0; kb < nkb; ++kb) {
        const int buf = kb & 1;
        if (kb + 1 < nkb) { CP_WAIT1(); } else { CP_WAIT0(); }
        __syncthreads();

        const uint32_t sKh = sSt + (uint32_t)buf * STAGEB;
        const uint32_t sKl = sKh + KTILEB;
        const uint32_t sVh = sKh + 2 * KTILEB;
        const uint32_t sVl = sKh + 3 * KTILEB;

        float s[8][4];
#pragma unroll
        for (int j = 0; j < 8; ++j)
#pragma unroll
            for (int e = 0; e < 4; ++e) s[j][e] = 0.f;

#pragma unroll
        for (int kc = 0; kc < 8; ++kc) {
            uint32_t aq_hi[4], aq_lo[4];
            ldsm_x4(aq_hi, sQh + aoff + kc * 32);
            ldsm_x4(aq_lo, sQl + aoff + kc * 32);
#pragma unroll
            for (int n16 = 0; n16 < 4; ++n16) {
                uint32_t bh[4], bl[4];
                ldsm_x4(bh, sKh + boff + n16 * 16 * (LDQ * 2) + kc * 32);
                ldsm_x4(bl, sKl + boff + n16 * 16 * (LDQ * 2) + kc * 32);
                mma16816(s[2 * n16],     aq_hi, &bh[0]);
                mma16816(s[2 * n16],     aq_hi, &bl[0]);
                mma16816(s[2 * n16],     aq_lo, &bh[0]);
                mma16816(s[2 * n16 + 1], aq_hi, &bh[2]);
                mma16816(s[2 * n16 + 1], aq_hi, &bl[2]);
                mma16816(s[2 * n16 + 1], aq_lo, &bh[2]);
            }
        }

        if (kb >= nkb - 2) {
            const int kc0 = kb * FBN + 2 * (lane & 3);
#pragma unroll
            for (int j = 0; j < 8; ++j)
#pragma unroll
                for (int e = 0; e < 4; ++e) {
                    int row = qrow0 + (e >> 1) * 8;
                    int col = kc0 + 8 * j + (e & 1);
                    if (col > row) s[j][e] = -1e30f;
                }
        }

        float alpha[2];
#pragma unroll
        for (int rr = 0; rr < 2; ++rr) {
            float mx = m_i[rr];
#pragma unroll
            for (int j = 0; j < 8; ++j)
                mx = fmaxf(mx, fmaxf(s[j][2 * rr], s[j][2 * rr + 1]));
            mx = fmaxf(mx, __shfl_xor_sync(0xffffffff, mx, 1));
            mx = fmaxf(mx, __shfl_xor_sync(0xffffffff, mx, 2));
            alpha[rr] = __expf(m_i[rr] - mx);
            float lsum = 0.f;
#pragma unroll
            for (int j = 0; j < 8; ++j) {
                float p0 = __expf(s[j][2 * rr] - mx);
                float p1 = __expf(s[j][2 * rr + 1] - mx);
                s[j][2 * rr] = p0; s[j][2 * rr + 1] = p1;
                lsum += p0 + p1;
            }
            m_i[rr] = mx;
            l_i[rr] = l_i[rr] * alpha[rr] + lsum;
        }
#pragma unroll
        for (int nf = 0; nf < 16; ++nf) {
            o[nf][0] *= alpha[0]; o[nf][1] *= alpha[0];
            o[nf][2] *= alpha[1]; o[nf][3] *= alpha[1];
        }

#pragma unroll
        for (int kc2 = 0; kc2 < 4; ++kc2) {
            const int j0 = 2 * kc2, j1 = 2 * kc2 + 1;
            uint32_t ap_hi[4], ap_lo[4];
            {
                float v00 = s[j0][0], v01 = s[j0][1], v02 = s[j0][2], v03 = s[j0][3];
                float v10 = s[j1][0], v11 = s[j1][1], v12 = s[j1][2], v13 = s[j1][3];
                float h00 = __bfloat162float(__float2bfloat16(v00));
                float h01 = __bfloat162float(__float2bfloat16(v01));
                float h02 = __bfloat162float(__float2bfloat16(v02));
                float h03 = __bfloat162float(__float2bfloat16(v03));
                float h10 = __bfloat162float(__float2bfloat16(v10));
                float h11 = __bfloat162float(__float2bfloat16(v11));
                float h12 = __bfloat162float(__float2bfloat16(v12));
                float h13 = __bfloat162float(__float2bfloat16(v13));
                ap_hi[0] = pack_bf16(h00, h01);
                ap_hi[1] = pack_bf16(h02, h03);
                ap_hi[2] = pack_bf16(h10, h11);
                ap_hi[3] = pack_bf16(h12, h13);
                ap_lo[0] = pack_bf16(v00 - h00, v01 - h01);
                ap_lo[1] = pack_bf16(v02 - h02, v03 - h03);
                ap_lo[2] = pack_bf16(v10 - h10, v11 - h11);
                ap_lo[3] = pack_bf16(v12 - h12, v13 - h13);
            }
            const uint32_t vrow = voff + kc2 * 16 * (LDQ * 2);
#pragma unroll
            for (int nf16 = 0; nf16 < 8; ++nf16) {
                uint32_t bvh[4], bvl[4];
                ldsm_x4_t(bvh, sVh + vrow + nf16 * 32);
                ldsm_x4_t(bvl, sVl + vrow + nf16 * 32);
                mma16816(o[2 * nf16],     ap_hi, &bvh[0]);
                mma16816(o[2 * nf16],     ap_lo, &bvh[0]);
                mma16816(o[2 * nf16],     ap_hi, &bvl[0]);
                mma16816(o[2 * nf16 + 1], ap_hi, &bvh[2]);
                mma16816(o[2 * nf16 + 1], ap_lo, &bvh[2]);
                mma16816(o[2 * nf16 + 1], ap_hi, &bvl[2]);
            }
        }

        __syncthreads();
        if (kb + 2 < nkb)
            fatt_load_kv(sSt + (uint32_t)buf * STAGEB, tid,
                         kp_hi, kp_lo, vp_hi, vp_lo, kb + 2);
    }

#pragma unroll
    for (int rr = 0; rr < 2; ++rr) {
        float lf = l_i[rr];
        lf += __shfl_xor_sync(0xffffffff, lf, 1);
        lf += __shfl_xor_sync(0xffffffff, lf, 2);
        float inv = 1.0f / lf;
        int trow = qrow0 + rr * 8;
        size_t rbase = ((size_t)(b * TT + trow)) * DD + h * HD + 2 * (lane & 3);
#pragma unroll
        for (int nf = 0; nf < 16; ++nf) {
            float v0 = o[nf][2 * rr] * inv;
            float v1 = o[nf][2 * rr + 1] * inv;
            __nv_bfloat16 h0 = __float2bfloat16(v0);
            __nv_bfloat16 h1 = __float2bfloat16(v1);
            __nv_bfloat16 l0 = __float2bfloat16(v0 - __bfloat162float(h0));
            __nv_bfloat16 l1 = __float2bfloat16(v1 - __bfloat162float(h1));
            *(__nv_bfloat162*)&Yhi[rbase + nf * 8] = __nv_bfloat162(h0, h1);
            *(__nv_bfloat162*)&Ylo[rbase + nf * 8] = __nv_bfloat162(l0, l1);
        }
    }
}

// ---------------------------- launch ---------------------------------------
static inline void split(const float* src, __nv_bfloat16* hi, __nv_bfloat16* lo,
                         size_t n)
{
    int n4 = (int)(n / 4);
    int nt = n4 / 2;
    split_kernel<<<(nt + 255) / 256, 256>>>(src, hi, lo, n4);
}

extern "C" void kernel_launch(void* const* d_in, const int* in_sizes, int n_in,
                              void* d_out, int out_size)
{
    const float* x   = (const float*)d_in[0];
    const float* Wq  = (const float*)d_in[1];
    const float* Wk  = (const float*)d_in[2];
    const float* Wv  = (const float*)d_in[3];
    const float* Wp  = (const float*)d_in[4];
    const float* qg  = (const float*)d_in[5];
    float* out = (float*)d_out;

    __nv_bfloat16 *xhi, *xlo, *wchi, *wclo, *wphi, *wplo, *yhi, *ylo;
    __nv_bfloat16 *qhi, *qlo, *khi, *klo, *vhi, *vlo;
    cudaGetSymbolAddress((void**)&xhi, g_xhi);   cudaGetSymbolAddress((void**)&xlo, g_xlo);
    cudaGetSymbolAddress((void**)&wchi, g_wchi); cudaGetSymbolAddress((void**)&wclo, g_wclo);
    cudaGetSymbolAddress((void**)&wphi, g_wphi); cudaGetSymbolAddress((void**)&wplo, g_wplo);
    cudaGetSymbolAddress((void**)&yhi, g_yhi);   cudaGetSymbolAddress((void**)&ylo, g_ylo);
    cudaGetSymbolAddress((void**)&qhi, g_qhi);   cudaGetSymbolAddress((void**)&qlo, g_qlo);
    cudaGetSymbolAddress((void**)&khi, g_khi);   cudaGetSymbolAddress((void**)&klo, g_klo);
    cudaGetSymbolAddress((void**)&vhi, g_vhi);   cudaGetSymbolAddress((void**)&vlo, g_vlo);

    cudaFuncSetAttribute(gemm_mma_kernel<0>,
                         cudaFuncAttributeMaxDynamicSharedMemorySize, GEMM_SMEM);
    cudaFuncSetAttribute(gemm_mma_kernel<1>,
                         cudaFuncAttributeMaxDynamicSharedMemorySize, GEMM_SMEM);
    cudaFuncSetAttribute(fattn_kernel,
                         cudaFuncAttributeMaxDynamicSharedMemorySize, FATT_SMEM);

    const float qscale = 1.0f / sqrtf((float)HD);

    // hi/lo splits: x, combined W = [Wq; Wk; Wv] (row-contiguous), Wp
    split(x,  xhi,  xlo,  (size_t)NTOK * KTOT);
    split(Wq, wchi,                          wclo,                          (size_t)DD * KTOT);
    split(Wk, wchi + (size_t)DD * KTOT,      wclo + (size_t)DD * KTOT,      (size_t)KVD * KTOT);
    split(Wv, wchi + (size_t)(DD+KVD)*KTOT,  wclo + (size_t)(DD+KVD)*KTOT,  (size_t)KVD * KTOT);
    split(Wp, wphi, wplo, (size_t)DD * KTOT);

    // fused QKV projection + RMSNorm/RoPE/split epilogue (no fp32 tmp)
    gemm_mma_kernel<1><<<dim3(QKVN / GBN, NTOK / GBM), 256, GEMM_SMEM>>>(
        xhi, xlo, wchi, wclo, nullptr, QKVN,
        qhi, qlo, khi, klo, vhi, vlo, qg, qscale);

    // tensor-core causal flash attention -> y bf16 hi/lo
    fattn_kernel<<<dim3(TT / FBM, HN, BB), 256, FATT_SMEM>>>(
        qhi, qlo, khi, klo, vhi, vlo, yhi, ylo);

    // output projection (fp32 out)
    gemm_mma_kernel<0><<<dim3(DD / GBN, NTOK / GBM), 256, GEMM_SMEM>>>(
        yhi, ylo, wphi, wplo, out, DD,
        nullptr, nullptr, nullptr, nullptr, nullptr, nullptr, nullptr, 0.f);
}

// round 7
// speedup vs baseline: 3.5626x; 1.0017x over previous
#include <cuda_runtime.h>
#include <cuda_bf16.h>
#include <cstdint>
#include <math.h>

// Problem constants
#define HN   16          // num_heads
#define KVH  4           // num_kv_heads
#define HD   128         // head_dim
#define BB   4           // batch
#define TT   2048        // seq len
#define DD   (HN*HD)     // 2048
#define KVD  (KVH*HD)    // 512
#define NTOK (BB*TT)     // 8192
#define KTOT DD          // inner dim of all GEMMs = 2048
#define QKVN (DD + 2*KVD)  // 3072 fused projection width
#define RMS_EPS 1.1920928955078125e-07f
#define LOG2E 1.4426950408889634f

// ---------------- scratch (device globals: allocation-free) ----------------
__device__ __nv_bfloat16 g_xhi[(size_t)NTOK * KTOT], g_xlo[(size_t)NTOK * KTOT];
__device__ __nv_bfloat16 g_wchi[(size_t)QKVN * KTOT], g_wclo[(size_t)QKVN * KTOT]; // Wq|Wk|Wv
__device__ __nv_bfloat16 g_wphi[(size_t)DD * KTOT],  g_wplo[(size_t)DD * KTOT];
__device__ __nv_bfloat16 g_yhi[(size_t)NTOK * KTOT], g_ylo[(size_t)NTOK * KTOT];

__device__ __nv_bfloat16 g_qhi[(size_t)BB * HN  * TT * HD], g_qlo[(size_t)BB * HN  * TT * HD];
__device__ __nv_bfloat16 g_khi[(size_t)BB * KVH * TT * HD], g_klo[(size_t)BB * KVH * TT * HD];
__device__ __nv_bfloat16 g_vhi[(size_t)BB * KVH * TT * HD], g_vlo[(size_t)BB * KVH * TT * HD];

// ======================= PTX helpers (baseline compute_103) ================
__device__ __forceinline__ uint32_t smem_u32(const void* p) {
    uint32_t a;
    asm("{ .reg .u64 t; cvta.to.shared.u64 t, %1; cvt.u32.u64 %0, t; }"
        : "=r"(a) : "l"(p));
    return a;
}
__device__ __forceinline__ void cp16(uint32_t dst, const void* src) {
    asm volatile("cp.async.cg.shared.global [%0], [%1], 16;" :: "r"(dst), "l"(src));
}
#define CP_COMMIT() asm volatile("cp.async.commit_group;" ::: "memory")
#define CP_WAIT1()  asm volatile("cp.async.wait_group 1;" ::: "memory")
#define CP_WAIT0()  asm volatile("cp.async.wait_group 0;" ::: "memory")

__device__ __forceinline__ void ldsm_x4(uint32_t* r, uint32_t addr) {
    asm volatile("ldmatrix.sync.aligned.m8n8.x4.shared.b16 {%0,%1,%2,%3}, [%4];"
                 : "=r"(r[0]), "=r"(r[1]), "=r"(r[2]), "=r"(r[3]) : "r"(addr));
}
__device__ __forceinline__ void ldsm_x4_t(uint32_t* r, uint32_t addr) {
    asm volatile("ldmatrix.sync.aligned.m8n8.x4.trans.shared.b16 {%0,%1,%2,%3}, [%4];"
                 : "=r"(r[0]), "=r"(r[1]), "=r"(r[2]), "=r"(r[3]) : "r"(addr));
}
__device__ __forceinline__ void mma16816(float* c, const uint32_t* a, const uint32_t* b) {
    asm volatile(
        "mma.sync.aligned.m16n8k16.row.col.f32.bf16.bf16.f32 "
        "{%0,%1,%2,%3}, {%4,%5,%6,%7}, {%8,%9}, {%0,%1,%2,%3};"
        : "+f"(c[0]), "+f"(c[1]), "+f"(c[2]), "+f"(c[3])
        : "r"(a[0]), "r"(a[1]), "r"(a[2]), "r"(a[3]), "r"(b[0]), "r"(b[1]));
}
__device__ __forceinline__ uint32_t pack_bf16(float x, float y) {
    __nv_bfloat162 t = __floats2bfloat162_rn(x, y);
    return *(uint32_t*)&t;
}

// ============ fp32 -> bf16 hi/lo split (grid-stride, MLP=4) ================
__global__ void __launch_bounds__(256) split_kernel(
    const float4* __restrict__ in, uint2* __restrict__ hi,
    uint2* __restrict__ lo, int n4)
{
    const int stride = gridDim.x * blockDim.x;
    for (int i = blockIdx.x * blockDim.x + threadIdx.x; i < n4; i += 4 * stride) {
        float4 v[4];
        int cnt = 0;
#pragma unroll
        for (int s = 0; s < 4; ++s) {
            int j = i + s * stride;
            if (j < n4) { v[s] = in[j]; cnt = s + 1; }
        }
#pragma unroll
        for (int s = 0; s < 4; ++s) {
            if (s >= cnt) break;
            int j = i + s * stride;
            float4 w = v[s];
            __nv_bfloat16 h0 = __float2bfloat16(w.x), h1 = __float2bfloat16(w.y);
            __nv_bfloat16 h2 = __float2bfloat16(w.z), h3 = __float2bfloat16(w.w);
            uint2 hv, lv;
            hv.x = pack_bf16(__bfloat162float(h0), __bfloat162float(h1));
            hv.y = pack_bf16(__bfloat162float(h2), __bfloat162float(h3));
            lv.x = pack_bf16(w.x - __bfloat162float(h0), w.y - __bfloat162float(h1));
            lv.y = pack_bf16(w.z - __bfloat162float(h2), w.w - __bfloat162float(h3));
            hi[j] = hv;
            lo[j] = lv;
        }
    }
}

// ========= mma.sync bf16-split GEMM: C[M,N] = A[M,K]*B[N,K]^T ==============
#define GBM 128
#define GBN 128
#define GBK 32
#define GNK (KTOT / GBK)       // 64
#define LDA 40
#define TILE_EL  (GBM * LDA)
#define STAGE_EL (4 * TILE_EL)
#define GEMM_SMEM (2 * STAGE_EL * 2)   // 81920 bytes
#define LDC 132                        // epilogue fp32 tile stride

__device__ __forceinline__ void gemm_load_stage(
    uint32_t sb, int tid, int k0,
    const __nv_bfloat16* gAhi, const __nv_bfloat16* gAlo,
    const __nv_bfloat16* gBhi, const __nv_bfloat16* gBlo)
{
#pragma unroll
    for (int i = 0; i < 2; ++i) {
        int ch = tid + i * 256;
        int r = ch >> 2, sg = ch & 3;
        uint32_t so = (uint32_t)((r * LDA + sg * 8) * 2);
        size_t go = (size_t)r * KTOT + k0 + sg * 8;
        cp16(sb + 0 * TILE_EL * 2 + so, gAhi + go);
        cp16(sb + 1 * TILE_EL * 2 + so, gAlo + go);
        cp16(sb + 2 * TILE_EL * 2 + so, gBhi + go);
        cp16(sb + 3 * TILE_EL * 2 + so, gBlo + go);
    }
    CP_COMMIT();
}

template<int MODE>
__global__ void __launch_bounds__(256, 2) gemm_mma_kernel(
    const __nv_bfloat16* __restrict__ Ahi, const __nv_bfloat16* __restrict__ Alo,
    const __nv_bfloat16* __restrict__ Bhi, const __nv_bfloat16* __restrict__ Blo,
    float* __restrict__ C, int N,
    __nv_bfloat16* __restrict__ qhi, __nv_bfloat16* __restrict__ qlo,
    __nv_bfloat16* __restrict__ khi, __nv_bfloat16* __restrict__ klo,
    __nv_bfloat16* __restrict__ vhi, __nv_bfloat16* __restrict__ vlo,
    const float* __restrict__ qg, float qscale)
{
    extern __shared__ __nv_bfloat16 smem[];
    const uint32_t sbase = smem_u32(smem);
    const int tid = threadIdx.x;
    const int lane = tid & 31, wid = tid >> 5;
    const int wm = wid >> 2, wn = wid & 3;
    const int m0 = blockIdx.y * GBM;
    const int n0 = blockIdx.x * GBN;

    const __nv_bfloat16* gAhi = Ahi + (size_t)m0 * KTOT;
    const __nv_bfloat16* gAlo = Alo + (size_t)m0 * KTOT;
    const __nv_bfloat16* gBhi = Bhi + (size_t)n0 * KTOT;
    const __nv_bfloat16* gBlo = Blo + (size_t)n0 * KTOT;

    float acc[4][4][4];
#pragma unroll
    for (int mi = 0; mi < 4; ++mi)
#pragma unroll
        for (int nj = 0; nj < 4; ++nj)
#pragma unroll
            for (int e = 0; e < 4; ++e) acc[mi][nj][e] = 0.f;

    const int arow = wm * 64 + (lane & 15);
    const uint32_t aoffbase = (uint32_t)(arow * LDA * 2) + ((lane >> 4) << 4);
    const int g = lane >> 3;
    const int brow = wn * 32 + (lane & 7) + ((g >> 1) << 3);
    const uint32_t boffbase = (uint32_t)(brow * LDA * 2) + ((g & 1) << 4);

    gemm_load_stage(sbase, tid, 0, gAhi, gAlo, gBhi, gBlo);
    gemm_load_stage(sbase + STAGE_EL * 2, tid, GBK, gAhi, gAlo, gBhi, gBlo);

    for (int kt = 0; kt < GNK; ++kt) {
        const int buf = kt & 1;
        if (kt + 1 < GNK) { CP_WAIT1(); } else { CP_WAIT0(); }
        __syncthreads();

        const uint32_t st   = sbase + (uint32_t)buf * STAGE_EL * 2;
        const uint32_t sAhi = st;
        const uint32_t sAlo = st + TILE_EL * 2;
        const uint32_t sBhi = st + 2 * TILE_EL * 2;
        const uint32_t sBlo = st + 3 * TILE_EL * 2;

#pragma unroll
        for (int kk = 0; kk < GBK; kk += 16) {
            const uint32_t akk = aoffbase + kk * 2;
            const uint32_t bkk = boffbase + kk * 2;
            uint32_t b_hi[4][2], b_lo[4][2];
#pragma unroll
            for (int nt = 0; nt < 2; ++nt) {
                uint32_t r[4];
                ldsm_x4(r, sBhi + bkk + nt * 16 * LDA * 2);
                b_hi[2 * nt][0] = r[0]; b_hi[2 * nt][1] = r[1];
                b_hi[2 * nt + 1][0] = r[2]; b_hi[2 * nt + 1][1] = r[3];
                ldsm_x4(r, sBlo + bkk + nt * 16 * LDA * 2);
                b_lo[2 * nt][0] = r[0]; b_lo[2 * nt][1] = r[1];
                b_lo[2 * nt + 1][0] = r[2]; b_lo[2 * nt + 1][1] = r[3];
            }
#pragma unroll
            for (int mi = 0; mi < 4; ++mi) {
                uint32_t a_hi[4], a_lo[4];
                ldsm_x4(a_hi, sAhi + akk + mi * 16 * LDA * 2);
                ldsm_x4(a_lo, sAlo + akk + mi * 16 * LDA * 2);
#pragma unroll
                for (int nj = 0; nj < 4; ++nj) {
                    mma16816(acc[mi][nj], a_hi, b_hi[nj]);
                    mma16816(acc[mi][nj], a_hi, b_lo[nj]);
                    mma16816(acc[mi][nj], a_lo, b_hi[nj]);
                }
            }
        }
        __syncthreads();
        if (kt + 2 < GNK)
            gemm_load_stage(st, tid, (kt + 2) * GBK, gAhi, gAlo, gBhi, gBlo);
    }

    if (MODE == 0) {
#pragma unroll
        for (int mi = 0; mi < 4; ++mi) {
            int r0 = m0 + wm * 64 + mi * 16 + (lane >> 2);
#pragma unroll
            for (int nj = 0; nj < 4; ++nj) {
                int c = n0 + wn * 32 + nj * 8 + ((lane & 3) << 1);
                *(float2*)&C[(size_t)r0 * N + c]       = make_float2(acc[mi][nj][0], acc[mi][nj][1]);
                *(float2*)&C[(size_t)(r0 + 8) * N + c] = make_float2(acc[mi][nj][2], acc[mi][nj][3]);
            }
        }
        return;
    }

    // ================= fused QKV epilogue (MODE 1) ==========================
    float* stile = (float*)smem;               // 128 x LDC fp32 tile
    float* sinv  = stile + 128 * LDC;          // 64-entry inv_freq table
    __syncthreads();

#pragma unroll
    for (int mi = 0; mi < 4; ++mi) {
        int r = wm * 64 + mi * 16 + (lane >> 2);
#pragma unroll
        for (int nj = 0; nj < 4; ++nj) {
            int c = wn * 32 + nj * 8 + ((lane & 3) << 1);
            stile[r * LDC + c]           = acc[mi][nj][0];
            stile[r * LDC + c + 1]       = acc[mi][nj][1];
            stile[(r + 8) * LDC + c]     = acc[mi][nj][2];
            stile[(r + 8) * LDC + c + 1] = acc[mi][nj][3];
        }
    }

    const bool isV = (n0 >= DD + KVD);
    const bool isK = (n0 >= DD) && !isV;
    if (!isV && tid < 64)
        sinv[tid] = 1.0f / powf(10000.0f, (float)tid * (1.0f / 64.0f));
    __syncthreads();

    if (!isV && tid < 128) {
        const int row = tid;
        const int t = (m0 + row) & (TT - 1);
        float ssq = 0.f;
#pragma unroll 8
        for (int d = 0; d < HD; ++d) {
            float x = stile[row * LDC + d];
            ssq += x * x;
        }
        float rms = rsqrtf(ssq * (1.0f / HD) + RMS_EPS);
        float gn = isK ? 1.0f : (qg[n0 >> 7] * qscale);
#pragma unroll 4
        for (int d = 0; d < 64; ++d) {
            float xa = stile[row * LDC + d] * rms;
            float xb = stile[row * LDC + d + 64] * rms;
            float s_, c_;
            sincosf((float)t * sinv[d], &s_, &c_);
            stile[row * LDC + d]      = (xa * c_ - xb * s_) * gn;
            stile[row * LDC + d + 64] = (xb * c_ + xa * s_) * gn;
        }
    }
    __syncthreads();

    __nv_bfloat16 *dhi, *dlo;
    int hloc, nh;
    if (isV)      { hloc = (n0 - DD - KVD) >> 7; nh = KVH; dhi = vhi; dlo = vlo; }
    else if (isK) { hloc = (n0 - DD) >> 7;       nh = KVH; dhi = khi; dlo = klo; }
    else          { hloc = n0 >> 7;              nh = HN;  dhi = qhi; dlo = qlo; }

#pragma unroll
    for (int p = 0; p < 16; ++p) {
        int row = p * 8 + wid;
        int token = m0 + row;
        int b = token >> 11, t = token & (TT - 1);
        size_t off = (((size_t)b * nh + hloc) * TT + t) * HD + lane * 4;
        float v0 = stile[row * LDC + lane * 4];
        float v1 = stile[row * LDC + lane * 4 + 1];
        float v2 = stile[row * LDC + lane * 4 + 2];
        float v3 = stile[row * LDC + lane * 4 + 3];
        __nv_bfloat16 h0 = __float2bfloat16(v0), h1 = __float2bfloat16(v1);
        __nv_bfloat16 h2 = __float2bfloat16(v2), h3 = __float2bfloat16(v3);
        uint2 hv, lv;
        hv.x = pack_bf16(__bfloat162float(h0), __bfloat162float(h1));
        hv.y = pack_bf16(__bfloat162float(h2), __bfloat162float(h3));
        lv.x = pack_bf16(v0 - __bfloat162float(h0), v1 - __bfloat162float(h1));
        lv.y = pack_bf16(v2 - __bfloat162float(h2), v3 - __bfloat162float(h3));
        *(uint2*)&dhi[off] = hv;
        *(uint2*)&dlo[off] = lv;
    }
}

// ============ tensor-core causal flash attention (bf16-split) ==============
#define FBM 128
#define FBN 64
#define LDQ 136
#define QSZB   (FBM * LDQ * 2)
#define KTILEB (FBN * LDQ * 2)
#define STAGEB (4 * KTILEB)
#define FATT_SMEM (2 * QSZB + 2 * STAGEB)

__device__ __forceinline__ void fatt_load_kv(
    uint32_t st, int tid,
    const __nv_bfloat16* kp_hi, const __nv_bfloat16* kp_lo,
    const __nv_bfloat16* vp_hi, const __nv_bfloat16* vp_lo, int kb)
{
    const size_t base = (size_t)kb * FBN * HD;
#pragma unroll
    for (int i = 0; i < 4; ++i) {
        int ch = tid + i * 256;
        int row = ch >> 4, seg = ch & 15;
        uint32_t so = (uint32_t)(row * (LDQ * 2) + seg * 16);
        size_t go = base + (size_t)row * HD + seg * 8;
        cp16(st + 0 * KTILEB + so, kp_hi + go);
        cp16(st + 1 * KTILEB + so, kp_lo + go);
        cp16(st + 2 * KTILEB + so, vp_hi + go);
        cp16(st + 3 * KTILEB + so, vp_lo + go);
    }
    CP_COMMIT();
}

__global__ void __launch_bounds__(256, 1) fattn_kernel(
    const __nv_bfloat16* __restrict__ Qhi, const __nv_bfloat16* __restrict__ Qlo,
    const __nv_bfloat16* __restrict__ Khi, const __nv_bfloat16* __restrict__ Klo,
    const __nv_bfloat16* __restrict__ Vhi, const __nv_bfloat16* __restrict__ Vlo,
    __nv_bfloat16* __restrict__ Yhi, __nv_bfloat16* __restrict__ Ylo)
{
    extern __shared__ char smraw[];
    const uint32_t sb = smem_u32(smraw);
    const uint32_t sQh = sb, sQl = sb + QSZB;
    const uint32_t sSt = sb + 2 * QSZB;

    const int tid = threadIdx.x;
    const int lane = tid & 31, wid = tid >> 5;
    const int qb = (int)(gridDim.x - 1 - blockIdx.x);
    const int h  = blockIdx.y;
    const int b  = blockIdx.z;
    const int hk = h / (HN / KVH);
    const int nkb = 2 * qb + 2;

    const __nv_bfloat16* qp_hi = Qhi + ((((size_t)b * HN + h) * TT) + (size_t)qb * FBM) * HD;
    const __nv_bfloat16* qp_lo = Qlo + ((((size_t)b * HN + h) * TT) + (size_t)qb * FBM) * HD;
    const __nv_bfloat16* kp_hi = Khi + (((size_t)b * KVH + hk) * TT) * HD;
    const __nv_bfloat16* kp_lo = Klo + (((size_t)b * KVH + hk) * TT) * HD;
    const __nv_bfloat16* vp_hi = Vhi + (((size_t)b * KVH + hk) * TT) * HD;
    const __nv_bfloat16* vp_lo = Vlo + (((size_t)b * KVH + hk) * TT) * HD;

#pragma unroll
    for (int i = 0; i < 8; ++i) {
        int ch = tid + i * 256;
        int row = ch >> 4, seg = ch & 15;
        uint32_t so = (uint32_t)(row * (LDQ * 2) + seg * 16);
        size_t go = (size_t)row * HD + seg * 8;
        cp16(sQh + so, qp_hi + go);
        cp16(sQl + so, qp_lo + go);
    }
    fatt_load_kv(sSt, tid, kp_hi, kp_lo, vp_hi, vp_lo, 0);
    if (nkb > 1)
        fatt_load_kv(sSt + STAGEB, tid, kp_hi, kp_lo, vp_hi, vp_lo, 1);

    const uint32_t aoff = (uint32_t)((wid * 16 + (lane & 15)) * (LDQ * 2)) + ((lane >> 4) << 4);
    const int g = lane >> 3;
    const uint32_t boff = (uint32_t)(((lane & 7) + ((g >> 1) << 3)) * (LDQ * 2)) + ((g & 1) << 4);
    const uint32_t voff = (uint32_t)((lane & 15) * (LDQ * 2)) + (((lane >> 4) & 1) << 4);

    float o[16][4];
#pragma unroll
    for (int nf = 0; nf < 16; ++nf)
#pragma unroll
        for (int e = 0; e < 4; ++e) o[nf][e] = 0.f;
    float m_i[2] = {-1e30f, -1e30f};
    float l_i[2] = {0.f, 0.f};

    const int qrow0 = qb * FBM + wid * 16 + (lane >> 2);

    for (int kb = 0; kb < nkb; ++kb) {
        const int buf = kb & 1;
        if (kb + 1 < nkb) { CP_WAIT1(); } else { CP_WAIT0(); }
        __syncthreads();

        const uint32_t sKh = sSt + (uint32_t)buf * STAGEB;
        const uint32_t sKl = sKh + KTILEB;
        const uint32_t sVh = sKh + 2 * KTILEB;
        const uint32_t sVl = sKh + 3 * KTILEB;

        // ---- S = Q K^T (3-term bf16 split) ----
        float s[8][4];
#pragma unroll
        for (int j = 0; j < 8; ++j)
#pragma unroll
            for (int e = 0; e < 4; ++e) s[j][e] = 0.f;

#pragma unroll
        for (int kc = 0; kc < 8; ++kc) {
            uint32_t aq_hi[4], aq_lo[4];
            ldsm_x4(aq_hi, sQh + aoff + kc * 32);
            ldsm_x4(aq_lo, sQl + aoff + kc * 32);
#pragma unroll
            for (int n16 = 0; n16 < 4; ++n16) {
                uint32_t bh[4], bl[4];
                ldsm_x4(bh, sKh + boff + n16 * 16 * (LDQ * 2) + kc * 32);
                ldsm_x4(bl, sKl + boff + n16 * 16 * (LDQ * 2) + kc * 32);
                mma16816(s[2 * n16],     aq_hi, &bh[0]);
                mma16816(s[2 * n16],     aq_hi, &bl[0]);
                mma16816(s[2 * n16],     aq_lo, &bh[0]);
                mma16816(s[2 * n16 + 1], aq_hi, &bh[2]);
                mma16816(s[2 * n16 + 1], aq_hi, &bl[2]);
                mma16816(s[2 * n16 + 1], aq_lo, &bh[2]);
            }
        }

        // ---- causal mask (diagonal blocks only) ----
        if (kb >= nkb - 2) {
            const int kc0 = kb * FBN + 2 * (lane & 3);
#pragma unroll
            for (int j = 0; j < 8; ++j)
#pragma unroll
                for (int e = 0; e < 4; ++e) {
                    int row = qrow0 + (e >> 1) * 8;
                    int col = kc0 + 8 * j + (e & 1);
                    if (col > row) s[j][e] = -1e30f;
                }
        }

        // ---- row max + alpha (serial part kept minimal) ----
        float mxl2[2], alpha[2];
#pragma unroll
        for (int rr = 0; rr < 2; ++rr) {
            float mx = m_i[rr];
#pragma unroll
            for (int j = 0; j < 8; ++j)
                mx = fmaxf(mx, fmaxf(s[j][2 * rr], s[j][2 * rr + 1]));
            mx = fmaxf(mx, __shfl_xor_sync(0xffffffff, mx, 1));
            mx = fmaxf(mx, __shfl_xor_sync(0xffffffff, mx, 2));
            alpha[rr] = __expf(m_i[rr] - mx);
            m_i[rr] = mx;
            mxl2[rr] = mx * LOG2E;
        }
#pragma unroll
        for (int nf = 0; nf < 16; ++nf) {
            o[nf][0] *= alpha[0]; o[nf][1] *= alpha[0];
            o[nf][2] *= alpha[1]; o[nf][3] *= alpha[1];
        }
        float lsum[2] = {0.f, 0.f};

        // ---- per-chunk: exp + pack + PV mma (interleaves in issue stream) --
#pragma unroll
        for (int kc2 = 0; kc2 < 4; ++kc2) {
            const int j0 = 2 * kc2, j1 = 2 * kc2 + 1;
            float p[8];
            p[0] = exp2f(fmaf(s[j0][0], LOG2E, -mxl2[0]));
            p[1] = exp2f(fmaf(s[j0][1], LOG2E, -mxl2[0]));
            p[2] = exp2f(fmaf(s[j0][2], LOG2E, -mxl2[1]));
            p[3] = exp2f(fmaf(s[j0][3], LOG2E, -mxl2[1]));
            p[4] = exp2f(fmaf(s[j1][0], LOG2E, -mxl2[0]));
            p[5] = exp2f(fmaf(s[j1][1], LOG2E, -mxl2[0]));
            p[6] = exp2f(fmaf(s[j1][2], LOG2E, -mxl2[1]));
            p[7] = exp2f(fmaf(s[j1][3], LOG2E, -mxl2[1]));
            lsum[0] += (p[0] + p[1]) + (p[4] + p[5]);
            lsum[1] += (p[2] + p[3]) + (p[6] + p[7]);

            uint32_t ap_hi[4], ap_lo[4];
            float h0 = __bfloat162float(__float2bfloat16(p[0]));
            float h1 = __bfloat162float(__float2bfloat16(p[1]));
            float h2 = __bfloat162float(__float2bfloat16(p[2]));
            float h3 = __bfloat162float(__float2bfloat16(p[3]));
            float h4 = __bfloat162float(__float2bfloat16(p[4]));
            float h5 = __bfloat162float(__float2bfloat16(p[5]));
            float h6 = __bfloat162float(__float2bfloat16(p[6]));
            float h7 = __bfloat162float(__float2bfloat16(p[7]));
            ap_hi[0] = pack_bf16(h0, h1);
            ap_hi[1] = pack_bf16(h2, h3);
            ap_hi[2] = pack_bf16(h4, h5);
            ap_hi[3] = pack_bf16(h6, h7);
            ap_lo[0] = pack_bf16(p[0] - h0, p[1] - h1);
            ap_lo[1] = pack_bf16(p[2] - h2, p[3] - h3);
            ap_lo[2] = pack_bf16(p[4] - h4, p[5] - h5);
            ap_lo[3] = pack_bf16(p[6] - h6, p[7] - h7);

            const uint32_t vrow = voff + kc2 * 16 * (LDQ * 2);
#pragma unroll
            for (int nf16 = 0; nf16 < 8; ++nf16) {
                uint32_t bvh[4], bvl[4];
                ldsm_x4_t(bvh, sVh + vrow + nf16 * 32);
                ldsm_x4_t(bvl, sVl + vrow + nf16 * 32);
                mma16816(o[2 * nf16],     ap_hi, &bvh[0]);
                mma16816(o[2 * nf16],     ap_lo, &bvh[0]);
                mma16816(o[2 * nf16],     ap_hi, &bvl[0]);
                mma16816(o[2 * nf16 + 1], ap_hi, &bvh[2]);
                mma16816(o[2 * nf16 + 1], ap_lo, &bvh[2]);
                mma16816(o[2 * nf16 + 1], ap_hi, &bvl[2]);
            }
        }
        l_i[0] = l_i[0] * alpha[0] + lsum[0];
        l_i[1] = l_i[1] * alpha[1] + lsum[1];

        __syncthreads();
        if (kb + 2 < nkb)
            fatt_load_kv(sSt + (uint32_t)buf * STAGEB, tid,
                         kp_hi, kp_lo, vp_hi, vp_lo, kb + 2);
    }

#pragma unroll
    for (int rr = 0; rr < 2; ++rr) {
        float lf = l_i[rr];
        lf += __shfl_xor_sync(0xffffffff, lf, 1);
        lf += __shfl_xor_sync(0xffffffff, lf, 2);
        float inv = 1.0f / lf;
        int trow = qrow0 + rr * 8;
        size_t rbase = ((size_t)(b * TT + trow)) * DD + h * HD + 2 * (lane & 3);
#pragma unroll
        for (int nf = 0; nf < 16; ++nf) {
            float v0 = o[nf][2 * rr] * inv;
            float v1 = o[nf][2 * rr + 1] * inv;
            __nv_bfloat16 h0 = __float2bfloat16(v0);
            __nv_bfloat16 h1 = __float2bfloat16(v1);
            __nv_bfloat16 l0 = __float2bfloat16(v0 - __bfloat162float(h0));
            __nv_bfloat16 l1 = __float2bfloat16(v1 - __bfloat162float(h1));
            *(__nv_bfloat162*)&Yhi[rbase + nf * 8] = __nv_bfloat162(h0, h1);
            *(__nv_bfloat162*)&Ylo[rbase + nf * 8] = __nv_bfloat162(l0, l1);
        }
    }
}

// ---------------------------- launch ---------------------------------------
static inline void split(const float* src, __nv_bfloat16* hi, __nv_bfloat16* lo,
                         size_t n)
{
    int n4 = (int)(n / 4);
    int blocks = (n4 + 1023) / 1024;
    if (blocks > 1184) blocks = 1184;
    split_kernel<<<blocks, 256>>>((const float4*)src, (uint2*)hi, (uint2*)lo, n4);
}

extern "C" void kernel_launch(void* const* d_in, const int* in_sizes, int n_in,
                              void* d_out, int out_size)
{
    const float* x   = (const float*)d_in[0];
    const float* Wq  = (const float*)d_in[1];
    const float* Wk  = (const float*)d_in[2];
    const float* Wv  = (const float*)d_in[3];
    const float* Wp  = (const float*)d_in[4];
    const float* qg  = (const float*)d_in[5];
    float* out = (float*)d_out;

    __nv_bfloat16 *xhi, *xlo, *wchi, *wclo, *wphi, *wplo, *yhi, *ylo;
    __nv_bfloat16 *qhi, *qlo, *khi, *klo, *vhi, *vlo;
    cudaGetSymbolAddress((void**)&xhi, g_xhi);   cudaGetSymbolAddress((void**)&xlo, g_xlo);
    cudaGetSymbolAddress((void**)&wchi, g_wchi); cudaGetSymbolAddress((void**)&wclo, g_wclo);
    cudaGetSymbolAddress((void**)&wphi, g_wphi); cudaGetSymbolAddress((void**)&wplo, g_wplo);
    cudaGetSymbolAddress((void**)&yhi, g_yhi);   cudaGetSymbolAddress((void**)&ylo, g_ylo);
    cudaGetSymbolAddress((void**)&qhi, g_qhi);   cudaGetSymbolAddress((void**)&qlo, g_qlo);
    cudaGetSymbolAddress((void**)&khi, g_khi);   cudaGetSymbolAddress((void**)&klo, g_klo);
    cudaGetSymbolAddress((void**)&vhi, g_vhi);   cudaGetSymbolAddress((void**)&vlo, g_vlo);

    cudaFuncSetAttribute(gemm_mma_kernel<0>,
                         cudaFuncAttributeMaxDynamicSharedMemorySize, GEMM_SMEM);
    cudaFuncSetAttribute(gemm_mma_kernel<1>,
                         cudaFuncAttributeMaxDynamicSharedMemorySize, GEMM_SMEM);
    cudaFuncSetAttribute(fattn_kernel,
                         cudaFuncAttributeMaxDynamicSharedMemorySize, FATT_SMEM);

    const float qscale = 1.0f / sqrtf((float)HD);

    // hi/lo splits: x, combined W = [Wq; Wk; Wv] (row-contiguous), Wp
    split(x,  xhi,  xlo,  (size_t)NTOK * KTOT);
    split(Wq, wchi,                          wclo,                          (size_t)DD * KTOT);
    split(Wk, wchi + (size_t)DD * KTOT,      wclo + (size_t)DD * KTOT,      (size_t)KVD * KTOT);
    split(Wv, wchi + (size_t)(DD+KVD)*KTOT,  wclo + (size_t)(DD+KVD)*KTOT,  (size_t)KVD * KTOT);
    split(Wp, wphi, wplo, (size_t)DD * KTOT);

    // fused QKV projection + RMSNorm/RoPE/split epilogue (no fp32 tmp)
    gemm_mma_kernel<1><<<dim3(QKVN / GBN, NTOK / GBM), 256, GEMM_SMEM>>>(
        xhi, xlo, wchi, wclo, nullptr, QKVN,
        qhi, qlo, khi, klo, vhi, vlo, qg, qscale);

    // tensor-core causal flash attention -> y bf16 hi/lo
    fattn_kernel<<<dim3(TT / FBM, HN, BB), 256, FATT_SMEM>>>(
        qhi, qlo, khi, klo, vhi, vlo, yhi, ylo);

    // output projection (fp32 out)
    gemm_mma_kernel<0><<<dim3(DD / GBN, NTOK / GBM), 256, GEMM_SMEM>>>(
        yhi, ylo, wphi, wplo, out, DD,
        nullptr, nullptr, nullptr, nullptr, nullptr, nullptr, nullptr, 0.f);
}

// round 8
// speedup vs baseline: 3.5724x; 1.0028x over previous
#include <cuda_runtime.h>
#include <cuda_bf16.h>
#include <cstdint>
#include <math.h>

// Problem constants
#define HN   16          // num_heads
#define KVH  4           // num_kv_heads
#define HD   128         // head_dim
#define BB   4           // batch
#define TT   2048        // seq len
#define DD   (HN*HD)     // 2048
#define KVD  (KVH*HD)    // 512
#define NTOK (BB*TT)     // 8192
#define KTOT DD          // inner dim of all GEMMs = 2048
#define QKVN (DD + 2*KVD)  // 3072 fused projection width
#define RMS_EPS 1.1920928955078125e-07f
#define LOG2E 1.4426950408889634f

// ---------------- scratch (device globals: allocation-free) ----------------
__device__ __nv_bfloat16 g_xhi[(size_t)NTOK * KTOT], g_xlo[(size_t)NTOK * KTOT];
__device__ __nv_bfloat16 g_wchi[(size_t)QKVN * KTOT], g_wclo[(size_t)QKVN * KTOT]; // Wq|Wk|Wv
__device__ __nv_bfloat16 g_wphi[(size_t)DD * KTOT],  g_wplo[(size_t)DD * KTOT];
__device__ __nv_bfloat16 g_yhi[(size_t)NTOK * KTOT], g_ylo[(size_t)NTOK * KTOT];

__device__ __nv_bfloat16 g_qhi[(size_t)BB * HN  * TT * HD], g_qlo[(size_t)BB * HN  * TT * HD];
__device__ __nv_bfloat16 g_khi[(size_t)BB * KVH * TT * HD], g_klo[(size_t)BB * KVH * TT * HD];
__device__ __nv_bfloat16 g_vhi[(size_t)BB * KVH * TT * HD], g_vlo[(size_t)BB * KVH * TT * HD];

// ======================= PTX helpers (baseline compute_103) ================
__device__ __forceinline__ uint32_t smem_u32(const void* p) {
    uint32_t a;
    asm("{ .reg .u64 t; cvta.to.shared.u64 t, %1; cvt.u32.u64 %0, t; }"
        : "=r"(a) : "l"(p));
    return a;
}
__device__ __forceinline__ void cp16(uint32_t dst, const void* src) {
    asm volatile("cp.async.cg.shared.global [%0], [%1], 16;" :: "r"(dst), "l"(src));
}
#define CP_COMMIT() asm volatile("cp.async.commit_group;" ::: "memory")
#define CP_WAIT2()  asm volatile("cp.async.wait_group 2;" ::: "memory")
#define CP_WAIT1()  asm volatile("cp.async.wait_group 1;" ::: "memory")
#define CP_WAIT0()  asm volatile("cp.async.wait_group 0;" ::: "memory")

__device__ __forceinline__ void ldsm_x4(uint32_t* r, uint32_t addr) {
    asm volatile("ldmatrix.sync.aligned.m8n8.x4.shared.b16 {%0,%1,%2,%3}, [%4];"
                 : "=r"(r[0]), "=r"(r[1]), "=r"(r[2]), "=r"(r[3]) : "r"(addr));
}
__device__ __forceinline__ void ldsm_x4_t(uint32_t* r, uint32_t addr) {
    asm volatile("ldmatrix.sync.aligned.m8n8.x4.trans.shared.b16 {%0,%1,%2,%3}, [%4];"
                 : "=r"(r[0]), "=r"(r[1]), "=r"(r[2]), "=r"(r[3]) : "r"(addr));
}
__device__ __forceinline__ void mma16816(float* c, const uint32_t* a, const uint32_t* b) {
    asm volatile(
        "mma.sync.aligned.m16n8k16.row.col.f32.bf16.bf16.f32 "
        "{%0,%1,%2,%3}, {%4,%5,%6,%7}, {%8,%9}, {%0,%1,%2,%3};"
        : "+f"(c[0]), "+f"(c[1]), "+f"(c[2]), "+f"(c[3])
        : "r"(a[0]), "r"(a[1]), "r"(a[2]), "r"(a[3]), "r"(b[0]), "r"(b[1]));
}
__device__ __forceinline__ uint32_t pack_bf16(float x, float y) {
    __nv_bfloat162 t = __floats2bfloat162_rn(x, y);
    return *(uint32_t*)&t;
}

// ============ fp32 -> bf16 hi/lo split (grid-stride) =======================
__global__ void __launch_bounds__(256) split_kernel(
    const float4* __restrict__ in, uint2* __restrict__ hi,
    uint2* __restrict__ lo, int n4)
{
    const int stride = gridDim.x * blockDim.x;
#pragma unroll 4
    for (int i = blockIdx.x * blockDim.x + threadIdx.x; i < n4; i += stride) {
        float4 w = in[i];
        __nv_bfloat16 h0 = __float2bfloat16(w.x), h1 = __float2bfloat16(w.y);
        __nv_bfloat16 h2 = __float2bfloat16(w.z), h3 = __float2bfloat16(w.w);
        uint2 hv, lv;
        hv.x = pack_bf16(__bfloat162float(h0), __bfloat162float(h1));
        hv.y = pack_bf16(__bfloat162float(h2), __bfloat162float(h3));
        lv.x = pack_bf16(w.x - __bfloat162float(h0), w.y - __bfloat162float(h1));
        lv.y = pack_bf16(w.z - __bfloat162float(h2), w.w - __bfloat162float(h3));
        hi[i] = hv;
        lo[i] = lv;
    }
}

// ========= mma.sync bf16-split GEMM: C[M,N] = A[M,K]*B[N,K]^T ==============
#define GBM 128
#define GBN 128
#define GBK 32
#define GNK (KTOT / GBK)       // 64
#define LDA 40
#define TILE_EL  (GBM * LDA)
#define STAGE_EL (4 * TILE_EL)
#define GEMM_SMEM (2 * STAGE_EL * 2)   // 81920 bytes
#define LDC 132                        // epilogue fp32 tile stride

__device__ __forceinline__ void gemm_load_stage(
    uint32_t sb, int tid, int k0,
    const __nv_bfloat16* gAhi, const __nv_bfloat16* gAlo,
    const __nv_bfloat16* gBhi, const __nv_bfloat16* gBlo)
{
#pragma unroll
    for (int i = 0; i < 2; ++i) {
        int ch = tid + i * 256;
        int r = ch >> 2, sg = ch & 3;
        uint32_t so = (uint32_t)((r * LDA + sg * 8) * 2);
        size_t go = (size_t)r * KTOT + k0 + sg * 8;
        cp16(sb + 0 * TILE_EL * 2 + so, gAhi + go);
        cp16(sb + 1 * TILE_EL * 2 + so, gAlo + go);
        cp16(sb + 2 * TILE_EL * 2 + so, gBhi + go);
        cp16(sb + 3 * TILE_EL * 2 + so, gBlo + go);
    }
    CP_COMMIT();
}

template<int MODE>
__global__ void __launch_bounds__(256, 2) gemm_mma_kernel(
    const __nv_bfloat16* __restrict__ Ahi, const __nv_bfloat16* __restrict__ Alo,
    const __nv_bfloat16* __restrict__ Bhi, const __nv_bfloat16* __restrict__ Blo,
    float* __restrict__ C, int N,
    __nv_bfloat16* __restrict__ qhi, __nv_bfloat16* __restrict__ qlo,
    __nv_bfloat16* __restrict__ khi, __nv_bfloat16* __restrict__ klo,
    __nv_bfloat16* __restrict__ vhi, __nv_bfloat16* __restrict__ vlo,
    const float* __restrict__ qg, float qscale)
{
    extern __shared__ __nv_bfloat16 smem[];
    const uint32_t sbase = smem_u32(smem);
    const int tid = threadIdx.x;
    const int lane = tid & 31, wid = tid >> 5;
    const int wm = wid >> 2, wn = wid & 3;
    const int m0 = blockIdx.y * GBM;
    const int n0 = blockIdx.x * GBN;

    const __nv_bfloat16* gAhi = Ahi + (size_t)m0 * KTOT;
    const __nv_bfloat16* gAlo = Alo + (size_t)m0 * KTOT;
    const __nv_bfloat16* gBhi = Bhi + (size_t)n0 * KTOT;
    const __nv_bfloat16* gBlo = Blo + (size_t)n0 * KTOT;

    float acc[4][4][4];
#pragma unroll
    for (int mi = 0; mi < 4; ++mi)
#pragma unroll
        for (int nj = 0; nj < 4; ++nj)
#pragma unroll
            for (int e = 0; e < 4; ++e) acc[mi][nj][e] = 0.f;

    const int arow = wm * 64 + (lane & 15);
    const uint32_t aoffbase = (uint32_t)(arow * LDA * 2) + ((lane >> 4) << 4);
    const int g = lane >> 3;
    const int brow = wn * 32 + (lane & 7) + ((g >> 1) << 3);
    const uint32_t boffbase = (uint32_t)(brow * LDA * 2) + ((g & 1) << 4);

    gemm_load_stage(sbase, tid, 0, gAhi, gAlo, gBhi, gBlo);
    gemm_load_stage(sbase + STAGE_EL * 2, tid, GBK, gAhi, gAlo, gBhi, gBlo);

    for (int kt = 0; kt < GNK; ++kt) {
        const int buf = kt & 1;
        if (kt + 1 < GNK) { CP_WAIT1(); } else { CP_WAIT0(); }
        __syncthreads();

        const uint32_t st   = sbase + (uint32_t)buf * STAGE_EL * 2;
        const uint32_t sAhi = st;
        const uint32_t sAlo = st + TILE_EL * 2;
        const uint32_t sBhi = st + 2 * TILE_EL * 2;
        const uint32_t sBlo = st + 3 * TILE_EL * 2;

#pragma unroll
        for (int kk = 0; kk < GBK; kk += 16) {
            const uint32_t akk = aoffbase + kk * 2;
            const uint32_t bkk = boffbase + kk * 2;
            uint32_t b_hi[4][2], b_lo[4][2];
#pragma unroll
            for (int nt = 0; nt < 2; ++nt) {
                uint32_t r[4];
                ldsm_x4(r, sBhi + bkk + nt * 16 * LDA * 2);
                b_hi[2 * nt][0] = r[0]; b_hi[2 * nt][1] = r[1];
                b_hi[2 * nt + 1][0] = r[2]; b_hi[2 * nt + 1][1] = r[3];
                ldsm_x4(r, sBlo + bkk + nt * 16 * LDA * 2);
                b_lo[2 * nt][0] = r[0]; b_lo[2 * nt][1] = r[1];
                b_lo[2 * nt + 1][0] = r[2]; b_lo[2 * nt + 1][1] = r[3];
            }
#pragma unroll
            for (int mi = 0; mi < 4; ++mi) {
                uint32_t a_hi[4], a_lo[4];
                ldsm_x4(a_hi, sAhi + akk + mi * 16 * LDA * 2);
                ldsm_x4(a_lo, sAlo + akk + mi * 16 * LDA * 2);
#pragma unroll
                for (int nj = 0; nj < 4; ++nj) {
                    mma16816(acc[mi][nj], a_hi, b_hi[nj]);
                    mma16816(acc[mi][nj], a_hi, b_lo[nj]);
                    mma16816(acc[mi][nj], a_lo, b_hi[nj]);
                }
            }
        }
        __syncthreads();
        if (kt + 2 < GNK)
            gemm_load_stage(st, tid, (kt + 2) * GBK, gAhi, gAlo, gBhi, gBlo);
    }

    if (MODE == 0) {
#pragma unroll
        for (int mi = 0; mi < 4; ++mi) {
            int r0 = m0 + wm * 64 + mi * 16 + (lane >> 2);
#pragma unroll
            for (int nj = 0; nj < 4; ++nj) {
                int c = n0 + wn * 32 + nj * 8 + ((lane & 3) << 1);
                *(float2*)&C[(size_t)r0 * N + c]       = make_float2(acc[mi][nj][0], acc[mi][nj][1]);
                *(float2*)&C[(size_t)(r0 + 8) * N + c] = make_float2(acc[mi][nj][2], acc[mi][nj][3]);
            }
        }
        return;
    }

    // ================= fused QKV epilogue (MODE 1) ==========================
    float* stile = (float*)smem;               // 128 x LDC fp32 tile
    float* sinv  = stile + 128 * LDC;          // 64-entry inv_freq table
    __syncthreads();

#pragma unroll
    for (int mi = 0; mi < 4; ++mi) {
        int r = wm * 64 + mi * 16 + (lane >> 2);
#pragma unroll
        for (int nj = 0; nj < 4; ++nj) {
            int c = wn * 32 + nj * 8 + ((lane & 3) << 1);
            stile[r * LDC + c]           = acc[mi][nj][0];
            stile[r * LDC + c + 1]       = acc[mi][nj][1];
            stile[(r + 8) * LDC + c]     = acc[mi][nj][2];
            stile[(r + 8) * LDC + c + 1] = acc[mi][nj][3];
        }
    }

    const bool isV = (n0 >= DD + KVD);
    const bool isK = (n0 >= DD) && !isV;
    if (!isV && tid < 64)
        sinv[tid] = 1.0f / powf(10000.0f, (float)tid * (1.0f / 64.0f));
    __syncthreads();

    if (!isV && tid < 128) {
        const int row = tid;
        const int t = (m0 + row) & (TT - 1);
        float ssq = 0.f;
#pragma unroll 8
        for (int d = 0; d < HD; ++d) {
            float x = stile[row * LDC + d];
            ssq += x * x;
        }
        float rms = rsqrtf(ssq * (1.0f / HD) + RMS_EPS);
        float gn = isK ? 1.0f : (qg[n0 >> 7] * qscale);
#pragma unroll 4
        for (int d = 0; d < 64; ++d) {
            float xa = stile[row * LDC + d] * rms;
            float xb = stile[row * LDC + d + 64] * rms;
            float s_, c_;
            sincosf((float)t * sinv[d], &s_, &c_);
            stile[row * LDC + d]      = (xa * c_ - xb * s_) * gn;
            stile[row * LDC + d + 64] = (xb * c_ + xa * s_) * gn;
        }
    }
    __syncthreads();

    __nv_bfloat16 *dhi, *dlo;
    int hloc, nh;
    if (isV)      { hloc = (n0 - DD - KVD) >> 7; nh = KVH; dhi = vhi; dlo = vlo; }
    else if (isK) { hloc = (n0 - DD) >> 7;       nh = KVH; dhi = khi; dlo = klo; }
    else          { hloc = n0 >> 7;              nh = HN;  dhi = qhi; dlo = qlo; }

#pragma unroll
    for (int p = 0; p < 16; ++p) {
        int row = p * 8 + wid;
        int token = m0 + row;
        int b = token >> 11, t = token & (TT - 1);
        size_t off = (((size_t)b * nh + hloc) * TT + t) * HD + lane * 4;
        float v0 = stile[row * LDC + lane * 4];
        float v1 = stile[row * LDC + lane * 4 + 1];
        float v2 = stile[row * LDC + lane * 4 + 2];
        float v3 = stile[row * LDC + lane * 4 + 3];
        __nv_bfloat16 h0 = __float2bfloat16(v0), h1 = __float2bfloat16(v1);
        __nv_bfloat16 h2 = __float2bfloat16(v2), h3 = __float2bfloat16(v3);
        uint2 hv, lv;
        hv.x = pack_bf16(__bfloat162float(h0), __bfloat162float(h1));
        hv.y = pack_bf16(__bfloat162float(h2), __bfloat162float(h3));
        lv.x = pack_bf16(v0 - __bfloat162float(h0), v1 - __bfloat162float(h1));
        lv.y = pack_bf16(v2 - __bfloat162float(h2), v3 - __bfloat162float(h3));
        *(uint2*)&dhi[off] = hv;
        *(uint2*)&dlo[off] = lv;
    }
}

// ============ tensor-core causal flash attention (bf16-split) ==============
// Q fragments in registers; 3-stage KV pipeline; 1 barrier per iteration.
// Q is pre-scaled by log2(e) in the QKV epilogue -> softmax in exp2 domain.
#define FBM 128
#define FBN 64
#define LDQ 136
#define QHALF  (FBM * LDQ * 2)        // 34816 bytes per Q array (hi or lo)
#define KTILEB (FBN * LDQ * 2)        // 17408 bytes per K/V array
#define STAGEB (4 * KTILEB)           // 69632
#define NSTAGE 3
#define FATT_SMEM (NSTAGE * STAGEB)   // 208896

__device__ __forceinline__ void fatt_load_kv(
    uint32_t st, int tid,
    const __nv_bfloat16* kp_hi, const __nv_bfloat16* kp_lo,
    const __nv_bfloat16* vp_hi, const __nv_bfloat16* vp_lo, int kb)
{
    const size_t base = (size_t)kb * FBN * HD;
#pragma unroll
    for (int i = 0; i < 4; ++i) {
        int ch = tid + i * 256;
        int row = ch >> 4, seg = ch & 15;
        uint32_t so = (uint32_t)(row * (LDQ * 2) + seg * 16);
        size_t go = base + (size_t)row * HD + seg * 8;
        cp16(st + 0 * KTILEB + so, kp_hi + go);
        cp16(st + 1 * KTILEB + so, kp_lo + go);
        cp16(st + 2 * KTILEB + so, vp_hi + go);
        cp16(st + 3 * KTILEB + so, vp_lo + go);
    }
    CP_COMMIT();
}

__global__ void __launch_bounds__(256, 1) fattn_kernel(
    const __nv_bfloat16* __restrict__ Qhi, const __nv_bfloat16* __restrict__ Qlo,
    const __nv_bfloat16* __restrict__ Khi, const __nv_bfloat16* __restrict__ Klo,
    const __nv_bfloat16* __restrict__ Vhi, const __nv_bfloat16* __restrict__ Vlo,
    __nv_bfloat16* __restrict__ Yhi, __nv_bfloat16* __restrict__ Ylo)
{
    extern __shared__ char smraw[];
    const uint32_t sSt = smem_u32(smraw);

    const int tid = threadIdx.x;
    const int lane = tid & 31, wid = tid >> 5;
    const int qb = (int)(gridDim.x - 1 - blockIdx.x);
    const int h  = blockIdx.y;
    const int b  = blockIdx.z;
    const int hk = h / (HN / KVH);
    const int nkb = 2 * qb + 2;

    const __nv_bfloat16* qp_hi = Qhi + ((((size_t)b * HN + h) * TT) + (size_t)qb * FBM) * HD;
    const __nv_bfloat16* qp_lo = Qlo + ((((size_t)b * HN + h) * TT) + (size_t)qb * FBM) * HD;
    const __nv_bfloat16* kp_hi = Khi + (((size_t)b * KVH + hk) * TT) * HD;
    const __nv_bfloat16* kp_lo = Klo + (((size_t)b * KVH + hk) * TT) * HD;
    const __nv_bfloat16* vp_hi = Vhi + (((size_t)b * KVH + hk) * TT) * HD;
    const __nv_bfloat16* vp_lo = Vlo + (((size_t)b * KVH + hk) * TT) * HD;

    // --- prologue: Q into stage-2 region (one cp.async group), then kv0/kv1
    const uint32_t sQh = sSt + 2 * STAGEB;
    const uint32_t sQl = sQh + QHALF;
#pragma unroll
    for (int i = 0; i < 8; ++i) {
        int ch = tid + i * 256;
        int row = ch >> 4, seg = ch & 15;
        uint32_t so = (uint32_t)(row * (LDQ * 2) + seg * 16);
        size_t go = (size_t)row * HD + seg * 8;
        cp16(sQh + so, qp_hi + go);
        cp16(sQl + so, qp_lo + go);
    }
    CP_COMMIT();
    fatt_load_kv(sSt, tid, kp_hi, kp_lo, vp_hi, vp_lo, 0);
    fatt_load_kv(sSt + STAGEB, tid, kp_hi, kp_lo, vp_hi, vp_lo, 1);

    // fragment lane bases
    const uint32_t aoff = (uint32_t)((wid * 16 + (lane & 15)) * (LDQ * 2)) + ((lane >> 4) << 4);
    const int g = lane >> 3;
    const uint32_t boff = (uint32_t)(((lane & 7) + ((g >> 1) << 3)) * (LDQ * 2)) + ((g & 1) << 4);
    const uint32_t voff = (uint32_t)((lane & 15) * (LDQ * 2)) + (((lane >> 4) & 1) << 4);

    // --- Q fragments -> registers (once)
    CP_WAIT2();           // Q group complete (kv0/kv1 may be pending)
    __syncthreads();
    uint32_t aq_hi[8][4], aq_lo[8][4];
#pragma unroll
    for (int kc = 0; kc < 8; ++kc) {
        ldsm_x4(aq_hi[kc], sQh + aoff + kc * 32);
        ldsm_x4(aq_lo[kc], sQl + aoff + kc * 32);
    }

    float o[16][4];
#pragma unroll
    for (int nf = 0; nf < 16; ++nf)
#pragma unroll
        for (int e = 0; e < 4; ++e) o[nf][e] = 0.f;
    float m_i[2] = {-1e30f, -1e30f};   // log2-domain running max
    float l_i[2] = {0.f, 0.f};

    const int qrow0 = qb * FBM + wid * 16 + (lane >> 2);

    for (int kb = 0; kb < nkb; ++kb) {
        const int slot = kb % NSTAGE;
        CP_WAIT1();        // stage kb complete (kb+1 may be pending)
        __syncthreads();   // data visible + all warps done with slot (kb+2)%3
        if (kb + 2 < nkb)
            fatt_load_kv(sSt + (uint32_t)((kb + 2) % NSTAGE) * STAGEB, tid,
                         kp_hi, kp_lo, vp_hi, vp_lo, kb + 2);

        const uint32_t sKh = sSt + (uint32_t)slot * STAGEB;
        const uint32_t sKl = sKh + KTILEB;
        const uint32_t sVh = sKh + 2 * KTILEB;
        const uint32_t sVl = sKh + 3 * KTILEB;

        // ---- S = Q K^T (3-term bf16 split), Q from registers ----
        float s[8][4];
#pragma unroll
        for (int j = 0; j < 8; ++j)
#pragma unroll
            for (int e = 0; e < 4; ++e) s[j][e] = 0.f;

#pragma unroll
        for (int kc = 0; kc < 8; ++kc) {
#pragma unroll
            for (int n16 = 0; n16 < 4; ++n16) {
                uint32_t bh[4], bl[4];
                ldsm_x4(bh, sKh + boff + n16 * 16 * (LDQ * 2) + kc * 32);
                ldsm_x4(bl, sKl + boff + n16 * 16 * (LDQ * 2) + kc * 32);
                mma16816(s[2 * n16],     aq_hi[kc], &bh[0]);
                mma16816(s[2 * n16],     aq_hi[kc], &bl[0]);
                mma16816(s[2 * n16],     aq_lo[kc], &bh[0]);
                mma16816(s[2 * n16 + 1], aq_hi[kc], &bh[2]);
                mma16816(s[2 * n16 + 1], aq_hi[kc], &bl[2]);
                mma16816(s[2 * n16 + 1], aq_lo[kc], &bh[2]);
            }
        }

        // ---- causal mask (diagonal blocks only) ----
        if (kb >= nkb - 2) {
            const int kc0 = kb * FBN + 2 * (lane & 3);
#pragma unroll
            for (int j = 0; j < 8; ++j)
#pragma unroll
                for (int e = 0; e < 4; ++e) {
                    int row = qrow0 + (e >> 1) * 8;
                    int col = kc0 + 8 * j + (e & 1);
                    if (col > row) s[j][e] = -1e30f;
                }
        }

        // ---- row max + alpha (log2 domain) ----
        float alpha[2], mx2[2];
#pragma unroll
        for (int rr = 0; rr < 2; ++rr) {
            float mx = m_i[rr];
#pragma unroll
            for (int j = 0; j < 8; ++j)
                mx = fmaxf(mx, fmaxf(s[j][2 * rr], s[j][2 * rr + 1]));
            mx = fmaxf(mx, __shfl_xor_sync(0xffffffff, mx, 1));
            mx = fmaxf(mx, __shfl_xor_sync(0xffffffff, mx, 2));
            alpha[rr] = exp2f(m_i[rr] - mx);
            m_i[rr] = mx;
            mx2[rr] = mx;
        }
#pragma unroll
        for (int nf = 0; nf < 16; ++nf) {
            o[nf][0] *= alpha[0]; o[nf][1] *= alpha[0];
            o[nf][2] *= alpha[1]; o[nf][3] *= alpha[1];
        }
        float lsum[2] = {0.f, 0.f};

        // ---- per-chunk: exp2 + pack + PV mma ----
#pragma unroll
        for (int kc2 = 0; kc2 < 4; ++kc2) {
            const int j0 = 2 * kc2, j1 = 2 * kc2 + 1;
            float p[8];
            p[0] = exp2f(s[j0][0] - mx2[0]);
            p[1] = exp2f(s[j0][1] - mx2[0]);
            p[2] = exp2f(s[j0][2] - mx2[1]);
            p[3] = exp2f(s[j0][3] - mx2[1]);
            p[4] = exp2f(s[j1][0] - mx2[0]);
            p[5] = exp2f(s[j1][1] - mx2[0]);
            p[6] = exp2f(s[j1][2] - mx2[1]);
            p[7] = exp2f(s[j1][3] - mx2[1]);
            lsum[0] += (p[0] + p[1]) + (p[4] + p[5]);
            lsum[1] += (p[2] + p[3]) + (p[6] + p[7]);

            uint32_t ap_hi[4], ap_lo[4];
            float h0 = __bfloat162float(__float2bfloat16(p[0]));
            float h1 = __bfloat162float(__float2bfloat16(p[1]));
            float h2 = __bfloat162float(__float2bfloat16(p[2]));
            float h3 = __bfloat162float(__float2bfloat16(p[3]));
            float h4 = __bfloat162float(__float2bfloat16(p[4]));
            float h5 = __bfloat162float(__float2bfloat16(p[5]));
            float h6 = __bfloat162float(__float2bfloat16(p[6]));
            float h7 = __bfloat162float(__float2bfloat16(p[7]));
            ap_hi[0] = pack_bf16(h0, h1);
            ap_hi[1] = pack_bf16(h2, h3);
            ap_hi[2] = pack_bf16(h4, h5);
            ap_hi[3] = pack_bf16(h6, h7);
            ap_lo[0] = pack_bf16(p[0] - h0, p[1] - h1);
            ap_lo[1] = pack_bf16(p[2] - h2, p[3] - h3);
            ap_lo[2] = pack_bf16(p[4] - h4, p[5] - h5);
            ap_lo[3] = pack_bf16(p[6] - h6, p[7] - h7);

            const uint32_t vrow = voff + kc2 * 16 * (LDQ * 2);
#pragma unroll
            for (int nf16 = 0; nf16 < 8; ++nf16) {
                uint32_t bvh[4], bvl[4];
                ldsm_x4_t(bvh, sVh + vrow + nf16 * 32);
                ldsm_x4_t(bvl, sVl + vrow + nf16 * 32);
                mma16816(o[2 * nf16],     ap_hi, &bvh[0]);
                mma16816(o[2 * nf16],     ap_lo, &bvh[0]);
                mma16816(o[2 * nf16],     ap_hi, &bvl[0]);
                mma16816(o[2 * nf16 + 1], ap_hi, &bvh[2]);
                mma16816(o[2 * nf16 + 1], ap_lo, &bvh[2]);
                mma16816(o[2 * nf16 + 1], ap_hi, &bvl[2]);
            }
        }
        l_i[0] = l_i[0] * alpha[0] + lsum[0];
        l_i[1] = l_i[1] * alpha[1] + lsum[1];
    }

    // ---- epilogue ----
#pragma unroll
    for (int rr = 0; rr < 2; ++rr) {
        float lf = l_i[rr];
        lf += __shfl_xor_sync(0xffffffff, lf, 1);
        lf += __shfl_xor_sync(0xffffffff, lf, 2);
        float inv = 1.0f / lf;
        int trow = qrow0 + rr * 8;
        size_t rbase = ((size_t)(b * TT + trow)) * DD + h * HD + 2 * (lane & 3);
#pragma unroll
        for (int nf = 0; nf < 16; ++nf) {
            float v0 = o[nf][2 * rr] * inv;
            float v1 = o[nf][2 * rr + 1] * inv;
            __nv_bfloat16 h0 = __float2bfloat16(v0);
            __nv_bfloat16 h1 = __float2bfloat16(v1);
            __nv_bfloat16 l0 = __float2bfloat16(v0 - __bfloat162float(h0));
            __nv_bfloat16 l1 = __float2bfloat16(v1 - __bfloat162float(h1));
            *(__nv_bfloat162*)&Yhi[rbase + nf * 8] = __nv_bfloat162(h0, h1);
            *(__nv_bfloat162*)&Ylo[rbase + nf * 8] = __nv_bfloat162(l0, l1);
        }
    }
}

// ---------------------------- launch ---------------------------------------
static inline void split(const float* src, __nv_bfloat16* hi, __nv_bfloat16* lo,
                         size_t n)
{
    int n4 = (int)(n / 4);
    int blocks = (n4 + 511) / 512;
    if (blocks > 2048) blocks = 2048;
    split_kernel<<<blocks, 256>>>((const float4*)src, (uint2*)hi, (uint2*)lo, n4);
}

extern "C" void kernel_launch(void* const* d_in, const int* in_sizes, int n_in,
                              void* d_out, int out_size)
{
    const float* x   = (const float*)d_in[0];
    const float* Wq  = (const float*)d_in[1];
    const float* Wk  = (const float*)d_in[2];
    const float* Wv  = (const float*)d_in[3];
    const float* Wp  = (const float*)d_in[4];
    const float* qg  = (const float*)d_in[5];
    float* out = (float*)d_out;

    __nv_bfloat16 *xhi, *xlo, *wchi, *wclo, *wphi, *wplo, *yhi, *ylo;
    __nv_bfloat16 *qhi, *qlo, *khi, *klo, *vhi, *vlo;
    cudaGetSymbolAddress((void**)&xhi, g_xhi);   cudaGetSymbolAddress((void**)&xlo, g_xlo);
    cudaGetSymbolAddress((void**)&wchi, g_wchi); cudaGetSymbolAddress((void**)&wclo, g_wclo);
    cudaGetSymbolAddress((void**)&wphi, g_wphi); cudaGetSymbolAddress((void**)&wplo, g_wplo);
    cudaGetSymbolAddress((void**)&yhi, g_yhi);   cudaGetSymbolAddress((void**)&ylo, g_ylo);
    cudaGetSymbolAddress((void**)&qhi, g_qhi);   cudaGetSymbolAddress((void**)&qlo, g_qlo);
    cudaGetSymbolAddress((void**)&khi, g_khi);   cudaGetSymbolAddress((void**)&klo, g_klo);
    cudaGetSymbolAddress((void**)&vhi, g_vhi);   cudaGetSymbolAddress((void**)&vlo, g_vlo);

    cudaFuncSetAttribute(gemm_mma_kernel<0>,
                         cudaFuncAttributeMaxDynamicSharedMemorySize, GEMM_SMEM);
    cudaFuncSetAttribute(gemm_mma_kernel<1>,
                         cudaFuncAttributeMaxDynamicSharedMemorySize, GEMM_SMEM);
    cudaFuncSetAttribute(fattn_kernel,
                         cudaFuncAttributeMaxDynamicSharedMemorySize, FATT_SMEM);

    // Pre-scale Q by log2(e) so flash-attention softmax runs in exp2 domain.
    const float qscale = LOG2E / sqrtf((float)HD);

    // hi/lo splits: x, combined W = [Wq; Wk; Wv] (row-contiguous), Wp
    split(x,  xhi,  xlo,  (size_t)NTOK * KTOT);
    split(Wq, wchi,                          wclo,                          (size_t)DD * KTOT);
    split(Wk, wchi + (size_t)DD * KTOT,      wclo + (size_t)DD * KTOT,      (size_t)KVD * KTOT);
    split(Wv, wchi + (size_t)(DD+KVD)*KTOT,  wclo + (size_t)(DD+KVD)*KTOT,  (size_t)KVD * KTOT);
    split(Wp, wphi, wplo, (size_t)DD * KTOT);

    // fused QKV projection + RMSNorm/RoPE/split epilogue (no fp32 tmp)
    gemm_mma_kernel<1><<<dim3(QKVN / GBN, NTOK / GBM), 256, GEMM_SMEM>>>(
        xhi, xlo, wchi, wclo, nullptr, QKVN,
        qhi, qlo, khi, klo, vhi, vlo, qg, qscale);

    // tensor-core causal flash attention -> y bf16 hi/lo
    fattn_kernel<<<dim3(TT / FBM, HN, BB), 256, FATT_SMEM>>>(
        qhi, qlo, khi, klo, vhi, vlo, yhi, ylo);

    // output projection (fp32 out)
    gemm_mma_kernel<0><<<dim3(DD / GBN, NTOK / GBM), 256, GEMM_SMEM>>>(
        yhi, ylo, wphi, wplo, out, DD,
        nullptr, nullptr, nullptr, nullptr, nullptr, nullptr, nullptr, 0.f);
}

// round 9
// speedup vs baseline: 3.6060x; 1.0094x over previous
#include <cuda_runtime.h>
#include <cuda_bf16.h>
#include <cstdint>
#include <math.h>

// Problem constants
#define HN   16          // num_heads
#define KVH  4           // num_kv_heads
#define HD   128         // head_dim
#define BB   4           // batch
#define TT   2048        // seq len
#define DD   (HN*HD)     // 2048
#define KVD  (KVH*HD)    // 512
#define NTOK (BB*TT)     // 8192
#define KTOT DD          // inner dim of all GEMMs = 2048
#define QKVN (DD + 2*KVD)  // 3072 fused projection width
#define RMS_EPS 1.1920928955078125e-07f
#define LOG2E 1.4426950408889634f

// ---------------- scratch (device globals: allocation-free) ----------------
__device__ __nv_bfloat16 g_xhi[(size_t)NTOK * KTOT], g_xlo[(size_t)NTOK * KTOT];
__device__ __nv_bfloat16 g_wchi[(size_t)QKVN * KTOT], g_wclo[(size_t)QKVN * KTOT]; // Wq|Wk|Wv
__device__ __nv_bfloat16 g_wphi[(size_t)DD * KTOT],  g_wplo[(size_t)DD * KTOT];
__device__ __nv_bfloat16 g_yhi[(size_t)NTOK * KTOT], g_ylo[(size_t)NTOK * KTOT];

__device__ __nv_bfloat16 g_qhi[(size_t)BB * HN  * TT * HD], g_qlo[(size_t)BB * HN  * TT * HD];
__device__ __nv_bfloat16 g_khi[(size_t)BB * KVH * TT * HD], g_klo[(size_t)BB * KVH * TT * HD];
__device__ __nv_bfloat16 g_vhi[(size_t)BB * KVH * TT * HD], g_vlo[(size_t)BB * KVH * TT * HD];

// ======================= PTX helpers (baseline compute_103) ================
__device__ __forceinline__ uint32_t smem_u32(const void* p) {
    uint32_t a;
    asm("{ .reg .u64 t; cvta.to.shared.u64 t, %1; cvt.u32.u64 %0, t; }"
        : "=r"(a) : "l"(p));
    return a;
}
__device__ __forceinline__ void cp16(uint32_t dst, const void* src) {
    asm volatile("cp.async.cg.shared.global [%0], [%1], 16;" :: "r"(dst), "l"(src));
}
#define CP_COMMIT() asm volatile("cp.async.commit_group;" ::: "memory")
#define CP_WAIT2()  asm volatile("cp.async.wait_group 2;" ::: "memory")
#define CP_WAIT1()  asm volatile("cp.async.wait_group 1;" ::: "memory")
#define CP_WAIT0()  asm volatile("cp.async.wait_group 0;" ::: "memory")

__device__ __forceinline__ void ldsm_x4(uint32_t* r, uint32_t addr) {
    asm volatile("ldmatrix.sync.aligned.m8n8.x4.shared.b16 {%0,%1,%2,%3}, [%4];"
                 : "=r"(r[0]), "=r"(r[1]), "=r"(r[2]), "=r"(r[3]) : "r"(addr));
}
__device__ __forceinline__ void ldsm_x4_t(uint32_t* r, uint32_t addr) {
    asm volatile("ldmatrix.sync.aligned.m8n8.x4.trans.shared.b16 {%0,%1,%2,%3}, [%4];"
                 : "=r"(r[0]), "=r"(r[1]), "=r"(r[2]), "=r"(r[3]) : "r"(addr));
}
__device__ __forceinline__ void mma16816(float* c, const uint32_t* a, const uint32_t* b) {
    asm volatile(
        "mma.sync.aligned.m16n8k16.row.col.f32.bf16.bf16.f32 "
        "{%0,%1,%2,%3}, {%4,%5,%6,%7}, {%8,%9}, {%0,%1,%2,%3};"
        : "+f"(c[0]), "+f"(c[1]), "+f"(c[2]), "+f"(c[3])
        : "r"(a[0]), "r"(a[1]), "r"(a[2]), "r"(a[3]), "r"(b[0]), "r"(b[1]));
}
__device__ __forceinline__ uint32_t pack_bf16(float x, float y) {
    __nv_bfloat162 t = __floats2bfloat162_rn(x, y);
    return *(uint32_t*)&t;
}

// ============ fp32 -> bf16 hi/lo split (grid-stride) =======================
__global__ void __launch_bounds__(256) split_kernel(
    const float4* __restrict__ in, uint2* __restrict__ hi,
    uint2* __restrict__ lo, int n4)
{
    const int stride = gridDim.x * blockDim.x;
#pragma unroll 4
    for (int i = blockIdx.x * blockDim.x + threadIdx.x; i < n4; i += stride) {
        float4 w = in[i];
        __nv_bfloat16 h0 = __float2bfloat16(w.x), h1 = __float2bfloat16(w.y);
        __nv_bfloat16 h2 = __float2bfloat16(w.z), h3 = __float2bfloat16(w.w);
        uint2 hv, lv;
        hv.x = pack_bf16(__bfloat162float(h0), __bfloat162float(h1));
        hv.y = pack_bf16(__bfloat162float(h2), __bfloat162float(h3));
        lv.x = pack_bf16(w.x - __bfloat162float(h0), w.y - __bfloat162float(h1));
        lv.y = pack_bf16(w.z - __bfloat162float(h2), w.w - __bfloat162float(h3));
        hi[i] = hv;
        lo[i] = lv;
    }
}

// ========= mma.sync bf16-split GEMM: C[M,N] = A[M,K]*B[N,K]^T ==============
#define GBM 128
#define GBN 128
#define GBK 32
#define GNK (KTOT / GBK)       // 64
#define LDA 40
#define TILE_EL  (GBM * LDA)
#define STAGE_EL (4 * TILE_EL)
#define GEMM_SMEM (2 * STAGE_EL * 2)   // 81920 bytes
#define LDC 132                        // epilogue fp32 tile stride

__device__ __forceinline__ void gemm_load_stage(
    uint32_t sb, int tid, int k0,
    const __nv_bfloat16* gAhi, const __nv_bfloat16* gAlo,
    const __nv_bfloat16* gBhi, const __nv_bfloat16* gBlo)
{
#pragma unroll
    for (int i = 0; i < 2; ++i) {
        int ch = tid + i * 256;
        int r = ch >> 2, sg = ch & 3;
        uint32_t so = (uint32_t)((r * LDA + sg * 8) * 2);
        size_t go = (size_t)r * KTOT + k0 + sg * 8;
        cp16(sb + 0 * TILE_EL * 2 + so, gAhi + go);
        cp16(sb + 1 * TILE_EL * 2 + so, gAlo + go);
        cp16(sb + 2 * TILE_EL * 2 + so, gBhi + go);
        cp16(sb + 3 * TILE_EL * 2 + so, gBlo + go);
    }
    CP_COMMIT();
}

template<int MODE>
__global__ void __launch_bounds__(256, 2) gemm_mma_kernel(
    const __nv_bfloat16* __restrict__ Ahi, const __nv_bfloat16* __restrict__ Alo,
    const __nv_bfloat16* __restrict__ Bhi, const __nv_bfloat16* __restrict__ Blo,
    float* __restrict__ C, int N,
    __nv_bfloat16* __restrict__ qhi, __nv_bfloat16* __restrict__ qlo,
    __nv_bfloat16* __restrict__ khi, __nv_bfloat16* __restrict__ klo,
    __nv_bfloat16* __restrict__ vhi, __nv_bfloat16* __restrict__ vlo,
    const float* __restrict__ qg, float qscale)
{
    extern __shared__ __nv_bfloat16 smem[];
    const uint32_t sbase = smem_u32(smem);
    const int tid = threadIdx.x;
    const int lane = tid & 31, wid = tid >> 5;
    const int wm = wid >> 2, wn = wid & 3;
    const int m0 = blockIdx.y * GBM;
    const int n0 = blockIdx.x * GBN;

    const __nv_bfloat16* gAhi = Ahi + (size_t)m0 * KTOT;
    const __nv_bfloat16* gAlo = Alo + (size_t)m0 * KTOT;
    const __nv_bfloat16* gBhi = Bhi + (size_t)n0 * KTOT;
    const __nv_bfloat16* gBlo = Blo + (size_t)n0 * KTOT;

    float acc[4][4][4];
#pragma unroll
    for (int mi = 0; mi < 4; ++mi)
#pragma unroll
        for (int nj = 0; nj < 4; ++nj)
#pragma unroll
            for (int e = 0; e < 4; ++e) acc[mi][nj][e] = 0.f;

    const int arow = wm * 64 + (lane & 15);
    const uint32_t aoffbase = (uint32_t)(arow * LDA * 2) + ((lane >> 4) << 4);
    const int g = lane >> 3;
    const int brow = wn * 32 + (lane & 7) + ((g >> 1) << 3);
    const uint32_t boffbase = (uint32_t)(brow * LDA * 2) + ((g & 1) << 4);

    gemm_load_stage(sbase, tid, 0, gAhi, gAlo, gBhi, gBlo);
    gemm_load_stage(sbase + STAGE_EL * 2, tid, GBK, gAhi, gAlo, gBhi, gBlo);

    for (int kt = 0; kt < GNK; ++kt) {
        const int buf = kt & 1;
        if (kt + 1 < GNK) { CP_WAIT1(); } else { CP_WAIT0(); }
        __syncthreads();

        const uint32_t st   = sbase + (uint32_t)buf * STAGE_EL * 2;
        const uint32_t sAhi = st;
        const uint32_t sAlo = st + TILE_EL * 2;
        const uint32_t sBhi = st + 2 * TILE_EL * 2;
        const uint32_t sBlo = st + 3 * TILE_EL * 2;

#pragma unroll
        for (int kk = 0; kk < GBK; kk += 16) {
            const uint32_t akk = aoffbase + kk * 2;
            const uint32_t bkk = boffbase + kk * 2;
            uint32_t b_hi[4][2], b_lo[4][2];
#pragma unroll
            for (int nt = 0; nt < 2; ++nt) {
                uint32_t r[4];
                ldsm_x4(r, sBhi + bkk + nt * 16 * LDA * 2);
                b_hi[2 * nt][0] = r[0]; b_hi[2 * nt][1] = r[1];
                b_hi[2 * nt + 1][0] = r[2]; b_hi[2 * nt + 1][1] = r[3];
                ldsm_x4(r, sBlo + bkk + nt * 16 * LDA * 2);
                b_lo[2 * nt][0] = r[0]; b_lo[2 * nt][1] = r[1];
                b_lo[2 * nt + 1][0] = r[2]; b_lo[2 * nt + 1][1] = r[3];
            }
#pragma unroll
            for (int mi = 0; mi < 4; ++mi) {
                uint32_t a_hi[4], a_lo[4];
                ldsm_x4(a_hi, sAhi + akk + mi * 16 * LDA * 2);
                ldsm_x4(a_lo, sAlo + akk + mi * 16 * LDA * 2);
#pragma unroll
                for (int nj = 0; nj < 4; ++nj) {
                    mma16816(acc[mi][nj], a_hi, b_hi[nj]);
                    mma16816(acc[mi][nj], a_hi, b_lo[nj]);
                    mma16816(acc[mi][nj], a_lo, b_hi[nj]);
                }
            }
        }
        __syncthreads();
        if (kt + 2 < GNK)
            gemm_load_stage(st, tid, (kt + 2) * GBK, gAhi, gAlo, gBhi, gBlo);
    }

    if (MODE == 0) {
#pragma unroll
        for (int mi = 0; mi < 4; ++mi) {
            int r0 = m0 + wm * 64 + mi * 16 + (lane >> 2);
#pragma unroll
            for (int nj = 0; nj < 4; ++nj) {
                int c = n0 + wn * 32 + nj * 8 + ((lane & 3) << 1);
                *(float2*)&C[(size_t)r0 * N + c]       = make_float2(acc[mi][nj][0], acc[mi][nj][1]);
                *(float2*)&C[(size_t)(r0 + 8) * N + c] = make_float2(acc[mi][nj][2], acc[mi][nj][3]);
            }
        }
        return;
    }

    // ================= fused QKV epilogue (MODE 1) ==========================
    float* stile = (float*)smem;               // 128 x LDC fp32 tile
    float* sinv  = stile + 128 * LDC;          // 64-entry inv_freq table
    __syncthreads();

#pragma unroll
    for (int mi = 0; mi < 4; ++mi) {
        int r = wm * 64 + mi * 16 + (lane >> 2);
#pragma unroll
        for (int nj = 0; nj < 4; ++nj) {
            int c = wn * 32 + nj * 8 + ((lane & 3) << 1);
            stile[r * LDC + c]           = acc[mi][nj][0];
            stile[r * LDC + c + 1]       = acc[mi][nj][1];
            stile[(r + 8) * LDC + c]     = acc[mi][nj][2];
            stile[(r + 8) * LDC + c + 1] = acc[mi][nj][3];
        }
    }

    const bool isV = (n0 >= DD + KVD);
    const bool isK = (n0 >= DD) && !isV;
    if (!isV && tid < 64)
        sinv[tid] = 1.0f / powf(10000.0f, (float)tid * (1.0f / 64.0f));
    __syncthreads();

    if (!isV && tid < 128) {
        const int row = tid;
        const int t = (m0 + row) & (TT - 1);
        float ssq = 0.f;
#pragma unroll 8
        for (int d = 0; d < HD; ++d) {
            float x = stile[row * LDC + d];
            ssq += x * x;
        }
        float rms = rsqrtf(ssq * (1.0f / HD) + RMS_EPS);
        float gn = isK ? 1.0f : (qg[n0 >> 7] * qscale);
#pragma unroll 4
        for (int d = 0; d < 64; ++d) {
            float xa = stile[row * LDC + d] * rms;
            float xb = stile[row * LDC + d + 64] * rms;
            float s_, c_;
            sincosf((float)t * sinv[d], &s_, &c_);
            stile[row * LDC + d]      = (xa * c_ - xb * s_) * gn;
            stile[row * LDC + d + 64] = (xb * c_ + xa * s_) * gn;
        }
    }
    __syncthreads();

    __nv_bfloat16 *dhi, *dlo;
    int hloc, nh;
    if (isV)      { hloc = (n0 - DD - KVD) >> 7; nh = KVH; dhi = vhi; dlo = vlo; }
    else if (isK) { hloc = (n0 - DD) >> 7;       nh = KVH; dhi = khi; dlo = klo; }
    else          { hloc = n0 >> 7;              nh = HN;  dhi = qhi; dlo = qlo; }

#pragma unroll
    for (int p = 0; p < 16; ++p) {
        int row = p * 8 + wid;
        int token = m0 + row;
        int b = token >> 11, t = token & (TT - 1);
        size_t off = (((size_t)b * nh + hloc) * TT + t) * HD + lane * 4;
        float v0 = stile[row * LDC + lane * 4];
        float v1 = stile[row * LDC + lane * 4 + 1];
        float v2 = stile[row * LDC + lane * 4 + 2];
        float v3 = stile[row * LDC + lane * 4 + 3];
        __nv_bfloat16 h0 = __float2bfloat16(v0), h1 = __float2bfloat16(v1);
        __nv_bfloat16 h2 = __float2bfloat16(v2), h3 = __float2bfloat16(v3);
        uint2 hv, lv;
        hv.x = pack_bf16(__bfloat162float(h0), __bfloat162float(h1));
        hv.y = pack_bf16(__bfloat162float(h2), __bfloat162float(h3));
        lv.x = pack_bf16(v0 - __bfloat162float(h0), v1 - __bfloat162float(h1));
        lv.y = pack_bf16(v2 - __bfloat162float(h2), v3 - __bfloat162float(h3));
        *(uint2*)&dhi[off] = hv;
        *(uint2*)&dlo[off] = lv;
    }
}

// ============ tensor-core causal flash attention (bf16-split) ==============
// 4-warp CTA (FBM=64, FBN=32), 2 CTAs/SM, Q in registers, 3-stage KV pipe.
// Q is pre-scaled by log2(e) in the QKV epilogue -> softmax in exp2 domain.
#define FBM 64
#define FBN 32
#define LDQ 136
#define QHALF  (FBM * LDQ * 2)        // 17408 bytes per Q array (hi or lo)
#define KTILEB (FBN * LDQ * 2)        // 8704 bytes per K/V array
#define STAGEB (4 * KTILEB)           // 34816
#define NSTAGE 3
#define FATT_SMEM (NSTAGE * STAGEB)   // 104448

__device__ __forceinline__ void fatt_load_kv(
    uint32_t st, int tid,
    const __nv_bfloat16* kp_hi, const __nv_bfloat16* kp_lo,
    const __nv_bfloat16* vp_hi, const __nv_bfloat16* vp_lo, int kb)
{
    const size_t base = (size_t)kb * FBN * HD;
#pragma unroll
    for (int i = 0; i < 4; ++i) {
        int ch = tid + i * 128;            // 0..511
        int row = ch >> 4, seg = ch & 15;  // row 0..31, seg 0..15
        uint32_t so = (uint32_t)(row * (LDQ * 2) + seg * 16);
        size_t go = base + (size_t)row * HD + seg * 8;
        cp16(st + 0 * KTILEB + so, kp_hi + go);
        cp16(st + 1 * KTILEB + so, kp_lo + go);
        cp16(st + 2 * KTILEB + so, vp_hi + go);
        cp16(st + 3 * KTILEB + so, vp_lo + go);
    }
    CP_COMMIT();
}

__global__ void __launch_bounds__(128, 2) fattn_kernel(
    const __nv_bfloat16* __restrict__ Qhi, const __nv_bfloat16* __restrict__ Qlo,
    const __nv_bfloat16* __restrict__ Khi, const __nv_bfloat16* __restrict__ Klo,
    const __nv_bfloat16* __restrict__ Vhi, const __nv_bfloat16* __restrict__ Vlo,
    __nv_bfloat16* __restrict__ Yhi, __nv_bfloat16* __restrict__ Ylo)
{
    extern __shared__ char smraw[];
    const uint32_t sSt = smem_u32(smraw);

    const int tid = threadIdx.x;
    const int lane = tid & 31, wid = tid >> 5;          // 4 warps
    const int qb = (int)(gridDim.x - 1 - blockIdx.x);   // heavy first
    const int h  = blockIdx.y;
    const int b  = blockIdx.z;
    const int hk = h / (HN / KVH);
    const int nkb = 2 * qb + 2;                         // 32-wide KV blocks

    const __nv_bfloat16* qp_hi = Qhi + ((((size_t)b * HN + h) * TT) + (size_t)qb * FBM) * HD;
    const __nv_bfloat16* qp_lo = Qlo + ((((size_t)b * HN + h) * TT) + (size_t)qb * FBM) * HD;
    const __nv_bfloat16* kp_hi = Khi + (((size_t)b * KVH + hk) * TT) * HD;
    const __nv_bfloat16* kp_lo = Klo + (((size_t)b * KVH + hk) * TT) * HD;
    const __nv_bfloat16* vp_hi = Vhi + (((size_t)b * KVH + hk) * TT) * HD;
    const __nv_bfloat16* vp_lo = Vlo + (((size_t)b * KVH + hk) * TT) * HD;

    // --- prologue: Q into stage-2 slot (exactly STAGEB bytes), then kv0/kv1
    const uint32_t sQh = sSt + 2 * STAGEB;
    const uint32_t sQl = sQh + QHALF;
#pragma unroll
    for (int i = 0; i < 8; ++i) {
        int ch = tid + i * 128;            // 0..1023
        int row = ch >> 4, seg = ch & 15;  // row 0..63
        uint32_t so = (uint32_t)(row * (LDQ * 2) + seg * 16);
        size_t go = (size_t)row * HD + seg * 8;
        cp16(sQh + so, qp_hi + go);
        cp16(sQl + so, qp_lo + go);
    }
    CP_COMMIT();
    fatt_load_kv(sSt, tid, kp_hi, kp_lo, vp_hi, vp_lo, 0);
    if (nkb > 1) fatt_load_kv(sSt + STAGEB, tid, kp_hi, kp_lo, vp_hi, vp_lo, 1);

    // fragment lane bases
    const uint32_t aoff = (uint32_t)((wid * 16 + (lane & 15)) * (LDQ * 2)) + ((lane >> 4) << 4);
    const int g = lane >> 3;
    const uint32_t boff = (uint32_t)(((lane & 7) + ((g >> 1) << 3)) * (LDQ * 2)) + ((g & 1) << 4);
    const uint32_t voff = (uint32_t)((lane & 15) * (LDQ * 2)) + (((lane >> 4) & 1) << 4);

    // --- Q fragments -> registers (once)
    if (nkb > 1) { CP_WAIT2(); } else { CP_WAIT1(); }
    __syncthreads();
    uint32_t aq_hi[8][4], aq_lo[8][4];
#pragma unroll
    for (int kc = 0; kc < 8; ++kc) {
        ldsm_x4(aq_hi[kc], sQh + aoff + kc * 32);
        ldsm_x4(aq_lo[kc], sQl + aoff + kc * 32);
    }

    float o[16][4];
#pragma unroll
    for (int nf = 0; nf < 16; ++nf)
#pragma unroll
        for (int e = 0; e < 4; ++e) o[nf][e] = 0.f;
    float m_i[2] = {-1e30f, -1e30f};   // log2-domain running max
    float l_i[2] = {0.f, 0.f};

    const int qrow0 = qb * FBM + wid * 16 + (lane >> 2);

    for (int kb = 0; kb < nkb; ++kb) {
        const int slot = kb % NSTAGE;
        if (kb + 1 < nkb) { CP_WAIT1(); } else { CP_WAIT0(); }
        __syncthreads();
        if (kb + 2 < nkb)
            fatt_load_kv(sSt + (uint32_t)((kb + 2) % NSTAGE) * STAGEB, tid,
                         kp_hi, kp_lo, vp_hi, vp_lo, kb + 2);

        const uint32_t sKh = sSt + (uint32_t)slot * STAGEB;
        const uint32_t sKl = sKh + KTILEB;
        const uint32_t sVh = sKh + 2 * KTILEB;
        const uint32_t sVl = sKh + 3 * KTILEB;

        // ---- S = Q K^T (3-term bf16 split), Q from registers ----
        float s[4][4];
#pragma unroll
        for (int j = 0; j < 4; ++j)
#pragma unroll
            for (int e = 0; e < 4; ++e) s[j][e] = 0.f;

#pragma unroll
        for (int kc = 0; kc < 8; ++kc) {
#pragma unroll
            for (int n16 = 0; n16 < 2; ++n16) {
                uint32_t bh[4], bl[4];
                ldsm_x4(bh, sKh + boff + n16 * 16 * (LDQ * 2) + kc * 32);
                ldsm_x4(bl, sKl + boff + n16 * 16 * (LDQ * 2) + kc * 32);
                mma16816(s[2 * n16],     aq_hi[kc], &bh[0]);
                mma16816(s[2 * n16],     aq_hi[kc], &bl[0]);
                mma16816(s[2 * n16],     aq_lo[kc], &bh[0]);
                mma16816(s[2 * n16 + 1], aq_hi[kc], &bh[2]);
                mma16816(s[2 * n16 + 1], aq_hi[kc], &bl[2]);
                mma16816(s[2 * n16 + 1], aq_lo[kc], &bh[2]);
            }
        }

        // ---- causal mask (diagonal 32-blocks only) ----
        if (kb >= nkb - 2) {
            const int kc0 = kb * FBN + 2 * (lane & 3);
#pragma unroll
            for (int j = 0; j < 4; ++j)
#pragma unroll
                for (int e = 0; e < 4; ++e) {
                    int row = qrow0 + (e >> 1) * 8;
                    int col = kc0 + 8 * j + (e & 1);
                    if (col > row) s[j][e] = -1e30f;
                }
        }

        // ---- row max + alpha (log2 domain) ----
        float alpha[2], mx2[2];
#pragma unroll
        for (int rr = 0; rr < 2; ++rr) {
            float mx = m_i[rr];
#pragma unroll
            for (int j = 0; j < 4; ++j)
                mx = fmaxf(mx, fmaxf(s[j][2 * rr], s[j][2 * rr + 1]));
            mx = fmaxf(mx, __shfl_xor_sync(0xffffffff, mx, 1));
            mx = fmaxf(mx, __shfl_xor_sync(0xffffffff, mx, 2));
            alpha[rr] = exp2f(m_i[rr] - mx);
            m_i[rr] = mx;
            mx2[rr] = mx;
        }
#pragma unroll
        for (int nf = 0; nf < 16; ++nf) {
            o[nf][0] *= alpha[0]; o[nf][1] *= alpha[0];
            o[nf][2] *= alpha[1]; o[nf][3] *= alpha[1];
        }
        float lsum[2] = {0.f, 0.f};

        // ---- per-chunk: exp2 + pack + PV mma ----
#pragma unroll
        for (int kc2 = 0; kc2 < 2; ++kc2) {
            const int j0 = 2 * kc2, j1 = 2 * kc2 + 1;
            float p[8];
            p[0] = exp2f(s[j0][0] - mx2[0]);
            p[1] = exp2f(s[j0][1] - mx2[0]);
            p[2] = exp2f(s[j0][2] - mx2[1]);
            p[3] = exp2f(s[j0][3] - mx2[1]);
            p[4] = exp2f(s[j1][0] - mx2[0]);
            p[5] = exp2f(s[j1][1] - mx2[0]);
            p[6] = exp2f(s[j1][2] - mx2[1]);
            p[7] = exp2f(s[j1][3] - mx2[1]);
            lsum[0] += (p[0] + p[1]) + (p[4] + p[5]);
            lsum[1] += (p[2] + p[3]) + (p[6] + p[7]);

            uint32_t ap_hi[4], ap_lo[4];
            float h0 = __bfloat162float(__float2bfloat16(p[0]));
            float h1 = __bfloat162float(__float2bfloat16(p[1]));
            float h2 = __bfloat162float(__float2bfloat16(p[2]));
            float h3 = __bfloat162float(__float2bfloat16(p[3]));
            float h4 = __bfloat162float(__float2bfloat16(p[4]));
            float h5 = __bfloat162float(__float2bfloat16(p[5]));
            float h6 = __bfloat162float(__float2bfloat16(p[6]));
            float h7 = __bfloat162float(__float2bfloat16(p[7]));
            ap_hi[0] = pack_bf16(h0, h1);
            ap_hi[1] = pack_bf16(h2, h3);
            ap_hi[2] = pack_bf16(h4, h5);
            ap_hi[3] = pack_bf16(h6, h7);
            ap_lo[0] = pack_bf16(p[0] - h0, p[1] - h1);
            ap_lo[1] = pack_bf16(p[2] - h2, p[3] - h3);
            ap_lo[2] = pack_bf16(p[4] - h4, p[5] - h5);
            ap_lo[3] = pack_bf16(p[6] - h6, p[7] - h7);

            const uint32_t vrow = voff + kc2 * 16 * (LDQ * 2);
#pragma unroll
            for (int nf16 = 0; nf16 < 8; ++nf16) {
                uint32_t bvh[4], bvl[4];
                ldsm_x4_t(bvh, sVh + vrow + nf16 * 32);
                ldsm_x4_t(bvl, sVl + vrow + nf16 * 32);
                mma16816(o[2 * nf16],     ap_hi, &bvh[0]);
                mma16816(o[2 * nf16],     ap_lo, &bvh[0]);
                mma16816(o[2 * nf16],     ap_hi, &bvl[0]);
                mma16816(o[2 * nf16 + 1], ap_hi, &bvh[2]);
                mma16816(o[2 * nf16 + 1], ap_lo, &bvh[2]);
                mma16816(o[2 * nf16 + 1], ap_hi, &bvl[2]);
            }
        }
        l_i[0] = l_i[0] * alpha[0] + lsum[0];
        l_i[1] = l_i[1] * alpha[1] + lsum[1];
    }

    // ---- epilogue ----
#pragma unroll
    for (int rr = 0; rr < 2; ++rr) {
        float lf = l_i[rr];
        lf += __shfl_xor_sync(0xffffffff, lf, 1);
        lf += __shfl_xor_sync(0xffffffff, lf, 2);
        float inv = 1.0f / lf;
        int trow = qrow0 + rr * 8;
        size_t rbase = ((size_t)(b * TT + trow)) * DD + h * HD + 2 * (lane & 3);
#pragma unroll
        for (int nf = 0; nf < 16; ++nf) {
            float v0 = o[nf][2 * rr] * inv;
            float v1 = o[nf][2 * rr + 1] * inv;
            __nv_bfloat16 h0 = __float2bfloat16(v0);
            __nv_bfloat16 h1 = __float2bfloat16(v1);
            __nv_bfloat16 l0 = __float2bfloat16(v0 - __bfloat162float(h0));
            __nv_bfloat16 l1 = __float2bfloat16(v1 - __bfloat162float(h1));
            *(__nv_bfloat162*)&Yhi[rbase + nf * 8] = __nv_bfloat162(h0, h1);
            *(__nv_bfloat162*)&Ylo[rbase + nf * 8] = __nv_bfloat162(l0, l1);
        }
    }
}

// ---------------------------- launch ---------------------------------------
static inline void split(const float* src, __nv_bfloat16* hi, __nv_bfloat16* lo,
                         size_t n)
{
    int n4 = (int)(n / 4);
    int blocks = (n4 + 511) / 512;
    if (blocks > 2048) blocks = 2048;
    split_kernel<<<blocks, 256>>>((const float4*)src, (uint2*)hi, (uint2*)lo, n4);
}

extern "C" void kernel_launch(void* const* d_in, const int* in_sizes, int n_in,
                              void* d_out, int out_size)
{
    const float* x   = (const float*)d_in[0];
    const float* Wq  = (const float*)d_in[1];
    const float* Wk  = (const float*)d_in[2];
    const float* Wv  = (const float*)d_in[3];
    const float* Wp  = (const float*)d_in[4];
    const float* qg  = (const float*)d_in[5];
    float* out = (float*)d_out;

    __nv_bfloat16 *xhi, *xlo, *wchi, *wclo, *wphi, *wplo, *yhi, *ylo;
    __nv_bfloat16 *qhi, *qlo, *khi, *klo, *vhi, *vlo;
    cudaGetSymbolAddress((void**)&xhi, g_xhi);   cudaGetSymbolAddress((void**)&xlo, g_xlo);
    cudaGetSymbolAddress((void**)&wchi, g_wchi); cudaGetSymbolAddress((void**)&wclo, g_wclo);
    cudaGetSymbolAddress((void**)&wphi, g_wphi); cudaGetSymbolAddress((void**)&wplo, g_wplo);
    cudaGetSymbolAddress((void**)&yhi, g_yhi);   cudaGetSymbolAddress((void**)&ylo, g_ylo);
    cudaGetSymbolAddress((void**)&qhi, g_qhi);   cudaGetSymbolAddress((void**)&qlo, g_qlo);
    cudaGetSymbolAddress((void**)&khi, g_khi);   cudaGetSymbolAddress((void**)&klo, g_klo);
    cudaGetSymbolAddress((void**)&vhi, g_vhi);   cudaGetSymbolAddress((void**)&vlo, g_vlo);

    cudaFuncSetAttribute(gemm_mma_kernel<0>,
                         cudaFuncAttributeMaxDynamicSharedMemorySize, GEMM_SMEM);
    cudaFuncSetAttribute(gemm_mma_kernel<1>,
                         cudaFuncAttributeMaxDynamicSharedMemorySize, GEMM_SMEM);
    cudaFuncSetAttribute(fattn_kernel,
                         cudaFuncAttributeMaxDynamicSharedMemorySize, FATT_SMEM);

    // Pre-scale Q by log2(e) so flash-attention softmax runs in exp2 domain.
    const float qscale = LOG2E / sqrtf((float)HD);

    // hi/lo splits: x, combined W = [Wq; Wk; Wv] (row-contiguous), Wp
    split(x,  xhi,  xlo,  (size_t)NTOK * KTOT);
    split(Wq, wchi,                          wclo,                          (size_t)DD * KTOT);
    split(Wk, wchi + (size_t)DD * KTOT,      wclo + (size_t)DD * KTOT,      (size_t)KVD * KTOT);
    split(Wv, wchi + (size_t)(DD+KVD)*KTOT,  wclo + (size_t)(DD+KVD)*KTOT,  (size_t)KVD * KTOT);
    split(Wp, wphi, wplo, (size_t)DD * KTOT);

    // fused QKV projection + RMSNorm/RoPE/split epilogue (no fp32 tmp)
    gemm_mma_kernel<1><<<dim3(QKVN / GBN, NTOK / GBM), 256, GEMM_SMEM>>>(
        xhi, xlo, wchi, wclo, nullptr, QKVN,
        qhi, qlo, khi, klo, vhi, vlo, qg, qscale);

    // tensor-core causal flash attention -> y bf16 hi/lo (2 CTAs/SM)
    fattn_kernel<<<dim3(TT / FBM, HN, BB), 128, FATT_SMEM>>>(
        qhi, qlo, khi, klo, vhi, vlo, yhi, ylo);

    // output projection (fp32 out)
    gemm_mma_kernel<0><<<dim3(DD / GBN, NTOK / GBM), 256, GEMM_SMEM>>>(
        yhi, ylo, wphi, wplo, out, DD,
        nullptr, nullptr, nullptr, nullptr, nullptr, nullptr, nullptr, 0.f);
}

// round 10
// speedup vs baseline: 4.6106x; 1.2786x over previous
#include <cuda_runtime.h>
#include <cuda_bf16.h>
#include <cuda_fp16.h>
#include <cstdint>
#include <math.h>

// Problem constants
#define HN   16          // num_heads
#define KVH  4           // num_kv_heads
#define HD   128         // head_dim
#define BB   4           // batch
#define TT   2048        // seq len
#define DD   (HN*HD)     // 2048
#define KVD  (KVH*HD)    // 512
#define NTOK (BB*TT)     // 8192
#define KTOT DD          // inner dim of all GEMMs = 2048
#define QKVN (DD + 2*KVD)  // 3072 fused projection width
#define RMS_EPS 1.1920928955078125e-07f
#define LOG2E 1.4426950408889634f

// ---------------- scratch (device globals: allocation-free) ----------------
// fp16 operands for projections (A plain fp16; B split hi/lo fp16)
__device__ __half g_xh [(size_t)NTOK * KTOT];
__device__ __half g_wch[(size_t)QKVN * KTOT], g_wcl[(size_t)QKVN * KTOT]; // Wq|Wk|Wv
__device__ __half g_wph[(size_t)DD * KTOT],   g_wpl[(size_t)DD * KTOT];
__device__ __half g_yh [(size_t)NTOK * KTOT];

// bf16 hi/lo Q/K/V for tensor-core attention (3-term path, unchanged)
__device__ __nv_bfloat16 g_qhi[(size_t)BB * HN  * TT * HD], g_qlo[(size_t)BB * HN  * TT * HD];
__device__ __nv_bfloat16 g_khi[(size_t)BB * KVH * TT * HD], g_klo[(size_t)BB * KVH * TT * HD];
__device__ __nv_bfloat16 g_vhi[(size_t)BB * KVH * TT * HD], g_vlo[(size_t)BB * KVH * TT * HD];

// ======================= PTX helpers (baseline compute_103) ================
__device__ __forceinline__ uint32_t smem_u32(const void* p) {
    uint32_t a;
    asm("{ .reg .u64 t; cvta.to.shared.u64 t, %1; cvt.u32.u64 %0, t; }"
        : "=r"(a) : "l"(p));
    return a;
}
__device__ __forceinline__ void cp16(uint32_t dst, const void* src) {
    asm volatile("cp.async.cg.shared.global [%0], [%1], 16;" :: "r"(dst), "l"(src));
}
#define CP_COMMIT() asm volatile("cp.async.commit_group;" ::: "memory")
#define CP_WAIT2()  asm volatile("cp.async.wait_group 2;" ::: "memory")
#define CP_WAIT1()  asm volatile("cp.async.wait_group 1;" ::: "memory")
#define CP_WAIT0()  asm volatile("cp.async.wait_group 0;" ::: "memory")

__device__ __forceinline__ void ldsm_x4(uint32_t* r, uint32_t addr) {
    asm volatile("ldmatrix.sync.aligned.m8n8.x4.shared.b16 {%0,%1,%2,%3}, [%4];"
                 : "=r"(r[0]), "=r"(r[1]), "=r"(r[2]), "=r"(r[3]) : "r"(addr));
}
__device__ __forceinline__ void ldsm_x4_t(uint32_t* r, uint32_t addr) {
    asm volatile("ldmatrix.sync.aligned.m8n8.x4.trans.shared.b16 {%0,%1,%2,%3}, [%4];"
                 : "=r"(r[0]), "=r"(r[1]), "=r"(r[2]), "=r"(r[3]) : "r"(addr));
}
// bf16 mma (attention)
__device__ __forceinline__ void mma16816(float* c, const uint32_t* a, const uint32_t* b) {
    asm volatile(
        "mma.sync.aligned.m16n8k16.row.col.f32.bf16.bf16.f32 "
        "{%0,%1,%2,%3}, {%4,%5,%6,%7}, {%8,%9}, {%0,%1,%2,%3};"
        : "+f"(c[0]), "+f"(c[1]), "+f"(c[2]), "+f"(c[3])
        : "r"(a[0]), "r"(a[1]), "r"(a[2]), "r"(a[3]), "r"(b[0]), "r"(b[1]));
}
// fp16 mma (projections)
__device__ __forceinline__ void mma16816h(float* c, const uint32_t* a, const uint32_t* b) {
    asm volatile(
        "mma.sync.aligned.m16n8k16.row.col.f32.f16.f16.f32 "
        "{%0,%1,%2,%3}, {%4,%5,%6,%7}, {%8,%9}, {%0,%1,%2,%3};"
        : "+f"(c[0]), "+f"(c[1]), "+f"(c[2]), "+f"(c[3])
        : "r"(a[0]), "r"(a[1]), "r"(a[2]), "r"(a[3]), "r"(b[0]), "r"(b[1]));
}
__device__ __forceinline__ uint32_t pack_bf16(float x, float y) {
    __nv_bfloat162 t = __floats2bfloat162_rn(x, y);
    return *(uint32_t*)&t;
}
__device__ __forceinline__ uint32_t pack_h16(float x, float y) {
    __half2 t = __floats2half2_rn(x, y);
    return *(uint32_t*)&t;
}

// ============ fp32 -> fp16 plain conversion (grid-stride) ==================
__global__ void __launch_bounds__(256) cvt16_kernel(
    const float4* __restrict__ in, uint2* __restrict__ out, int n4)
{
    const int stride = gridDim.x * blockDim.x;
#pragma unroll 4
    for (int i = blockIdx.x * blockDim.x + threadIdx.x; i < n4; i += stride) {
        float4 w = in[i];
        uint2 v;
        v.x = pack_h16(w.x, w.y);
        v.y = pack_h16(w.z, w.w);
        out[i] = v;
    }
}

// ============ fp32 -> fp16 hi/lo split (grid-stride) =======================
__global__ void __launch_bounds__(256) split16_kernel(
    const float4* __restrict__ in, uint2* __restrict__ hi,
    uint2* __restrict__ lo, int n4)
{
    const int stride = gridDim.x * blockDim.x;
#pragma unroll 4
    for (int i = blockIdx.x * blockDim.x + threadIdx.x; i < n4; i += stride) {
        float4 w = in[i];
        __half h0 = __float2half_rn(w.x), h1 = __float2half_rn(w.y);
        __half h2 = __float2half_rn(w.z), h3 = __float2half_rn(w.w);
        uint2 hv, lv;
        hv.x = pack_h16(__half2float(h0), __half2float(h1));
        hv.y = pack_h16(__half2float(h2), __half2float(h3));
        lv.x = pack_h16(w.x - __half2float(h0), w.y - __half2float(h1));
        lv.y = pack_h16(w.z - __half2float(h2), w.w - __half2float(h3));
        hi[i] = hv;
        lo[i] = lv;
    }
}

// ==== fp16 2-term GEMM: C[M,N] = A[M,K] * (Bhi+Blo)[N,K]^T (fp32 out) ======
// 3-slot cp.async pipeline, one barrier per K-step. MODE 1 = fused QKV epi.
#define GBM 128
#define GBN 128
#define GBK 32
#define GNK (KTOT / GBK)       // 64
#define LDA 40
#define TILE_EL (GBM * LDA)    // 5120 elements
#define TILE_B  (TILE_EL * 2)  // 10240 bytes
#define STAGE_B (3 * TILE_B)   // 30720 bytes (A, Bhi, Blo)
#define NST 3
#define GEMM_SMEM (NST * STAGE_B)  // 92160 bytes
#define LDC 132                    // epilogue fp32 tile stride

__device__ __forceinline__ void gemm_load_stage(
    uint32_t sb, int tid, int k0,
    const __half* gA, const __half* gBh, const __half* gBl)
{
#pragma unroll
    for (int i = 0; i < 2; ++i) {
        int ch = tid + i * 256;
        int r = ch >> 2, sg = ch & 3;
        uint32_t so = (uint32_t)((r * LDA + sg * 8) * 2);
        size_t go = (size_t)r * KTOT + k0 + sg * 8;
        cp16(sb + so, gA + go);
        cp16(sb + TILE_B + so, gBh + go);
        cp16(sb + 2 * TILE_B + so, gBl + go);
    }
    CP_COMMIT();
}

template<int MODE>
__global__ void __launch_bounds__(256, 2) gemm_mma_kernel(
    const __half* __restrict__ A,
    const __half* __restrict__ Bh, const __half* __restrict__ Bl,
    float* __restrict__ C, int N,
    __nv_bfloat16* __restrict__ qhi, __nv_bfloat16* __restrict__ qlo,
    __nv_bfloat16* __restrict__ khi, __nv_bfloat16* __restrict__ klo,
    __nv_bfloat16* __restrict__ vhi, __nv_bfloat16* __restrict__ vlo,
    const float* __restrict__ qg, float qscale)
{
    extern __shared__ __half smem[];
    const uint32_t sbase = smem_u32(smem);
    const int tid = threadIdx.x;
    const int lane = tid & 31, wid = tid >> 5;
    const int wm = wid >> 2, wn = wid & 3;
    const int m0 = blockIdx.y * GBM;
    const int n0 = blockIdx.x * GBN;

    const __half* gA  = A  + (size_t)m0 * KTOT;
    const __half* gBh = Bh + (size_t)n0 * KTOT;
    const __half* gBl = Bl + (size_t)n0 * KTOT;

    float acc[4][4][4];
#pragma unroll
    for (int mi = 0; mi < 4; ++mi)
#pragma unroll
        for (int nj = 0; nj < 4; ++nj)
#pragma unroll
            for (int e = 0; e < 4; ++e) acc[mi][nj][e] = 0.f;

    const int arow = wm * 64 + (lane & 15);
    const uint32_t aoffbase = (uint32_t)(arow * LDA * 2) + ((lane >> 4) << 4);
    const int g = lane >> 3;
    const int brow = wn * 32 + (lane & 7) + ((g >> 1) << 3);
    const uint32_t boffbase = (uint32_t)(brow * LDA * 2) + ((g & 1) << 4);

    gemm_load_stage(sbase, tid, 0, gA, gBh, gBl);
    gemm_load_stage(sbase + STAGE_B, tid, GBK, gA, gBh, gBl);

    for (int kt = 0; kt < GNK; ++kt) {
        const int slot = kt % NST;
        if (kt + 1 < GNK) { CP_WAIT1(); } else { CP_WAIT0(); }
        __syncthreads();
        if (kt + 2 < GNK)
            gemm_load_stage(sbase + (uint32_t)((kt + 2) % NST) * STAGE_B,
                            tid, (kt + 2) * GBK, gA, gBh, gBl);

        const uint32_t st  = sbase + (uint32_t)slot * STAGE_B;
        const uint32_t sA  = st;
        const uint32_t sBh = st + TILE_B;
        const uint32_t sBl = st + 2 * TILE_B;

#pragma unroll
        for (int kk = 0; kk < GBK; kk += 16) {
            const uint32_t akk = aoffbase + kk * 2;
            const uint32_t bkk = boffbase + kk * 2;
            uint32_t b_hi[4][2], b_lo[4][2];
#pragma unroll
            for (int nt = 0; nt < 2; ++nt) {
                uint32_t r[4];
                ldsm_x4(r, sBh + bkk + nt * 16 * LDA * 2);
                b_hi[2 * nt][0] = r[0]; b_hi[2 * nt][1] = r[1];
                b_hi[2 * nt + 1][0] = r[2]; b_hi[2 * nt + 1][1] = r[3];
                ldsm_x4(r, sBl + bkk + nt * 16 * LDA * 2);
                b_lo[2 * nt][0] = r[0]; b_lo[2 * nt][1] = r[1];
                b_lo[2 * nt + 1][0] = r[2]; b_lo[2 * nt + 1][1] = r[3];
            }
#pragma unroll
            for (int mi = 0; mi < 4; ++mi) {
                uint32_t a[4];
                ldsm_x4(a, sA + akk + mi * 16 * LDA * 2);
#pragma unroll
                for (int nj = 0; nj < 4; ++nj) {
                    mma16816h(acc[mi][nj], a, b_hi[nj]);
                    mma16816h(acc[mi][nj], a, b_lo[nj]);
                }
            }
        }
    }

    if (MODE == 0) {
#pragma unroll
        for (int mi = 0; mi < 4; ++mi) {
            int r0 = m0 + wm * 64 + mi * 16 + (lane >> 2);
#pragma unroll
            for (int nj = 0; nj < 4; ++nj) {
                int c = n0 + wn * 32 + nj * 8 + ((lane & 3) << 1);
                *(float2*)&C[(size_t)r0 * N + c]       = make_float2(acc[mi][nj][0], acc[mi][nj][1]);
                *(float2*)&C[(size_t)(r0 + 8) * N + c] = make_float2(acc[mi][nj][2], acc[mi][nj][3]);
            }
        }
        return;
    }

    // ================= fused QKV epilogue (MODE 1) ==========================
    float* stile = (float*)smem;               // 128 x LDC fp32 tile
    float* sinv  = stile + 128 * LDC;          // 64-entry inv_freq table
    __syncthreads();                           // mainloop smem fully consumed

#pragma unroll
    for (int mi = 0; mi < 4; ++mi) {
        int r = wm * 64 + mi * 16 + (lane >> 2);
#pragma unroll
        for (int nj = 0; nj < 4; ++nj) {
            int c = wn * 32 + nj * 8 + ((lane & 3) << 1);
            stile[r * LDC + c]           = acc[mi][nj][0];
            stile[r * LDC + c + 1]       = acc[mi][nj][1];
            stile[(r + 8) * LDC + c]     = acc[mi][nj][2];
            stile[(r + 8) * LDC + c + 1] = acc[mi][nj][3];
        }
    }

    const bool isV = (n0 >= DD + KVD);
    const bool isK = (n0 >= DD) && !isV;
    if (!isV && tid < 64)
        sinv[tid] = 1.0f / powf(10000.0f, (float)tid * (1.0f / 64.0f));
    __syncthreads();

    if (!isV && tid < 128) {
        const int row = tid;
        const int t = (m0 + row) & (TT - 1);
        float ssq = 0.f;
#pragma unroll 8
        for (int d = 0; d < HD; ++d) {
            float x = stile[row * LDC + d];
            ssq += x * x;
        }
        float rms = rsqrtf(ssq * (1.0f / HD) + RMS_EPS);
        float gn = isK ? 1.0f : (qg[n0 >> 7] * qscale);
#pragma unroll 4
        for (int d = 0; d < 64; ++d) {
            float xa = stile[row * LDC + d] * rms;
            float xb = stile[row * LDC + d + 64] * rms;
            float s_, c_;
            sincosf((float)t * sinv[d], &s_, &c_);
            stile[row * LDC + d]      = (xa * c_ - xb * s_) * gn;
            stile[row * LDC + d + 64] = (xb * c_ + xa * s_) * gn;
        }
    }
    __syncthreads();

    __nv_bfloat16 *dhi, *dlo;
    int hloc, nh;
    if (isV)      { hloc = (n0 - DD - KVD) >> 7; nh = KVH; dhi = vhi; dlo = vlo; }
    else if (isK) { hloc = (n0 - DD) >> 7;       nh = KVH; dhi = khi; dlo = klo; }
    else          { hloc = n0 >> 7;              nh = HN;  dhi = qhi; dlo = qlo; }

#pragma unroll
    for (int p = 0; p < 16; ++p) {
        int row = p * 8 + wid;
        int token = m0 + row;
        int b = token >> 11, t = token & (TT - 1);
        size_t off = (((size_t)b * nh + hloc) * TT + t) * HD + lane * 4;
        float v0 = stile[row * LDC + lane * 4];
        float v1 = stile[row * LDC + lane * 4 + 1];
        float v2 = stile[row * LDC + lane * 4 + 2];
        float v3 = stile[row * LDC + lane * 4 + 3];
        __nv_bfloat16 h0 = __float2bfloat16(v0), h1 = __float2bfloat16(v1);
        __nv_bfloat16 h2 = __float2bfloat16(v2), h3 = __float2bfloat16(v3);
        uint2 hv, lv;
        hv.x = pack_bf16(__bfloat162float(h0), __bfloat162float(h1));
        hv.y = pack_bf16(__bfloat162float(h2), __bfloat162float(h3));
        lv.x = pack_bf16(v0 - __bfloat162float(h0), v1 - __bfloat162float(h1));
        lv.y = pack_bf16(v2 - __bfloat162float(h2), v3 - __bfloat162float(h3));
        *(uint2*)&dhi[off] = hv;
        *(uint2*)&dlo[off] = lv;
    }
}

// ============ tensor-core causal flash attention (bf16-split) ==============
// 4-warp CTA (FBM=64, FBN=32), 2 CTAs/SM, Q in registers, 3-stage KV pipe.
// Q is pre-scaled by log2(e) -> softmax in exp2 domain. Output y: fp16 plain.
#define FBM 64
#define FBN 32
#define LDQ 136
#define QHALF  (FBM * LDQ * 2)        // 17408 bytes per Q array (hi or lo)
#define KTILEB (FBN * LDQ * 2)        // 8704 bytes per K/V array
#define STAGEB (4 * KTILEB)           // 34816
#define NSTAGE 3
#define FATT_SMEM (NSTAGE * STAGEB)   // 104448

__device__ __forceinline__ void fatt_load_kv(
    uint32_t st, int tid,
    const __nv_bfloat16* kp_hi, const __nv_bfloat16* kp_lo,
    const __nv_bfloat16* vp_hi, const __nv_bfloat16* vp_lo, int kb)
{
    const size_t base = (size_t)kb * FBN * HD;
#pragma unroll
    for (int i = 0; i < 4; ++i) {
        int ch = tid + i * 128;            // 0..511
        int row = ch >> 4, seg = ch & 15;  // row 0..31, seg 0..15
        uint32_t so = (uint32_t)(row * (LDQ * 2) + seg * 16);
        size_t go = base + (size_t)row * HD + seg * 8;
        cp16(st + 0 * KTILEB + so, kp_hi + go);
        cp16(st + 1 * KTILEB + so, kp_lo + go);
        cp16(st + 2 * KTILEB + so, vp_hi + go);
        cp16(st + 3 * KTILEB + so, vp_lo + go);
    }
    CP_COMMIT();
}

__global__ void __launch_bounds__(128, 2) fattn_kernel(
    const __nv_bfloat16* __restrict__ Qhi, const __nv_bfloat16* __restrict__ Qlo,
    const __nv_bfloat16* __restrict__ Khi, const __nv_bfloat16* __restrict__ Klo,
    const __nv_bfloat16* __restrict__ Vhi, const __nv_bfloat16* __restrict__ Vlo,
    __half* __restrict__ Yh)
{
    extern __shared__ char smraw[];
    const uint32_t sSt = smem_u32(smraw);

    const int tid = threadIdx.x;
    const int lane = tid & 31, wid = tid >> 5;          // 4 warps
    const int qb = (int)(gridDim.x - 1 - blockIdx.x);   // heavy first
    const int h  = blockIdx.y;
    const int b  = blockIdx.z;
    const int hk = h / (HN / KVH);
    const int nkb = 2 * qb + 2;                         // 32-wide KV blocks

    const __nv_bfloat16* qp_hi = Qhi + ((((size_t)b * HN + h) * TT) + (size_t)qb * FBM) * HD;
    const __nv_bfloat16* qp_lo = Qlo + ((((size_t)b * HN + h) * TT) + (size_t)qb * FBM) * HD;
    const __nv_bfloat16* kp_hi = Khi + (((size_t)b * KVH + hk) * TT) * HD;
    const __nv_bfloat16* kp_lo = Klo + (((size_t)b * KVH + hk) * TT) * HD;
    const __nv_bfloat16* vp_hi = Vhi + (((size_t)b * KVH + hk) * TT) * HD;
    const __nv_bfloat16* vp_lo = Vlo + (((size_t)b * KVH + hk) * TT) * HD;

    // --- prologue: Q into stage-2 slot (exactly STAGEB bytes), then kv0/kv1
    const uint32_t sQh = sSt + 2 * STAGEB;
    const uint32_t sQl = sQh + QHALF;
#pragma unroll
    for (int i = 0; i < 8; ++i) {
        int ch = tid + i * 128;            // 0..1023
        int row = ch >> 4, seg = ch & 15;  // row 0..63
        uint32_t so = (uint32_t)(row * (LDQ * 2) + seg * 16);
        size_t go = (size_t)row * HD + seg * 8;
        cp16(sQh + so, qp_hi + go);
        cp16(sQl + so, qp_lo + go);
    }
    CP_COMMIT();
    fatt_load_kv(sSt, tid, kp_hi, kp_lo, vp_hi, vp_lo, 0);
    if (nkb > 1) fatt_load_kv(sSt + STAGEB, tid, kp_hi, kp_lo, vp_hi, vp_lo, 1);

    // fragment lane bases
    const uint32_t aoff = (uint32_t)((wid * 16 + (lane & 15)) * (LDQ * 2)) + ((lane >> 4) << 4);
    const int g = lane >> 3;
    const uint32_t boff = (uint32_t)(((lane & 7) + ((g >> 1) << 3)) * (LDQ * 2)) + ((g & 1) << 4);
    const uint32_t voff = (uint32_t)((lane & 15) * (LDQ * 2)) + (((lane >> 4) & 1) << 4);

    // --- Q fragments -> registers (once)
    if (nkb > 1) { CP_WAIT2(); } else { CP_WAIT1(); }
    __syncthreads();
    uint32_t aq_hi[8][4], aq_lo[8][4];
#pragma unroll
    for (int kc = 0; kc < 8; ++kc) {
        ldsm_x4(aq_hi[kc], sQh + aoff + kc * 32);
        ldsm_x4(aq_lo[kc], sQl + aoff + kc * 32);
    }

    float o[16][4];
#pragma unroll
    for (int nf = 0; nf < 16; ++nf)
#pragma unroll
        for (int e = 0; e < 4; ++e) o[nf][e] = 0.f;
    float m_i[2] = {-1e30f, -1e30f};   // log2-domain running max
    float l_i[2] = {0.f, 0.f};

    const int qrow0 = qb * FBM + wid * 16 + (lane >> 2);

    for (int kb = 0; kb < nkb; ++kb) {
        const int slot = kb % NSTAGE;
        if (kb + 1 < nkb) { CP_WAIT1(); } else { CP_WAIT0(); }
        __syncthreads();
        if (kb + 2 < nkb)
            fatt_load_kv(sSt + (uint32_t)((kb + 2) % NSTAGE) * STAGEB, tid,
                         kp_hi, kp_lo, vp_hi, vp_lo, kb + 2);

        const uint32_t sKh = sSt + (uint32_t)slot * STAGEB;
        const uint32_t sKl = sKh + KTILEB;
        const uint32_t sVh = sKh + 2 * KTILEB;
        const uint32_t sVl = sKh + 3 * KTILEB;

        // ---- S = Q K^T (3-term bf16 split), Q from registers ----
        float s[4][4];
#pragma unroll
        for (int j = 0; j < 4; ++j)
#pragma unroll
            for (int e = 0; e < 4; ++e) s[j][e] = 0.f;

#pragma unroll
        for (int kc = 0; kc < 8; ++kc) {
#pragma unroll
            for (int n16 = 0; n16 < 2; ++n16) {
                uint32_t bh[4], bl[4];
                ldsm_x4(bh, sKh + boff + n16 * 16 * (LDQ * 2) + kc * 32);
                ldsm_x4(bl, sKl + boff + n16 * 16 * (LDQ * 2) + kc * 32);
                mma16816(s[2 * n16],     aq_hi[kc], &bh[0]);
                mma16816(s[2 * n16],     aq_hi[kc], &bl[0]);
                mma16816(s[2 * n16],     aq_lo[kc], &bh[0]);
                mma16816(s[2 * n16 + 1], aq_hi[kc], &bh[2]);
                mma16816(s[2 * n16 + 1], aq_hi[kc], &bl[2]);
                mma16816(s[2 * n16 + 1], aq_lo[kc], &bh[2]);
            }
        }

        // ---- causal mask (diagonal 32-blocks only) ----
        if (kb >= nkb - 2) {
            const int kc0 = kb * FBN + 2 * (lane & 3);
#pragma unroll
            for (int j = 0; j < 4; ++j)
#pragma unroll
                for (int e = 0; e < 4; ++e) {
                    int row = qrow0 + (e >> 1) * 8;
                    int col = kc0 + 8 * j + (e & 1);
                    if (col > row) s[j][e] = -1e30f;
                }
        }

        // ---- row max + alpha (log2 domain) ----
        float alpha[2], mx2[2];
#pragma unroll
        for (int rr = 0; rr < 2; ++rr) {
            float mx = m_i[rr];
#pragma unroll
            for (int j = 0; j < 4; ++j)
                mx = fmaxf(mx, fmaxf(s[j][2 * rr], s[j][2 * rr + 1]));
            mx = fmaxf(mx, __shfl_xor_sync(0xffffffff, mx, 1));
            mx = fmaxf(mx, __shfl_xor_sync(0xffffffff, mx, 2));
            alpha[rr] = exp2f(m_i[rr] - mx);
            m_i[rr] = mx;
            mx2[rr] = mx;
        }
#pragma unroll
        for (int nf = 0; nf < 16; ++nf) {
            o[nf][0] *= alpha[0]; o[nf][1] *= alpha[0];
            o[nf][2] *= alpha[1]; o[nf][3] *= alpha[1];
        }
        float lsum[2] = {0.f, 0.f};

        // ---- per-chunk: exp2 + pack + PV mma ----
#pragma unroll
        for (int kc2 = 0; kc2 < 2; ++kc2) {
            const int j0 = 2 * kc2, j1 = 2 * kc2 + 1;
            float p[8];
            p[0] = exp2f(s[j0][0] - mx2[0]);
            p[1] = exp2f(s[j0][1] - mx2[0]);
            p[2] = exp2f(s[j0][2] - mx2[1]);
            p[3] = exp2f(s[j0][3] - mx2[1]);
            p[4] = exp2f(s[j1][0] - mx2[0]);
            p[5] = exp2f(s[j1][1] - mx2[0]);
            p[6] = exp2f(s[j1][2] - mx2[1]);
            p[7] = exp2f(s[j1][3] - mx2[1]);
            lsum[0] += (p[0] + p[1]) + (p[4] + p[5]);
            lsum[1] += (p[2] + p[3]) + (p[6] + p[7]);

            uint32_t ap_hi[4], ap_lo[4];
            float h0 = __bfloat162float(__float2bfloat16(p[0]));
            float h1 = __bfloat162float(__float2bfloat16(p[1]));
            float h2 = __bfloat162float(__float2bfloat16(p[2]));
            float h3 = __bfloat162float(__float2bfloat16(p[3]));
            float h4 = __bfloat162float(__float2bfloat16(p[4]));
            float h5 = __bfloat162float(__float2bfloat16(p[5]));
            float h6 = __bfloat162float(__float2bfloat16(p[6]));
            float h7 = __bfloat162float(__float2bfloat16(p[7]));
            ap_hi[0] = pack_bf16(h0, h1);
            ap_hi[1] = pack_bf16(h2, h3);
            ap_hi[2] = pack_bf16(h4, h5);
            ap_hi[3] = pack_bf16(h6, h7);
            ap_lo[0] = pack_bf16(p[0] - h0, p[1] - h1);
            ap_lo[1] = pack_bf16(p[2] - h2, p[3] - h3);
            ap_lo[2] = pack_bf16(p[4] - h4, p[5] - h5);
            ap_lo[3] = pack_bf16(p[6] - h6, p[7] - h7);

            const uint32_t vrow = voff + kc2 * 16 * (LDQ * 2);
#pragma unroll
            for (int nf16 = 0; nf16 < 8; ++nf16) {
                uint32_t bvh[4], bvl[4];
                ldsm_x4_t(bvh, sVh + vrow + nf16 * 32);
                ldsm_x4_t(bvl, sVl + vrow + nf16 * 32);
                mma16816(o[2 * nf16],     ap_hi, &bvh[0]);
                mma16816(o[2 * nf16],     ap_lo, &bvh[0]);
                mma16816(o[2 * nf16],     ap_hi, &bvl[0]);
                mma16816(o[2 * nf16 + 1], ap_hi, &bvh[2]);
                mma16816(o[2 * nf16 + 1], ap_lo, &bvh[2]);
                mma16816(o[2 * nf16 + 1], ap_hi, &bvl[2]);
            }
        }
        l_i[0] = l_i[0] * alpha[0] + lsum[0];
        l_i[1] = l_i[1] * alpha[1] + lsum[1];
    }

    // ---- epilogue: normalize, write fp16 y ----
#pragma unroll
    for (int rr = 0; rr < 2; ++rr) {
        float lf = l_i[rr];
        lf += __shfl_xor_sync(0xffffffff, lf, 1);
        lf += __shfl_xor_sync(0xffffffff, lf, 2);
        float inv = 1.0f / lf;
        int trow = qrow0 + rr * 8;
        size_t rbase = ((size_t)(b * TT + trow)) * DD + h * HD + 2 * (lane & 3);
#pragma unroll
        for (int nf = 0; nf < 16; ++nf) {
            float v0 = o[nf][2 * rr] * inv;
            float v1 = o[nf][2 * rr + 1] * inv;
            *(uint32_t*)&Yh[rbase + nf * 8] = pack_h16(v0, v1);
        }
    }
}

// ---------------------------- launch ---------------------------------------
static inline void launch_cvt16(const float* src, __half* dst, size_t n)
{
    int n4 = (int)(n / 4);
    int blocks = (n4 + 511) / 512;
    if (blocks > 2048) blocks = 2048;
    cvt16_kernel<<<blocks, 256>>>((const float4*)src, (uint2*)dst, n4);
}
static inline void launch_split16(const float* src, __half* hi, __half* lo, size_t n)
{
    int n4 = (int)(n / 4);
    int blocks = (n4 + 511) / 512;
    if (blocks > 2048) blocks = 2048;
    split16_kernel<<<blocks, 256>>>((const float4*)src, (uint2*)hi, (uint2*)lo, n4);
}

extern "C" void kernel_launch(void* const* d_in, const int* in_sizes, int n_in,
                              void* d_out, int out_size)
{
    const float* x   = (const float*)d_in[0];
    const float* Wq  = (const float*)d_in[1];
    const float* Wk  = (const float*)d_in[2];
    const float* Wv  = (const float*)d_in[3];
    const float* Wp  = (const float*)d_in[4];
    const float* qg  = (const float*)d_in[5];
    float* out = (float*)d_out;

    __half *xh, *wch, *wcl, *wph, *wpl, *yh;
    __nv_bfloat16 *qhi, *qlo, *khi, *klo, *vhi, *vlo;
    cudaGetSymbolAddress((void**)&xh,  g_xh);
    cudaGetSymbolAddress((void**)&wch, g_wch); cudaGetSymbolAddress((void**)&wcl, g_wcl);
    cudaGetSymbolAddress((void**)&wph, g_wph); cudaGetSymbolAddress((void**)&wpl, g_wpl);
    cudaGetSymbolAddress((void**)&yh,  g_yh);
    cudaGetSymbolAddress((void**)&qhi, g_qhi); cudaGetSymbolAddress((void**)&qlo, g_qlo);
    cudaGetSymbolAddress((void**)&khi, g_khi); cudaGetSymbolAddress((void**)&klo, g_klo);
    cudaGetSymbolAddress((void**)&vhi, g_vhi); cudaGetSymbolAddress((void**)&vlo, g_vlo);

    cudaFuncSetAttribute(gemm_mma_kernel<0>,
                         cudaFuncAttributeMaxDynamicSharedMemorySize, GEMM_SMEM);
    cudaFuncSetAttribute(gemm_mma_kernel<1>,
                         cudaFuncAttributeMaxDynamicSharedMemorySize, GEMM_SMEM);
    cudaFuncSetAttribute(fattn_kernel,
                         cudaFuncAttributeMaxDynamicSharedMemorySize, FATT_SMEM);

    // Pre-scale Q by log2(e) so flash-attention softmax runs in exp2 domain.
    const float qscale = LOG2E / sqrtf((float)HD);

    // conversions: x plain fp16; W = [Wq;Wk;Wv] and Wp split fp16 hi/lo
    launch_cvt16(x, xh, (size_t)NTOK * KTOT);
    launch_split16(Wq, wch,                         wcl,                         (size_t)DD * KTOT);
    launch_split16(Wk, wch + (size_t)DD * KTOT,     wcl + (size_t)DD * KTOT,     (size_t)KVD * KTOT);
    launch_split16(Wv, wch + (size_t)(DD+KVD)*KTOT, wcl + (size_t)(DD+KVD)*KTOT, (size_t)KVD * KTOT);
    launch_split16(Wp, wph, wpl, (size_t)DD * KTOT);

    // fused QKV projection + RMSNorm/RoPE/split epilogue
    gemm_mma_kernel<1><<<dim3(QKVN / GBN, NTOK / GBM), 256, GEMM_SMEM>>>(
        xh, wch, wcl, nullptr, QKVN,
        qhi, qlo, khi, klo, vhi, vlo, qg, qscale);

    // tensor-core causal flash attention -> y fp16 (2 CTAs/SM)
    fattn_kernel<<<dim3(TT / FBM, HN, BB), 128, FATT_SMEM>>>(
        qhi, qlo, khi, klo, vhi, vlo, yh);

    // output projection (fp32 out)
    gemm_mma_kernel<0><<<dim3(DD / GBN, NTOK / GBM), 256, GEMM_SMEM>>>(
        yh, wph, wpl, out, DD,
        nullptr, nullptr, nullptr, nullptr, nullptr, nullptr, nullptr, 0.f);
}

// round 11
// speedup vs baseline: 5.3132x; 1.1524x over previous
#include <cuda_runtime.h>
#include <cuda_bf16.h>
#include <cuda_fp16.h>
#include <cstdint>
#include <math.h>

// Problem constants
#define HN   16          // num_heads
#define KVH  4           // num_kv_heads
#define HD   128         // head_dim
#define BB   4           // batch
#define TT   2048        // seq len
#define DD   (HN*HD)     // 2048
#define KVD  (KVH*HD)    // 512
#define NTOK (BB*TT)     // 8192
#define KTOT DD          // inner dim of all GEMMs = 2048
#define QKVN (DD + 2*KVD)  // 3072 fused projection width
#define RMS_EPS 1.1920928955078125e-07f
#define LOG2E 1.4426950408889634f

// ---------------- scratch (device globals: allocation-free) ----------------
// fp16 operands for projections (A plain fp16; B split hi/lo fp16)
__device__ __half g_xh [(size_t)NTOK * KTOT];
__device__ __half g_wch[(size_t)QKVN * KTOT], g_wcl[(size_t)QKVN * KTOT]; // Wq|Wk|Wv
__device__ __half g_wph[(size_t)DD * KTOT],   g_wpl[(size_t)DD * KTOT];
__device__ __half g_yh [(size_t)NTOK * KTOT];

// fp16 Q (hi/lo split) + plain fp16 K/V for attention
__device__ __half g_qh[(size_t)BB * HN  * TT * HD], g_ql[(size_t)BB * HN  * TT * HD];
__device__ __half g_kh[(size_t)BB * KVH * TT * HD];
__device__ __half g_vh[(size_t)BB * KVH * TT * HD];

// ======================= PTX helpers (baseline compute_103) ================
__device__ __forceinline__ uint32_t smem_u32(const void* p) {
    uint32_t a;
    asm("{ .reg .u64 t; cvta.to.shared.u64 t, %1; cvt.u32.u64 %0, t; }"
        : "=r"(a) : "l"(p));
    return a;
}
__device__ __forceinline__ void cp16(uint32_t dst, const void* src) {
    asm volatile("cp.async.cg.shared.global [%0], [%1], 16;" :: "r"(dst), "l"(src));
}
#define CP_COMMIT() asm volatile("cp.async.commit_group;" ::: "memory")
#define CP_WAIT2()  asm volatile("cp.async.wait_group 2;" ::: "memory")
#define CP_WAIT1()  asm volatile("cp.async.wait_group 1;" ::: "memory")
#define CP_WAIT0()  asm volatile("cp.async.wait_group 0;" ::: "memory")

__device__ __forceinline__ void ldsm_x4(uint32_t* r, uint32_t addr) {
    asm volatile("ldmatrix.sync.aligned.m8n8.x4.shared.b16 {%0,%1,%2,%3}, [%4];"
                 : "=r"(r[0]), "=r"(r[1]), "=r"(r[2]), "=r"(r[3]) : "r"(addr));
}
__device__ __forceinline__ void ldsm_x4_t(uint32_t* r, uint32_t addr) {
    asm volatile("ldmatrix.sync.aligned.m8n8.x4.trans.shared.b16 {%0,%1,%2,%3}, [%4];"
                 : "=r"(r[0]), "=r"(r[1]), "=r"(r[2]), "=r"(r[3]) : "r"(addr));
}
// fp16 mma
__device__ __forceinline__ void mma16816h(float* c, const uint32_t* a, const uint32_t* b) {
    asm volatile(
        "mma.sync.aligned.m16n8k16.row.col.f32.f16.f16.f32 "
        "{%0,%1,%2,%3}, {%4,%5,%6,%7}, {%8,%9}, {%0,%1,%2,%3};"
        : "+f"(c[0]), "+f"(c[1]), "+f"(c[2]), "+f"(c[3])
        : "r"(a[0]), "r"(a[1]), "r"(a[2]), "r"(a[3]), "r"(b[0]), "r"(b[1]));
}
__device__ __forceinline__ uint32_t pack_h16(float x, float y) {
    __half2 t = __floats2half2_rn(x, y);
    return *(uint32_t*)&t;
}

// ============ fp32 -> fp16 plain conversion (grid-stride) ==================
__global__ void __launch_bounds__(256) cvt16_kernel(
    const float4* __restrict__ in, uint2* __restrict__ out, int n4)
{
    const int stride = gridDim.x * blockDim.x;
#pragma unroll 4
    for (int i = blockIdx.x * blockDim.x + threadIdx.x; i < n4; i += stride) {
        float4 w = in[i];
        uint2 v;
        v.x = pack_h16(w.x, w.y);
        v.y = pack_h16(w.z, w.w);
        out[i] = v;
    }
}

// ============ fp32 -> fp16 hi/lo split (grid-stride) =======================
__global__ void __launch_bounds__(256) split16_kernel(
    const float4* __restrict__ in, uint2* __restrict__ hi,
    uint2* __restrict__ lo, int n4)
{
    const int stride = gridDim.x * blockDim.x;
#pragma unroll 4
    for (int i = blockIdx.x * blockDim.x + threadIdx.x; i < n4; i += stride) {
        float4 w = in[i];
        __half h0 = __float2half_rn(w.x), h1 = __float2half_rn(w.y);
        __half h2 = __float2half_rn(w.z), h3 = __float2half_rn(w.w);
        uint2 hv, lv;
        hv.x = pack_h16(__half2float(h0), __half2float(h1));
        hv.y = pack_h16(__half2float(h2), __half2float(h3));
        lv.x = pack_h16(w.x - __half2float(h0), w.y - __half2float(h1));
        lv.y = pack_h16(w.z - __half2float(h2), w.w - __half2float(h3));
        hi[i] = hv;
        lo[i] = lv;
    }
}

// ==== fp16 2-term GEMM: C[M,N] = A[M,K] * (Bhi+Blo)[N,K]^T (fp32 out) ======
// 3-slot cp.async pipeline, one barrier per K-step. MODE 1 = fused QKV epi.
#define GBM 128
#define GBN 128
#define GBK 32
#define GNK (KTOT / GBK)       // 64
#define LDA 40
#define TILE_EL (GBM * LDA)    // 5120 elements
#define TILE_B  (TILE_EL * 2)  // 10240 bytes
#define STAGE_B (3 * TILE_B)   // 30720 bytes (A, Bhi, Blo)
#define NST 3
#define GEMM_SMEM (NST * STAGE_B)  // 92160 bytes
#define LDC 132                    // epilogue fp32 tile stride

__device__ __forceinline__ void gemm_load_stage(
    uint32_t sb, int tid, int k0,
    const __half* gA, const __half* gBh, const __half* gBl)
{
#pragma unroll
    for (int i = 0; i < 2; ++i) {
        int ch = tid + i * 256;
        int r = ch >> 2, sg = ch & 3;
        uint32_t so = (uint32_t)((r * LDA + sg * 8) * 2);
        size_t go = (size_t)r * KTOT + k0 + sg * 8;
        cp16(sb + so, gA + go);
        cp16(sb + TILE_B + so, gBh + go);
        cp16(sb + 2 * TILE_B + so, gBl + go);
    }
    CP_COMMIT();
}

template<int MODE>
__global__ void __launch_bounds__(256, 2) gemm_mma_kernel(
    const __half* __restrict__ A,
    const __half* __restrict__ Bh, const __half* __restrict__ Bl,
    float* __restrict__ C, int N,
    __half* __restrict__ qh, __half* __restrict__ ql,
    __half* __restrict__ kh, __half* __restrict__ vh,
    const float* __restrict__ qg, float qscale)
{
    extern __shared__ __half smem[];
    const uint32_t sbase = smem_u32(smem);
    const int tid = threadIdx.x;
    const int lane = tid & 31, wid = tid >> 5;
    const int wm = wid >> 2, wn = wid & 3;
    const int m0 = blockIdx.y * GBM;
    const int n0 = blockIdx.x * GBN;

    const __half* gA  = A  + (size_t)m0 * KTOT;
    const __half* gBh = Bh + (size_t)n0 * KTOT;
    const __half* gBl = Bl + (size_t)n0 * KTOT;

    float acc[4][4][4];
#pragma unroll
    for (int mi = 0; mi < 4; ++mi)
#pragma unroll
        for (int nj = 0; nj < 4; ++nj)
#pragma unroll
            for (int e = 0; e < 4; ++e) acc[mi][nj][e] = 0.f;

    const int arow = wm * 64 + (lane & 15);
    const uint32_t aoffbase = (uint32_t)(arow * LDA * 2) + ((lane >> 4) << 4);
    const int g = lane >> 3;
    const int brow = wn * 32 + (lane & 7) + ((g >> 1) << 3);
    const uint32_t boffbase = (uint32_t)(brow * LDA * 2) + ((g & 1) << 4);

    gemm_load_stage(sbase, tid, 0, gA, gBh, gBl);
    gemm_load_stage(sbase + STAGE_B, tid, GBK, gA, gBh, gBl);

    for (int kt = 0; kt < GNK; ++kt) {
        const int slot = kt % NST;
        if (kt + 1 < GNK) { CP_WAIT1(); } else { CP_WAIT0(); }
        __syncthreads();
        if (kt + 2 < GNK)
            gemm_load_stage(sbase + (uint32_t)((kt + 2) % NST) * STAGE_B,
                            tid, (kt + 2) * GBK, gA, gBh, gBl);

        const uint32_t st  = sbase + (uint32_t)slot * STAGE_B;
        const uint32_t sA  = st;
        const uint32_t sBh = st + TILE_B;
        const uint32_t sBl = st + 2 * TILE_B;

#pragma unroll
        for (int kk = 0; kk < GBK; kk += 16) {
            const uint32_t akk = aoffbase + kk * 2;
            const uint32_t bkk = boffbase + kk * 2;
            uint32_t b_hi[4][2], b_lo[4][2];
#pragma unroll
            for (int nt = 0; nt < 2; ++nt) {
                uint32_t r[4];
                ldsm_x4(r, sBh + bkk + nt * 16 * LDA * 2);
                b_hi[2 * nt][0] = r[0]; b_hi[2 * nt][1] = r[1];
                b_hi[2 * nt + 1][0] = r[2]; b_hi[2 * nt + 1][1] = r[3];
                ldsm_x4(r, sBl + bkk + nt * 16 * LDA * 2);
                b_lo[2 * nt][0] = r[0]; b_lo[2 * nt][1] = r[1];
                b_lo[2 * nt + 1][0] = r[2]; b_lo[2 * nt + 1][1] = r[3];
            }
#pragma unroll
            for (int mi = 0; mi < 4; ++mi) {
                uint32_t a[4];
                ldsm_x4(a, sA + akk + mi * 16 * LDA * 2);
#pragma unroll
                for (int nj = 0; nj < 4; ++nj) {
                    mma16816h(acc[mi][nj], a, b_hi[nj]);
                    mma16816h(acc[mi][nj], a, b_lo[nj]);
                }
            }
        }
    }

    if (MODE == 0) {
#pragma unroll
        for (int mi = 0; mi < 4; ++mi) {
            int r0 = m0 + wm * 64 + mi * 16 + (lane >> 2);
#pragma unroll
            for (int nj = 0; nj < 4; ++nj) {
                int c = n0 + wn * 32 + nj * 8 + ((lane & 3) << 1);
                *(float2*)&C[(size_t)r0 * N + c]       = make_float2(acc[mi][nj][0], acc[mi][nj][1]);
                *(float2*)&C[(size_t)(r0 + 8) * N + c] = make_float2(acc[mi][nj][2], acc[mi][nj][3]);
            }
        }
        return;
    }

    // ================= fused QKV epilogue (MODE 1) ==========================
    float* stile = (float*)smem;               // 128 x LDC fp32 tile
    float* sinv  = stile + 128 * LDC;          // 64-entry inv_freq table
    __syncthreads();                           // mainloop smem fully consumed

#pragma unroll
    for (int mi = 0; mi < 4; ++mi) {
        int r = wm * 64 + mi * 16 + (lane >> 2);
#pragma unroll
        for (int nj = 0; nj < 4; ++nj) {
            int c = wn * 32 + nj * 8 + ((lane & 3) << 1);
            stile[r * LDC + c]           = acc[mi][nj][0];
            stile[r * LDC + c + 1]       = acc[mi][nj][1];
            stile[(r + 8) * LDC + c]     = acc[mi][nj][2];
            stile[(r + 8) * LDC + c + 1] = acc[mi][nj][3];
        }
    }

    const bool isV = (n0 >= DD + KVD);
    const bool isK = (n0 >= DD) && !isV;
    if (!isV && tid < 64)
        sinv[tid] = 1.0f / powf(10000.0f, (float)tid * (1.0f / 64.0f));
    __syncthreads();

    if (!isV && tid < 128) {
        const int row = tid;
        const int t = (m0 + row) & (TT - 1);
        float ssq = 0.f;
#pragma unroll 8
        for (int d = 0; d < HD; ++d) {
            float x = stile[row * LDC + d];
            ssq += x * x;
        }
        float rms = rsqrtf(ssq * (1.0f / HD) + RMS_EPS);
        float gn = isK ? 1.0f : (qg[n0 >> 7] * qscale);
#pragma unroll 4
        for (int d = 0; d < 64; ++d) {
            float xa = stile[row * LDC + d] * rms;
            float xb = stile[row * LDC + d + 64] * rms;
            float s_, c_;
            sincosf((float)t * sinv[d], &s_, &c_);
            stile[row * LDC + d]      = (xa * c_ - xb * s_) * gn;
            stile[row * LDC + d + 64] = (xb * c_ + xa * s_) * gn;
        }
    }
    __syncthreads();

    __half* dst = nullptr;
    int hloc, nh;
    if (isV)      { hloc = (n0 - DD - KVD) >> 7; nh = KVH; dst = vh; }
    else if (isK) { hloc = (n0 - DD) >> 7;       nh = KVH; dst = kh; }
    else          { hloc = n0 >> 7;              nh = HN; }

#pragma unroll
    for (int p = 0; p < 16; ++p) {
        int row = p * 8 + wid;
        int token = m0 + row;
        int b = token >> 11, t = token & (TT - 1);
        size_t off = (((size_t)b * nh + hloc) * TT + t) * HD + lane * 4;
        float v0 = stile[row * LDC + lane * 4];
        float v1 = stile[row * LDC + lane * 4 + 1];
        float v2 = stile[row * LDC + lane * 4 + 2];
        float v3 = stile[row * LDC + lane * 4 + 3];
        if (isK || isV) {
            uint2 pv;
            pv.x = pack_h16(v0, v1);
            pv.y = pack_h16(v2, v3);
            *(uint2*)&dst[off] = pv;
        } else {
            __half h0 = __float2half_rn(v0), h1 = __float2half_rn(v1);
            __half h2 = __float2half_rn(v2), h3 = __float2half_rn(v3);
            uint2 hv, lv;
            hv.x = pack_h16(__half2float(h0), __half2float(h1));
            hv.y = pack_h16(__half2float(h2), __half2float(h3));
            lv.x = pack_h16(v0 - __half2float(h0), v1 - __half2float(h1));
            lv.y = pack_h16(v2 - __half2float(h2), v3 - __half2float(h3));
            *(uint2*)&qh[off] = hv;
            *(uint2*)&ql[off] = lv;
        }
    }
}

// ============ tensor-core causal flash attention (fp16 2-term) =============
// 4-warp CTA (FBM=64, FBN=32), 2 CTAs/SM, Q(hi/lo) in registers, K/V plain
// fp16, 3-stage KV pipe. S = (Qhi+Qlo)·K, PV = (Phi+Plo)·V. exp2 domain.
#define FBM 64
#define FBN 32
#define LDQ 136
#define QHALF  (FBM * LDQ * 2)        // 17408 bytes per Q array (hi or lo)
#define KTILEB (FBN * LDQ * 2)        // 8704 bytes per K/V tile
#define STAGEB (2 * KTILEB)           // 17408 (K + V)
#define NSTAGE 3
#define FATT_SMEM (NSTAGE * STAGEB + 2 * QHALF)   // 87040

__device__ __forceinline__ void fatt_load_kv(
    uint32_t st, int tid, const __half* kp, const __half* vp, int kb)
{
    const size_t base = (size_t)kb * FBN * HD;
#pragma unroll
    for (int i = 0; i < 4; ++i) {
        int ch = tid + i * 128;            // 0..511
        int row = ch >> 4, seg = ch & 15;  // row 0..31, seg 0..15
        uint32_t so = (uint32_t)(row * (LDQ * 2) + seg * 16);
        size_t go = base + (size_t)row * HD + seg * 8;
        cp16(st + so, kp + go);
        cp16(st + KTILEB + so, vp + go);
    }
    CP_COMMIT();
}

__global__ void __launch_bounds__(128, 2) fattn_kernel(
    const __half* __restrict__ Qh, const __half* __restrict__ Ql,
    const __half* __restrict__ Kp, const __half* __restrict__ Vp,
    __half* __restrict__ Yh)
{
    extern __shared__ char smraw[];
    const uint32_t sSt = smem_u32(smraw);

    const int tid = threadIdx.x;
    const int lane = tid & 31, wid = tid >> 5;          // 4 warps
    const int qb = (int)(gridDim.x - 1 - blockIdx.x);   // heavy first
    const int h  = blockIdx.y;
    const int b  = blockIdx.z;
    const int hk = h / (HN / KVH);
    const int nkb = 2 * qb + 2;                         // 32-wide KV blocks

    const __half* qp_hi = Qh + ((((size_t)b * HN + h) * TT) + (size_t)qb * FBM) * HD;
    const __half* qp_lo = Ql + ((((size_t)b * HN + h) * TT) + (size_t)qb * FBM) * HD;
    const __half* kp = Kp + (((size_t)b * KVH + hk) * TT) * HD;
    const __half* vp = Vp + (((size_t)b * KVH + hk) * TT) * HD;

    // --- prologue: Q into dedicated region (one group), then kv0/kv1
    const uint32_t sQh = sSt + NSTAGE * STAGEB;
    const uint32_t sQl = sQh + QHALF;
#pragma unroll
    for (int i = 0; i < 8; ++i) {
        int ch = tid + i * 128;            // 0..1023
        int row = ch >> 4, seg = ch & 15;  // row 0..63
        uint32_t so = (uint32_t)(row * (LDQ * 2) + seg * 16);
        size_t go = (size_t)row * HD + seg * 8;
        cp16(sQh + so, qp_hi + go);
        cp16(sQl + so, qp_lo + go);
    }
    CP_COMMIT();
    fatt_load_kv(sSt, tid, kp, vp, 0);
    if (nkb > 1) fatt_load_kv(sSt + STAGEB, tid, kp, vp, 1);

    // fragment lane bases
    const uint32_t aoff = (uint32_t)((wid * 16 + (lane & 15)) * (LDQ * 2)) + ((lane >> 4) << 4);
    const int g = lane >> 3;
    const uint32_t boff = (uint32_t)(((lane & 7) + ((g >> 1) << 3)) * (LDQ * 2)) + ((g & 1) << 4);
    const uint32_t voff = (uint32_t)((lane & 15) * (LDQ * 2)) + (((lane >> 4) & 1) << 4);

    // --- Q fragments -> registers (once)
    if (nkb > 1) { CP_WAIT2(); } else { CP_WAIT1(); }
    __syncthreads();
    uint32_t aq_hi[8][4], aq_lo[8][4];
#pragma unroll
    for (int kc = 0; kc < 8; ++kc) {
        ldsm_x4(aq_hi[kc], sQh + aoff + kc * 32);
        ldsm_x4(aq_lo[kc], sQl + aoff + kc * 32);
    }

    float o[16][4];
#pragma unroll
    for (int nf = 0; nf < 16; ++nf)
#pragma unroll
        for (int e = 0; e < 4; ++e) o[nf][e] = 0.f;
    float m_i[2] = {-1e30f, -1e30f};   // log2-domain running max
    float l_i[2] = {0.f, 0.f};

    const int qrow0 = qb * FBM + wid * 16 + (lane >> 2);

    for (int kb = 0; kb < nkb; ++kb) {
        const int slot = kb % NSTAGE;
        if (kb + 1 < nkb) { CP_WAIT1(); } else { CP_WAIT0(); }
        __syncthreads();
        if (kb + 2 < nkb)
            fatt_load_kv(sSt + (uint32_t)((kb + 2) % NSTAGE) * STAGEB, tid,
                         kp, vp, kb + 2);

        const uint32_t sK = sSt + (uint32_t)slot * STAGEB;
        const uint32_t sV = sK + KTILEB;

        // ---- S = (Qhi+Qlo) K^T, Q from registers, K plain fp16 ----
        float s[4][4];
#pragma unroll
        for (int j = 0; j < 4; ++j)
#pragma unroll
            for (int e = 0; e < 4; ++e) s[j][e] = 0.f;

#pragma unroll
        for (int kc = 0; kc < 8; ++kc) {
#pragma unroll
            for (int n16 = 0; n16 < 2; ++n16) {
                uint32_t bk[4];
                ldsm_x4(bk, sK + boff + n16 * 16 * (LDQ * 2) + kc * 32);
                mma16816h(s[2 * n16],     aq_hi[kc], &bk[0]);
                mma16816h(s[2 * n16],     aq_lo[kc], &bk[0]);
                mma16816h(s[2 * n16 + 1], aq_hi[kc], &bk[2]);
                mma16816h(s[2 * n16 + 1], aq_lo[kc], &bk[2]);
            }
        }

        // ---- causal mask (diagonal 32-blocks only) ----
        if (kb >= nkb - 2) {
            const int kc0 = kb * FBN + 2 * (lane & 3);
#pragma unroll
            for (int j = 0; j < 4; ++j)
#pragma unroll
                for (int e = 0; e < 4; ++e) {
                    int row = qrow0 + (e >> 1) * 8;
                    int col = kc0 + 8 * j + (e & 1);
                    if (col > row) s[j][e] = -1e30f;
                }
        }

        // ---- row max + alpha (log2 domain) ----
        float alpha[2], mx2[2];
#pragma unroll
        for (int rr = 0; rr < 2; ++rr) {
            float mx = m_i[rr];
#pragma unroll
            for (int j = 0; j < 4; ++j)
                mx = fmaxf(mx, fmaxf(s[j][2 * rr], s[j][2 * rr + 1]));
            mx = fmaxf(mx, __shfl_xor_sync(0xffffffff, mx, 1));
            mx = fmaxf(mx, __shfl_xor_sync(0xffffffff, mx, 2));
            alpha[rr] = exp2f(m_i[rr] - mx);
            m_i[rr] = mx;
            mx2[rr] = mx;
        }
#pragma unroll
        for (int nf = 0; nf < 16; ++nf) {
            o[nf][0] *= alpha[0]; o[nf][1] *= alpha[0];
            o[nf][2] *= alpha[1]; o[nf][3] *= alpha[1];
        }
        float lsum[2] = {0.f, 0.f};

        // ---- per-chunk: exp2 + fp16 hi/lo pack + PV mma ----
#pragma unroll
        for (int kc2 = 0; kc2 < 2; ++kc2) {
            const int j0 = 2 * kc2, j1 = 2 * kc2 + 1;
            float p[8];
            p[0] = exp2f(s[j0][0] - mx2[0]);
            p[1] = exp2f(s[j0][1] - mx2[0]);
            p[2] = exp2f(s[j0][2] - mx2[1]);
            p[3] = exp2f(s[j0][3] - mx2[1]);
            p[4] = exp2f(s[j1][0] - mx2[0]);
            p[5] = exp2f(s[j1][1] - mx2[0]);
            p[6] = exp2f(s[j1][2] - mx2[1]);
            p[7] = exp2f(s[j1][3] - mx2[1]);
            lsum[0] += (p[0] + p[1]) + (p[4] + p[5]);
            lsum[1] += (p[2] + p[3]) + (p[6] + p[7]);

            uint32_t ap_hi[4], ap_lo[4];
            float h0 = __half2float(__float2half_rn(p[0]));
            float h1 = __half2float(__float2half_rn(p[1]));
            float h2 = __half2float(__float2half_rn(p[2]));
            float h3 = __half2float(__float2half_rn(p[3]));
            float h4 = __half2float(__float2half_rn(p[4]));
            float h5 = __half2float(__float2half_rn(p[5]));
            float h6 = __half2float(__float2half_rn(p[6]));
            float h7 = __half2float(__float2half_rn(p[7]));
            ap_hi[0] = pack_h16(h0, h1);
            ap_hi[1] = pack_h16(h2, h3);
            ap_hi[2] = pack_h16(h4, h5);
            ap_hi[3] = pack_h16(h6, h7);
            ap_lo[0] = pack_h16(p[0] - h0, p[1] - h1);
            ap_lo[1] = pack_h16(p[2] - h2, p[3] - h3);
            ap_lo[2] = pack_h16(p[4] - h4, p[5] - h5);
            ap_lo[3] = pack_h16(p[6] - h6, p[7] - h7);

            const uint32_t vrow = voff + kc2 * 16 * (LDQ * 2);
#pragma unroll
            for (int nf16 = 0; nf16 < 8; ++nf16) {
                uint32_t bv[4];
                ldsm_x4_t(bv, sV + vrow + nf16 * 32);
                mma16816h(o[2 * nf16],     ap_hi, &bv[0]);
                mma16816h(o[2 * nf16],     ap_lo, &bv[0]);
                mma16816h(o[2 * nf16 + 1], ap_hi, &bv[2]);
                mma16816h(o[2 * nf16 + 1], ap_lo, &bv[2]);
            }
        }
        l_i[0] = l_i[0] * alpha[0] + lsum[0];
        l_i[1] = l_i[1] * alpha[1] + lsum[1];
    }

    // ---- epilogue: normalize, write fp16 y ----
#pragma unroll
    for (int rr = 0; rr < 2; ++rr) {
        float lf = l_i[rr];
        lf += __shfl_xor_sync(0xffffffff, lf, 1);
        lf += __shfl_xor_sync(0xffffffff, lf, 2);
        float inv = 1.0f / lf;
        int trow = qrow0 + rr * 8;
        size_t rbase = ((size_t)(b * TT + trow)) * DD + h * HD + 2 * (lane & 3);
#pragma unroll
        for (int nf = 0; nf < 16; ++nf) {
            float v0 = o[nf][2 * rr] * inv;
            float v1 = o[nf][2 * rr + 1] * inv;
            *(uint32_t*)&Yh[rbase + nf * 8] = pack_h16(v0, v1);
        }
    }
}

// ---------------------------- launch ---------------------------------------
static inline void launch_cvt16(const float* src, __half* dst, size_t n)
{
    int n4 = (int)(n / 4);
    int blocks = (n4 + 511) / 512;
    if (blocks > 2048) blocks = 2048;
    cvt16_kernel<<<blocks, 256>>>((const float4*)src, (uint2*)dst, n4);
}
static inline void launch_split16(const float* src, __half* hi, __half* lo, size_t n)
{
    int n4 = (int)(n / 4);
    int blocks = (n4 + 511) / 512;
    if (blocks > 2048) blocks = 2048;
    split16_kernel<<<blocks, 256>>>((const float4*)src, (uint2*)hi, (uint2*)lo, n4);
}

extern "C" void kernel_launch(void* const* d_in, const int* in_sizes, int n_in,
                              void* d_out, int out_size)
{
    const float* x   = (const float*)d_in[0];
    const float* Wq  = (const float*)d_in[1];
    const float* Wk  = (const float*)d_in[2];
    const float* Wv  = (const float*)d_in[3];
    const float* Wp  = (const float*)d_in[4];
    const float* qg  = (const float*)d_in[5];
    float* out = (float*)d_out;

    __half *xh, *wch, *wcl, *wph, *wpl, *yh, *qh, *ql, *kh, *vh;
    cudaGetSymbolAddress((void**)&xh,  g_xh);
    cudaGetSymbolAddress((void**)&wch, g_wch); cudaGetSymbolAddress((void**)&wcl, g_wcl);
    cudaGetSymbolAddress((void**)&wph, g_wph); cudaGetSymbolAddress((void**)&wpl, g_wpl);
    cudaGetSymbolAddress((void**)&yh,  g_yh);
    cudaGetSymbolAddress((void**)&qh,  g_qh);  cudaGetSymbolAddress((void**)&ql,  g_ql);
    cudaGetSymbolAddress((void**)&kh,  g_kh);  cudaGetSymbolAddress((void**)&vh,  g_vh);

    cudaFuncSetAttribute(gemm_mma_kernel<0>,
                         cudaFuncAttributeMaxDynamicSharedMemorySize, GEMM_SMEM);
    cudaFuncSetAttribute(gemm_mma_kernel<1>,
                         cudaFuncAttributeMaxDynamicSharedMemorySize, GEMM_SMEM);
    cudaFuncSetAttribute(fattn_kernel,
                         cudaFuncAttributeMaxDynamicSharedMemorySize, FATT_SMEM);

    // Pre-scale Q by log2(e) so flash-attention softmax runs in exp2 domain.
    const float qscale = LOG2E / sqrtf((float)HD);

    // conversions: x plain fp16; W = [Wq;Wk;Wv] and Wp split fp16 hi/lo
    launch_cvt16(x, xh, (size_t)NTOK * KTOT);
    launch_split16(Wq, wch,                         wcl,                         (size_t)DD * KTOT);
    launch_split16(Wk, wch + (size_t)DD * KTOT,     wcl + (size_t)DD * KTOT,     (size_t)KVD * KTOT);
    launch_split16(Wv, wch + (size_t)(DD+KVD)*KTOT, wcl + (size_t)(DD+KVD)*KTOT, (size_t)KVD * KTOT);
    launch_split16(Wp, wph, wpl, (size_t)DD * KTOT);

    // fused QKV projection + RMSNorm/RoPE epilogue (Q hi/lo, K/V plain fp16)
    gemm_mma_kernel<1><<<dim3(QKVN / GBN, NTOK / GBM), 256, GEMM_SMEM>>>(
        xh, wch, wcl, nullptr, QKVN,
        qh, ql, kh, vh, qg, qscale);

    // tensor-core causal flash attention -> y fp16 (2 CTAs/SM)
    fattn_kernel<<<dim3(TT / FBM, HN, BB), 128, FATT_SMEM>>>(
        qh, ql, kh, vh, yh);

    // output projection (fp32 out)
    gemm_mma_kernel<0><<<dim3(DD / GBN, NTOK / GBM), 256, GEMM_SMEM>>>(
        yh, wph, wpl, out, DD,
        nullptr, nullptr, nullptr, nullptr, nullptr, 0.f);
}

// round 12
// speedup vs baseline: 7.3007x; 1.3741x over previous
#include <cuda_runtime.h>
#include <cuda_fp16.h>
#include <cstdint>
#include <math.h>

// Problem constants
#define HN   16          // num_heads
#define KVH  4           // num_kv_heads
#define HD   128         // head_dim
#define BB   4           // batch
#define TT   2048        // seq len
#define DD   (HN*HD)     // 2048
#define KVD  (KVH*HD)    // 512
#define NTOK (BB*TT)     // 8192
#define KTOT DD          // inner dim of all GEMMs = 2048
#define QKVN (DD + 2*KVD)  // 3072 fused projection width
#define RMS_EPS 1.1920928955078125e-07f
#define LOG2E 1.4426950408889634f

// ---------------- scratch (device globals: allocation-free) ----------------
// plain fp16 operands for projections
__device__ __half g_xh [(size_t)NTOK * KTOT];
__device__ __half g_wch[(size_t)QKVN * KTOT];   // Wq|Wk|Wv plain fp16
__device__ __half g_wph[(size_t)DD * KTOT];     // Wproj plain fp16
__device__ __half g_yh [(size_t)NTOK * KTOT];

// fp16 Q (hi/lo split) + plain fp16 K/V for attention
__device__ __half g_qh[(size_t)BB * HN  * TT * HD], g_ql[(size_t)BB * HN  * TT * HD];
__device__ __half g_kh[(size_t)BB * KVH * TT * HD];
__device__ __half g_vh[(size_t)BB * KVH * TT * HD];

// ======================= PTX helpers (baseline compute_103) ================
__device__ __forceinline__ uint32_t smem_u32(const void* p) {
    uint32_t a;
    asm("{ .reg .u64 t; cvta.to.shared.u64 t, %1; cvt.u32.u64 %0, t; }"
        : "=r"(a) : "l"(p));
    return a;
}
__device__ __forceinline__ void cp16(uint32_t dst, const void* src) {
    asm volatile("cp.async.cg.shared.global [%0], [%1], 16;" :: "r"(dst), "l"(src));
}
#define CP_COMMIT() asm volatile("cp.async.commit_group;" ::: "memory")
#define CP_WAIT2()  asm volatile("cp.async.wait_group 2;" ::: "memory")
#define CP_WAIT1()  asm volatile("cp.async.wait_group 1;" ::: "memory")
#define CP_WAIT0()  asm volatile("cp.async.wait_group 0;" ::: "memory")

__device__ __forceinline__ void ldsm_x4(uint32_t* r, uint32_t addr) {
    asm volatile("ldmatrix.sync.aligned.m8n8.x4.shared.b16 {%0,%1,%2,%3}, [%4];"
                 : "=r"(r[0]), "=r"(r[1]), "=r"(r[2]), "=r"(r[3]) : "r"(addr));
}
__device__ __forceinline__ void ldsm_x4_t(uint32_t* r, uint32_t addr) {
    asm volatile("ldmatrix.sync.aligned.m8n8.x4.trans.shared.b16 {%0,%1,%2,%3}, [%4];"
                 : "=r"(r[0]), "=r"(r[1]), "=r"(r[2]), "=r"(r[3]) : "r"(addr));
}
__device__ __forceinline__ void mma16816h(float* c, const uint32_t* a, const uint32_t* b) {
    asm volatile(
        "mma.sync.aligned.m16n8k16.row.col.f32.f16.f16.f32 "
        "{%0,%1,%2,%3}, {%4,%5,%6,%7}, {%8,%9}, {%0,%1,%2,%3};"
        : "+f"(c[0]), "+f"(c[1]), "+f"(c[2]), "+f"(c[3])
        : "r"(a[0]), "r"(a[1]), "r"(a[2]), "r"(a[3]), "r"(b[0]), "r"(b[1]));
}
__device__ __forceinline__ uint32_t pack_h16(float x, float y) {
    __half2 t = __floats2half2_rn(x, y);
    return *(uint32_t*)&t;
}

// ============ fp32 -> fp16 plain conversion (grid-stride) ==================
__global__ void __launch_bounds__(256) cvt16_kernel(
    const float4* __restrict__ in, uint2* __restrict__ out, int n4)
{
    const int stride = gridDim.x * blockDim.x;
#pragma unroll 4
    for (int i = blockIdx.x * blockDim.x + threadIdx.x; i < n4; i += stride) {
        float4 w = in[i];
        uint2 v;
        v.x = pack_h16(w.x, w.y);
        v.y = pack_h16(w.z, w.w);
        out[i] = v;
    }
}

// ==== plain fp16 GEMM: C[M,N] = A[M,K] * B[N,K]^T (fp32 accum/out) =========
// 3-slot cp.async pipeline, one barrier per K-step. MODE 1 = fused QKV epi.
#define GBM 128
#define GBN 128
#define GBK 32
#define GNK (KTOT / GBK)       // 64
#define LDA 40
#define TILE_EL (GBM * LDA)    // 5120 elements
#define TILE_B  (TILE_EL * 2)  // 10240 bytes
#define STAGE_B (2 * TILE_B)   // 20480 bytes (A, B)
#define NST 3
#define LDC 132                // epilogue fp32 tile stride
#define GEMM_SMEM (128 * LDC * 4 + 256)   // 67840 >= NST*STAGE_B (61440)

__device__ __forceinline__ void gemm_load_stage(
    uint32_t sb, int tid, int k0, const __half* gA, const __half* gB)
{
#pragma unroll
    for (int i = 0; i < 2; ++i) {
        int ch = tid + i * 256;
        int r = ch >> 2, sg = ch & 3;
        uint32_t so = (uint32_t)((r * LDA + sg * 8) * 2);
        size_t go = (size_t)r * KTOT + k0 + sg * 8;
        cp16(sb + so, gA + go);
        cp16(sb + TILE_B + so, gB + go);
    }
    CP_COMMIT();
}

template<int MODE>
__global__ void __launch_bounds__(256, 2) gemm_mma_kernel(
    const __half* __restrict__ A, const __half* __restrict__ B,
    float* __restrict__ C, int N,
    __half* __restrict__ qh, __half* __restrict__ ql,
    __half* __restrict__ kh, __half* __restrict__ vh,
    const float* __restrict__ qg, float qscale)
{
    extern __shared__ __half smem[];
    const uint32_t sbase = smem_u32(smem);
    const int tid = threadIdx.x;
    const int lane = tid & 31, wid = tid >> 5;
    const int wm = wid >> 2, wn = wid & 3;
    const int m0 = blockIdx.y * GBM;
    const int n0 = blockIdx.x * GBN;

    const __half* gA = A + (size_t)m0 * KTOT;
    const __half* gB = B + (size_t)n0 * KTOT;

    float acc[4][4][4];
#pragma unroll
    for (int mi = 0; mi < 4; ++mi)
#pragma unroll
        for (int nj = 0; nj < 4; ++nj)
#pragma unroll
            for (int e = 0; e < 4; ++e) acc[mi][nj][e] = 0.f;

    const int arow = wm * 64 + (lane & 15);
    const uint32_t aoffbase = (uint32_t)(arow * LDA * 2) + ((lane >> 4) << 4);
    const int g = lane >> 3;
    const int brow = wn * 32 + (lane & 7) + ((g >> 1) << 3);
    const uint32_t boffbase = (uint32_t)(brow * LDA * 2) + ((g & 1) << 4);

    gemm_load_stage(sbase, tid, 0, gA, gB);
    gemm_load_stage(sbase + STAGE_B, tid, GBK, gA, gB);

    for (int kt = 0; kt < GNK; ++kt) {
        const int slot = kt % NST;
        if (kt + 1 < GNK) { CP_WAIT1(); } else { CP_WAIT0(); }
        __syncthreads();
        if (kt + 2 < GNK)
            gemm_load_stage(sbase + (uint32_t)((kt + 2) % NST) * STAGE_B,
                            tid, (kt + 2) * GBK, gA, gB);

        const uint32_t st = sbase + (uint32_t)slot * STAGE_B;
        const uint32_t sA = st;
        const uint32_t sB = st + TILE_B;

#pragma unroll
        for (int kk = 0; kk < GBK; kk += 16) {
            const uint32_t akk = aoffbase + kk * 2;
            const uint32_t bkk = boffbase + kk * 2;
            uint32_t bfr[4][2];
#pragma unroll
            for (int nt = 0; nt < 2; ++nt) {
                uint32_t r[4];
                ldsm_x4(r, sB + bkk + nt * 16 * LDA * 2);
                bfr[2 * nt][0] = r[0]; bfr[2 * nt][1] = r[1];
                bfr[2 * nt + 1][0] = r[2]; bfr[2 * nt + 1][1] = r[3];
            }
#pragma unroll
            for (int mi = 0; mi < 4; ++mi) {
                uint32_t a[4];
                ldsm_x4(a, sA + akk + mi * 16 * LDA * 2);
#pragma unroll
                for (int nj = 0; nj < 4; ++nj)
                    mma16816h(acc[mi][nj], a, bfr[nj]);
            }
        }
    }

    if (MODE == 0) {
#pragma unroll
        for (int mi = 0; mi < 4; ++mi) {
            int r0 = m0 + wm * 64 + mi * 16 + (lane >> 2);
#pragma unroll
            for (int nj = 0; nj < 4; ++nj) {
                int c = n0 + wn * 32 + nj * 8 + ((lane & 3) << 1);
                *(float2*)&C[(size_t)r0 * N + c]       = make_float2(acc[mi][nj][0], acc[mi][nj][1]);
                *(float2*)&C[(size_t)(r0 + 8) * N + c] = make_float2(acc[mi][nj][2], acc[mi][nj][3]);
            }
        }
        return;
    }

    // ================= fused QKV epilogue (MODE 1) ==========================
    float* stile = (float*)smem;               // 128 x LDC fp32 tile
    float* sinv  = stile + 128 * LDC;          // 64-entry inv_freq table
    __syncthreads();                           // mainloop smem fully consumed

#pragma unroll
    for (int mi = 0; mi < 4; ++mi) {
        int r = wm * 64 + mi * 16 + (lane >> 2);
#pragma unroll
        for (int nj = 0; nj < 4; ++nj) {
            int c = wn * 32 + nj * 8 + ((lane & 3) << 1);
            stile[r * LDC + c]           = acc[mi][nj][0];
            stile[r * LDC + c + 1]       = acc[mi][nj][1];
            stile[(r + 8) * LDC + c]     = acc[mi][nj][2];
            stile[(r + 8) * LDC + c + 1] = acc[mi][nj][3];
        }
    }

    const bool isV = (n0 >= DD + KVD);
    const bool isK = (n0 >= DD) && !isV;
    if (!isV && tid < 64)
        sinv[tid] = 1.0f / powf(10000.0f, (float)tid * (1.0f / 64.0f));
    __syncthreads();

    if (!isV && tid < 128) {
        const int row = tid;
        const int t = (m0 + row) & (TT - 1);
        float ssq = 0.f;
#pragma unroll 8
        for (int d = 0; d < HD; ++d) {
            float x = stile[row * LDC + d];
            ssq += x * x;
        }
        float rms = rsqrtf(ssq * (1.0f / HD) + RMS_EPS);
        float gn = isK ? 1.0f : (qg[n0 >> 7] * qscale);
#pragma unroll 4
        for (int d = 0; d < 64; ++d) {
            float xa = stile[row * LDC + d] * rms;
            float xb = stile[row * LDC + d + 64] * rms;
            float s_, c_;
            sincosf((float)t * sinv[d], &s_, &c_);
            stile[row * LDC + d]      = (xa * c_ - xb * s_) * gn;
            stile[row * LDC + d + 64] = (xb * c_ + xa * s_) * gn;
        }
    }
    __syncthreads();

    __half* dst = nullptr;
    int hloc, nh;
    if (isV)      { hloc = (n0 - DD - KVD) >> 7; nh = KVH; dst = vh; }
    else if (isK) { hloc = (n0 - DD) >> 7;       nh = KVH; dst = kh; }
    else          { hloc = n0 >> 7;              nh = HN; }

#pragma unroll
    for (int p = 0; p < 16; ++p) {
        int row = p * 8 + wid;
        int token = m0 + row;
        int b = token >> 11, t = token & (TT - 1);
        size_t off = (((size_t)b * nh + hloc) * TT + t) * HD + lane * 4;
        float v0 = stile[row * LDC + lane * 4];
        float v1 = stile[row * LDC + lane * 4 + 1];
        float v2 = stile[row * LDC + lane * 4 + 2];
        float v3 = stile[row * LDC + lane * 4 + 3];
        if (isK || isV) {
            uint2 pv;
            pv.x = pack_h16(v0, v1);
            pv.y = pack_h16(v2, v3);
            *(uint2*)&dst[off] = pv;
        } else {
            __half h0 = __float2half_rn(v0), h1 = __float2half_rn(v1);
            __half h2 = __float2half_rn(v2), h3 = __float2half_rn(v3);
            uint2 hv, lv;
            hv.x = pack_h16(__half2float(h0), __half2float(h1));
            hv.y = pack_h16(__half2float(h2), __half2float(h3));
            lv.x = pack_h16(v0 - __half2float(h0), v1 - __half2float(h1));
            lv.y = pack_h16(v2 - __half2float(h2), v3 - __half2float(h3));
            *(uint2*)&qh[off] = hv;
            *(uint2*)&ql[off] = lv;
        }
    }
}

// ============ tensor-core causal flash attention (fp16 2-term) =============
// 4-warp CTA (FBM=64, FBN=32), 2 CTAs/SM, Q(hi/lo) in registers, K/V plain
// fp16, 3-stage KV pipe. S = (Qhi+Qlo)·K, PV = (Phi+Plo)·V. exp2 domain.
#define FBM 64
#define FBN 32
#define LDQ 136
#define QHALF  (FBM * LDQ * 2)        // 17408 bytes per Q array (hi or lo)
#define KTILEB (FBN * LDQ * 2)        // 8704 bytes per K/V tile
#define STAGEB (2 * KTILEB)           // 17408 (K + V)
#define NSTAGE 3
#define FATT_SMEM (NSTAGE * STAGEB + 2 * QHALF)   // 87040

__device__ __forceinline__ void fatt_load_kv(
    uint32_t st, int tid, const __half* kp, const __half* vp, int kb)
{
    const size_t base = (size_t)kb * FBN * HD;
#pragma unroll
    for (int i = 0; i < 4; ++i) {
        int ch = tid + i * 128;            // 0..511
        int row = ch >> 4, seg = ch & 15;  // row 0..31, seg 0..15
        uint32_t so = (uint32_t)(row * (LDQ * 2) + seg * 16);
        size_t go = base + (size_t)row * HD + seg * 8;
        cp16(st + so, kp + go);
        cp16(st + KTILEB + so, vp + go);
    }
    CP_COMMIT();
}

__global__ void __launch_bounds__(128, 2) fattn_kernel(
    const __half* __restrict__ Qh, const __half* __restrict__ Ql,
    const __half* __restrict__ Kp, const __half* __restrict__ Vp,
    __half* __restrict__ Yh)
{
    extern __shared__ char smraw[];
    const uint32_t sSt = smem_u32(smraw);

    const int tid = threadIdx.x;
    const int lane = tid & 31, wid = tid >> 5;          // 4 warps
    const int qb = (int)(gridDim.x - 1 - blockIdx.x);   // heavy first
    const int h  = blockIdx.y;
    const int b  = blockIdx.z;
    const int hk = h / (HN / KVH);
    const int nkb = 2 * qb + 2;                         // 32-wide KV blocks

    const __half* qp_hi = Qh + ((((size_t)b * HN + h) * TT) + (size_t)qb * FBM) * HD;
    const __half* qp_lo = Ql + ((((size_t)b * HN + h) * TT) + (size_t)qb * FBM) * HD;
    const __half* kp = Kp + (((size_t)b * KVH + hk) * TT) * HD;
    const __half* vp = Vp + (((size_t)b * KVH + hk) * TT) * HD;

    // --- prologue: Q into dedicated region (one group), then kv0/kv1
    const uint32_t sQh = sSt + NSTAGE * STAGEB;
    const uint32_t sQl = sQh + QHALF;
#pragma unroll
    for (int i = 0; i < 8; ++i) {
        int ch = tid + i * 128;            // 0..1023
        int row = ch >> 4, seg = ch & 15;  // row 0..63
        uint32_t so = (uint32_t)(row * (LDQ * 2) + seg * 16);
        size_t go = (size_t)row * HD + seg * 8;
        cp16(sQh + so, qp_hi + go);
        cp16(sQl + so, qp_lo + go);
    }
    CP_COMMIT();
    fatt_load_kv(sSt, tid, kp, vp, 0);
    if (nkb > 1) fatt_load_kv(sSt + STAGEB, tid, kp, vp, 1);

    // fragment lane bases
    const uint32_t aoff = (uint32_t)((wid * 16 + (lane & 15)) * (LDQ * 2)) + ((lane >> 4) << 4);
    const int g = lane >> 3;
    const uint32_t boff = (uint32_t)(((lane & 7) + ((g >> 1) << 3)) * (LDQ * 2)) + ((g & 1) << 4);
    const uint32_t voff = (uint32_t)((lane & 15) * (LDQ * 2)) + (((lane >> 4) & 1) << 4);

    // --- Q fragments -> registers (once)
    if (nkb > 1) { CP_WAIT2(); } else { CP_WAIT1(); }
    __syncthreads();
    uint32_t aq_hi[8][4], aq_lo[8][4];
#pragma unroll
    for (int kc = 0; kc < 8; ++kc) {
        ldsm_x4(aq_hi[kc], sQh + aoff + kc * 32);
        ldsm_x4(aq_lo[kc], sQl + aoff + kc * 32);
    }

    float o[16][4];
#pragma unroll
    for (int nf = 0; nf < 16; ++nf)
#pragma unroll
        for (int e = 0; e < 4; ++e) o[nf][e] = 0.f;
    float m_i[2] = {-1e30f, -1e30f};   // log2-domain running max
    float l_i[2] = {0.f, 0.f};

    const int qrow0 = qb * FBM + wid * 16 + (lane >> 2);

    for (int kb = 0; kb < nkb; ++kb) {
        const int slot = kb % NSTAGE;
        if (kb + 1 < nkb) { CP_WAIT1(); } else { CP_WAIT0(); }
        __syncthreads();
        if (kb + 2 < nkb)
            fatt_load_kv(sSt + (uint32_t)((kb + 2) % NSTAGE) * STAGEB, tid,
                         kp, vp, kb + 2);

        const uint32_t sK = sSt + (uint32_t)slot * STAGEB;
        const uint32_t sV = sK + KTILEB;

        // ---- S = (Qhi+Qlo) K^T, Q from registers, K plain fp16 ----
        float s[4][4];
#pragma unroll
        for (int j = 0; j < 4; ++j)
#pragma unroll
            for (int e = 0; e < 4; ++e) s[j][e] = 0.f;

#pragma unroll
        for (int kc = 0; kc < 8; ++kc) {
#pragma unroll
            for (int n16 = 0; n16 < 2; ++n16) {
                uint32_t bk[4];
                ldsm_x4(bk, sK + boff + n16 * 16 * (LDQ * 2) + kc * 32);
                mma16816h(s[2 * n16],     aq_hi[kc], &bk[0]);
                mma16816h(s[2 * n16],     aq_lo[kc], &bk[0]);
                mma16816h(s[2 * n16 + 1], aq_hi[kc], &bk[2]);
                mma16816h(s[2 * n16 + 1], aq_lo[kc], &bk[2]);
            }
        }

        // ---- causal mask (diagonal 32-blocks only) ----
        if (kb >= nkb - 2) {
            const int kc0 = kb * FBN + 2 * (lane & 3);
#pragma unroll
            for (int j = 0; j < 4; ++j)
#pragma unroll
                for (int e = 0; e < 4; ++e) {
                    int row = qrow0 + (e >> 1) * 8;
                    int col = kc0 + 8 * j + (e & 1);
                    if (col > row) s[j][e] = -1e30f;
                }
        }

        // ---- row max + alpha (log2 domain) ----
        float alpha[2], mx2[2];
#pragma unroll
        for (int rr = 0; rr < 2; ++rr) {
            float mx = m_i[rr];
#pragma unroll
            for (int j = 0; j < 4; ++j)
                mx = fmaxf(mx, fmaxf(s[j][2 * rr], s[j][2 * rr + 1]));
            mx = fmaxf(mx, __shfl_xor_sync(0xffffffff, mx, 1));
            mx = fmaxf(mx, __shfl_xor_sync(0xffffffff, mx, 2));
            alpha[rr] = exp2f(m_i[rr] - mx);
            m_i[rr] = mx;
            mx2[rr] = mx;
        }
#pragma unroll
        for (int nf = 0; nf < 16; ++nf) {
            o[nf][0] *= alpha[0]; o[nf][1] *= alpha[0];
            o[nf][2] *= alpha[1]; o[nf][3] *= alpha[1];
        }
        float lsum[2] = {0.f, 0.f};

        // ---- per-chunk: exp2 + fp16 hi/lo pack + PV mma ----
#pragma unroll
        for (int kc2 = 0; kc2 < 2; ++kc2) {
            const int j0 = 2 * kc2, j1 = 2 * kc2 + 1;
            float p[8];
            p[0] = exp2f(s[j0][0] - mx2[0]);
            p[1] = exp2f(s[j0][1] - mx2[0]);
            p[2] = exp2f(s[j0][2] - mx2[1]);
            p[3] = exp2f(s[j0][3] - mx2[1]);
            p[4] = exp2f(s[j1][0] - mx2[0]);
            p[5] = exp2f(s[j1][1] - mx2[0]);
            p[6] = exp2f(s[j1][2] - mx2[1]);
            p[7] = exp2f(s[j1][3] - mx2[1]);
            lsum[0] += (p[0] + p[1]) + (p[4] + p[5]);
            lsum[1] += (p[2] + p[3]) + (p[6] + p[7]);

            uint32_t ap_hi[4], ap_lo[4];
            float h0 = __half2float(__float2half_rn(p[0]));
            float h1 = __half2float(__float2half_rn(p[1]));
            float h2 = __half2float(__float2half_rn(p[2]));
            float h3 = __half2float(__float2half_rn(p[3]));
            float h4 = __half2float(__float2half_rn(p[4]));
            float h5 = __half2float(__float2half_rn(p[5]));
            float h6 = __half2float(__float2half_rn(p[6]));
            float h7 = __half2float(__float2half_rn(p[7]));
            ap_hi[0] = pack_h16(h0, h1);
            ap_hi[1] = pack_h16(h2, h3);
            ap_hi[2] = pack_h16(h4, h5);
            ap_hi[3] = pack_h16(h6, h7);
            ap_lo[0] = pack_h16(p[0] - h0, p[1] - h1);
            ap_lo[1] = pack_h16(p[2] - h2, p[3] - h3);
            ap_lo[2] = pack_h16(p[4] - h4, p[5] - h5);
            ap_lo[3] = pack_h16(p[6] - h6, p[7] - h7);

            const uint32_t vrow = voff + kc2 * 16 * (LDQ * 2);
#pragma unroll
            for (int nf16 = 0; nf16 < 8; ++nf16) {
                uint32_t bv[4];
                ldsm_x4_t(bv, sV + vrow + nf16 * 32);
                mma16816h(o[2 * nf16],     ap_hi, &bv[0]);
                mma16816h(o[2 * nf16],     ap_lo, &bv[0]);
                mma16816h(o[2 * nf16 + 1], ap_hi, &bv[2]);
                mma16816h(o[2 * nf16 + 1], ap_lo, &bv[2]);
            }
        }
        l_i[0] = l_i[0] * alpha[0] + lsum[0];
        l_i[1] = l_i[1] * alpha[1] + lsum[1];
    }

    // ---- epilogue: normalize, write fp16 y ----
#pragma unroll
    for (int rr = 0; rr < 2; ++rr) {
        float lf = l_i[rr];
        lf += __shfl_xor_sync(0xffffffff, lf, 1);
        lf += __shfl_xor_sync(0xffffffff, lf, 2);
        float inv = 1.0f / lf;
        int trow = qrow0 + rr * 8;
        size_t rbase = ((size_t)(b * TT + trow)) * DD + h * HD + 2 * (lane & 3);
#pragma unroll
        for (int nf = 0; nf < 16; ++nf) {
            float v0 = o[nf][2 * rr] * inv;
            float v1 = o[nf][2 * rr + 1] * inv;
            *(uint32_t*)&Yh[rbase + nf * 8] = pack_h16(v0, v1);
        }
    }
}

// ---------------------------- launch ---------------------------------------
static inline void launch_cvt16(const float* src, __half* dst, size_t n)
{
    int n4 = (int)(n / 4);
    int blocks = (n4 + 511) / 512;
    if (blocks > 2048) blocks = 2048;
    cvt16_kernel<<<blocks, 256>>>((const float4*)src, (uint2*)dst, n4);
}

extern "C" void kernel_launch(void* const* d_in, const int* in_sizes, int n_in,
                              void* d_out, int out_size)
{
    const float* x   = (const float*)d_in[0];
    const float* Wq  = (const float*)d_in[1];
    const float* Wk  = (const float*)d_in[2];
    const float* Wv  = (const float*)d_in[3];
    const float* Wp  = (const float*)d_in[4];
    const float* qg  = (const float*)d_in[5];
    float* out = (float*)d_out;

    __half *xh, *wch, *wph, *yh, *qh, *ql, *kh, *vh;
    cudaGetSymbolAddress((void**)&xh,  g_xh);
    cudaGetSymbolAddress((void**)&wch, g_wch);
    cudaGetSymbolAddress((void**)&wph, g_wph);
    cudaGetSymbolAddress((void**)&yh,  g_yh);
    cudaGetSymbolAddress((void**)&qh,  g_qh);  cudaGetSymbolAddress((void**)&ql,  g_ql);
    cudaGetSymbolAddress((void**)&kh,  g_kh);  cudaGetSymbolAddress((void**)&vh,  g_vh);

    cudaFuncSetAttribute(gemm_mma_kernel<0>,
                         cudaFuncAttributeMaxDynamicSharedMemorySize, GEMM_SMEM);
    cudaFuncSetAttribute(gemm_mma_kernel<1>,
                         cudaFuncAttributeMaxDynamicSharedMemorySize, GEMM_SMEM);
    cudaFuncSetAttribute(fattn_kernel,
                         cudaFuncAttributeMaxDynamicSharedMemorySize, FATT_SMEM);

    // Pre-scale Q by log2(e) so flash-attention softmax runs in exp2 domain.
    const float qscale = LOG2E / sqrtf((float)HD);

    // conversions: everything plain fp16
    launch_cvt16(x,  xh, (size_t)NTOK * KTOT);
    launch_cvt16(Wq, wch,                          (size_t)DD * KTOT);
    launch_cvt16(Wk, wch + (size_t)DD * KTOT,      (size_t)KVD * KTOT);
    launch_cvt16(Wv, wch + (size_t)(DD+KVD)*KTOT,  (size_t)KVD * KTOT);
    launch_cvt16(Wp, wph, (size_t)DD * KTOT);

    // fused QKV projection + RMSNorm/RoPE epilogue (Q hi/lo, K/V plain fp16)
    gemm_mma_kernel<1><<<dim3(QKVN / GBN, NTOK / GBM), 256, GEMM_SMEM>>>(
        xh, wch, nullptr, QKVN,
        qh, ql, kh, vh, qg, qscale);

    // tensor-core causal flash attention -> y fp16 (2 CTAs/SM)
    fattn_kernel<<<dim3(TT / FBM, HN, BB), 128, FATT_SMEM>>>(
        qh, ql, kh, vh, yh);

    // output projection (fp32 out)
    gemm_mma_kernel<0><<<dim3(DD / GBN, NTOK / GBM), 256, GEMM_SMEM>>>(
        yh, wph, out, DD,
        nullptr, nullptr, nullptr, nullptr, nullptr, 0.f);
}

// round 13
// speedup vs baseline: 7.7381x; 1.0599x over previous
#include <cuda_runtime.h>
#include <cuda_fp16.h>
#include <cstdint>
#include <math.h>

// Problem constants
#define HN   16          // num_heads
#define KVH  4           // num_kv_heads
#define HD   128         // head_dim
#define BB   4           // batch
#define TT   2048        // seq len
#define DD   (HN*HD)     // 2048
#define KVD  (KVH*HD)    // 512
#define NTOK (BB*TT)     // 8192
#define KTOT DD          // inner dim of all GEMMs = 2048
#define QKVN (DD + 2*KVD)  // 3072 fused projection width
#define RMS_EPS 1.1920928955078125e-07f
#define LOG2E 1.4426950408889634f

// ---------------- scratch (device globals: allocation-free) ----------------
__device__ __half g_xh [(size_t)NTOK * KTOT];
__device__ __half g_wch[(size_t)QKVN * KTOT];   // Wq|Wk|Wv plain fp16
__device__ __half g_wph[(size_t)DD * KTOT];     // Wproj plain fp16
__device__ __half g_yh [(size_t)NTOK * KTOT];

// fp16 Q (hi/lo split) + plain fp16 K/V for attention
__device__ __half g_qh[(size_t)BB * HN  * TT * HD], g_ql[(size_t)BB * HN  * TT * HD];
__device__ __half g_kh[(size_t)BB * KVH * TT * HD];
__device__ __half g_vh[(size_t)BB * KVH * TT * HD];

// ======================= PTX helpers (baseline compute_103) ================
__device__ __forceinline__ uint32_t smem_u32(const void* p) {
    uint32_t a;
    asm("{ .reg .u64 t; cvta.to.shared.u64 t, %1; cvt.u32.u64 %0, t; }"
        : "=r"(a) : "l"(p));
    return a;
}
__device__ __forceinline__ void cp16(uint32_t dst, const void* src) {
    asm volatile("cp.async.cg.shared.global [%0], [%1], 16;" :: "r"(dst), "l"(src));
}
#define CP_COMMIT() asm volatile("cp.async.commit_group;" ::: "memory")
#define CP_WAIT2()  asm volatile("cp.async.wait_group 2;" ::: "memory")
#define CP_WAIT1()  asm volatile("cp.async.wait_group 1;" ::: "memory")
#define CP_WAIT0()  asm volatile("cp.async.wait_group 0;" ::: "memory")

__device__ __forceinline__ void ldsm_x4(uint32_t* r, uint32_t addr) {
    asm volatile("ldmatrix.sync.aligned.m8n8.x4.shared.b16 {%0,%1,%2,%3}, [%4];"
                 : "=r"(r[0]), "=r"(r[1]), "=r"(r[2]), "=r"(r[3]) : "r"(addr));
}
__device__ __forceinline__ void ldsm_x4_t(uint32_t* r, uint32_t addr) {
    asm volatile("ldmatrix.sync.aligned.m8n8.x4.trans.shared.b16 {%0,%1,%2,%3}, [%4];"
                 : "=r"(r[0]), "=r"(r[1]), "=r"(r[2]), "=r"(r[3]) : "r"(addr));
}
__device__ __forceinline__ void mma16816h(float* c, const uint32_t* a, const uint32_t* b) {
    asm volatile(
        "mma.sync.aligned.m16n8k16.row.col.f32.f16.f16.f32 "
        "{%0,%1,%2,%3}, {%4,%5,%6,%7}, {%8,%9}, {%0,%1,%2,%3};"
        : "+f"(c[0]), "+f"(c[1]), "+f"(c[2]), "+f"(c[3])
        : "r"(a[0]), "r"(a[1]), "r"(a[2]), "r"(a[3]), "r"(b[0]), "r"(b[1]));
}
__device__ __forceinline__ uint32_t pack_h16(float x, float y) {
    __half2 t = __floats2half2_rn(x, y);
    return *(uint32_t*)&t;
}

// ============ fp32 -> fp16 plain conversion (grid-stride) ==================
__global__ void __launch_bounds__(256) cvt16_kernel(
    const float4* __restrict__ in, uint2* __restrict__ out, int n4)
{
    const int stride = gridDim.x * blockDim.x;
#pragma unroll 4
    for (int i = blockIdx.x * blockDim.x + threadIdx.x; i < n4; i += stride) {
        float4 w = in[i];
        uint2 v;
        v.x = pack_h16(w.x, w.y);
        v.y = pack_h16(w.z, w.w);
        out[i] = v;
    }
}

// ===== all four weight tensors -> fp16 in ONE launch =======================
#define SQ4 ((DD  * KTOT) / 4)
#define SK4 ((KVD * KTOT) / 4)
__global__ void __launch_bounds__(256) wcvt_kernel(
    const float4* __restrict__ wq, const float4* __restrict__ wk,
    const float4* __restrict__ wv, const float4* __restrict__ wp,
    uint2* __restrict__ wch, uint2* __restrict__ wph)
{
    const int total = SQ4 + 2 * SK4 + SQ4;
    const int stride = gridDim.x * blockDim.x;
#pragma unroll 2
    for (int i = blockIdx.x * blockDim.x + threadIdx.x; i < total; i += stride) {
        const float4* src;
        uint2* dst;
        int idx = i;
        if (idx < SQ4)                   { src = wq; dst = wch; }
        else if ((idx -= SQ4) < SK4)     { src = wk; dst = wch + SQ4; }
        else if ((idx -= SK4) < SK4)     { src = wv; dst = wch + SQ4 + SK4; }
        else { idx -= SK4;                 src = wp; dst = wph; }
        float4 w = src[idx];
        uint2 v;
        v.x = pack_h16(w.x, w.y);
        v.y = pack_h16(w.z, w.w);
        dst[idx] = v;
    }
}

// ==== plain fp16 GEMM: C[M,N] = A[M,K] * B[N,K]^T (fp32 accum/out) =========
// 3-slot cp.async pipeline, one barrier per K-step. MODE 1 = fused QKV epi.
#define GBM 128
#define GBN 128
#define GBK 32
#define GNK (KTOT / GBK)       // 64
#define LDA 40
#define TILE_EL (GBM * LDA)    // 5120 elements
#define TILE_B  (TILE_EL * 2)  // 10240 bytes
#define STAGE_B (2 * TILE_B)   // 20480 bytes (A, B)
#define NST 3
#define LDC 132                // epilogue fp32 tile stride
#define GEMM_SMEM (128 * LDC * 4 + 256)   // 67840 >= NST*STAGE_B (61440)

__device__ __forceinline__ void gemm_load_stage(
    uint32_t sb, int tid, int k0, const __half* gA, const __half* gB)
{
#pragma unroll
    for (int i = 0; i < 2; ++i) {
        int ch = tid + i * 256;
        int r = ch >> 2, sg = ch & 3;
        uint32_t so = (uint32_t)((r * LDA + sg * 8) * 2);
        size_t go = (size_t)r * KTOT + k0 + sg * 8;
        cp16(sb + so, gA + go);
        cp16(sb + TILE_B + so, gB + go);
    }
    CP_COMMIT();
}

template<int MODE>
__global__ void __launch_bounds__(256, 2) gemm_mma_kernel(
    const __half* __restrict__ A, const __half* __restrict__ B,
    float* __restrict__ C, int N,
    __half* __restrict__ qh, __half* __restrict__ ql,
    __half* __restrict__ kh, __half* __restrict__ vh,
    const float* __restrict__ qg, float qscale)
{
    extern __shared__ __half smem[];
    const uint32_t sbase = smem_u32(smem);
    const int tid = threadIdx.x;
    const int lane = tid & 31, wid = tid >> 5;
    const int wm = wid >> 2, wn = wid & 3;
    const int m0 = blockIdx.y * GBM;
    const int n0 = blockIdx.x * GBN;

    const __half* gA = A + (size_t)m0 * KTOT;
    const __half* gB = B + (size_t)n0 * KTOT;

    float acc[4][4][4];
#pragma unroll
    for (int mi = 0; mi < 4; ++mi)
#pragma unroll
        for (int nj = 0; nj < 4; ++nj)
#pragma unroll
            for (int e = 0; e < 4; ++e) acc[mi][nj][e] = 0.f;

    const int arow = wm * 64 + (lane & 15);
    const uint32_t aoffbase = (uint32_t)(arow * LDA * 2) + ((lane >> 4) << 4);
    const int g = lane >> 3;
    const int brow = wn * 32 + (lane & 7) + ((g >> 1) << 3);
    const uint32_t boffbase = (uint32_t)(brow * LDA * 2) + ((g & 1) << 4);

    gemm_load_stage(sbase, tid, 0, gA, gB);
    gemm_load_stage(sbase + STAGE_B, tid, GBK, gA, gB);

    for (int kt = 0; kt < GNK; ++kt) {
        const int slot = kt % NST;
        if (kt + 1 < GNK) { CP_WAIT1(); } else { CP_WAIT0(); }
        __syncthreads();
        if (kt + 2 < GNK)
            gemm_load_stage(sbase + (uint32_t)((kt + 2) % NST) * STAGE_B,
                            tid, (kt + 2) * GBK, gA, gB);

        const uint32_t st = sbase + (uint32_t)slot * STAGE_B;
        const uint32_t sA = st;
        const uint32_t sB = st + TILE_B;

#pragma unroll
        for (int kk = 0; kk < GBK; kk += 16) {
            const uint32_t akk = aoffbase + kk * 2;
            const uint32_t bkk = boffbase + kk * 2;
            uint32_t bfr[4][2];
#pragma unroll
            for (int nt = 0; nt < 2; ++nt) {
                uint32_t r[4];
                ldsm_x4(r, sB + bkk + nt * 16 * LDA * 2);
                bfr[2 * nt][0] = r[0]; bfr[2 * nt][1] = r[1];
                bfr[2 * nt + 1][0] = r[2]; bfr[2 * nt + 1][1] = r[3];
            }
#pragma unroll
            for (int mi = 0; mi < 4; ++mi) {
                uint32_t a[4];
                ldsm_x4(a, sA + akk + mi * 16 * LDA * 2);
#pragma unroll
                for (int nj = 0; nj < 4; ++nj)
                    mma16816h(acc[mi][nj], a, bfr[nj]);
            }
        }
    }

    if (MODE == 0) {
#pragma unroll
        for (int mi = 0; mi < 4; ++mi) {
            int r0 = m0 + wm * 64 + mi * 16 + (lane >> 2);
#pragma unroll
            for (int nj = 0; nj < 4; ++nj) {
                int c = n0 + wn * 32 + nj * 8 + ((lane & 3) << 1);
                *(float2*)&C[(size_t)r0 * N + c]       = make_float2(acc[mi][nj][0], acc[mi][nj][1]);
                *(float2*)&C[(size_t)(r0 + 8) * N + c] = make_float2(acc[mi][nj][2], acc[mi][nj][3]);
            }
        }
        return;
    }

    // ================= fused QKV epilogue (MODE 1) ==========================
    float* stile = (float*)smem;               // 128 x LDC fp32 tile
    float* sinv  = stile + 128 * LDC;          // 64-entry inv_freq table
    __syncthreads();                           // mainloop smem fully consumed

#pragma unroll
    for (int mi = 0; mi < 4; ++mi) {
        int r = wm * 64 + mi * 16 + (lane >> 2);
#pragma unroll
        for (int nj = 0; nj < 4; ++nj) {
            int c = wn * 32 + nj * 8 + ((lane & 3) << 1);
            stile[r * LDC + c]           = acc[mi][nj][0];
            stile[r * LDC + c + 1]       = acc[mi][nj][1];
            stile[(r + 8) * LDC + c]     = acc[mi][nj][2];
            stile[(r + 8) * LDC + c + 1] = acc[mi][nj][3];
        }
    }

    const bool isV = (n0 >= DD + KVD);
    const bool isK = (n0 >= DD) && !isV;
    if (!isV && tid < 64)
        sinv[tid] = 1.0f / powf(10000.0f, (float)tid * (1.0f / 64.0f));
    __syncthreads();

    if (!isV && tid < 128) {
        const int row = tid;
        const int t = (m0 + row) & (TT - 1);
        float ssq = 0.f;
#pragma unroll 8
        for (int d = 0; d < HD; ++d) {
            float x = stile[row * LDC + d];
            ssq += x * x;
        }
        float rms = rsqrtf(ssq * (1.0f / HD) + RMS_EPS);
        float gn = isK ? 1.0f : (qg[n0 >> 7] * qscale);
#pragma unroll 4
        for (int d = 0; d < 64; ++d) {
            float xa = stile[row * LDC + d] * rms;
            float xb = stile[row * LDC + d + 64] * rms;
            float s_, c_;
            sincosf((float)t * sinv[d], &s_, &c_);
            stile[row * LDC + d]      = (xa * c_ - xb * s_) * gn;
            stile[row * LDC + d + 64] = (xb * c_ + xa * s_) * gn;
        }
    }
    __syncthreads();

    __half* dst = nullptr;
    int hloc, nh;
    if (isV)      { hloc = (n0 - DD - KVD) >> 7; nh = KVH; dst = vh; }
    else if (isK) { hloc = (n0 - DD) >> 7;       nh = KVH; dst = kh; }
    else          { hloc = n0 >> 7;              nh = HN; }

#pragma unroll
    for (int p = 0; p < 16; ++p) {
        int row = p * 8 + wid;
        int token = m0 + row;
        int b = token >> 11, t = token & (TT - 1);
        size_t off = (((size_t)b * nh + hloc) * TT + t) * HD + lane * 4;
        float v0 = stile[row * LDC + lane * 4];
        float v1 = stile[row * LDC + lane * 4 + 1];
        float v2 = stile[row * LDC + lane * 4 + 2];
        float v3 = stile[row * LDC + lane * 4 + 3];
        if (isK || isV) {
            uint2 pv;
            pv.x = pack_h16(v0, v1);
            pv.y = pack_h16(v2, v3);
            *(uint2*)&dst[off] = pv;
        } else {
            __half h0 = __float2half_rn(v0), h1 = __float2half_rn(v1);
            __half h2 = __float2half_rn(v2), h3 = __float2half_rn(v3);
            uint2 hv, lv;
            hv.x = pack_h16(__half2float(h0), __half2float(h1));
            hv.y = pack_h16(__half2float(h2), __half2float(h3));
            lv.x = pack_h16(v0 - __half2float(h0), v1 - __half2float(h1));
            lv.y = pack_h16(v2 - __half2float(h2), v3 - __half2float(h3));
            *(uint2*)&qh[off] = hv;
            *(uint2*)&ql[off] = lv;
        }
    }
}

// ============ tensor-core causal flash attention ===========================
// 4-warp CTA (FBM=64, FBN=32), 2 CTAs/SM, Q(hi/lo) in registers, K/V plain
// fp16, 3-stage KV pipe. S = (Qhi+Qlo)·K (2-term), PV = P·V (1-term fp16).
#define FBM 64
#define FBN 32
#define LDQ 136
#define QHALF  (FBM * LDQ * 2)        // 17408 bytes per Q array (hi or lo)
#define KTILEB (FBN * LDQ * 2)        // 8704 bytes per K/V tile
#define STAGEB (2 * KTILEB)           // 17408 (K + V)
#define NSTAGE 3
#define FATT_SMEM (NSTAGE * STAGEB + 2 * QHALF)   // 87040

__device__ __forceinline__ void fatt_load_kv(
    uint32_t st, int tid, const __half* kp, const __half* vp, int kb)
{
    const size_t base = (size_t)kb * FBN * HD;
#pragma unroll
    for (int i = 0; i < 4; ++i) {
        int ch = tid + i * 128;            // 0..511
        int row = ch >> 4, seg = ch & 15;  // row 0..31, seg 0..15
        uint32_t so = (uint32_t)(row * (LDQ * 2) + seg * 16);
        size_t go = base + (size_t)row * HD + seg * 8;
        cp16(st + so, kp + go);
        cp16(st + KTILEB + so, vp + go);
    }
    CP_COMMIT();
}

__global__ void __launch_bounds__(128, 2) fattn_kernel(
    const __half* __restrict__ Qh, const __half* __restrict__ Ql,
    const __half* __restrict__ Kp, const __half* __restrict__ Vp,
    __half* __restrict__ Yh)
{
    extern __shared__ char smraw[];
    const uint32_t sSt = smem_u32(smraw);

    const int tid = threadIdx.x;
    const int lane = tid & 31, wid = tid >> 5;          // 4 warps
    const int qb = (int)(gridDim.x - 1 - blockIdx.x);   // heavy first
    const int h  = blockIdx.y;
    const int b  = blockIdx.z;
    const int hk = h / (HN / KVH);
    const int nkb = 2 * qb + 2;                         // 32-wide KV blocks

    const __half* qp_hi = Qh + ((((size_t)b * HN + h) * TT) + (size_t)qb * FBM) * HD;
    const __half* qp_lo = Ql + ((((size_t)b * HN + h) * TT) + (size_t)qb * FBM) * HD;
    const __half* kp = Kp + (((size_t)b * KVH + hk) * TT) * HD;
    const __half* vp = Vp + (((size_t)b * KVH + hk) * TT) * HD;

    // --- prologue: Q into dedicated region (one group), then kv0/kv1
    const uint32_t sQh = sSt + NSTAGE * STAGEB;
    const uint32_t sQl = sQh + QHALF;
#pragma unroll
    for (int i = 0; i < 8; ++i) {
        int ch = tid + i * 128;            // 0..1023
        int row = ch >> 4, seg = ch & 15;  // row 0..63
        uint32_t so = (uint32_t)(row * (LDQ * 2) + seg * 16);
        size_t go = (size_t)row * HD + seg * 8;
        cp16(sQh + so, qp_hi + go);
        cp16(sQl + so, qp_lo + go);
    }
    CP_COMMIT();
    fatt_load_kv(sSt, tid, kp, vp, 0);
    if (nkb > 1) fatt_load_kv(sSt + STAGEB, tid, kp, vp, 1);

    // fragment lane bases
    const uint32_t aoff = (uint32_t)((wid * 16 + (lane & 15)) * (LDQ * 2)) + ((lane >> 4) << 4);
    const int g = lane >> 3;
    const uint32_t boff = (uint32_t)(((lane & 7) + ((g >> 1) << 3)) * (LDQ * 2)) + ((g & 1) << 4);
    const uint32_t voff = (uint32_t)((lane & 15) * (LDQ * 2)) + (((lane >> 4) & 1) << 4);

    // --- Q fragments -> registers (once)
    if (nkb > 1) { CP_WAIT2(); } else { CP_WAIT1(); }
    __syncthreads();
    uint32_t aq_hi[8][4], aq_lo[8][4];
#pragma unroll
    for (int kc = 0; kc < 8; ++kc) {
        ldsm_x4(aq_hi[kc], sQh + aoff + kc * 32);
        ldsm_x4(aq_lo[kc], sQl + aoff + kc * 32);
    }

    float o[16][4];
#pragma unroll
    for (int nf = 0; nf < 16; ++nf)
#pragma unroll
        for (int e = 0; e < 4; ++e) o[nf][e] = 0.f;
    float m_i[2] = {-1e30f, -1e30f};   // log2-domain running max
    float l_i[2] = {0.f, 0.f};

    const int qrow0 = qb * FBM + wid * 16 + (lane >> 2);

    for (int kb = 0; kb < nkb; ++kb) {
        const int slot = kb % NSTAGE;
        if (kb + 1 < nkb) { CP_WAIT1(); } else { CP_WAIT0(); }
        __syncthreads();
        if (kb + 2 < nkb)
            fatt_load_kv(sSt + (uint32_t)((kb + 2) % NSTAGE) * STAGEB, tid,
                         kp, vp, kb + 2);

        const uint32_t sK = sSt + (uint32_t)slot * STAGEB;
        const uint32_t sV = sK + KTILEB;

        // ---- S = (Qhi+Qlo) K^T, Q from registers, K plain fp16 ----
        float s[4][4];
#pragma unroll
        for (int j = 0; j < 4; ++j)
#pragma unroll
            for (int e = 0; e < 4; ++e) s[j][e] = 0.f;

#pragma unroll
        for (int kc = 0; kc < 8; ++kc) {
#pragma unroll
            for (int n16 = 0; n16 < 2; ++n16) {
                uint32_t bk[4];
                ldsm_x4(bk, sK + boff + n16 * 16 * (LDQ * 2) + kc * 32);
                mma16816h(s[2 * n16],     aq_hi[kc], &bk[0]);
                mma16816h(s[2 * n16],     aq_lo[kc], &bk[0]);
                mma16816h(s[2 * n16 + 1], aq_hi[kc], &bk[2]);
                mma16816h(s[2 * n16 + 1], aq_lo[kc], &bk[2]);
            }
        }

        // ---- causal mask (diagonal 32-blocks only) ----
        if (kb >= nkb - 2) {
            const int kc0 = kb * FBN + 2 * (lane & 3);
#pragma unroll
            for (int j = 0; j < 4; ++j)
#pragma unroll
                for (int e = 0; e < 4; ++e) {
                    int row = qrow0 + (e >> 1) * 8;
                    int col = kc0 + 8 * j + (e & 1);
                    if (col > row) s[j][e] = -1e30f;
                }
        }

        // ---- row max + alpha (log2 domain) ----
        float alpha[2], mx2[2];
#pragma unroll
        for (int rr = 0; rr < 2; ++rr) {
            float mx = m_i[rr];
#pragma unroll
            for (int j = 0; j < 4; ++j)
                mx = fmaxf(mx, fmaxf(s[j][2 * rr], s[j][2 * rr + 1]));
            mx = fmaxf(mx, __shfl_xor_sync(0xffffffff, mx, 1));
            mx = fmaxf(mx, __shfl_xor_sync(0xffffffff, mx, 2));
            alpha[rr] = exp2f(m_i[rr] - mx);
            m_i[rr] = mx;
            mx2[rr] = mx;
        }
#pragma unroll
        for (int nf = 0; nf < 16; ++nf) {
            o[nf][0] *= alpha[0]; o[nf][1] *= alpha[0];
            o[nf][2] *= alpha[1]; o[nf][3] *= alpha[1];
        }
        float lsum[2] = {0.f, 0.f};

        // ---- per-chunk: exp2 + fp16 pack + single-term PV mma ----
#pragma unroll
        for (int kc2 = 0; kc2 < 2; ++kc2) {
            const int j0 = 2 * kc2, j1 = 2 * kc2 + 1;
            float p[8];
            p[0] = exp2f(s[j0][0] - mx2[0]);
            p[1] = exp2f(s[j0][1] - mx2[0]);
            p[2] = exp2f(s[j0][2] - mx2[1]);
            p[3] = exp2f(s[j0][3] - mx2[1]);
            p[4] = exp2f(s[j1][0] - mx2[0]);
            p[5] = exp2f(s[j1][1] - mx2[0]);
            p[6] = exp2f(s[j1][2] - mx2[1]);
            p[7] = exp2f(s[j1][3] - mx2[1]);
            lsum[0] += (p[0] + p[1]) + (p[4] + p[5]);
            lsum[1] += (p[2] + p[3]) + (p[6] + p[7]);

            uint32_t ap[4];
            ap[0] = pack_h16(p[0], p[1]);
            ap[1] = pack_h16(p[2], p[3]);
            ap[2] = pack_h16(p[4], p[5]);
            ap[3] = pack_h16(p[6], p[7]);

            const uint32_t vrow = voff + kc2 * 16 * (LDQ * 2);
#pragma unroll
            for (int nf16 = 0; nf16 < 8; ++nf16) {
                uint32_t bv[4];
                ldsm_x4_t(bv, sV + vrow + nf16 * 32);
                mma16816h(o[2 * nf16],     ap, &bv[0]);
                mma16816h(o[2 * nf16 + 1], ap, &bv[2]);
            }
        }
        l_i[0] = l_i[0] * alpha[0] + lsum[0];
        l_i[1] = l_i[1] * alpha[1] + lsum[1];
    }

    // ---- epilogue: normalize, write fp16 y ----
#pragma unroll
    for (int rr = 0; rr < 2; ++rr) {
        float lf = l_i[rr];
        lf += __shfl_xor_sync(0xffffffff, lf, 1);
        lf += __shfl_xor_sync(0xffffffff, lf, 2);
        float inv = 1.0f / lf;
        int trow = qrow0 + rr * 8;
        size_t rbase = ((size_t)(b * TT + trow)) * DD + h * HD + 2 * (lane & 3);
#pragma unroll
        for (int nf = 0; nf < 16; ++nf) {
            float v0 = o[nf][2 * rr] * inv;
            float v1 = o[nf][2 * rr + 1] * inv;
            *(uint32_t*)&Yh[rbase + nf * 8] = pack_h16(v0, v1);
        }
    }
}

// ---------------------------- launch ---------------------------------------
static inline void launch_cvt16(const float* src, __half* dst, size_t n)
{
    int n4 = (int)(n / 4);
    int blocks = (n4 + 511) / 512;
    if (blocks > 2048) blocks = 2048;
    cvt16_kernel<<<blocks, 256>>>((const float4*)src, (uint2*)dst, n4);
}

extern "C" void kernel_launch(void* const* d_in, const int* in_sizes, int n_in,
                              void* d_out, int out_size)
{
    const float* x   = (const float*)d_in[0];
    const float* Wq  = (const float*)d_in[1];
    const float* Wk  = (const float*)d_in[2];
    const float* Wv  = (const float*)d_in[3];
    const float* Wp  = (const float*)d_in[4];
    const float* qg  = (const float*)d_in[5];
    float* out = (float*)d_out;

    __half *xh, *wch, *wph, *yh, *qh, *ql, *kh, *vh;
    cudaGetSymbolAddress((void**)&xh,  g_xh);
    cudaGetSymbolAddress((void**)&wch, g_wch);
    cudaGetSymbolAddress((void**)&wph, g_wph);
    cudaGetSymbolAddress((void**)&yh,  g_yh);
    cudaGetSymbolAddress((void**)&qh,  g_qh);  cudaGetSymbolAddress((void**)&ql,  g_ql);
    cudaGetSymbolAddress((void**)&kh,  g_kh);  cudaGetSymbolAddress((void**)&vh,  g_vh);

    cudaFuncSetAttribute(gemm_mma_kernel<0>,
                         cudaFuncAttributeMaxDynamicSharedMemorySize, GEMM_SMEM);
    cudaFuncSetAttribute(gemm_mma_kernel<1>,
                         cudaFuncAttributeMaxDynamicSharedMemorySize, GEMM_SMEM);
    cudaFuncSetAttribute(fattn_kernel,
                         cudaFuncAttributeMaxDynamicSharedMemorySize, FATT_SMEM);

    // Pre-scale Q by log2(e) so flash-attention softmax runs in exp2 domain.
    const float qscale = LOG2E / sqrtf((float)HD);

    // conversions: x in its own launch; all four weight tensors in one launch
    launch_cvt16(x, xh, (size_t)NTOK * KTOT);
    wcvt_kernel<<<2048, 256>>>((const float4*)Wq, (const float4*)Wk,
                               (const float4*)Wv, (const float4*)Wp,
                               (uint2*)wch, (uint2*)wph);

    // fused QKV projection + RMSNorm/RoPE epilogue (Q hi/lo, K/V plain fp16)
    gemm_mma_kernel<1><<<dim3(QKVN / GBN, NTOK / GBM), 256, GEMM_SMEM>>>(
        xh, wch, nullptr, QKVN,
        qh, ql, kh, vh, qg, qscale);

    // tensor-core causal flash attention -> y fp16 (2 CTAs/SM)
    fattn_kernel<<<dim3(TT / FBM, HN, BB), 128, FATT_SMEM>>>(
        qh, ql, kh, vh, yh);

    // output projection (fp32 out)
    gemm_mma_kernel<0><<<dim3(DD / GBN, NTOK / GBM), 256, GEMM_SMEM>>>(
        yh, wph, out, DD,
        nullptr, nullptr, nullptr, nullptr, nullptr, 0.f);
}

// round 14
// speedup vs baseline: 8.2366x; 1.0644x over previous
#include <cuda_runtime.h>
#include <cuda_fp16.h>
#include <cstdint>
#include <math.h>

// Problem constants
#define HN   16          // num_heads
#define KVH  4           // num_kv_heads
#define HD   128         // head_dim
#define BB   4           // batch
#define TT   2048        // seq len
#define DD   (HN*HD)     // 2048
#define KVD  (KVH*HD)    // 512
#define NTOK (BB*TT)     // 8192
#define KTOT DD          // inner dim of all GEMMs = 2048
#define QKVN (DD + 2*KVD)  // 3072 fused projection width
#define RMS_EPS 1.1920928955078125e-07f
#define LOG2E 1.4426950408889634f

// ---------------- scratch (device globals: allocation-free) ----------------
__device__ __half g_xh [(size_t)NTOK * KTOT];
__device__ __half g_wch[(size_t)QKVN * KTOT];   // Wq|Wk|Wv plain fp16
__device__ __half g_wph[(size_t)DD * KTOT];     // Wproj plain fp16
__device__ __half g_yh [(size_t)NTOK * KTOT];

// plain fp16 Q/K/V for attention
__device__ __half g_qh[(size_t)BB * HN  * TT * HD];
__device__ __half g_kh[(size_t)BB * KVH * TT * HD];
__device__ __half g_vh[(size_t)BB * KVH * TT * HD];

// ======================= PTX helpers (baseline compute_103) ================
__device__ __forceinline__ uint32_t smem_u32(const void* p) {
    uint32_t a;
    asm("{ .reg .u64 t; cvta.to.shared.u64 t, %1; cvt.u32.u64 %0, t; }"
        : "=r"(a) : "l"(p));
    return a;
}
__device__ __forceinline__ void cp16(uint32_t dst, const void* src) {
    asm volatile("cp.async.cg.shared.global [%0], [%1], 16;" :: "r"(dst), "l"(src));
}
#define CP_COMMIT() asm volatile("cp.async.commit_group;" ::: "memory")
#define CP_WAIT2()  asm volatile("cp.async.wait_group 2;" ::: "memory")
#define CP_WAIT1()  asm volatile("cp.async.wait_group 1;" ::: "memory")
#define CP_WAIT0()  asm volatile("cp.async.wait_group 0;" ::: "memory")

__device__ __forceinline__ void ldsm_x4(uint32_t* r, uint32_t addr) {
    asm volatile("ldmatrix.sync.aligned.m8n8.x4.shared.b16 {%0,%1,%2,%3}, [%4];"
                 : "=r"(r[0]), "=r"(r[1]), "=r"(r[2]), "=r"(r[3]) : "r"(addr));
}
__device__ __forceinline__ void ldsm_x4_t(uint32_t* r, uint32_t addr) {
    asm volatile("ldmatrix.sync.aligned.m8n8.x4.trans.shared.b16 {%0,%1,%2,%3}, [%4];"
                 : "=r"(r[0]), "=r"(r[1]), "=r"(r[2]), "=r"(r[3]) : "r"(addr));
}
__device__ __forceinline__ void mma16816h(float* c, const uint32_t* a, const uint32_t* b) {
    asm volatile(
        "mma.sync.aligned.m16n8k16.row.col.f32.f16.f16.f32 "
        "{%0,%1,%2,%3}, {%4,%5,%6,%7}, {%8,%9}, {%0,%1,%2,%3};"
        : "+f"(c[0]), "+f"(c[1]), "+f"(c[2]), "+f"(c[3])
        : "r"(a[0]), "r"(a[1]), "r"(a[2]), "r"(a[3]), "r"(b[0]), "r"(b[1]));
}
__device__ __forceinline__ uint32_t pack_h16(float x, float y) {
    __half2 t = __floats2half2_rn(x, y);
    return *(uint32_t*)&t;
}

// ============ fp32 -> fp16 plain conversion (grid-stride) ==================
__global__ void __launch_bounds__(256) cvt16_kernel(
    const float4* __restrict__ in, uint2* __restrict__ out, int n4)
{
    const int stride = gridDim.x * blockDim.x;
#pragma unroll 4
    for (int i = blockIdx.x * blockDim.x + threadIdx.x; i < n4; i += stride) {
        float4 w = in[i];
        uint2 v;
        v.x = pack_h16(w.x, w.y);
        v.y = pack_h16(w.z, w.w);
        out[i] = v;
    }
}

// ===== all four weight tensors -> fp16 in ONE launch =======================
#define SQ4 ((DD  * KTOT) / 4)
#define SK4 ((KVD * KTOT) / 4)
__global__ void __launch_bounds__(256) wcvt_kernel(
    const float4* __restrict__ wq, const float4* __restrict__ wk,
    const float4* __restrict__ wv, const float4* __restrict__ wp,
    uint2* __restrict__ wch, uint2* __restrict__ wph)
{
    const int total = SQ4 + 2 * SK4 + SQ4;
    const int stride = gridDim.x * blockDim.x;
#pragma unroll 2
    for (int i = blockIdx.x * blockDim.x + threadIdx.x; i < total; i += stride) {
        const float4* src;
        uint2* dst;
        int idx = i;
        if (idx < SQ4)                   { src = wq; dst = wch; }
        else if ((idx -= SQ4) < SK4)     { src = wk; dst = wch + SQ4; }
        else if ((idx -= SK4) < SK4)     { src = wv; dst = wch + SQ4 + SK4; }
        else { idx -= SK4;                 src = wp; dst = wph; }
        float4 w = src[idx];
        uint2 v;
        v.x = pack_h16(w.x, w.y);
        v.y = pack_h16(w.z, w.w);
        dst[idx] = v;
    }
}

// ==== plain fp16 GEMM: C[M,N] = A[M,K] * B[N,K]^T (fp32 accum/out) =========
// 3-slot cp.async pipeline, one barrier per K-step. MODE 1 = fused QKV epi.
#define GBM 128
#define GBN 128
#define GBK 32
#define GNK (KTOT / GBK)       // 64
#define LDA 40
#define TILE_EL (GBM * LDA)    // 5120 elements
#define TILE_B  (TILE_EL * 2)  // 10240 bytes
#define STAGE_B (2 * TILE_B)   // 20480 bytes (A, B)
#define NST 3
#define LDC 132                // epilogue fp32 tile stride
#define GEMM_SMEM (128 * LDC * 4 + 256)   // 67840 >= NST*STAGE_B (61440)

__device__ __forceinline__ void gemm_load_stage(
    uint32_t sb, int tid, int k0, const __half* gA, const __half* gB)
{
#pragma unroll
    for (int i = 0; i < 2; ++i) {
        int ch = tid + i * 256;
        int r = ch >> 2, sg = ch & 3;
        uint32_t so = (uint32_t)((r * LDA + sg * 8) * 2);
        size_t go = (size_t)r * KTOT + k0 + sg * 8;
        cp16(sb + so, gA + go);
        cp16(sb + TILE_B + so, gB + go);
    }
    CP_COMMIT();
}

template<int MODE>
__global__ void __launch_bounds__(256, 2) gemm_mma_kernel(
    const __half* __restrict__ A, const __half* __restrict__ B,
    float* __restrict__ C, int N,
    __half* __restrict__ qh, __half* __restrict__ kh, __half* __restrict__ vh,
    const float* __restrict__ qg, float qscale)
{
    extern __shared__ __half smem[];
    const uint32_t sbase = smem_u32(smem);
    const int tid = threadIdx.x;
    const int lane = tid & 31, wid = tid >> 5;
    const int wm = wid >> 2, wn = wid & 3;
    const int m0 = blockIdx.y * GBM;
    const int n0 = blockIdx.x * GBN;

    const __half* gA = A + (size_t)m0 * KTOT;
    const __half* gB = B + (size_t)n0 * KTOT;

    float acc[4][4][4];
#pragma unroll
    for (int mi = 0; mi < 4; ++mi)
#pragma unroll
        for (int nj = 0; nj < 4; ++nj)
#pragma unroll
            for (int e = 0; e < 4; ++e) acc[mi][nj][e] = 0.f;

    const int arow = wm * 64 + (lane & 15);
    const uint32_t aoffbase = (uint32_t)(arow * LDA * 2) + ((lane >> 4) << 4);
    const int g = lane >> 3;
    const int brow = wn * 32 + (lane & 7) + ((g >> 1) << 3);
    const uint32_t boffbase = (uint32_t)(brow * LDA * 2) + ((g & 1) << 4);

    gemm_load_stage(sbase, tid, 0, gA, gB);
    gemm_load_stage(sbase + STAGE_B, tid, GBK, gA, gB);

    for (int kt = 0; kt < GNK; ++kt) {
        const int slot = kt % NST;
        if (kt + 1 < GNK) { CP_WAIT1(); } else { CP_WAIT0(); }
        __syncthreads();
        if (kt + 2 < GNK)
            gemm_load_stage(sbase + (uint32_t)((kt + 2) % NST) * STAGE_B,
                            tid, (kt + 2) * GBK, gA, gB);

        const uint32_t st = sbase + (uint32_t)slot * STAGE_B;
        const uint32_t sA = st;
        const uint32_t sB = st + TILE_B;

#pragma unroll
        for (int kk = 0; kk < GBK; kk += 16) {
            const uint32_t akk = aoffbase + kk * 2;
            const uint32_t bkk = boffbase + kk * 2;
            uint32_t bfr[4][2];
#pragma unroll
            for (int nt = 0; nt < 2; ++nt) {
                uint32_t r[4];
                ldsm_x4(r, sB + bkk + nt * 16 * LDA * 2);
                bfr[2 * nt][0] = r[0]; bfr[2 * nt][1] = r[1];
                bfr[2 * nt + 1][0] = r[2]; bfr[2 * nt + 1][1] = r[3];
            }
#pragma unroll
            for (int mi = 0; mi < 4; ++mi) {
                uint32_t a[4];
                ldsm_x4(a, sA + akk + mi * 16 * LDA * 2);
#pragma unroll
                for (int nj = 0; nj < 4; ++nj)
                    mma16816h(acc[mi][nj], a, bfr[nj]);
            }
        }
    }

    if (MODE == 0) {
#pragma unroll
        for (int mi = 0; mi < 4; ++mi) {
            int r0 = m0 + wm * 64 + mi * 16 + (lane >> 2);
#pragma unroll
            for (int nj = 0; nj < 4; ++nj) {
                int c = n0 + wn * 32 + nj * 8 + ((lane & 3) << 1);
                *(float2*)&C[(size_t)r0 * N + c]       = make_float2(acc[mi][nj][0], acc[mi][nj][1]);
                *(float2*)&C[(size_t)(r0 + 8) * N + c] = make_float2(acc[mi][nj][2], acc[mi][nj][3]);
            }
        }
        return;
    }

    // ================= fused QKV epilogue (MODE 1) ==========================
    float* stile = (float*)smem;               // 128 x LDC fp32 tile
    float* sinv  = stile + 128 * LDC;          // 64-entry inv_freq table
    __syncthreads();                           // mainloop smem fully consumed

#pragma unroll
    for (int mi = 0; mi < 4; ++mi) {
        int r = wm * 64 + mi * 16 + (lane >> 2);
#pragma unroll
        for (int nj = 0; nj < 4; ++nj) {
            int c = wn * 32 + nj * 8 + ((lane & 3) << 1);
            stile[r * LDC + c]           = acc[mi][nj][0];
            stile[r * LDC + c + 1]       = acc[mi][nj][1];
            stile[(r + 8) * LDC + c]     = acc[mi][nj][2];
            stile[(r + 8) * LDC + c + 1] = acc[mi][nj][3];
        }
    }

    const bool isV = (n0 >= DD + KVD);
    const bool isK = (n0 >= DD) && !isV;
    if (!isV && tid < 64)
        sinv[tid] = 1.0f / powf(10000.0f, (float)tid * (1.0f / 64.0f));
    __syncthreads();

    if (!isV && tid < 128) {
        const int row = tid;
        const int t = (m0 + row) & (TT - 1);
        float ssq = 0.f;
#pragma unroll 8
        for (int d = 0; d < HD; ++d) {
            float x = stile[row * LDC + d];
            ssq += x * x;
        }
        float rms = rsqrtf(ssq * (1.0f / HD) + RMS_EPS);
        float gn = isK ? 1.0f : (qg[n0 >> 7] * qscale);
#pragma unroll 4
        for (int d = 0; d < 64; ++d) {
            float xa = stile[row * LDC + d] * rms;
            float xb = stile[row * LDC + d + 64] * rms;
            float s_, c_;
            sincosf((float)t * sinv[d], &s_, &c_);
            stile[row * LDC + d]      = (xa * c_ - xb * s_) * gn;
            stile[row * LDC + d + 64] = (xb * c_ + xa * s_) * gn;
        }
    }
    __syncthreads();

    __half* dst;
    int hloc, nh;
    if (isV)      { hloc = (n0 - DD - KVD) >> 7; nh = KVH; dst = vh; }
    else if (isK) { hloc = (n0 - DD) >> 7;       nh = KVH; dst = kh; }
    else          { hloc = n0 >> 7;              nh = HN;  dst = qh; }

#pragma unroll
    for (int p = 0; p < 16; ++p) {
        int row = p * 8 + wid;
        int token = m0 + row;
        int b = token >> 11, t = token & (TT - 1);
        size_t off = (((size_t)b * nh + hloc) * TT + t) * HD + lane * 4;
        float v0 = stile[row * LDC + lane * 4];
        float v1 = stile[row * LDC + lane * 4 + 1];
        float v2 = stile[row * LDC + lane * 4 + 2];
        float v3 = stile[row * LDC + lane * 4 + 3];
        uint2 pv;
        pv.x = pack_h16(v0, v1);
        pv.y = pack_h16(v2, v3);
        *(uint2*)&dst[off] = pv;
    }
}

// ============ tensor-core causal flash attention ===========================
// 4-warp CTA (FBM=64, FBN=32), 2 CTAs/SM, Q plain fp16 in registers, K/V
// plain fp16, 3-stage KV pipe. S = Q·K (1-term), PV = P·V (1-term).
#define FBM 64
#define FBN 32
#define LDQ 136
#define QHALF  (FBM * LDQ * 2)        // 17408 bytes for Q tile
#define KTILEB (FBN * LDQ * 2)        // 8704 bytes per K/V tile
#define STAGEB (2 * KTILEB)           // 17408 (K + V)
#define NSTAGE 3
#define FATT_SMEM (NSTAGE * STAGEB + QHALF)   // 69632

__device__ __forceinline__ void fatt_load_kv(
    uint32_t st, int tid, const __half* kp, const __half* vp, int kb)
{
    const size_t base = (size_t)kb * FBN * HD;
#pragma unroll
    for (int i = 0; i < 4; ++i) {
        int ch = tid + i * 128;            // 0..511
        int row = ch >> 4, seg = ch & 15;  // row 0..31, seg 0..15
        uint32_t so = (uint32_t)(row * (LDQ * 2) + seg * 16);
        size_t go = base + (size_t)row * HD + seg * 8;
        cp16(st + so, kp + go);
        cp16(st + KTILEB + so, vp + go);
    }
    CP_COMMIT();
}

__global__ void __launch_bounds__(128, 2) fattn_kernel(
    const __half* __restrict__ Qp,
    const __half* __restrict__ Kp, const __half* __restrict__ Vp,
    __half* __restrict__ Yh)
{
    extern __shared__ char smraw[];
    const uint32_t sSt = smem_u32(smraw);

    const int tid = threadIdx.x;
    const int lane = tid & 31, wid = tid >> 5;          // 4 warps
    const int qb = (int)(gridDim.x - 1 - blockIdx.x);   // heavy first
    const int h  = blockIdx.y;
    const int b  = blockIdx.z;
    const int hk = h / (HN / KVH);
    const int nkb = 2 * qb + 2;                         // 32-wide KV blocks

    const __half* qp = Qp + ((((size_t)b * HN + h) * TT) + (size_t)qb * FBM) * HD;
    const __half* kp = Kp + (((size_t)b * KVH + hk) * TT) * HD;
    const __half* vp = Vp + (((size_t)b * KVH + hk) * TT) * HD;

    // --- prologue: Q into dedicated region (one group), then kv0/kv1
    const uint32_t sQ = sSt + NSTAGE * STAGEB;
#pragma unroll
    for (int i = 0; i < 8; ++i) {
        int ch = tid + i * 128;            // 0..1023
        int row = ch >> 4, seg = ch & 15;  // row 0..63
        uint32_t so = (uint32_t)(row * (LDQ * 2) + seg * 16);
        size_t go = (size_t)row * HD + seg * 8;
        cp16(sQ + so, qp + go);
    }
    CP_COMMIT();
    fatt_load_kv(sSt, tid, kp, vp, 0);
    if (nkb > 1) fatt_load_kv(sSt + STAGEB, tid, kp, vp, 1);

    // fragment lane bases
    const uint32_t aoff = (uint32_t)((wid * 16 + (lane & 15)) * (LDQ * 2)) + ((lane >> 4) << 4);
    const int g = lane >> 3;
    const uint32_t boff = (uint32_t)(((lane & 7) + ((g >> 1) << 3)) * (LDQ * 2)) + ((g & 1) << 4);
    const uint32_t voff = (uint32_t)((lane & 15) * (LDQ * 2)) + (((lane >> 4) & 1) << 4);

    // --- Q fragments -> registers (once)
    if (nkb > 1) { CP_WAIT2(); } else { CP_WAIT1(); }
    __syncthreads();
    uint32_t aq[8][4];
#pragma unroll
    for (int kc = 0; kc < 8; ++kc)
        ldsm_x4(aq[kc], sQ + aoff + kc * 32);

    float o[16][4];
#pragma unroll
    for (int nf = 0; nf < 16; ++nf)
#pragma unroll
        for (int e = 0; e < 4; ++e) o[nf][e] = 0.f;
    float m_i[2] = {-1e30f, -1e30f};   // log2-domain running max
    float l_i[2] = {0.f, 0.f};

    const int qrow0 = qb * FBM + wid * 16 + (lane >> 2);

    for (int kb = 0; kb < nkb; ++kb) {
        const int slot = kb % NSTAGE;
        if (kb + 1 < nkb) { CP_WAIT1(); } else { CP_WAIT0(); }
        __syncthreads();
        if (kb + 2 < nkb)
            fatt_load_kv(sSt + (uint32_t)((kb + 2) % NSTAGE) * STAGEB, tid,
                         kp, vp, kb + 2);

        const uint32_t sK = sSt + (uint32_t)slot * STAGEB;
        const uint32_t sV = sK + KTILEB;

        // ---- S = Q K^T (single fp16 term), Q from registers ----
        float s[4][4];
#pragma unroll
        for (int j = 0; j < 4; ++j)
#pragma unroll
            for (int e = 0; e < 4; ++e) s[j][e] = 0.f;

#pragma unroll
        for (int kc = 0; kc < 8; ++kc) {
#pragma unroll
            for (int n16 = 0; n16 < 2; ++n16) {
                uint32_t bk[4];
                ldsm_x4(bk, sK + boff + n16 * 16 * (LDQ * 2) + kc * 32);
                mma16816h(s[2 * n16],     aq[kc], &bk[0]);
                mma16816h(s[2 * n16 + 1], aq[kc], &bk[2]);
            }
        }

        // ---- causal mask (diagonal 32-blocks only) ----
        if (kb >= nkb - 2) {
            const int kc0 = kb * FBN + 2 * (lane & 3);
#pragma unroll
            for (int j = 0; j < 4; ++j)
#pragma unroll
                for (int e = 0; e < 4; ++e) {
                    int row = qrow0 + (e >> 1) * 8;
                    int col = kc0 + 8 * j + (e & 1);
                    if (col > row) s[j][e] = -1e30f;
                }
        }

        // ---- row max + alpha (log2 domain) ----
        float alpha[2], mx2[2];
#pragma unroll
        for (int rr = 0; rr < 2; ++rr) {
            float mx = m_i[rr];
#pragma unroll
            for (int j = 0; j < 4; ++j)
                mx = fmaxf(mx, fmaxf(s[j][2 * rr], s[j][2 * rr + 1]));
            mx = fmaxf(mx, __shfl_xor_sync(0xffffffff, mx, 1));
            mx = fmaxf(mx, __shfl_xor_sync(0xffffffff, mx, 2));
            alpha[rr] = exp2f(m_i[rr] - mx);
            m_i[rr] = mx;
            mx2[rr] = mx;
        }
#pragma unroll
        for (int nf = 0; nf < 16; ++nf) {
            o[nf][0] *= alpha[0]; o[nf][1] *= alpha[0];
            o[nf][2] *= alpha[1]; o[nf][3] *= alpha[1];
        }
        float lsum[2] = {0.f, 0.f};

        // ---- per-chunk: exp2 + fp16 pack + single-term PV mma ----
#pragma unroll
        for (int kc2 = 0; kc2 < 2; ++kc2) {
            const int j0 = 2 * kc2, j1 = 2 * kc2 + 1;
            float p[8];
            p[0] = exp2f(s[j0][0] - mx2[0]);
            p[1] = exp2f(s[j0][1] - mx2[0]);
            p[2] = exp2f(s[j0][2] - mx2[1]);
            p[3] = exp2f(s[j0][3] - mx2[1]);
            p[4] = exp2f(s[j1][0] - mx2[0]);
            p[5] = exp2f(s[j1][1] - mx2[0]);
            p[6] = exp2f(s[j1][2] - mx2[1]);
            p[7] = exp2f(s[j1][3] - mx2[1]);
            lsum[0] += (p[0] + p[1]) + (p[4] + p[5]);
            lsum[1] += (p[2] + p[3]) + (p[6] + p[7]);

            uint32_t ap[4];
            ap[0] = pack_h16(p[0], p[1]);
            ap[1] = pack_h16(p[2], p[3]);
            ap[2] = pack_h16(p[4], p[5]);
            ap[3] = pack_h16(p[6], p[7]);

            const uint32_t vrow = voff + kc2 * 16 * (LDQ * 2);
#pragma unroll
            for (int nf16 = 0; nf16 < 8; ++nf16) {
                uint32_t bv[4];
                ldsm_x4_t(bv, sV + vrow + nf16 * 32);
                mma16816h(o[2 * nf16],     ap, &bv[0]);
                mma16816h(o[2 * nf16 + 1], ap, &bv[2]);
            }
        }
        l_i[0] = l_i[0] * alpha[0] + lsum[0];
        l_i[1] = l_i[1] * alpha[1] + lsum[1];
    }

    // ---- epilogue: normalize, write fp16 y ----
#pragma unroll
    for (int rr = 0; rr < 2; ++rr) {
        float lf = l_i[rr];
        lf += __shfl_xor_sync(0xffffffff, lf, 1);
        lf += __shfl_xor_sync(0xffffffff, lf, 2);
        float inv = 1.0f / lf;
        int trow = qrow0 + rr * 8;
        size_t rbase = ((size_t)(b * TT + trow)) * DD + h * HD + 2 * (lane & 3);
#pragma unroll
        for (int nf = 0; nf < 16; ++nf) {
            float v0 = o[nf][2 * rr] * inv;
            float v1 = o[nf][2 * rr + 1] * inv;
            *(uint32_t*)&Yh[rbase + nf * 8] = pack_h16(v0, v1);
        }
    }
}

// ---------------------------- launch ---------------------------------------
static inline void launch_cvt16(const float* src, __half* dst, size_t n)
{
    int n4 = (int)(n / 4);
    int blocks = (n4 + 511) / 512;
    if (blocks > 2048) blocks = 2048;
    cvt16_kernel<<<blocks, 256>>>((const float4*)src, (uint2*)dst, n4);
}

extern "C" void kernel_launch(void* const* d_in, const int* in_sizes, int n_in,
                              void* d_out, int out_size)
{
    const float* x   = (const float*)d_in[0];
    const float* Wq  = (const float*)d_in[1];
    const float* Wk  = (const float*)d_in[2];
    const float* Wv  = (const float*)d_in[3];
    const float* Wp  = (const float*)d_in[4];
    const float* qg  = (const float*)d_in[5];
    float* out = (float*)d_out;

    __half *xh, *wch, *wph, *yh, *qh, *kh, *vh;
    cudaGetSymbolAddress((void**)&xh,  g_xh);
    cudaGetSymbolAddress((void**)&wch, g_wch);
    cudaGetSymbolAddress((void**)&wph, g_wph);
    cudaGetSymbolAddress((void**)&yh,  g_yh);
    cudaGetSymbolAddress((void**)&qh,  g_qh);
    cudaGetSymbolAddress((void**)&kh,  g_kh);
    cudaGetSymbolAddress((void**)&vh,  g_vh);

    cudaFuncSetAttribute(gemm_mma_kernel<0>,
                         cudaFuncAttributeMaxDynamicSharedMemorySize, GEMM_SMEM);
    cudaFuncSetAttribute(gemm_mma_kernel<1>,
                         cudaFuncAttributeMaxDynamicSharedMemorySize, GEMM_SMEM);
    cudaFuncSetAttribute(fattn_kernel,
                         cudaFuncAttributeMaxDynamicSharedMemorySize, FATT_SMEM);

    // Pre-scale Q by log2(e) so flash-attention softmax runs in exp2 domain.
    const float qscale = LOG2E / sqrtf((float)HD);

    // conversions: x in its own launch; all four weight tensors in one launch
    launch_cvt16(x, xh, (size_t)NTOK * KTOT);
    wcvt_kernel<<<2048, 256>>>((const float4*)Wq, (const float4*)Wk,
                               (const float4*)Wv, (const float4*)Wp,
                               (uint2*)wch, (uint2*)wph);

    // fused QKV projection + RMSNorm/RoPE epilogue (Q/K/V plain fp16)
    gemm_mma_kernel<1><<<dim3(QKVN / GBN, NTOK / GBM), 256, GEMM_SMEM>>>(
        xh, wch, nullptr, QKVN,
        qh, kh, vh, qg, qscale);

    // tensor-core causal flash attention -> y fp16 (2 CTAs/SM)
    fattn_kernel<<<dim3(TT / FBM, HN, BB), 128, FATT_SMEM>>>(
        qh, kh, vh, yh);

    // output projection (fp32 out)
    gemm_mma_kernel<0><<<dim3(DD / GBN, NTOK / GBM), 256, GEMM_SMEM>>>(
        yh, wph, out, DD,
        nullptr, nullptr, nullptr, nullptr, 0.f);
}

// round 15
// speedup vs baseline: 8.5318x; 1.0358x over previous
#include <cuda_runtime.h>
#include <cuda_fp16.h>
#include <cstdint>
#include <math.h>

// Problem constants
#define HN   16          // num_heads
#define KVH  4           // num_kv_heads
#define HD   128         // head_dim
#define BB   4           // batch
#define TT   2048        // seq len
#define DD   (HN*HD)     // 2048
#define KVD  (KVH*HD)    // 512
#define NTOK (BB*TT)     // 8192
#define KTOT DD          // inner dim of all GEMMs = 2048
#define QKVN (DD + 2*KVD)  // 3072 fused projection width
#define RMS_EPS 1.1920928955078125e-07f
#define LOG2E 1.4426950408889634f

// ---------------- scratch (device globals: allocation-free) ----------------
__device__ __half g_xh [(size_t)NTOK * KTOT];
__device__ __half g_wch[(size_t)QKVN * KTOT];   // Wq|Wk|Wv plain fp16
__device__ __half g_wph[(size_t)DD * KTOT];     // Wproj plain fp16
__device__ __half g_yh [(size_t)NTOK * KTOT];

// plain fp16 Q/K/V for attention
__device__ __half g_qh[(size_t)BB * HN  * TT * HD];
__device__ __half g_kh[(size_t)BB * KVH * TT * HD];
__device__ __half g_vh[(size_t)BB * KVH * TT * HD];

// ======================= PTX helpers (baseline compute_103) ================
__device__ __forceinline__ uint32_t smem_u32(const void* p) {
    uint32_t a;
    asm("{ .reg .u64 t; cvta.to.shared.u64 t, %1; cvt.u32.u64 %0, t; }"
        : "=r"(a) : "l"(p));
    return a;
}
__device__ __forceinline__ void cp16(uint32_t dst, const void* src) {
    asm volatile("cp.async.cg.shared.global [%0], [%1], 16;" :: "r"(dst), "l"(src));
}
#define CP_COMMIT() asm volatile("cp.async.commit_group;" ::: "memory")
#define CP_WAIT2()  asm volatile("cp.async.wait_group 2;" ::: "memory")
#define CP_WAIT1()  asm volatile("cp.async.wait_group 1;" ::: "memory")
#define CP_WAIT0()  asm volatile("cp.async.wait_group 0;" ::: "memory")

__device__ __forceinline__ void ldsm_x4(uint32_t* r, uint32_t addr) {
    asm volatile("ldmatrix.sync.aligned.m8n8.x4.shared.b16 {%0,%1,%2,%3}, [%4];"
                 : "=r"(r[0]), "=r"(r[1]), "=r"(r[2]), "=r"(r[3]) : "r"(addr));
}
__device__ __forceinline__ void ldsm_x4_t(uint32_t* r, uint32_t addr) {
    asm volatile("ldmatrix.sync.aligned.m8n8.x4.trans.shared.b16 {%0,%1,%2,%3}, [%4];"
                 : "=r"(r[0]), "=r"(r[1]), "=r"(r[2]), "=r"(r[3]) : "r"(addr));
}
__device__ __forceinline__ void mma16816h(float* c, const uint32_t* a, const uint32_t* b) {
    asm volatile(
        "mma.sync.aligned.m16n8k16.row.col.f32.f16.f16.f32 "
        "{%0,%1,%2,%3}, {%4,%5,%6,%7}, {%8,%9}, {%0,%1,%2,%3};"
        : "+f"(c[0]), "+f"(c[1]), "+f"(c[2]), "+f"(c[3])
        : "r"(a[0]), "r"(a[1]), "r"(a[2]), "r"(a[3]), "r"(b[0]), "r"(b[1]));
}
__device__ __forceinline__ uint32_t pack_h16(float x, float y) {
    __half2 t = __floats2half2_rn(x, y);
    return *(uint32_t*)&t;
}

// ============ fp32 -> fp16 plain conversion (grid-stride) ==================
__global__ void __launch_bounds__(256) cvt16_kernel(
    const float4* __restrict__ in, uint2* __restrict__ out, int n4)
{
    const int stride = gridDim.x * blockDim.x;
#pragma unroll 4
    for (int i = blockIdx.x * blockDim.x + threadIdx.x; i < n4; i += stride) {
        float4 w = in[i];
        uint2 v;
        v.x = pack_h16(w.x, w.y);
        v.y = pack_h16(w.z, w.w);
        out[i] = v;
    }
}

// ===== all four weight tensors -> fp16 in ONE launch =======================
#define SQ4 ((DD  * KTOT) / 4)
#define SK4 ((KVD * KTOT) / 4)
__global__ void __launch_bounds__(256) wcvt_kernel(
    const float4* __restrict__ wq, const float4* __restrict__ wk,
    const float4* __restrict__ wv, const float4* __restrict__ wp,
    uint2* __restrict__ wch, uint2* __restrict__ wph)
{
    const int total = SQ4 + 2 * SK4 + SQ4;
    const int stride = gridDim.x * blockDim.x;
#pragma unroll 2
    for (int i = blockIdx.x * blockDim.x + threadIdx.x; i < total; i += stride) {
        const float4* src;
        uint2* dst;
        int idx = i;
        if (idx < SQ4)                   { src = wq; dst = wch; }
        else if ((idx -= SQ4) < SK4)     { src = wk; dst = wch + SQ4; }
        else if ((idx -= SK4) < SK4)     { src = wv; dst = wch + SQ4 + SK4; }
        else { idx -= SK4;                 src = wp; dst = wph; }
        float4 w = src[idx];
        uint2 v;
        v.x = pack_h16(w.x, w.y);
        v.y = pack_h16(w.z, w.w);
        dst[idx] = v;
    }
}

// ==== plain fp16 GEMM: C[M,N] = A[M,K] * B[N,K]^T (fp32 accum/out) =========
// 3-slot cp.async pipeline, one barrier per K-step. MODE 1 = fused QKV epi.
#define GBM 128
#define GBN 128
#define GBK 32
#define GNK (KTOT / GBK)       // 64
#define LDA 40
#define TILE_EL (GBM * LDA)    // 5120 elements
#define TILE_B  (TILE_EL * 2)  // 10240 bytes
#define STAGE_B (2 * TILE_B)   // 20480 bytes (A, B)
#define NST 3
#define LDC 132                // epilogue fp32 tile stride
#define GEMM_SMEM (128 * LDC * 4 + 256)   // 67840 >= NST*STAGE_B (61440)

__device__ __forceinline__ void gemm_load_stage(
    uint32_t sb, int tid, int k0, const __half* gA, const __half* gB)
{
#pragma unroll
    for (int i = 0; i < 2; ++i) {
        int ch = tid + i * 256;
        int r = ch >> 2, sg = ch & 3;
        uint32_t so = (uint32_t)((r * LDA + sg * 8) * 2);
        size_t go = (size_t)r * KTOT + k0 + sg * 8;
        cp16(sb + so, gA + go);
        cp16(sb + TILE_B + so, gB + go);
    }
    CP_COMMIT();
}

template<int MODE>
__global__ void __launch_bounds__(256, 2) gemm_mma_kernel(
    const __half* __restrict__ A, const __half* __restrict__ B,
    float* __restrict__ C, int N,
    __half* __restrict__ qh, __half* __restrict__ kh, __half* __restrict__ vh,
    const float* __restrict__ qg, float qscale)
{
    extern __shared__ __half smem[];
    const uint32_t sbase = smem_u32(smem);
    const int tid = threadIdx.x;
    const int lane = tid & 31, wid = tid >> 5;
    const int wm = wid >> 2, wn = wid & 3;
    const int m0 = blockIdx.y * GBM;
    const int n0 = blockIdx.x * GBN;

    const __half* gA = A + (size_t)m0 * KTOT;
    const __half* gB = B + (size_t)n0 * KTOT;

    float acc[4][4][4];
#pragma unroll
    for (int mi = 0; mi < 4; ++mi)
#pragma unroll
        for (int nj = 0; nj < 4; ++nj)
#pragma unroll
            for (int e = 0; e < 4; ++e) acc[mi][nj][e] = 0.f;

    const int arow = wm * 64 + (lane & 15);
    const uint32_t aoffbase = (uint32_t)(arow * LDA * 2) + ((lane >> 4) << 4);
    const int g = lane >> 3;
    const int brow = wn * 32 + (lane & 7) + ((g >> 1) << 3);
    const uint32_t boffbase = (uint32_t)(brow * LDA * 2) + ((g & 1) << 4);

    gemm_load_stage(sbase, tid, 0, gA, gB);
    gemm_load_stage(sbase + STAGE_B, tid, GBK, gA, gB);

    for (int kt = 0; kt < GNK; ++kt) {
        const int slot = kt % NST;
        if (kt + 1 < GNK) { CP_WAIT1(); } else { CP_WAIT0(); }
        __syncthreads();
        if (kt + 2 < GNK)
            gemm_load_stage(sbase + (uint32_t)((kt + 2) % NST) * STAGE_B,
                            tid, (kt + 2) * GBK, gA, gB);

        const uint32_t st = sbase + (uint32_t)slot * STAGE_B;
        const uint32_t sA = st;
        const uint32_t sB = st + TILE_B;

#pragma unroll
        for (int kk = 0; kk < GBK; kk += 16) {
            const uint32_t akk = aoffbase + kk * 2;
            const uint32_t bkk = boffbase + kk * 2;
            uint32_t bfr[4][2];
#pragma unroll
            for (int nt = 0; nt < 2; ++nt) {
                uint32_t r[4];
                ldsm_x4(r, sB + bkk + nt * 16 * LDA * 2);
                bfr[2 * nt][0] = r[0]; bfr[2 * nt][1] = r[1];
                bfr[2 * nt + 1][0] = r[2]; bfr[2 * nt + 1][1] = r[3];
            }
#pragma unroll
            for (int mi = 0; mi < 4; ++mi) {
                uint32_t a[4];
                ldsm_x4(a, sA + akk + mi * 16 * LDA * 2);
#pragma unroll
                for (int nj = 0; nj < 4; ++nj)
                    mma16816h(acc[mi][nj], a, bfr[nj]);
            }
        }
    }

    if (MODE == 0) {
#pragma unroll
        for (int mi = 0; mi < 4; ++mi) {
            int r0 = m0 + wm * 64 + mi * 16 + (lane >> 2);
#pragma unroll
            for (int nj = 0; nj < 4; ++nj) {
                int c = n0 + wn * 32 + nj * 8 + ((lane & 3) << 1);
                *(float2*)&C[(size_t)r0 * N + c]       = make_float2(acc[mi][nj][0], acc[mi][nj][1]);
                *(float2*)&C[(size_t)(r0 + 8) * N + c] = make_float2(acc[mi][nj][2], acc[mi][nj][3]);
            }
        }
        return;
    }

    // ================= fused QKV epilogue (MODE 1) ==========================
    float* stile = (float*)smem;               // 128 x LDC fp32 tile
    float* sinv  = stile + 128 * LDC;          // 64-entry inv_freq table
    __syncthreads();                           // mainloop smem fully consumed

#pragma unroll
    for (int mi = 0; mi < 4; ++mi) {
        int r = wm * 64 + mi * 16 + (lane >> 2);
#pragma unroll
        for (int nj = 0; nj < 4; ++nj) {
            int c = wn * 32 + nj * 8 + ((lane & 3) << 1);
            stile[r * LDC + c]           = acc[mi][nj][0];
            stile[r * LDC + c + 1]       = acc[mi][nj][1];
            stile[(r + 8) * LDC + c]     = acc[mi][nj][2];
            stile[(r + 8) * LDC + c + 1] = acc[mi][nj][3];
        }
    }

    const bool isV = (n0 >= DD + KVD);
    const bool isK = (n0 >= DD) && !isV;
    if (!isV && tid < 64)
        sinv[tid] = 1.0f / powf(10000.0f, (float)tid * (1.0f / 64.0f));
    __syncthreads();

    if (!isV && tid < 128) {
        const int row = tid;
        const int t = (m0 + row) & (TT - 1);
        float ssq = 0.f;
#pragma unroll 8
        for (int d = 0; d < HD; ++d) {
            float x = stile[row * LDC + d];
            ssq += x * x;
        }
        float rms = rsqrtf(ssq * (1.0f / HD) + RMS_EPS);
        float gn = isK ? 1.0f : (qg[n0 >> 7] * qscale);
#pragma unroll 4
        for (int d = 0; d < 64; ++d) {
            float xa = stile[row * LDC + d] * rms;
            float xb = stile[row * LDC + d + 64] * rms;
            float s_, c_;
            sincosf((float)t * sinv[d], &s_, &c_);
            stile[row * LDC + d]      = (xa * c_ - xb * s_) * gn;
            stile[row * LDC + d + 64] = (xb * c_ + xa * s_) * gn;
        }
    }
    __syncthreads();

    __half* dst;
    int hloc, nh;
    if (isV)      { hloc = (n0 - DD - KVD) >> 7; nh = KVH; dst = vh; }
    else if (isK) { hloc = (n0 - DD) >> 7;       nh = KVH; dst = kh; }
    else          { hloc = n0 >> 7;              nh = HN;  dst = qh; }

#pragma unroll
    for (int p = 0; p < 16; ++p) {
        int row = p * 8 + wid;
        int token = m0 + row;
        int b = token >> 11, t = token & (TT - 1);
        size_t off = (((size_t)b * nh + hloc) * TT + t) * HD + lane * 4;
        float v0 = stile[row * LDC + lane * 4];
        float v1 = stile[row * LDC + lane * 4 + 1];
        float v2 = stile[row * LDC + lane * 4 + 2];
        float v3 = stile[row * LDC + lane * 4 + 3];
        uint2 pv;
        pv.x = pack_h16(v0, v1);
        pv.y = pack_h16(v2, v3);
        *(uint2*)&dst[off] = pv;
    }
}

// ============ tensor-core causal flash attention ===========================
// 4-warp CTA (FBM=64, FBN=64), 2 CTAs/SM, Q fp16 in registers, K/V fp16,
// double-buffered KV pipe. S = Q·K (1-term), PV = P·V (1-term). exp2 domain.
#define FBM 64
#define FBN 64
#define LDQ 136
#define QTILEB (FBM * LDQ * 2)        // 17408 bytes for Q tile
#define KTILEB (FBN * LDQ * 2)        // 17408 bytes per K/V tile
#define STAGEB (2 * KTILEB)           // 34816 (K + V)
#define NSTAGE 2
#define FATT_SMEM (NSTAGE * STAGEB + QTILEB)   // 87040

__device__ __forceinline__ void fatt_load_kv(
    uint32_t st, int tid, const __half* kp, const __half* vp, int kb)
{
    const size_t base = (size_t)kb * FBN * HD;
#pragma unroll
    for (int i = 0; i < 8; ++i) {
        int ch = tid + i * 128;            // 0..1023
        int row = ch >> 4, seg = ch & 15;  // row 0..63, seg 0..15
        uint32_t so = (uint32_t)(row * (LDQ * 2) + seg * 16);
        size_t go = base + (size_t)row * HD + seg * 8;
        cp16(st + so, kp + go);
        cp16(st + KTILEB + so, vp + go);
    }
    CP_COMMIT();
}

__global__ void __launch_bounds__(128, 2) fattn_kernel(
    const __half* __restrict__ Qp,
    const __half* __restrict__ Kp, const __half* __restrict__ Vp,
    __half* __restrict__ Yh)
{
    extern __shared__ char smraw[];
    const uint32_t sSt = smem_u32(smraw);

    const int tid = threadIdx.x;
    const int lane = tid & 31, wid = tid >> 5;          // 4 warps
    const int qb = (int)(gridDim.x - 1 - blockIdx.x);   // heavy first
    const int h  = blockIdx.y;
    const int b  = blockIdx.z;
    const int hk = h / (HN / KVH);
    const int nkb = qb + 1;                             // 64-wide KV blocks

    const __half* qp = Qp + ((((size_t)b * HN + h) * TT) + (size_t)qb * FBM) * HD;
    const __half* kp = Kp + (((size_t)b * KVH + hk) * TT) * HD;
    const __half* vp = Vp + (((size_t)b * KVH + hk) * TT) * HD;

    // --- prologue: Q (one group), then kv0 / kv1
    const uint32_t sQ = sSt + NSTAGE * STAGEB;
#pragma unroll
    for (int i = 0; i < 8; ++i) {
        int ch = tid + i * 128;
        int row = ch >> 4, seg = ch & 15;
        uint32_t so = (uint32_t)(row * (LDQ * 2) + seg * 16);
        size_t go = (size_t)row * HD + seg * 8;
        cp16(sQ + so, qp + go);
    }
    CP_COMMIT();
    fatt_load_kv(sSt, tid, kp, vp, 0);
    if (nkb > 1) fatt_load_kv(sSt + STAGEB, tid, kp, vp, 1);

    // fragment lane bases
    const uint32_t aoff = (uint32_t)((wid * 16 + (lane & 15)) * (LDQ * 2)) + ((lane >> 4) << 4);
    const int g = lane >> 3;
    const uint32_t boff = (uint32_t)(((lane & 7) + ((g >> 1) << 3)) * (LDQ * 2)) + ((g & 1) << 4);
    const uint32_t voff = (uint32_t)((lane & 15) * (LDQ * 2)) + (((lane >> 4) & 1) << 4);

    // --- Q fragments -> registers (once)
    if (nkb > 1) { CP_WAIT2(); } else { CP_WAIT1(); }
    __syncthreads();
    uint32_t aq[8][4];
#pragma unroll
    for (int kc = 0; kc < 8; ++kc)
        ldsm_x4(aq[kc], sQ + aoff + kc * 32);

    float o[16][4];
#pragma unroll
    for (int nf = 0; nf < 16; ++nf)
#pragma unroll
        for (int e = 0; e < 4; ++e) o[nf][e] = 0.f;
    float m_i[2] = {-1e30f, -1e30f};   // log2-domain running max
    float l_i[2] = {0.f, 0.f};

    const int qrow0 = qb * FBM + wid * 16 + (lane >> 2);

    for (int kb = 0; kb < nkb; ++kb) {
        const int slot = kb & 1;
        if (kb + 1 < nkb) { CP_WAIT1(); } else { CP_WAIT0(); }
        __syncthreads();

        const uint32_t sK = sSt + (uint32_t)slot * STAGEB;
        const uint32_t sV = sK + KTILEB;

        // ---- S = Q K^T (single fp16 term), Q from registers ----
        float s[8][4];
#pragma unroll
        for (int j = 0; j < 8; ++j)
#pragma unroll
            for (int e = 0; e < 4; ++e) s[j][e] = 0.f;

#pragma unroll
        for (int kc = 0; kc < 8; ++kc) {
#pragma unroll
            for (int n16 = 0; n16 < 4; ++n16) {
                uint32_t bk[4];
                ldsm_x4(bk, sK + boff + n16 * 16 * (LDQ * 2) + kc * 32);
                mma16816h(s[2 * n16],     aq[kc], &bk[0]);
                mma16816h(s[2 * n16 + 1], aq[kc], &bk[2]);
            }
        }

        // ---- causal mask (diagonal block only) ----
        if (kb == nkb - 1) {
            const int kc0 = kb * FBN + 2 * (lane & 3);
#pragma unroll
            for (int j = 0; j < 8; ++j)
#pragma unroll
                for (int e = 0; e < 4; ++e) {
                    int row = qrow0 + (e >> 1) * 8;
                    int col = kc0 + 8 * j + (e & 1);
                    if (col > row) s[j][e] = -1e30f;
                }
        }

        // ---- row max + alpha (log2 domain) ----
        float alpha[2], mx2[2];
#pragma unroll
        for (int rr = 0; rr < 2; ++rr) {
            float mx = m_i[rr];
#pragma unroll
            for (int j = 0; j < 8; ++j)
                mx = fmaxf(mx, fmaxf(s[j][2 * rr], s[j][2 * rr + 1]));
            mx = fmaxf(mx, __shfl_xor_sync(0xffffffff, mx, 1));
            mx = fmaxf(mx, __shfl_xor_sync(0xffffffff, mx, 2));
            alpha[rr] = exp2f(m_i[rr] - mx);
            m_i[rr] = mx;
            mx2[rr] = mx;
        }
#pragma unroll
        for (int nf = 0; nf < 16; ++nf) {
            o[nf][0] *= alpha[0]; o[nf][1] *= alpha[0];
            o[nf][2] *= alpha[1]; o[nf][3] *= alpha[1];
        }
        float lsum[2] = {0.f, 0.f};

        // ---- per-chunk: exp2 + fp16 pack + single-term PV mma ----
#pragma unroll
        for (int kc2 = 0; kc2 < 4; ++kc2) {
            const int j0 = 2 * kc2, j1 = 2 * kc2 + 1;
            float p[8];
            p[0] = exp2f(s[j0][0] - mx2[0]);
            p[1] = exp2f(s[j0][1] - mx2[0]);
            p[2] = exp2f(s[j0][2] - mx2[1]);
            p[3] = exp2f(s[j0][3] - mx2[1]);
            p[4] = exp2f(s[j1][0] - mx2[0]);
            p[5] = exp2f(s[j1][1] - mx2[0]);
            p[6] = exp2f(s[j1][2] - mx2[1]);
            p[7] = exp2f(s[j1][3] - mx2[1]);
            lsum[0] += (p[0] + p[1]) + (p[4] + p[5]);
            lsum[1] += (p[2] + p[3]) + (p[6] + p[7]);

            uint32_t ap[4];
            ap[0] = pack_h16(p[0], p[1]);
            ap[1] = pack_h16(p[2], p[3]);
            ap[2] = pack_h16(p[4], p[5]);
            ap[3] = pack_h16(p[6], p[7]);

            const uint32_t vrow = voff + kc2 * 16 * (LDQ * 2);
#pragma unroll
            for (int nf16 = 0; nf16 < 8; ++nf16) {
                uint32_t bv[4];
                ldsm_x4_t(bv, sV + vrow + nf16 * 32);
                mma16816h(o[2 * nf16],     ap, &bv[0]);
                mma16816h(o[2 * nf16 + 1], ap, &bv[2]);
            }
        }
        l_i[0] = l_i[0] * alpha[0] + lsum[0];
        l_i[1] = l_i[1] * alpha[1] + lsum[1];

        // ---- prefetch kb+2 into this slot (after everyone is done) ----
        if (kb + 2 < nkb) {
            __syncthreads();
            fatt_load_kv(sSt + (uint32_t)slot * STAGEB, tid, kp, vp, kb + 2);
        }
    }

    // ---- epilogue: normalize, write fp16 y ----
#pragma unroll
    for (int rr = 0; rr < 2; ++rr) {
        float lf = l_i[rr];
        lf += __shfl_xor_sync(0xffffffff, lf, 1);
        lf += __shfl_xor_sync(0xffffffff, lf, 2);
        float inv = 1.0f / lf;
        int trow = qrow0 + rr * 8;
        size_t rbase = ((size_t)(b * TT + trow)) * DD + h * HD + 2 * (lane & 3);
#pragma unroll
        for (int nf = 0; nf < 16; ++nf) {
            float v0 = o[nf][2 * rr] * inv;
            float v1 = o[nf][2 * rr + 1] * inv;
            *(uint32_t*)&Yh[rbase + nf * 8] = pack_h16(v0, v1);
        }
    }
}

// ---------------------------- launch ---------------------------------------
static inline void launch_cvt16(const float* src, __half* dst, size_t n)
{
    int n4 = (int)(n / 4);
    int blocks = (n4 + 511) / 512;
    if (blocks > 2048) blocks = 2048;
    cvt16_kernel<<<blocks, 256>>>((const float4*)src, (uint2*)dst, n4);
}

extern "C" void kernel_launch(void* const* d_in, const int* in_sizes, int n_in,
                              void* d_out, int out_size)
{
    const float* x   = (const float*)d_in[0];
    const float* Wq  = (const float*)d_in[1];
    const float* Wk  = (const float*)d_in[2];
    const float* Wv  = (const float*)d_in[3];
    const float* Wp  = (const float*)d_in[4];
    const float* qg  = (const float*)d_in[5];
    float* out = (float*)d_out;

    __half *xh, *wch, *wph, *yh, *qh, *kh, *vh;
    cudaGetSymbolAddress((void**)&xh,  g_xh);
    cudaGetSymbolAddress((void**)&wch, g_wch);
    cudaGetSymbolAddress((void**)&wph, g_wph);
    cudaGetSymbolAddress((void**)&yh,  g_yh);
    cudaGetSymbolAddress((void**)&qh,  g_qh);
    cudaGetSymbolAddress((void**)&kh,  g_kh);
    cudaGetSymbolAddress((void**)&vh,  g_vh);

    cudaFuncSetAttribute(gemm_mma_kernel<0>,
                         cudaFuncAttributeMaxDynamicSharedMemorySize, GEMM_SMEM);
    cudaFuncSetAttribute(gemm_mma_kernel<1>,
                         cudaFuncAttributeMaxDynamicSharedMemorySize, GEMM_SMEM);
    cudaFuncSetAttribute(fattn_kernel,
                         cudaFuncAttributeMaxDynamicSharedMemorySize, FATT_SMEM);

    // Pre-scale Q by log2(e) so flash-attention softmax runs in exp2 domain.
    const float qscale = LOG2E / sqrtf((float)HD);

    // conversions: x in its own launch; all four weight tensors in one launch
    launch_cvt16(x, xh, (size_t)NTOK * KTOT);
    wcvt_kernel<<<2048, 256>>>((const float4*)Wq, (const float4*)Wk,
                               (const float4*)Wv, (const float4*)Wp,
                               (uint2*)wch, (uint2*)wph);

    // fused QKV projection + RMSNorm/RoPE epilogue (Q/K/V plain fp16)
    gemm_mma_kernel<1><<<dim3(QKVN / GBN, NTOK / GBM), 256, GEMM_SMEM>>>(
        xh, wch, nullptr, QKVN,
        qh, kh, vh, qg, qscale);

    // tensor-core causal flash attention -> y fp16 (2 CTAs/SM)
    fattn_kernel<<<dim3(TT / FBM, HN, BB), 128, FATT_SMEM>>>(
        qh, kh, vh, yh);

    // output projection (fp32 out)
    gemm_mma_kernel<0><<<dim3(DD / GBN, NTOK / GBM), 256, GEMM_SMEM>>>(
        yh, wph, out, DD,
        nullptr, nullptr, nullptr, nullptr, 0.f);
}

// round 16
// speedup vs baseline: 9.3806x; 1.0995x over previous
#include <cuda_runtime.h>
#include <cuda_fp16.h>
#include <cstdint>
#include <math.h>

// Problem constants
#define HN   16          // num_heads
#define KVH  4           // num_kv_heads
#define HD   128         // head_dim
#define BB   4           // batch
#define TT   2048        // seq len
#define DD   (HN*HD)     // 2048
#define KVD  (KVH*HD)    // 512
#define NTOK (BB*TT)     // 8192
#define KTOT DD          // inner dim of all GEMMs = 2048
#define QKVN (DD + 2*KVD)  // 3072 fused projection width
#define RMS_EPS 1.1920928955078125e-07f
#define LOG2E 1.4426950408889634f

// ---------------- scratch (device globals: allocation-free) ----------------
__device__ __half g_xh [(size_t)NTOK * KTOT];
__device__ __half g_wch[(size_t)QKVN * KTOT];   // Wq|Wk|Wv plain fp16
__device__ __half g_wph[(size_t)DD * KTOT];     // Wproj plain fp16
__device__ __half g_yh [(size_t)NTOK * KTOT];

// plain fp16 Q/K/V for attention
__device__ __half g_qh[(size_t)BB * HN  * TT * HD];
__device__ __half g_kh[(size_t)BB * KVH * TT * HD];
__device__ __half g_vh[(size_t)BB * KVH * TT * HD];

// ======================= PTX helpers (baseline compute_103) ================
__device__ __forceinline__ uint32_t smem_u32(const void* p) {
    uint32_t a;
    asm("{ .reg .u64 t; cvta.to.shared.u64 t, %1; cvt.u32.u64 %0, t; }"
        : "=r"(a) : "l"(p));
    return a;
}
__device__ __forceinline__ void cp16(uint32_t dst, const void* src) {
    asm volatile("cp.async.cg.shared.global [%0], [%1], 16;" :: "r"(dst), "l"(src));
}
#define CP_COMMIT() asm volatile("cp.async.commit_group;" ::: "memory")
#define CP_WAIT2()  asm volatile("cp.async.wait_group 2;" ::: "memory")
#define CP_WAIT1()  asm volatile("cp.async.wait_group 1;" ::: "memory")
#define CP_WAIT0()  asm volatile("cp.async.wait_group 0;" ::: "memory")

__device__ __forceinline__ void ldsm_x4(uint32_t* r, uint32_t addr) {
    asm volatile("ldmatrix.sync.aligned.m8n8.x4.shared.b16 {%0,%1,%2,%3}, [%4];"
                 : "=r"(r[0]), "=r"(r[1]), "=r"(r[2]), "=r"(r[3]) : "r"(addr));
}
__device__ __forceinline__ void ldsm_x4_t(uint32_t* r, uint32_t addr) {
    asm volatile("ldmatrix.sync.aligned.m8n8.x4.trans.shared.b16 {%0,%1,%2,%3}, [%4];"
                 : "=r"(r[0]), "=r"(r[1]), "=r"(r[2]), "=r"(r[3]) : "r"(addr));
}
__device__ __forceinline__ void mma16816h(float* c, const uint32_t* a, const uint32_t* b) {
    asm volatile(
        "mma.sync.aligned.m16n8k16.row.col.f32.f16.f16.f32 "
        "{%0,%1,%2,%3}, {%4,%5,%6,%7}, {%8,%9}, {%0,%1,%2,%3};"
        : "+f"(c[0]), "+f"(c[1]), "+f"(c[2]), "+f"(c[3])
        : "r"(a[0]), "r"(a[1]), "r"(a[2]), "r"(a[3]), "r"(b[0]), "r"(b[1]));
}
__device__ __forceinline__ uint32_t pack_h16(float x, float y) {
    __half2 t = __floats2half2_rn(x, y);
    return *(uint32_t*)&t;
}

// ============ fp32 -> fp16 conversion (one thread per float4) ==============
__global__ void __launch_bounds__(256) cvt16_kernel(
    const float4* __restrict__ in, uint2* __restrict__ out, int n4)
{
    int i = blockIdx.x * blockDim.x + threadIdx.x;
    if (i >= n4) return;
    float4 w = in[i];
    uint2 v;
    v.x = pack_h16(w.x, w.y);
    v.y = pack_h16(w.z, w.w);
    out[i] = v;
}

// ===== all four weight tensors -> fp16, one thread per float4 ==============
#define SQ4 ((DD  * KTOT) / 4)
#define SK4 ((KVD * KTOT) / 4)
#define WTOT4 (SQ4 + 2 * SK4 + SQ4)
__global__ void __launch_bounds__(256) wcvt_kernel(
    const float4* __restrict__ wq, const float4* __restrict__ wk,
    const float4* __restrict__ wv, const float4* __restrict__ wp,
    uint2* __restrict__ wch, uint2* __restrict__ wph)
{
    int i = blockIdx.x * blockDim.x + threadIdx.x;
    if (i >= WTOT4) return;
    const float4* src;
    uint2* dst;
    int idx = i;
    if (idx < SQ4)                   { src = wq; dst = wch; }
    else if ((idx -= SQ4) < SK4)     { src = wk; dst = wch + SQ4; }
    else if ((idx -= SK4) < SK4)     { src = wv; dst = wch + SQ4 + SK4; }
    else { idx -= SK4;                 src = wp; dst = wph; }
    float4 w = src[idx];
    uint2 v;
    v.x = pack_h16(w.x, w.y);
    v.y = pack_h16(w.z, w.w);
    dst[idx] = v;
}

// ==== plain fp16 GEMM: C[M,N] = A[M,K] * B[N,K]^T (fp32 accum/out) =========
// GBK=64, 3-slot cp.async pipeline, one barrier per K-step (32 steps).
#define GBM 128
#define GBN 128
#define GBK 64
#define GNK (KTOT / GBK)       // 32
#define LDA 72                 // 64 + 8 pad (144B rows, ldsm conflict-free)
#define TILE_EL (GBM * LDA)    // 9216 elements
#define TILE_B  (TILE_EL * 2)  // 18432 bytes
#define STAGE_B (2 * TILE_B)   // 36864 bytes (A, B)
#define NST 3
#define LDC 132                // epilogue fp32 tile stride
#define GEMM_SMEM (NST * STAGE_B)   // 110592 (>= epilogue 67840)

__device__ __forceinline__ void gemm_load_stage(
    uint32_t sb, int tid, int k0, const __half* gA, const __half* gB)
{
#pragma unroll
    for (int i = 0; i < 4; ++i) {
        int ch = tid + i * 256;            // 0..1023
        int r = ch >> 3, sg = ch & 7;      // row 0..127, seg 0..7 (16B)
        uint32_t so = (uint32_t)((r * LDA + sg * 8) * 2);
        size_t go = (size_t)r * KTOT + k0 + sg * 8;
        cp16(sb + so, gA + go);
        cp16(sb + TILE_B + so, gB + go);
    }
    CP_COMMIT();
}

template<int MODE>
__global__ void __launch_bounds__(256, 2) gemm_mma_kernel(
    const __half* __restrict__ A, const __half* __restrict__ B,
    float* __restrict__ C, int N,
    __half* __restrict__ qh, __half* __restrict__ kh, __half* __restrict__ vh,
    const float* __restrict__ qg, float qscale)
{
    extern __shared__ __half smem[];
    const uint32_t sbase = smem_u32(smem);
    const int tid = threadIdx.x;
    const int lane = tid & 31, wid = tid >> 5;
    const int wm = wid >> 2, wn = wid & 3;
    const int m0 = blockIdx.y * GBM;
    const int n0 = blockIdx.x * GBN;

    const __half* gA = A + (size_t)m0 * KTOT;
    const __half* gB = B + (size_t)n0 * KTOT;

    float acc[4][4][4];
#pragma unroll
    for (int mi = 0; mi < 4; ++mi)
#pragma unroll
        for (int nj = 0; nj < 4; ++nj)
#pragma unroll
            for (int e = 0; e < 4; ++e) acc[mi][nj][e] = 0.f;

    const int arow = wm * 64 + (lane & 15);
    const uint32_t aoffbase = (uint32_t)(arow * LDA * 2) + ((lane >> 4) << 4);
    const int g = lane >> 3;
    const int brow = wn * 32 + (lane & 7) + ((g >> 1) << 3);
    const uint32_t boffbase = (uint32_t)(brow * LDA * 2) + ((g & 1) << 4);

    gemm_load_stage(sbase, tid, 0, gA, gB);
    gemm_load_stage(sbase + STAGE_B, tid, GBK, gA, gB);

    for (int kt = 0; kt < GNK; ++kt) {
        const int slot = kt % NST;
        if (kt + 1 < GNK) { CP_WAIT1(); } else { CP_WAIT0(); }
        __syncthreads();
        if (kt + 2 < GNK)
            gemm_load_stage(sbase + (uint32_t)((kt + 2) % NST) * STAGE_B,
                            tid, (kt + 2) * GBK, gA, gB);

        const uint32_t st = sbase + (uint32_t)slot * STAGE_B;
        const uint32_t sA = st;
        const uint32_t sB = st + TILE_B;

#pragma unroll
        for (int kk = 0; kk < GBK; kk += 16) {
            const uint32_t akk = aoffbase + kk * 2;
            const uint32_t bkk = boffbase + kk * 2;
            uint32_t bfr[4][2];
#pragma unroll
            for (int nt = 0; nt < 2; ++nt) {
                uint32_t r[4];
                ldsm_x4(r, sB + bkk + nt * 16 * LDA * 2);
                bfr[2 * nt][0] = r[0]; bfr[2 * nt][1] = r[1];
                bfr[2 * nt + 1][0] = r[2]; bfr[2 * nt + 1][1] = r[3];
            }
#pragma unroll
            for (int mi = 0; mi < 4; ++mi) {
                uint32_t a[4];
                ldsm_x4(a, sA + akk + mi * 16 * LDA * 2);
#pragma unroll
                for (int nj = 0; nj < 4; ++nj)
                    mma16816h(acc[mi][nj], a, bfr[nj]);
            }
        }
    }

    if (MODE == 0) {
#pragma unroll
        for (int mi = 0; mi < 4; ++mi) {
            int r0 = m0 + wm * 64 + mi * 16 + (lane >> 2);
#pragma unroll
            for (int nj = 0; nj < 4; ++nj) {
                int c = n0 + wn * 32 + nj * 8 + ((lane & 3) << 1);
                *(float2*)&C[(size_t)r0 * N + c]       = make_float2(acc[mi][nj][0], acc[mi][nj][1]);
                *(float2*)&C[(size_t)(r0 + 8) * N + c] = make_float2(acc[mi][nj][2], acc[mi][nj][3]);
            }
        }
        return;
    }

    // ================= fused QKV epilogue (MODE 1) ==========================
    float* stile = (float*)smem;               // 128 x LDC fp32 tile
    float* sinv  = stile + 128 * LDC;          // 64-entry inv_freq table
    __syncthreads();                           // mainloop smem fully consumed

#pragma unroll
    for (int mi = 0; mi < 4; ++mi) {
        int r = wm * 64 + mi * 16 + (lane >> 2);
#pragma unroll
        for (int nj = 0; nj < 4; ++nj) {
            int c = wn * 32 + nj * 8 + ((lane & 3) << 1);
            stile[r * LDC + c]           = acc[mi][nj][0];
            stile[r * LDC + c + 1]       = acc[mi][nj][1];
            stile[(r + 8) * LDC + c]     = acc[mi][nj][2];
            stile[(r + 8) * LDC + c + 1] = acc[mi][nj][3];
        }
    }

    const bool isV = (n0 >= DD + KVD);
    const bool isK = (n0 >= DD) && !isV;
    if (!isV && tid < 64)
        sinv[tid] = 1.0f / powf(10000.0f, (float)tid * (1.0f / 64.0f));
    __syncthreads();

    if (!isV && tid < 128) {
        const int row = tid;
        const int t = (m0 + row) & (TT - 1);
        float ssq = 0.f;
#pragma unroll 8
        for (int d = 0; d < HD; ++d) {
            float x = stile[row * LDC + d];
            ssq += x * x;
        }
        float rms = rsqrtf(ssq * (1.0f / HD) + RMS_EPS);
        float gn = isK ? 1.0f : (qg[n0 >> 7] * qscale);
#pragma unroll 4
        for (int d = 0; d < 64; ++d) {
            float xa = stile[row * LDC + d] * rms;
            float xb = stile[row * LDC + d + 64] * rms;
            float s_, c_;
            sincosf((float)t * sinv[d], &s_, &c_);
            stile[row * LDC + d]      = (xa * c_ - xb * s_) * gn;
            stile[row * LDC + d + 64] = (xb * c_ + xa * s_) * gn;
        }
    }
    __syncthreads();

    __half* dst;
    int hloc, nh;
    if (isV)      { hloc = (n0 - DD - KVD) >> 7; nh = KVH; dst = vh; }
    else if (isK) { hloc = (n0 - DD) >> 7;       nh = KVH; dst = kh; }
    else          { hloc = n0 >> 7;              nh = HN;  dst = qh; }

#pragma unroll
    for (int p = 0; p < 16; ++p) {
        int row = p * 8 + wid;
        int token = m0 + row;
        int b = token >> 11, t = token & (TT - 1);
        size_t off = (((size_t)b * nh + hloc) * TT + t) * HD + lane * 4;
        float v0 = stile[row * LDC + lane * 4];
        float v1 = stile[row * LDC + lane * 4 + 1];
        float v2 = stile[row * LDC + lane * 4 + 2];
        float v3 = stile[row * LDC + lane * 4 + 3];
        uint2 pv;
        pv.x = pack_h16(v0, v1);
        pv.y = pack_h16(v2, v3);
        *(uint2*)&dst[off] = pv;
    }
}

// ============ tensor-core causal flash attention ===========================
// 4-warp CTA (FBM=64, FBN=64), 2 CTAs/SM, Q fp16 in registers, K/V fp16,
// double-buffered KV pipe. S = Q·K (1-term), PV = P·V (1-term). exp2 domain.
#define FBM 64
#define FBN 64
#define LDQ 136
#define QTILEB (FBM * LDQ * 2)        // 17408 bytes for Q tile
#define KTILEB (FBN * LDQ * 2)        // 17408 bytes per K/V tile
#define STAGEB (2 * KTILEB)           // 34816 (K + V)
#define NSTAGE 2
#define FATT_SMEM (NSTAGE * STAGEB + QTILEB)   // 87040

__device__ __forceinline__ void fatt_load_kv(
    uint32_t st, int tid, const __half* kp, const __half* vp, int kb)
{
    const size_t base = (size_t)kb * FBN * HD;
#pragma unroll
    for (int i = 0; i < 8; ++i) {
        int ch = tid + i * 128;            // 0..1023
        int row = ch >> 4, seg = ch & 15;  // row 0..63, seg 0..15
        uint32_t so = (uint32_t)(row * (LDQ * 2) + seg * 16);
        size_t go = base + (size_t)row * HD + seg * 8;
        cp16(st + so, kp + go);
        cp16(st + KTILEB + so, vp + go);
    }
    CP_COMMIT();
}

__global__ void __launch_bounds__(128, 2) fattn_kernel(
    const __half* __restrict__ Qp,
    const __half* __restrict__ Kp, const __half* __restrict__ Vp,
    __half* __restrict__ Yh)
{
    extern __shared__ char smraw[];
    const uint32_t sSt = smem_u32(smraw);

    const int tid = threadIdx.x;
    const int lane = tid & 31, wid = tid >> 5;          // 4 warps
    const int qb = (int)(gridDim.x - 1 - blockIdx.x);   // heavy first
    const int h  = blockIdx.y;
    const int b  = blockIdx.z;
    const int hk = h / (HN / KVH);
    const int nkb = qb + 1;                             // 64-wide KV blocks

    const __half* qp = Qp + ((((size_t)b * HN + h) * TT) + (size_t)qb * FBM) * HD;
    const __half* kp = Kp + (((size_t)b * KVH + hk) * TT) * HD;
    const __half* vp = Vp + (((size_t)b * KVH + hk) * TT) * HD;

    // --- prologue: Q (one group), then kv0 / kv1
    const uint32_t sQ = sSt + NSTAGE * STAGEB;
#pragma unroll
    for (int i = 0; i < 8; ++i) {
        int ch = tid + i * 128;
        int row = ch >> 4, seg = ch & 15;
        uint32_t so = (uint32_t)(row * (LDQ * 2) + seg * 16);
        size_t go = (size_t)row * HD + seg * 8;
        cp16(sQ + so, qp + go);
    }
    CP_COMMIT();
    fatt_load_kv(sSt, tid, kp, vp, 0);
    if (nkb > 1) fatt_load_kv(sSt + STAGEB, tid, kp, vp, 1);

    // fragment lane bases
    const uint32_t aoff = (uint32_t)((wid * 16 + (lane & 15)) * (LDQ * 2)) + ((lane >> 4) << 4);
    const int g = lane >> 3;
    const uint32_t boff = (uint32_t)(((lane & 7) + ((g >> 1) << 3)) * (LDQ * 2)) + ((g & 1) << 4);
    const uint32_t voff = (uint32_t)((lane & 15) * (LDQ * 2)) + (((lane >> 4) & 1) << 4);

    // --- Q fragments -> registers (once)
    if (nkb > 1) { CP_WAIT2(); } else { CP_WAIT1(); }
    __syncthreads();
    uint32_t aq[8][4];
#pragma unroll
    for (int kc = 0; kc < 8; ++kc)
        ldsm_x4(aq[kc], sQ + aoff + kc * 32);

    float o[16][4];
#pragma unroll
    for (int nf = 0; nf < 16; ++nf)
#pragma unroll
        for (int e = 0; e < 4; ++e) o[nf][e] = 0.f;
    float m_i[2] = {-1e30f, -1e30f};   // log2-domain running max
    float l_i[2] = {0.f, 0.f};

    const int qrow0 = qb * FBM + wid * 16 + (lane >> 2);

    for (int kb = 0; kb < nkb; ++kb) {
        const int slot = kb & 1;
        if (kb + 1 < nkb) { CP_WAIT1(); } else { CP_WAIT0(); }
        __syncthreads();

        const uint32_t sK = sSt + (uint32_t)slot * STAGEB;
        const uint32_t sV = sK + KTILEB;

        // ---- S = Q K^T (single fp16 term), Q from registers ----
        float s[8][4];
#pragma unroll
        for (int j = 0; j < 8; ++j)
#pragma unroll
            for (int e = 0; e < 4; ++e) s[j][e] = 0.f;

#pragma unroll
        for (int kc = 0; kc < 8; ++kc) {
#pragma unroll
            for (int n16 = 0; n16 < 4; ++n16) {
                uint32_t bk[4];
                ldsm_x4(bk, sK + boff + n16 * 16 * (LDQ * 2) + kc * 32);
                mma16816h(s[2 * n16],     aq[kc], &bk[0]);
                mma16816h(s[2 * n16 + 1], aq[kc], &bk[2]);
            }
        }

        // ---- causal mask (diagonal block only) ----
        if (kb == nkb - 1) {
            const int kc0 = kb * FBN + 2 * (lane & 3);
#pragma unroll
            for (int j = 0; j < 8; ++j)
#pragma unroll
                for (int e = 0; e < 4; ++e) {
                    int row = qrow0 + (e >> 1) * 8;
                    int col = kc0 + 8 * j + (e & 1);
                    if (col > row) s[j][e] = -1e30f;
                }
        }

        // ---- row max + alpha (log2 domain) ----
        float alpha[2], mx2[2];
#pragma unroll
        for (int rr = 0; rr < 2; ++rr) {
            float mx = m_i[rr];
#pragma unroll
            for (int j = 0; j < 8; ++j)
                mx = fmaxf(mx, fmaxf(s[j][2 * rr], s[j][2 * rr + 1]));
            mx = fmaxf(mx, __shfl_xor_sync(0xffffffff, mx, 1));
            mx = fmaxf(mx, __shfl_xor_sync(0xffffffff, mx, 2));
            alpha[rr] = exp2f(m_i[rr] - mx);
            m_i[rr] = mx;
            mx2[rr] = mx;
        }
#pragma unroll
        for (int nf = 0; nf < 16; ++nf) {
            o[nf][0] *= alpha[0]; o[nf][1] *= alpha[0];
            o[nf][2] *= alpha[1]; o[nf][3] *= alpha[1];
        }
        float lsum[2] = {0.f, 0.f};

        // ---- per-chunk: exp2 + fp16 pack + single-term PV mma ----
#pragma unroll
        for (int kc2 = 0; kc2 < 4; ++kc2) {
            const int j0 = 2 * kc2, j1 = 2 * kc2 + 1;
            float p[8];
            p[0] = exp2f(s[j0][0] - mx2[0]);
            p[1] = exp2f(s[j0][1] - mx2[0]);
            p[2] = exp2f(s[j0][2] - mx2[1]);
            p[3] = exp2f(s[j0][3] - mx2[1]);
            p[4] = exp2f(s[j1][0] - mx2[0]);
            p[5] = exp2f(s[j1][1] - mx2[0]);
            p[6] = exp2f(s[j1][2] - mx2[1]);
            p[7] = exp2f(s[j1][3] - mx2[1]);
            lsum[0] += (p[0] + p[1]) + (p[4] + p[5]);
            lsum[1] += (p[2] + p[3]) + (p[6] + p[7]);

            uint32_t ap[4];
            ap[0] = pack_h16(p[0], p[1]);
            ap[1] = pack_h16(p[2], p[3]);
            ap[2] = pack_h16(p[4], p[5]);
            ap[3] = pack_h16(p[6], p[7]);

            const uint32_t vrow = voff + kc2 * 16 * (LDQ * 2);
#pragma unroll
            for (int nf16 = 0; nf16 < 8; ++nf16) {
                uint32_t bv[4];
                ldsm_x4_t(bv, sV + vrow + nf16 * 32);
                mma16816h(o[2 * nf16],     ap, &bv[0]);
                mma16816h(o[2 * nf16 + 1], ap, &bv[2]);
            }
        }
        l_i[0] = l_i[0] * alpha[0] + lsum[0];
        l_i[1] = l_i[1] * alpha[1] + lsum[1];

        // ---- prefetch kb+2 into this slot (after everyone is done) ----
        if (kb + 2 < nkb) {
            __syncthreads();
            fatt_load_kv(sSt + (uint32_t)slot * STAGEB, tid, kp, vp, kb + 2);
        }
    }

    // ---- epilogue: normalize, write fp16 y ----
#pragma unroll
    for (int rr = 0; rr < 2; ++rr) {
        float lf = l_i[rr];
        lf += __shfl_xor_sync(0xffffffff, lf, 1);
        lf += __shfl_xor_sync(0xffffffff, lf, 2);
        float inv = 1.0f / lf;
        int trow = qrow0 + rr * 8;
        size_t rbase = ((size_t)(b * TT + trow)) * DD + h * HD + 2 * (lane & 3);
#pragma unroll
        for (int nf = 0; nf < 16; ++nf) {
            float v0 = o[nf][2 * rr] * inv;
            float v1 = o[nf][2 * rr + 1] * inv;
            *(uint32_t*)&Yh[rbase + nf * 8] = pack_h16(v0, v1);
        }
    }
}

// ---------------------------- launch ---------------------------------------
static inline void launch_cvt16(const float* src, __half* dst, size_t n)
{
    int n4 = (int)(n / 4);
    cvt16_kernel<<<(n4 + 255) / 256, 256>>>((const float4*)src, (uint2*)dst, n4);
}

extern "C" void kernel_launch(void* const* d_in, const int* in_sizes, int n_in,
                              void* d_out, int out_size)
{
    const float* x   = (const float*)d_in[0];
    const float* Wq  = (const float*)d_in[1];
    const float* Wk  = (const float*)d_in[2];
    const float* Wv  = (const float*)d_in[3];
    const float* Wp  = (const float*)d_in[4];
    const float* qg  = (const float*)d_in[5];
    float* out = (float*)d_out;

    __half *xh, *wch, *wph, *yh, *qh, *kh, *vh;
    cudaGetSymbolAddress((void**)&xh,  g_xh);
    cudaGetSymbolAddress((void**)&wch, g_wch);
    cudaGetSymbolAddress((void**)&wph, g_wph);
    cudaGetSymbolAddress((void**)&yh,  g_yh);
    cudaGetSymbolAddress((void**)&qh,  g_qh);
    cudaGetSymbolAddress((void**)&kh,  g_kh);
    cudaGetSymbolAddress((void**)&vh,  g_vh);

    cudaFuncSetAttribute(gemm_mma_kernel<0>,
                         cudaFuncAttributeMaxDynamicSharedMemorySize, GEMM_SMEM);
    cudaFuncSetAttribute(gemm_mma_kernel<1>,
                         cudaFuncAttributeMaxDynamicSharedMemorySize, GEMM_SMEM);
    cudaFuncSetAttribute(fattn_kernel,
                         cudaFuncAttributeMaxDynamicSharedMemorySize, FATT_SMEM);

    // Pre-scale Q by log2(e) so flash-attention softmax runs in exp2 domain.
    const float qscale = LOG2E / sqrtf((float)HD);

    // conversions: one thread per float4 (max MLP), x + all weights
    launch_cvt16(x, xh, (size_t)NTOK * KTOT);
    wcvt_kernel<<<(WTOT4 + 255) / 256, 256>>>(
        (const float4*)Wq, (const float4*)Wk, (const float4*)Wv,
        (const float4*)Wp, (uint2*)wch, (uint2*)wph);

    // fused QKV projection + RMSNorm/RoPE epilogue (Q/K/V plain fp16)
    gemm_mma_kernel<1><<<dim3(QKVN / GBN, NTOK / GBM), 256, GEMM_SMEM>>>(
        xh, wch, nullptr, QKVN,
        qh, kh, vh, qg, qscale);

    // tensor-core causal flash attention -> y fp16 (2 CTAs/SM)
    fattn_kernel<<<dim3(TT / FBM, HN, BB), 128, FATT_SMEM>>>(
        qh, kh, vh, yh);

    // output projection (fp32 out)
    gemm_mma_kernel<0><<<dim3(DD / GBN, NTOK / GBM), 256, GEMM_SMEM>>>(
        yh, wph, out, DD,
        nullptr, nullptr, nullptr, nullptr, 0.f);
}

// round 17
// speedup vs baseline: 9.7504x; 1.0394x over previous
#include <cuda_runtime.h>
#include <cuda_fp16.h>
#include <cstdint>
#include <math.h>

// Problem constants
#define HN   16          // num_heads
#define KVH  4           // num_kv_heads
#define HD   128         // head_dim
#define BB   4           // batch
#define TT   2048        // seq len
#define DD   (HN*HD)     // 2048
#define KVD  (KVH*HD)    // 512
#define NTOK (BB*TT)     // 8192
#define KTOT DD          // inner dim of all GEMMs = 2048
#define QKVN (DD + 2*KVD)  // 3072 fused projection width
#define RMS_EPS 1.1920928955078125e-07f
#define LOG2E 1.4426950408889634f

// ---------------- scratch (device globals: allocation-free) ----------------
__device__ __half g_xh [(size_t)NTOK * KTOT];
__device__ __half g_wch[(size_t)QKVN * KTOT];   // Wq|Wk|Wv plain fp16
__device__ __half g_wph[(size_t)DD * KTOT];     // Wproj plain fp16
__device__ __half g_yh [(size_t)NTOK * KTOT];

// plain fp16 Q/K/V for attention
__device__ __half g_qh[(size_t)BB * HN  * TT * HD];
__device__ __half g_kh[(size_t)BB * KVH * TT * HD];
__device__ __half g_vh[(size_t)BB * KVH * TT * HD];

// ======================= PTX helpers (baseline compute_103) ================
__device__ __forceinline__ uint32_t smem_u32(const void* p) {
    uint32_t a;
    asm("{ .reg .u64 t; cvta.to.shared.u64 t, %1; cvt.u32.u64 %0, t; }"
        : "=r"(a) : "l"(p));
    return a;
}
__device__ __forceinline__ void cp16(uint32_t dst, const void* src) {
    asm volatile("cp.async.cg.shared.global [%0], [%1], 16;" :: "r"(dst), "l"(src));
}
#define CP_COMMIT() asm volatile("cp.async.commit_group;" ::: "memory")
#define CP_WAIT2()  asm volatile("cp.async.wait_group 2;" ::: "memory")
#define CP_WAIT1()  asm volatile("cp.async.wait_group 1;" ::: "memory")
#define CP_WAIT0()  asm volatile("cp.async.wait_group 0;" ::: "memory")

__device__ __forceinline__ void ldsm_x4(uint32_t* r, uint32_t addr) {
    asm volatile("ldmatrix.sync.aligned.m8n8.x4.shared.b16 {%0,%1,%2,%3}, [%4];"
                 : "=r"(r[0]), "=r"(r[1]), "=r"(r[2]), "=r"(r[3]) : "r"(addr));
}
__device__ __forceinline__ void ldsm_x4_t(uint32_t* r, uint32_t addr) {
    asm volatile("ldmatrix.sync.aligned.m8n8.x4.trans.shared.b16 {%0,%1,%2,%3}, [%4];"
                 : "=r"(r[0]), "=r"(r[1]), "=r"(r[2]), "=r"(r[3]) : "r"(addr));
}
__device__ __forceinline__ void mma16816h(float* c, const uint32_t* a, const uint32_t* b) {
    asm volatile(
        "mma.sync.aligned.m16n8k16.row.col.f32.f16.f16.f32 "
        "{%0,%1,%2,%3}, {%4,%5,%6,%7}, {%8,%9}, {%0,%1,%2,%3};"
        : "+f"(c[0]), "+f"(c[1]), "+f"(c[2]), "+f"(c[3])
        : "r"(a[0]), "r"(a[1]), "r"(a[2]), "r"(a[3]), "r"(b[0]), "r"(b[1]));
}
__device__ __forceinline__ uint32_t pack_h16(float x, float y) {
    __half2 t = __floats2half2_rn(x, y);
    return *(uint32_t*)&t;
}

// ============ fp32 -> fp16 conversion (one thread per float4) ==============
__global__ void __launch_bounds__(256) cvt16_kernel(
    const float4* __restrict__ in, uint2* __restrict__ out, int n4)
{
    int i = blockIdx.x * blockDim.x + threadIdx.x;
    if (i >= n4) return;
    float4 w = in[i];
    uint2 v;
    v.x = pack_h16(w.x, w.y);
    v.y = pack_h16(w.z, w.w);
    out[i] = v;
}

// ===== all four weight tensors -> fp16, one thread per float4 ==============
#define SQ4 ((DD  * KTOT) / 4)
#define SK4 ((KVD * KTOT) / 4)
#define WTOT4 (SQ4 + 2 * SK4 + SQ4)
__global__ void __launch_bounds__(256) wcvt_kernel(
    const float4* __restrict__ wq, const float4* __restrict__ wk,
    const float4* __restrict__ wv, const float4* __restrict__ wp,
    uint2* __restrict__ wch, uint2* __restrict__ wph)
{
    int i = blockIdx.x * blockDim.x + threadIdx.x;
    if (i >= WTOT4) return;
    const float4* src;
    uint2* dst;
    int idx = i;
    if (idx < SQ4)                   { src = wq; dst = wch; }
    else if ((idx -= SQ4) < SK4)     { src = wk; dst = wch + SQ4; }
    else if ((idx -= SK4) < SK4)     { src = wv; dst = wch + SQ4 + SK4; }
    else { idx -= SK4;                 src = wp; dst = wph; }
    float4 w = src[idx];
    uint2 v;
    v.x = pack_h16(w.x, w.y);
    v.y = pack_h16(w.z, w.w);
    dst[idx] = v;
}

// ==== plain fp16 GEMM: C[M,N] = A[M,K] * B[N,K]^T (fp32 accum/out) =========
// GBK=64, 3-slot cp.async pipeline, one barrier per K-step (32 steps).
#define GBM 128
#define GBN 128
#define GBK 64
#define GNK (KTOT / GBK)       // 32
#define LDA 72                 // 64 + 8 pad (144B rows, ldsm conflict-free)
#define TILE_EL (GBM * LDA)    // 9216 elements
#define TILE_B  (TILE_EL * 2)  // 18432 bytes
#define STAGE_B (2 * TILE_B)   // 36864 bytes (A, B)
#define NST 3
#define LDC 132                // epilogue fp32 tile stride
#define GEMM_SMEM (NST * STAGE_B)   // 110592 (>= epilogue 67840)

__device__ __forceinline__ void gemm_load_stage(
    uint32_t sb, int tid, int k0, const __half* gA, const __half* gB)
{
#pragma unroll
    for (int i = 0; i < 4; ++i) {
        int ch = tid + i * 256;            // 0..1023
        int r = ch >> 3, sg = ch & 7;      // row 0..127, seg 0..7 (16B)
        uint32_t so = (uint32_t)((r * LDA + sg * 8) * 2);
        size_t go = (size_t)r * KTOT + k0 + sg * 8;
        cp16(sb + so, gA + go);
        cp16(sb + TILE_B + so, gB + go);
    }
    CP_COMMIT();
}

template<int MODE>
__global__ void __launch_bounds__(256, 2) gemm_mma_kernel(
    const __half* __restrict__ A, const __half* __restrict__ B,
    float* __restrict__ C, int N,
    __half* __restrict__ qh, __half* __restrict__ kh, __half* __restrict__ vh,
    const float* __restrict__ qg, float qscale)
{
    extern __shared__ __half smem[];
    const uint32_t sbase = smem_u32(smem);
    const int tid = threadIdx.x;
    const int lane = tid & 31, wid = tid >> 5;
    const int wm = wid >> 2, wn = wid & 3;
    const int m0 = blockIdx.y * GBM;
    const int n0 = blockIdx.x * GBN;

    const __half* gA = A + (size_t)m0 * KTOT;
    const __half* gB = B + (size_t)n0 * KTOT;

    float acc[4][4][4];
#pragma unroll
    for (int mi = 0; mi < 4; ++mi)
#pragma unroll
        for (int nj = 0; nj < 4; ++nj)
#pragma unroll
            for (int e = 0; e < 4; ++e) acc[mi][nj][e] = 0.f;

    const int arow = wm * 64 + (lane & 15);
    const uint32_t aoffbase = (uint32_t)(arow * LDA * 2) + ((lane >> 4) << 4);
    const int g = lane >> 3;
    const int brow = wn * 32 + (lane & 7) + ((g >> 1) << 3);
    const uint32_t boffbase = (uint32_t)(brow * LDA * 2) + ((g & 1) << 4);

    gemm_load_stage(sbase, tid, 0, gA, gB);
    gemm_load_stage(sbase + STAGE_B, tid, GBK, gA, gB);

    for (int kt = 0; kt < GNK; ++kt) {
        const int slot = kt % NST;
        if (kt + 1 < GNK) { CP_WAIT1(); } else { CP_WAIT0(); }
        __syncthreads();
        if (kt + 2 < GNK)
            gemm_load_stage(sbase + (uint32_t)((kt + 2) % NST) * STAGE_B,
                            tid, (kt + 2) * GBK, gA, gB);

        const uint32_t st = sbase + (uint32_t)slot * STAGE_B;
        const uint32_t sA = st;
        const uint32_t sB = st + TILE_B;

#pragma unroll
        for (int kk = 0; kk < GBK; kk += 16) {
            const uint32_t akk = aoffbase + kk * 2;
            const uint32_t bkk = boffbase + kk * 2;
            uint32_t bfr[4][2];
#pragma unroll
            for (int nt = 0; nt < 2; ++nt) {
                uint32_t r[4];
                ldsm_x4(r, sB + bkk + nt * 16 * LDA * 2);
                bfr[2 * nt][0] = r[0]; bfr[2 * nt][1] = r[1];
                bfr[2 * nt + 1][0] = r[2]; bfr[2 * nt + 1][1] = r[3];
            }
#pragma unroll
            for (int mi = 0; mi < 4; ++mi) {
                uint32_t a[4];
                ldsm_x4(a, sA + akk + mi * 16 * LDA * 2);
#pragma unroll
                for (int nj = 0; nj < 4; ++nj)
                    mma16816h(acc[mi][nj], a, bfr[nj]);
            }
        }
    }

    if (MODE == 0) {
#pragma unroll
        for (int mi = 0; mi < 4; ++mi) {
            int r0 = m0 + wm * 64 + mi * 16 + (lane >> 2);
#pragma unroll
            for (int nj = 0; nj < 4; ++nj) {
                int c = n0 + wn * 32 + nj * 8 + ((lane & 3) << 1);
                *(float2*)&C[(size_t)r0 * N + c]       = make_float2(acc[mi][nj][0], acc[mi][nj][1]);
                *(float2*)&C[(size_t)(r0 + 8) * N + c] = make_float2(acc[mi][nj][2], acc[mi][nj][3]);
            }
        }
        return;
    }

    // ================= fused QKV epilogue (MODE 1) ==========================
    float* stile = (float*)smem;               // 128 x LDC fp32 tile
    float* sinv  = stile + 128 * LDC;          // 64-entry inv_freq table
    __syncthreads();                           // mainloop smem fully consumed

#pragma unroll
    for (int mi = 0; mi < 4; ++mi) {
        int r = wm * 64 + mi * 16 + (lane >> 2);
#pragma unroll
        for (int nj = 0; nj < 4; ++nj) {
            int c = wn * 32 + nj * 8 + ((lane & 3) << 1);
            stile[r * LDC + c]           = acc[mi][nj][0];
            stile[r * LDC + c + 1]       = acc[mi][nj][1];
            stile[(r + 8) * LDC + c]     = acc[mi][nj][2];
            stile[(r + 8) * LDC + c + 1] = acc[mi][nj][3];
        }
    }

    const bool isV = (n0 >= DD + KVD);
    const bool isK = (n0 >= DD) && !isV;
    if (!isV && tid < 64)
        sinv[tid] = 1.0f / powf(10000.0f, (float)tid * (1.0f / 64.0f));
    __syncthreads();

    if (!isV && tid < 128) {
        const int row = tid;
        const int t = (m0 + row) & (TT - 1);
        float ssq = 0.f;
#pragma unroll 8
        for (int d = 0; d < HD; ++d) {
            float x = stile[row * LDC + d];
            ssq += x * x;
        }
        float rms = rsqrtf(ssq * (1.0f / HD) + RMS_EPS);
        float gn = isK ? 1.0f : (qg[n0 >> 7] * qscale);
#pragma unroll 4
        for (int d = 0; d < 64; ++d) {
            float xa = stile[row * LDC + d] * rms;
            float xb = stile[row * LDC + d + 64] * rms;
            float s_, c_;
            sincosf((float)t * sinv[d], &s_, &c_);
            stile[row * LDC + d]      = (xa * c_ - xb * s_) * gn;
            stile[row * LDC + d + 64] = (xb * c_ + xa * s_) * gn;
        }
    }
    __syncthreads();

    __half* dst;
    int hloc, nh;
    if (isV)      { hloc = (n0 - DD - KVD) >> 7; nh = KVH; dst = vh; }
    else if (isK) { hloc = (n0 - DD) >> 7;       nh = KVH; dst = kh; }
    else          { hloc = n0 >> 7;              nh = HN;  dst = qh; }

#pragma unroll
    for (int p = 0; p < 16; ++p) {
        int row = p * 8 + wid;
        int token = m0 + row;
        int b = token >> 11, t = token & (TT - 1);
        size_t off = (((size_t)b * nh + hloc) * TT + t) * HD + lane * 4;
        float v0 = stile[row * LDC + lane * 4];
        float v1 = stile[row * LDC + lane * 4 + 1];
        float v2 = stile[row * LDC + lane * 4 + 2];
        float v3 = stile[row * LDC + lane * 4 + 3];
        uint2 pv;
        pv.x = pack_h16(v0, v1);
        pv.y = pack_h16(v2, v3);
        *(uint2*)&dst[off] = pv;
    }
}

// ============ tensor-core causal flash attention ===========================
// 4-warp CTA (FBM=64, FBN=64), 2 CTAs/SM, Q fp16 in registers, K/V fp16.
// XOR-swizzled smem (256B rows, chunk ^= row&7) -> 3-stage pipe, ONE barrier
// per iteration. S = Q·K (1-term), PV = P·V (1-term). exp2 domain.
#define FBM 64
#define FBN 64
#define QTILEB (FBM * HD * 2)         // 16384 bytes for Q tile (swizzled)
#define KTILEB (FBN * HD * 2)         // 16384 bytes per K/V tile
#define STAGEB (2 * KTILEB)           // 32768 (K + V)
#define NSTAGE 3
#define FATT_SMEM (NSTAGE * STAGEB + QTILEB)   // 114688

// swizzled byte offset for [row][chunk16] in a 64x128-half tile
__device__ __forceinline__ uint32_t swz(int row, int chunk) {
    return ((uint32_t)row << 8) + (uint32_t)((chunk ^ (row & 7)) << 4);
}

__device__ __forceinline__ void fatt_load_kv(
    uint32_t st, int tid, const __half* kp, const __half* vp, int kb)
{
    const size_t base = (size_t)kb * FBN * HD;
#pragma unroll
    for (int i = 0; i < 8; ++i) {
        int ch = tid + i * 128;            // 0..1023
        int row = ch >> 4, seg = ch & 15;  // row 0..63, chunk 0..15
        uint32_t so = swz(row, seg);
        size_t go = base + (size_t)row * HD + seg * 8;
        cp16(st + so, kp + go);
        cp16(st + KTILEB + so, vp + go);
    }
    CP_COMMIT();
}

__global__ void __launch_bounds__(128, 2) fattn_kernel(
    const __half* __restrict__ Qp,
    const __half* __restrict__ Kp, const __half* __restrict__ Vp,
    __half* __restrict__ Yh)
{
    extern __shared__ char smraw[];
    const uint32_t sSt = smem_u32(smraw);

    const int tid = threadIdx.x;
    const int lane = tid & 31, wid = tid >> 5;          // 4 warps
    const int qb = (int)(gridDim.x - 1 - blockIdx.x);   // heavy first
    const int h  = blockIdx.y;
    const int b  = blockIdx.z;
    const int hk = h / (HN / KVH);
    const int nkb = qb + 1;                             // 64-wide KV blocks

    const __half* qp = Qp + ((((size_t)b * HN + h) * TT) + (size_t)qb * FBM) * HD;
    const __half* kp = Kp + (((size_t)b * KVH + hk) * TT) * HD;
    const __half* vp = Vp + (((size_t)b * KVH + hk) * TT) * HD;

    // --- prologue: Q (one group), then kv0 / kv1
    const uint32_t sQ = sSt + NSTAGE * STAGEB;
#pragma unroll
    for (int i = 0; i < 8; ++i) {
        int ch = tid + i * 128;
        int row = ch >> 4, seg = ch & 15;
        uint32_t so = swz(row, seg);
        size_t go = (size_t)row * HD + seg * 8;
        cp16(sQ + so, qp + go);
    }
    CP_COMMIT();
    fatt_load_kv(sSt, tid, kp, vp, 0);
    if (nkb > 1) fatt_load_kv(sSt + STAGEB, tid, kp, vp, 1);

    // per-lane fragment constants (row&7 == lane&7 in every pattern)
    const int lx = lane & 7;                 // swizzle XOR constant
    const int qrow = wid * 16 + (lane & 15); // Q fragment row
    const int qc0 = lane >> 4;               // Q chunk lsb (0/1)
    const int krb = (lane & 7) + (((lane >> 4) & 1) << 3);  // K frag row base
    const int kc0 = (lane >> 3) & 1;         // K chunk lsb
    const int vrow = lane & 15;              // V frag row base
    const int vc0 = (lane >> 4) & 1;         // V chunk lsb

    // --- Q fragments -> registers (once)
    if (nkb > 1) { CP_WAIT2(); } else { CP_WAIT1(); }
    __syncthreads();
    uint32_t aq[8][4];
#pragma unroll
    for (int kc = 0; kc < 8; ++kc) {
        uint32_t addr = sQ + ((uint32_t)qrow << 8)
                      + (uint32_t)(((((kc << 1) | qc0)) ^ lx) << 4);
        ldsm_x4(aq[kc], addr);
    }

    float o[16][4];
#pragma unroll
    for (int nf = 0; nf < 16; ++nf)
#pragma unroll
        for (int e = 0; e < 4; ++e) o[nf][e] = 0.f;
    float m_i[2] = {-1e30f, -1e30f};   // log2-domain running max
    float l_i[2] = {0.f, 0.f};

    const int qrow0 = qb * FBM + wid * 16 + (lane >> 2);

    for (int kb = 0; kb < nkb; ++kb) {
        const int slot = kb % NSTAGE;
        if (kb + 1 < nkb) { CP_WAIT1(); } else { CP_WAIT0(); }
        __syncthreads();
        // prefetch kb+2 into slot (kb+2)%3 == (kb-1)%3: all warps finished
        // iteration kb-1 before reaching this barrier, so the slot is free.
        if (kb + 2 < nkb)
            fatt_load_kv(sSt + (uint32_t)((kb + 2) % NSTAGE) * STAGEB, tid,
                         kp, vp, kb + 2);

        const uint32_t sK = sSt + (uint32_t)slot * STAGEB;
        const uint32_t sV = sK + KTILEB;

        // ---- S = Q K^T (single fp16 term), Q from registers ----
        float s[8][4];
#pragma unroll
        for (int j = 0; j < 8; ++j)
#pragma unroll
            for (int e = 0; e < 4; ++e) s[j][e] = 0.f;

#pragma unroll
        for (int kc = 0; kc < 8; ++kc) {
            const uint32_t kch = (uint32_t)(((((kc << 1) | kc0)) ^ lx) << 4);
#pragma unroll
            for (int n16 = 0; n16 < 4; ++n16) {
                uint32_t bk[4];
                uint32_t addr = sK + ((uint32_t)(krb + n16 * 16) << 8) + kch;
                ldsm_x4(bk, addr);
                mma16816h(s[2 * n16],     aq[kc], &bk[0]);
                mma16816h(s[2 * n16 + 1], aq[kc], &bk[2]);
            }
        }

        // ---- causal mask (diagonal block only) ----
        if (kb == nkb - 1) {
            const int kc_base = kb * FBN + 2 * (lane & 3);
#pragma unroll
            for (int j = 0; j < 8; ++j)
#pragma unroll
                for (int e = 0; e < 4; ++e) {
                    int row = qrow0 + (e >> 1) * 8;
                    int col = kc_base + 8 * j + (e & 1);
                    if (col > row) s[j][e] = -1e30f;
                }
        }

        // ---- row max + alpha (log2 domain) ----
        float alpha[2], mx2[2];
#pragma unroll
        for (int rr = 0; rr < 2; ++rr) {
            float mx = m_i[rr];
#pragma unroll
            for (int j = 0; j < 8; ++j)
                mx = fmaxf(mx, fmaxf(s[j][2 * rr], s[j][2 * rr + 1]));
            mx = fmaxf(mx, __shfl_xor_sync(0xffffffff, mx, 1));
            mx = fmaxf(mx, __shfl_xor_sync(0xffffffff, mx, 2));
            alpha[rr] = exp2f(m_i[rr] - mx);
            m_i[rr] = mx;
            mx2[rr] = mx;
        }
#pragma unroll
        for (int nf = 0; nf < 16; ++nf) {
            o[nf][0] *= alpha[0]; o[nf][1] *= alpha[0];
            o[nf][2] *= alpha[1]; o[nf][3] *= alpha[1];
        }
        float lsum[2] = {0.f, 0.f};

        // ---- per-chunk: exp2 + fp16 pack + single-term PV mma ----
#pragma unroll
        for (int kc2 = 0; kc2 < 4; ++kc2) {
            const int j0 = 2 * kc2, j1 = 2 * kc2 + 1;
            float p[8];
            p[0] = exp2f(s[j0][0] - mx2[0]);
            p[1] = exp2f(s[j0][1] - mx2[0]);
            p[2] = exp2f(s[j0][2] - mx2[1]);
            p[3] = exp2f(s[j0][3] - mx2[1]);
            p[4] = exp2f(s[j1][0] - mx2[0]);
            p[5] = exp2f(s[j1][1] - mx2[0]);
            p[6] = exp2f(s[j1][2] - mx2[1]);
            p[7] = exp2f(s[j1][3] - mx2[1]);
            lsum[0] += (p[0] + p[1]) + (p[4] + p[5]);
            lsum[1] += (p[2] + p[3]) + (p[6] + p[7]);

            uint32_t ap[4];
            ap[0] = pack_h16(p[0], p[1]);
            ap[1] = pack_h16(p[2], p[3]);
            ap[2] = pack_h16(p[4], p[5]);
            ap[3] = pack_h16(p[6], p[7]);

            const uint32_t vrbase = (uint32_t)(vrow + kc2 * 16) << 8;
#pragma unroll
            for (int nf16 = 0; nf16 < 8; ++nf16) {
                uint32_t bv[4];
                uint32_t addr = sV + vrbase
                              + (uint32_t)(((((nf16 << 1) | vc0)) ^ lx) << 4);
                ldsm_x4_t(bv, addr);
                mma16816h(o[2 * nf16],     ap, &bv[0]);
                mma16816h(o[2 * nf16 + 1], ap, &bv[2]);
            }
        }
        l_i[0] = l_i[0] * alpha[0] + lsum[0];
        l_i[1] = l_i[1] * alpha[1] + lsum[1];
    }

    // ---- epilogue: normalize, write fp16 y ----
#pragma unroll
    for (int rr = 0; rr < 2; ++rr) {
        float lf = l_i[rr];
        lf += __shfl_xor_sync(0xffffffff, lf, 1);
        lf += __shfl_xor_sync(0xffffffff, lf, 2);
        float inv = 1.0f / lf;
        int trow = qrow0 + rr * 8;
        size_t rbase = ((size_t)(b * TT + trow)) * DD + h * HD + 2 * (lane & 3);
#pragma unroll
        for (int nf = 0; nf < 16; ++nf) {
            float v0 = o[nf][2 * rr] * inv;
            float v1 = o[nf][2 * rr + 1] * inv;
            *(uint32_t*)&Yh[rbase + nf * 8] = pack_h16(v0, v1);
        }
    }
}

// ---------------------------- launch ---------------------------------------
static inline void launch_cvt16(const float* src, __half* dst, size_t n)
{
    int n4 = (int)(n / 4);
    cvt16_kernel<<<(n4 + 255) / 256, 256>>>((const float4*)src, (uint2*)dst, n4);
}

extern "C" void kernel_launch(void* const* d_in, const int* in_sizes, int n_in,
                              void* d_out, int out_size)
{
    const float* x   = (const float*)d_in[0];
    const float* Wq  = (const float*)d_in[1];
    const float* Wk  = (const float*)d_in[2];
    const float* Wv  = (const float*)d_in[3];
    const float* Wp  = (const float*)d_in[4];
    const float* qg  = (const float*)d_in[5];
    float* out = (float*)d_out;

    __half *xh, *wch, *wph, *yh, *qh, *kh, *vh;
    cudaGetSymbolAddress((void**)&xh,  g_xh);
    cudaGetSymbolAddress((void**)&wch, g_wch);
    cudaGetSymbolAddress((void**)&wph, g_wph);
    cudaGetSymbolAddress((void**)&yh,  g_yh);
    cudaGetSymbolAddress((void**)&qh,  g_qh);
    cudaGetSymbolAddress((void**)&kh,  g_kh);
    cudaGetSymbolAddress((void**)&vh,  g_vh);

    cudaFuncSetAttribute(gemm_mma_kernel<0>,
                         cudaFuncAttributeMaxDynamicSharedMemorySize, GEMM_SMEM);
    cudaFuncSetAttribute(gemm_mma_kernel<1>,
                         cudaFuncAttributeMaxDynamicSharedMemorySize, GEMM_SMEM);
    cudaFuncSetAttribute(fattn_kernel,
                         cudaFuncAttributeMaxDynamicSharedMemorySize, FATT_SMEM);

    // Pre-scale Q by log2(e) so flash-attention softmax runs in exp2 domain.
    const float qscale = LOG2E / sqrtf((float)HD);

    // conversions: one thread per float4 (max MLP), x + all weights
    launch_cvt16(x, xh, (size_t)NTOK * KTOT);
    wcvt_kernel<<<(WTOT4 + 255) / 256, 256>>>(
        (const float4*)Wq, (const float4*)Wk, (const float4*)Wv,
        (const float4*)Wp, (uint2*)wch, (uint2*)wph);

    // fused QKV projection + RMSNorm/RoPE epilogue (Q/K/V plain fp16)
    gemm_mma_kernel<1><<<dim3(QKVN / GBN, NTOK / GBM), 256, GEMM_SMEM>>>(
        xh, wch, nullptr, QKVN,
        qh, kh, vh, qg, qscale);

    // tensor-core causal flash attention -> y fp16 (2 CTAs/SM, 3-stage swz)
    fattn_kernel<<<dim3(TT / FBM, HN, BB), 128, FATT_SMEM>>>(
        qh, kh, vh, yh);

    // output projection (fp32 out)
    gemm_mma_kernel<0><<<dim3(DD / GBN, NTOK / GBM), 256, GEMM_SMEM>>>(
        yh, wph, out, DD,
        nullptr, nullptr, nullptr, nullptr, 0.f);
}